// round 7
// baseline (speedup 1.0000x reference)
#include <cuda_runtime.h>
#include <cuda_bf16.h>
#include <math.h>
#include <stdint.h>

#define NN   2048
#define DD   512
#define HH   8
#define DPEC 16
#define WALKC 8
#define LLC  3
#define EEC  32768
#define DFFC 2048
#define MAXD 256

// ============================ PTX helpers (sm_80-baseline ISA only) ============================
__device__ __forceinline__ uint32_t smem_to_u32(const void* p) {
    uint32_t a;
    asm("{ .reg .u64 t; cvta.to.shared.u64 t, %1; cvt.u32.u64 %0, t; }" : "=r"(a) : "l"(p));
    return a;
}
#define CP_ASYNC16(dst, src) \
    asm volatile("cp.async.cg.shared.global [%0], [%1], 16;" :: "r"(dst), "l"(src))
#define CP_COMMIT() asm volatile("cp.async.commit_group;" ::: "memory")
#define CP_WAIT2()  asm volatile("cp.async.wait_group 2;" ::: "memory")
#define CP_WAIT1()  asm volatile("cp.async.wait_group 1;" ::: "memory")
#define CP_WAIT0()  asm volatile("cp.async.wait_group 0;" ::: "memory")

__device__ __forceinline__ void ldsm4(uint32_t* r, uint32_t addr) {
    asm volatile("ldmatrix.sync.aligned.m8n8.x4.shared.b16 {%0,%1,%2,%3}, [%4];"
        : "=r"(r[0]), "=r"(r[1]), "=r"(r[2]), "=r"(r[3]) : "r"(addr));
}
__device__ __forceinline__ void ldsm4t(uint32_t* r, uint32_t addr) {
    asm volatile("ldmatrix.sync.aligned.m8n8.x4.trans.shared.b16 {%0,%1,%2,%3}, [%4];"
        : "=r"(r[0]), "=r"(r[1]), "=r"(r[2]), "=r"(r[3]) : "r"(addr));
}
__device__ __forceinline__ void mma16816(float* c, const uint32_t* a, const uint32_t* b) {
    asm volatile("mma.sync.aligned.m16n8k16.row.col.f32.bf16.bf16.f32 "
        "{%0,%1,%2,%3}, {%4,%5,%6,%7}, {%8,%9}, {%0,%1,%2,%3};"
        : "+f"(c[0]), "+f"(c[1]), "+f"(c[2]), "+f"(c[3])
        : "r"(a[0]), "r"(a[1]), "r"(a[2]), "r"(a[3]), "r"(b[0]), "r"(b[1]));
}

// 128-byte-row swizzle (attention tiles)
#define ASM_OFF(row, ch) ((uint32_t)((row) * 128 + ((((ch)) ^ ((row) & 7)) << 4)))
// 64-byte-row swizzle (BK=32 GEMM tiles): 8 bank-groups covered per 8 rows
#define ASM32_OFF(row, ch) ((uint32_t)((row) * 64 + ((((ch) ^ (((row) >> 1) & 3))) << 4)))

// ============================ static device scratch ============================
__device__ uint32_t g_bm[NN*64];
__device__ float g_deg[NN];
__device__ float g_invdeg[NN];
__device__ int   g_nbr[NN*MAXD];
__device__ int   g_cnt[NN];
__device__ __nv_bfloat16 g_T2b[NN*NN];
__device__ __nv_bfloat16 g_T3b[NN*NN];
__device__ __nv_bfloat16 g_T4b[NN*NN];
__device__ float g_rw [NN*WALKC];
__device__ float g_pe [NN*DPEC];
__device__ float g_pep[LLC*NN*HH];
__device__ float g_x   [NN*DD];
__device__ float g_x1  [NN*DD];
__device__ float g_o   [NN*DD];
__device__ __nv_bfloat16 g_Ahi[NN*DD];
__device__ __nv_bfloat16 g_Alo[NN*DD];
__device__ __nv_bfloat16 g_Hhi[NN*DFFC];
__device__ __nv_bfloat16 g_Hlo[NN*DFFC];
__device__ __nv_bfloat16 g_QKVhi[NN*3*DD];
__device__ __nv_bfloat16 g_QKVlo[NN*3*DD];
__device__ __nv_bfloat16 g_qkvW_hi[LLC*3*DD*DD];
__device__ __nv_bfloat16 g_qkvW_lo[LLC*3*DD*DD];
__device__ __nv_bfloat16 g_outW_hi[LLC*DD*DD];
__device__ __nv_bfloat16 g_outW_lo[LLC*DD*DD];
__device__ __nv_bfloat16 g_f1W_hi[LLC*DD*DFFC];
__device__ __nv_bfloat16 g_f1W_lo[LLC*DD*DFFC];
__device__ __nv_bfloat16 g_f2W_hi[LLC*DFFC*DD];
__device__ __nv_bfloat16 g_f2W_lo[LLC*DFFC*DD];
__device__ float g_part [4*HH*NN*64];
__device__ float g_plsum[4*HH*NN];

// ============================ PE pipeline (sparse) ============================
__global__ void zero_bm_kernel() {
    int idx = blockIdx.x * blockDim.x + threadIdx.x;
    if (idx < NN * 64) g_bm[idx] = 0u;
}
__global__ void scatter_bm_kernel(const int* __restrict__ ei) {
    int e = blockIdx.x * blockDim.x + threadIdx.x;
    if (e < EEC) {
        int s = ei[e], t = ei[EEC + e];
        atomicOr(&g_bm[s * 64 + (t >> 5)], 1u << (t & 31));
        atomicOr(&g_bm[t * 64 + (s >> 5)], 1u << (s & 31));
    }
}
__global__ void build_bm_kernel() {
    __shared__ int cnt;
    int i = blockIdx.x, t = threadIdx.x;
    if (t == 0) cnt = 0;
    __syncthreads();
    uint32_t w = g_bm[i * 64 + t];
    int c = __popc(w);
    int pos = (c > 0) ? atomicAdd(&cnt, c) : 0;
    while (w) {
        int b = __ffs(w) - 1;
        w &= w - 1;
        if (pos < MAXD) g_nbr[i * MAXD + pos] = t * 32 + b;
        pos++;
    }
    __syncthreads();
    if (t == 0) {
        int cc = cnt < MAXD ? cnt : MAXD;
        g_cnt[i] = cc;
        float d = cnt < 1 ? 1.f : (float)cnt;
        g_deg[i] = d;
        g_invdeg[i] = 1.f / d;
    }
}
__global__ void __launch_bounds__(256) t2_kernel() {
    __shared__ float rowbuf[NN];
    int i = blockIdx.x, t = threadIdx.x;
    #pragma unroll
    for (int u = 0; u < NN / 256; u++) rowbuf[t + u * 256] = 0.f;
    __syncthreads();
    int cnt = g_cnt[i];
    float inv_i = g_invdeg[i];
    for (int c = t >> 3; c < cnt; c += 32) {
        int j = g_nbr[i * MAXD + c];
        float w = inv_i * g_invdeg[j];
        int cj = g_cnt[j];
        const int* nbj = g_nbr + j * MAXD;
        for (int k = t & 7; k < cj; k += 8) atomicAdd(&rowbuf[nbj[k]], w);
    }
    __syncthreads();
    __nv_bfloat16* out = g_T2b + (size_t)i * NN;
    #pragma unroll
    for (int u = 0; u < NN / 256; u++) {
        int idx = t + u * 256;
        out[idx] = __float2bfloat16_rn(rowbuf[idx]);
    }
}
__global__ void __launch_bounds__(256) spmm_bf_kernel(const __nv_bfloat16* __restrict__ IN,
                                                      __nv_bfloat16* __restrict__ OUT) {
    int i = blockIdx.x, t = threadIdx.x;
    int cnt = g_cnt[i];
    float inv = g_invdeg[i];
    const int* nb = g_nbr + i * MAXD;
    float2 acc[4];
    #pragma unroll
    for (int u = 0; u < 4; u++) acc[u] = make_float2(0.f, 0.f);
    for (int c = 0; c < cnt; c++) {
        const __nv_bfloat162* row = reinterpret_cast<const __nv_bfloat162*>(IN + (size_t)nb[c] * NN);
        #pragma unroll
        for (int u = 0; u < 4; u++) {
            float2 v = __bfloat1622float2(row[t + u * 256]);
            acc[u].x += v.x; acc[u].y += v.y;
        }
    }
    __nv_bfloat162* out = reinterpret_cast<__nv_bfloat162*>(OUT + (size_t)i * NN);
    #pragma unroll
    for (int u = 0; u < 4; u++)
        out[t + u * 256] = __floats2bfloat162_rn(acc[u].x * inv, acc[u].y * inv);
}
__global__ void diag2_kernel() {
    __shared__ float sh[256];
    __shared__ float res[7];
    int i = blockIdx.x, t = threadIdx.x;
    float inv_i = g_invdeg[i], d_i = g_deg[i];
    int cnt = g_cnt[i];
    const __nv_bfloat16* r2 = g_T2b + (size_t)i * NN;
    const __nv_bfloat16* r3 = g_T3b + (size_t)i * NN;
    const __nv_bfloat16* r4 = g_T4b + (size_t)i * NN;
    float s[7] = {};
    for (int c = t; c < cnt; c += 256) {
        int j = g_nbr[i * MAXD + c];
        float wj = g_invdeg[j];
        s[0] += wj;
        s[1] += __bfloat162float(r2[j]) * wj;
    }
    for (int j = t; j < NN; j += 256) {
        float w = g_invdeg[j];
        float t2 = __bfloat162float(r2[j]);
        float t3 = __bfloat162float(r3[j]);
        float t4 = __bfloat162float(r4[j]);
        s[2] += t2 * t2 * w;
        s[3] += t3 * t2 * w;
        s[4] += t3 * t3 * w;
        s[5] += t4 * t3 * w;
        s[6] += t4 * t4 * w;
    }
    for (int v = 0; v < 7; v++) {
        sh[t] = s[v]; __syncthreads();
        for (int k = 128; k > 0; k >>= 1) { if (t < k) sh[t] += sh[t + k]; __syncthreads(); }
        if (t == 0) res[v] = sh[0];
        __syncthreads();
    }
    if (t == 0) {
        bool self = (g_bm[i * 64 + (i >> 5)] >> (i & 31)) & 1u;
        g_rw[i * WALKC + 0] = self ? inv_i : 0.f;
        g_rw[i * WALKC + 1] = inv_i * res[0];
        g_rw[i * WALKC + 2] = res[1];
        g_rw[i * WALKC + 3] = d_i * res[2];
        g_rw[i * WALKC + 4] = d_i * res[3];
        g_rw[i * WALKC + 5] = d_i * res[4];
        g_rw[i * WALKC + 6] = d_i * res[5];
        g_rw[i * WALKC + 7] = d_i * res[6];
    }
}
__global__ void pe_kernel(const float* __restrict__ W, const float* __restrict__ b) {
    int i = blockIdx.x * blockDim.x + threadIdx.x;
    if (i >= NN) return;
    float r[WALKC];
    #pragma unroll
    for (int w = 0; w < WALKC; w++) r[w] = g_rw[i * WALKC + w];
    #pragma unroll
    for (int d = 0; d < DPEC; d++) {
        float s = b[d];
        #pragma unroll
        for (int w = 0; w < WALKC; w++) s += r[w] * W[w * DPEC + d];
        g_pe[i * DPEC + d] = s;
    }
}
__global__ void pep_kernel(const float* __restrict__ W, const float* __restrict__ b) {
    int i = blockIdx.x * blockDim.x + threadIdx.x;
    if (i >= NN) return;
    float p[DPEC];
    #pragma unroll
    for (int d = 0; d < DPEC; d++) p[d] = g_pe[i * DPEC + d];
    for (int l = 0; l < LLC; l++) {
        #pragma unroll
        for (int h = 0; h < HH; h++) {
            float s = b[l * HH + h];
            #pragma unroll
            for (int d = 0; d < DPEC; d++) s += p[d] * W[(l * DPEC + d) * HH + h];
            g_pep[(size_t)l * NN * HH + i * HH + h] = s;
        }
    }
}

// ============================ conversions ============================
__global__ void split_copy_kernel(const float* __restrict__ src) {
    int idx = blockIdx.x * blockDim.x + threadIdx.x;
    if (idx < NN * DD) {
        float v = src[idx];
        g_x[idx] = v;
        __nv_bfloat16 h = __float2bfloat16_rn(v);
        g_Ahi[idx] = h;
        g_Alo[idx] = __float2bfloat16_rn(v - __bfloat162float(h));
    }
}
__global__ void convW_kernel(const float* __restrict__ W, __nv_bfloat16* __restrict__ hi,
                             __nv_bfloat16* __restrict__ lo, int K, int N) {
    __shared__ float tile[32][33];
    size_t lw = (size_t)blockIdx.z * K * N;
    int n0 = blockIdx.x * 32, k0 = blockIdx.y * 32;
    int tx = threadIdx.x, ty = threadIdx.y;
    #pragma unroll
    for (int r = 0; r < 4; r++)
        tile[ty + r * 8][tx] = W[lw + (size_t)(k0 + ty + r * 8) * N + n0 + tx];
    __syncthreads();
    #pragma unroll
    for (int r = 0; r < 4; r++) {
        int ni = ty + r * 8;
        float v = tile[tx][ni];
        __nv_bfloat16 h = __float2bfloat16_rn(v);
        size_t o = lw + (size_t)(n0 + ni) * K + k0 + tx;
        hi[o] = h;
        lo[o] = __float2bfloat16_rn(v - __bfloat162float(h));
    }
}

// ============================ mma.sync bf16x3 GEMM (BK=32, 3-stage, templated TM) ============================
template<int EPI, int TM>  // EPI: 0 fp32 out; 2 bf16 hi/lo out; 3 GELU + bf16 hi/lo out
__global__ void __launch_bounds__(256) mma_gemm_kernel(
    const __nv_bfloat16* __restrict__ Ahi, const __nv_bfloat16* __restrict__ Alo,
    const __nv_bfloat16* __restrict__ Bhi, const __nv_bfloat16* __restrict__ Blo,
    const float* __restrict__ bias, float* __restrict__ C,
    __nv_bfloat16* __restrict__ Chi, __nv_bfloat16* __restrict__ Clo, int N, int K)
{
    constexpr int MBN    = TM / 64;
    constexpr int ABYTES = TM * 64;                // one A matrix (TM rows x 32 bf16)
    constexpr int STAGE  = 2 * ABYTES + 16384;     // Ah, Al, Bh(8K), Bl(8K)
    extern __shared__ char smem[];
    const int tid  = threadIdx.x;
    const int lane = tid & 31;
    const int wid  = tid >> 5;
    const int m0 = blockIdx.y * TM, n0 = blockIdx.x * 128;
    const int wrow = (wid >> 1) * (16 * MBN);
    const int wcol = (wid & 1) * 64;
    const uint32_t sbase = smem_to_u32(smem);
    const int sub = lane >> 3;

    float acc[MBN][8][4];
    #pragma unroll
    for (int a = 0; a < MBN; a++)
        #pragma unroll
        for (int b = 0; b < 8; b++)
            #pragma unroll
            for (int c = 0; c < 4; c++) acc[a][b][c] = 0.f;

    const int nc = K >> 5;   // BK = 32

    auto loadChunk = [&](int c) {
        uint32_t sb = sbase + (uint32_t)(c % 3) * STAGE;
        int k0 = c << 5;
        #pragma unroll
        for (int t2 = 0; t2 < 2; t2++) {
            const __nv_bfloat16* s = t2 ? Alo : Ahi;
            #pragma unroll
            for (int it = 0; it < TM / 64; it++) {
                int idx = it * 256 + tid;
                int row = idx >> 2, ch = idx & 3;
                CP_ASYNC16(sb + t2 * ABYTES + ASM32_OFF(row, ch),
                           s + (size_t)(m0 + row) * K + k0 + ch * 8);
            }
        }
        #pragma unroll
        for (int t2 = 0; t2 < 2; t2++) {
            const __nv_bfloat16* s = t2 ? Blo : Bhi;
            #pragma unroll
            for (int it = 0; it < 2; it++) {
                int idx = it * 256 + tid;
                int row = idx >> 2, ch = idx & 3;
                CP_ASYNC16(sb + 2 * ABYTES + t2 * 8192 + ASM32_OFF(row, ch),
                           s + (size_t)(n0 + row) * K + k0 + ch * 8);
            }
        }
        CP_COMMIT();
    };

    loadChunk(0); loadChunk(1); loadChunk(2);   // nc >= 3 always here

    for (int c = 0; c < nc; c++) {
        if (c + 3 <= nc) CP_WAIT2();
        else if (c + 2 == nc) CP_WAIT1();
        else CP_WAIT0();
        __syncthreads();
        uint32_t sb = sbase + (uint32_t)(c % 3) * STAGE;
        uint32_t sAh = sb, sAl = sb + ABYTES, sBh = sb + 2 * ABYTES, sBl = sb + 2 * ABYTES + 8192;
        #pragma unroll
        for (int ks = 0; ks < 2; ks++) {
            uint32_t ah[MBN][4], al[MBN][4], bh[4][4], bl[4][4];
            {
                int row16 = (lane & 7) + ((sub & 1) << 3);
                int kc = ks * 2 + (sub >> 1);
                #pragma unroll
                for (int mb = 0; mb < MBN; mb++) {
                    int row = wrow + mb * 16 + row16;
                    uint32_t off = ASM32_OFF(row, kc);
                    ldsm4(ah[mb], sAh + off);
                    ldsm4(al[mb], sAl + off);
                }
            }
            {
                int kc = ks * 2 + (sub & 1);
                int nr = ((sub >> 1) << 3) + (lane & 7);
                #pragma unroll
                for (int j = 0; j < 4; j++) {
                    int row = wcol + j * 16 + nr;
                    uint32_t off = ASM32_OFF(row, kc);
                    ldsm4(bh[j], sBh + off);
                    ldsm4(bl[j], sBl + off);
                }
            }
            #pragma unroll
            for (int mb = 0; mb < MBN; mb++)
                #pragma unroll
                for (int j = 0; j < 4; j++) {
                    mma16816(acc[mb][2*j],     ah[mb], &bh[j][0]);
                    mma16816(acc[mb][2*j],     ah[mb], &bl[j][0]);
                    mma16816(acc[mb][2*j],     al[mb], &bh[j][0]);
                    mma16816(acc[mb][2*j + 1], ah[mb], &bh[j][2]);
                    mma16816(acc[mb][2*j + 1], ah[mb], &bl[j][2]);
                    mma16816(acc[mb][2*j + 1], al[mb], &bh[j][2]);
                }
        }
        __syncthreads();
        if (c + 3 < nc) loadChunk(c + 3);
    }

    const int r_l = lane >> 2;
    const int c_l = (lane & 3) << 1;
    #pragma unroll
    for (int mb = 0; mb < MBN; mb++) {
        #pragma unroll
        for (int nb = 0; nb < 8; nb++) {
            int row = m0 + wrow + mb * 16 + r_l;
            int col = n0 + wcol + nb * 8 + c_l;
            float b0 = bias[col], b1 = bias[col + 1];
            float v0 = acc[mb][nb][0] + b0;
            float v1 = acc[mb][nb][1] + b1;
            float v2 = acc[mb][nb][2] + b0;
            float v3 = acc[mb][nb][3] + b1;
            if (EPI == 3) {
                v0 = 0.5f * v0 * (1.f + erff(v0 * 0.70710678118654752f));
                v1 = 0.5f * v1 * (1.f + erff(v1 * 0.70710678118654752f));
                v2 = 0.5f * v2 * (1.f + erff(v2 * 0.70710678118654752f));
                v3 = 0.5f * v3 * (1.f + erff(v3 * 0.70710678118654752f));
            }
            if (EPI == 0) {
                *reinterpret_cast<float2*>(C + (size_t)row * N + col)       = make_float2(v0, v1);
                *reinterpret_cast<float2*>(C + (size_t)(row + 8) * N + col) = make_float2(v2, v3);
            } else {
                __nv_bfloat162 h01 = __floats2bfloat162_rn(v0, v1);
                __nv_bfloat162 h23 = __floats2bfloat162_rn(v2, v3);
                __nv_bfloat162 l01 = __floats2bfloat162_rn(v0 - __bfloat162float(h01.x),
                                                           v1 - __bfloat162float(h01.y));
                __nv_bfloat162 l23 = __floats2bfloat162_rn(v2 - __bfloat162float(h23.x),
                                                           v3 - __bfloat162float(h23.y));
                *reinterpret_cast<__nv_bfloat162*>(Chi + (size_t)row * N + col)       = h01;
                *reinterpret_cast<__nv_bfloat162*>(Chi + (size_t)(row + 8) * N + col) = h23;
                *reinterpret_cast<__nv_bfloat162*>(Clo + (size_t)row * N + col)       = l01;
                *reinterpret_cast<__nv_bfloat162*>(Clo + (size_t)(row + 8) * N + col) = l23;
            }
        }
    }
}

// ============================ tensor-core attention (double-buffered K/V) ============================
#define AT_QH   0
#define AT_QL   16384
#define AT_KV   32768
#define AT_BIAS 98304
#define AT_SMEM (98304 + 512)

__global__ void __launch_bounds__(128) attn_tc_kernel(
    const __nv_bfloat16* __restrict__ qh, const __nv_bfloat16* __restrict__ ql,
    const float* __restrict__ pep, float* __restrict__ part, float* __restrict__ plsum)
{
    extern __shared__ char sm[];
    const int h = blockIdx.y, sl = blockIdx.z;
    const int q0 = blockIdx.x * 128;
    const int tid = threadIdx.x, lane = tid & 31, wid = tid >> 5;
    const int wrow = wid * 32;
    const int sub = lane >> 3;
    const uint32_t sb = smem_to_u32(sm);
    float* bias = reinterpret_cast<float*>(sm + AT_BIAS);

    #pragma unroll
    for (int it = 0; it < 8; it++) {
        int idx = it * 128 + tid;
        int row = idx >> 3, ch = idx & 7;
        size_t g = (size_t)(q0 + row) * 1536 + h * 64 + ch * 8;
        uint32_t off = ASM_OFF(row, ch);
        CP_ASYNC16(sb + AT_QH + off, qh + g);
        CP_ASYNC16(sb + AT_QL + off, ql + g);
    }
    {
        const int kk = sl * 512;
        uint32_t stb = sb + AT_KV;
        #pragma unroll
        for (int it = 0; it < 4; it++) {
            int idx = it * 128 + tid;
            int row = idx >> 3, ch = idx & 7;
            size_t gk = (size_t)(kk + row) * 1536 + 512 + h * 64 + ch * 8;
            uint32_t off = ASM_OFF(row, ch);
            CP_ASYNC16(stb + off,         qh + gk);
            CP_ASYNC16(stb + 8192 + off,  ql + gk);
            CP_ASYNC16(stb + 16384 + off, qh + gk + 512);
            CP_ASYNC16(stb + 24576 + off, ql + gk + 512);
        }
        if (tid < 64) bias[tid] = pep[(size_t)(kk + tid) * HH + h];
    }
    CP_COMMIT();

    float O[2][8][4];
    float ls[2][2] = {{0.f, 0.f}, {0.f, 0.f}};
    #pragma unroll
    for (int mb = 0; mb < 2; mb++)
        #pragma unroll
        for (int nb = 0; nb < 8; nb++)
            #pragma unroll
            for (int u = 0; u < 4; u++) O[mb][nb][u] = 0.f;

    for (int c = 0; c < 8; c++) {
        CP_WAIT0();
        __syncthreads();
        if (c < 7) {
            const int kn = sl * 512 + (c + 1) * 64;
            uint32_t stb = sb + AT_KV + (uint32_t)((c + 1) & 1) * 32768;
            #pragma unroll
            for (int it = 0; it < 4; it++) {
                int idx = it * 128 + tid;
                int row = idx >> 3, ch = idx & 7;
                size_t gk = (size_t)(kn + row) * 1536 + 512 + h * 64 + ch * 8;
                uint32_t off = ASM_OFF(row, ch);
                CP_ASYNC16(stb + off,         qh + gk);
                CP_ASYNC16(stb + 8192 + off,  ql + gk);
                CP_ASYNC16(stb + 16384 + off, qh + gk + 512);
                CP_ASYNC16(stb + 24576 + off, ql + gk + 512);
            }
            if (tid < 64) bias[((c + 1) & 1) * 64 + tid] = pep[(size_t)(kn + tid) * HH + h];
            CP_COMMIT();
        }
        const uint32_t stc = sb + AT_KV + (uint32_t)(c & 1) * 32768;
        const uint32_t sKH = stc, sKL = stc + 8192, sVH = stc + 16384, sVL = stc + 24576;
        const float* bs = bias + (c & 1) * 64;

        float S[2][8][4];
        #pragma unroll
        for (int mb = 0; mb < 2; mb++)
            #pragma unroll
            for (int nb = 0; nb < 8; nb++)
                #pragma unroll
                for (int u = 0; u < 4; u++) S[mb][nb][u] = 0.f;
        #pragma unroll
        for (int kb = 0; kb < 4; kb++) {
            uint32_t ah[2][4], al[2][4];
            int r16 = (lane & 7) + ((sub & 1) << 3);
            int chA = kb * 2 + (sub >> 1);
            #pragma unroll
            for (int mb = 0; mb < 2; mb++) {
                int row = wrow + mb * 16 + r16;
                uint32_t off = ASM_OFF(row, chA);
                ldsm4(ah[mb], sb + AT_QH + off);
                ldsm4(al[mb], sb + AT_QL + off);
            }
            int chB = kb * 2 + (sub & 1);
            int nr = ((sub >> 1) << 3) + (lane & 7);
            #pragma unroll
            for (int j = 0; j < 4; j++) {
                uint32_t bh[4], bl[4];
                int row = j * 16 + nr;
                uint32_t off = ASM_OFF(row, chB);
                ldsm4(bh, sKH + off);
                ldsm4(bl, sKL + off);
                #pragma unroll
                for (int mb = 0; mb < 2; mb++) {
                    mma16816(S[mb][2*j],   ah[mb], &bh[0]);
                    mma16816(S[mb][2*j],   al[mb], &bh[0]);
                    mma16816(S[mb][2*j],   ah[mb], &bl[0]);
                    mma16816(S[mb][2*j+1], ah[mb], &bh[2]);
                    mma16816(S[mb][2*j+1], al[mb], &bh[2]);
                    mma16816(S[mb][2*j+1], ah[mb], &bl[2]);
                }
            }
        }

        uint32_t Ph[2][8][2], Pl[2][8][2];
        #pragma unroll
        for (int mb = 0; mb < 2; mb++)
            #pragma unroll
            for (int nb = 0; nb < 8; nb++) {
                int col = nb * 8 + ((lane & 3) << 1);
                float b0 = bs[col], b1 = bs[col + 1];
                float p0 = __expf(fmaf(S[mb][nb][0], 0.125f, -b0));
                float p1 = __expf(fmaf(S[mb][nb][1], 0.125f, -b1));
                float p2 = __expf(fmaf(S[mb][nb][2], 0.125f, -b0));
                float p3 = __expf(fmaf(S[mb][nb][3], 0.125f, -b1));
                ls[mb][0] += p0 + p1;
                ls[mb][1] += p2 + p3;
                __nv_bfloat162 h01 = __floats2bfloat162_rn(p0, p1);
                __nv_bfloat162 h23 = __floats2bfloat162_rn(p2, p3);
                __nv_bfloat162 l01 = __floats2bfloat162_rn(p0 - __bfloat162float(h01.x),
                                                           p1 - __bfloat162float(h01.y));
                __nv_bfloat162 l23 = __floats2bfloat162_rn(p2 - __bfloat162float(h23.x),
                                                           p3 - __bfloat162float(h23.y));
                Ph[mb][nb][0] = *reinterpret_cast<uint32_t*>(&h01);
                Ph[mb][nb][1] = *reinterpret_cast<uint32_t*>(&h23);
                Pl[mb][nb][0] = *reinterpret_cast<uint32_t*>(&l01);
                Pl[mb][nb][1] = *reinterpret_cast<uint32_t*>(&l23);
            }

        #pragma unroll
        for (int kb2 = 0; kb2 < 4; kb2++) {
            int krow = kb2 * 16 + ((sub & 1) << 3) + (lane & 7);
            #pragma unroll
            for (int dI = 0; dI < 4; dI++) {
                uint32_t vh[4], vl[4];
                int ch = dI * 2 + (sub >> 1);
                uint32_t off = ASM_OFF(krow, ch);
                ldsm4t(vh, sVH + off);
                ldsm4t(vl, sVL + off);
                #pragma unroll
                for (int mb = 0; mb < 2; mb++) {
                    uint32_t pa[4] = {Ph[mb][2*kb2][0], Ph[mb][2*kb2][1],
                                      Ph[mb][2*kb2+1][0], Ph[mb][2*kb2+1][1]};
                    uint32_t la[4] = {Pl[mb][2*kb2][0], Pl[mb][2*kb2][1],
                                      Pl[mb][2*kb2+1][0], Pl[mb][2*kb2+1][1]};
                    mma16816(O[mb][2*dI],   pa, &vh[0]);
                    mma16816(O[mb][2*dI],   la, &vh[0]);
                    mma16816(O[mb][2*dI],   pa, &vl[0]);
                    mma16816(O[mb][2*dI+1], pa, &vh[2]);
                    mma16816(O[mb][2*dI+1], la, &vh[2]);
                    mma16816(O[mb][2*dI+1], pa, &vl[2]);
                }
            }
        }
    }

    #pragma unroll
    for (int mb = 0; mb < 2; mb++)
        #pragma unroll
        for (int r = 0; r < 2; r++) {
            float v = ls[mb][r];
            v += __shfl_xor_sync(0xffffffffu, v, 1);
            v += __shfl_xor_sync(0xffffffffu, v, 2);
            ls[mb][r] = v;
        }
    const size_t base = (size_t)(sl * HH + h) * NN;
    #pragma unroll
    for (int mb = 0; mb < 2; mb++) {
        int rowA = q0 + wrow + mb * 16 + (lane >> 2);
        int rowB = rowA + 8;
        if ((lane & 3) == 0) {
            plsum[base + rowA] = ls[mb][0];
            plsum[base + rowB] = ls[mb][1];
        }
        #pragma unroll
        for (int nb = 0; nb < 8; nb++) {
            int col = nb * 8 + ((lane & 3) << 1);
            *reinterpret_cast<float2*>(part + (base + rowA) * 64 + col) = make_float2(O[mb][nb][0], O[mb][nb][1]);
            *reinterpret_cast<float2*>(part + (base + rowB) * 64 + col) = make_float2(O[mb][nb][2], O[mb][nb][3]);
        }
    }
}

__global__ void attn_combine_kernel(const float* __restrict__ part, const float* __restrict__ pls,
                                    __nv_bfloat16* __restrict__ ohi, __nv_bfloat16* __restrict__ olo) {
    int i = blockIdx.x, t = threadIdx.x;
    #pragma unroll
    for (int rep = 0; rep < 2; rep++) {
        int idx = t + rep * 256;
        int h = idx >> 6, d = idx & 63;
        float v = 0.f, l = 0.f;
        #pragma unroll
        for (int s = 0; s < 4; s++) {
            l += pls[(size_t)(s * HH + h) * NN + i];
            v += part[((size_t)(s * HH + h) * NN + i) * 64 + d];
        }
        float r = v / l;
        __nv_bfloat16 hb = __float2bfloat16_rn(r);
        ohi[(size_t)i * DD + idx] = hb;
        olo[(size_t)i * DD + idx] = __float2bfloat16_rn(r - __bfloat162float(hb));
    }
}

// ============================ LN (fp32 out + bf16 hi/lo) ============================
__global__ void ln_kernel(const float* __restrict__ a, const float* __restrict__ b,
                          const float* __restrict__ g, const float* __restrict__ be,
                          float* __restrict__ out,
                          __nv_bfloat16* __restrict__ ohi, __nv_bfloat16* __restrict__ olo) {
    __shared__ float sh[256];
    __shared__ float s_mu, s_r;
    int i = blockIdx.x, t = threadIdx.x;
    float v0 = a[(size_t)i * DD + t]       + b[(size_t)i * DD + t];
    float v1 = a[(size_t)i * DD + 256 + t] + b[(size_t)i * DD + 256 + t];
    sh[t] = v0 + v1; __syncthreads();
    for (int k = 128; k > 0; k >>= 1) { if (t < k) sh[t] += sh[t + k]; __syncthreads(); }
    if (t == 0) s_mu = sh[0] * (1.f / DD);
    __syncthreads();
    float mu = s_mu;
    float d0 = v0 - mu, d1 = v1 - mu;
    sh[t] = d0 * d0 + d1 * d1; __syncthreads();
    for (int k = 128; k > 0; k >>= 1) { if (t < k) sh[t] += sh[t + k]; __syncthreads(); }
    if (t == 0) s_r = rsqrtf(sh[0] * (1.f / DD) + 1e-5f);
    __syncthreads();
    float r = s_r;
    float o0 = d0 * r * g[t]       + be[t];
    float o1 = d1 * r * g[256 + t] + be[256 + t];
    out[(size_t)i * DD + t]       = o0;
    out[(size_t)i * DD + 256 + t] = o1;
    __nv_bfloat16 h0 = __float2bfloat16_rn(o0);
    __nv_bfloat16 h1 = __float2bfloat16_rn(o1);
    ohi[(size_t)i * DD + t]       = h0;
    ohi[(size_t)i * DD + 256 + t] = h1;
    olo[(size_t)i * DD + t]       = __float2bfloat16_rn(o0 - __bfloat162float(h0));
    olo[(size_t)i * DD + 256 + t] = __float2bfloat16_rn(o1 - __bfloat162float(h1));
}

// ============================ launch ============================
extern "C" void kernel_launch(void* const* d_in, const int* in_sizes, int n_in,
                              void* d_out, int out_size) {
    const float* node_features = (const float*)d_in[0];
    const int*   edge_index    = (const int*)  d_in[1];
    const float* pe_proj_W     = (const float*)d_in[2];
    const float* pe_proj_b     = (const float*)d_in[3];
    const float* qkv_W         = (const float*)d_in[4];
    const float* qkv_b         = (const float*)d_in[5];
    const float* peb_W         = (const float*)d_in[6];
    const float* peb_b         = (const float*)d_in[7];
    const float* out_W         = (const float*)d_in[8];
    const float* out_b         = (const float*)d_in[9];
    const float* ffn_W1        = (const float*)d_in[10];
    const float* ffn_b1        = (const float*)d_in[11];
    const float* ffn_W2        = (const float*)d_in[12];
    const float* ffn_b2        = (const float*)d_in[13];
    const float* ln1_g         = (const float*)d_in[14];
    const float* ln1_b         = (const float*)d_in[15];
    const float* ln2_g         = (const float*)d_in[16];
    const float* ln2_b         = (const float*)d_in[17];
    float* outp = (float*)d_out;

    float *x_, *x1_, *o_, *pep_, *part_, *pls_;
    __nv_bfloat16 *Ahi_, *Alo_, *Hhi_, *Hlo_, *Qh_, *Ql_, *T2b_, *T3b_, *T4b_;
    __nv_bfloat16 *qWh_, *qWl_, *oWh_, *oWl_, *f1h_, *f1l_, *f2h_, *f2l_;
    cudaGetSymbolAddress((void**)&x_,   g_x);
    cudaGetSymbolAddress((void**)&x1_,  g_x1);
    cudaGetSymbolAddress((void**)&o_,   g_o);
    cudaGetSymbolAddress((void**)&pep_, g_pep);
    cudaGetSymbolAddress((void**)&part_,g_part);
    cudaGetSymbolAddress((void**)&pls_, g_plsum);
    cudaGetSymbolAddress((void**)&Ahi_, g_Ahi);
    cudaGetSymbolAddress((void**)&Alo_, g_Alo);
    cudaGetSymbolAddress((void**)&Hhi_, g_Hhi);
    cudaGetSymbolAddress((void**)&Hlo_, g_Hlo);
    cudaGetSymbolAddress((void**)&Qh_,  g_QKVhi);
    cudaGetSymbolAddress((void**)&Ql_,  g_QKVlo);
    cudaGetSymbolAddress((void**)&T2b_, g_T2b);
    cudaGetSymbolAddress((void**)&T3b_, g_T3b);
    cudaGetSymbolAddress((void**)&T4b_, g_T4b);
    cudaGetSymbolAddress((void**)&qWh_, g_qkvW_hi);
    cudaGetSymbolAddress((void**)&qWl_, g_qkvW_lo);
    cudaGetSymbolAddress((void**)&oWh_, g_outW_hi);
    cudaGetSymbolAddress((void**)&oWl_, g_outW_lo);
    cudaGetSymbolAddress((void**)&f1h_, g_f1W_hi);
    cudaGetSymbolAddress((void**)&f1l_, g_f1W_lo);
    cudaGetSymbolAddress((void**)&f2h_, g_f2W_hi);
    cudaGetSymbolAddress((void**)&f2l_, g_f2W_lo);

    constexpr int GS128 = 3 * (2 * 128 * 64 + 16384);   // 98304 = 96 KB -> 2 CTA/SM
    constexpr int GS64  = 3 * (2 * 64  * 64 + 16384);   // 73728 = 72 KB -> 3 CTA/SM
    cudaFuncSetAttribute(mma_gemm_kernel<2,128>, cudaFuncAttributeMaxDynamicSharedMemorySize, GS128);
    cudaFuncSetAttribute(mma_gemm_kernel<3,128>, cudaFuncAttributeMaxDynamicSharedMemorySize, GS128);
    cudaFuncSetAttribute(mma_gemm_kernel<0,64>,  cudaFuncAttributeMaxDynamicSharedMemorySize, GS64);
    cudaFuncSetAttribute(attn_tc_kernel, cudaFuncAttributeMaxDynamicSharedMemorySize, AT_SMEM);

    static cudaStream_t s_side = nullptr;
    static cudaEvent_t  ev_fork = nullptr, ev_pe = nullptr;
    if (s_side == nullptr) {
        cudaStreamCreateWithFlags(&s_side, cudaStreamNonBlocking);
        cudaEventCreateWithFlags(&ev_fork, cudaEventDisableTiming);
        cudaEventCreateWithFlags(&ev_pe,   cudaEventDisableTiming);
    }

    // ---- fork: PE pipeline on side stream ----
    cudaEventRecord(ev_fork, 0);
    cudaStreamWaitEvent(s_side, ev_fork, 0);
    zero_bm_kernel<<<(NN*64)/256, 256, 0, s_side>>>();
    scatter_bm_kernel<<<EEC/256, 256, 0, s_side>>>(edge_index);
    build_bm_kernel<<<NN, 64, 0, s_side>>>();
    t2_kernel<<<NN, 256, 0, s_side>>>();
    spmm_bf_kernel<<<NN, 256, 0, s_side>>>(T2b_, T3b_);
    spmm_bf_kernel<<<NN, 256, 0, s_side>>>(T3b_, T4b_);
    diag2_kernel<<<NN, 256, 0, s_side>>>();
    pe_kernel<<<(NN + 127) / 128, 128, 0, s_side>>>(pe_proj_W, pe_proj_b);
    pep_kernel<<<(NN + 127) / 128, 128, 0, s_side>>>(peb_W, peb_b);
    cudaEventRecord(ev_pe, s_side);

    // ---- main stream: only qkv prerequisites first, rest of convW after qkv launch ----
    convW_kernel<<<dim3(1536/32, 512/32, LLC),  dim3(32,8)>>>(qkv_W,  qWh_, qWl_, DD,  3*DD);
    split_copy_kernel<<<(NN*DD)/256, 256>>>(node_features);

    for (int l = 0; l < LLC; l++) {
        mma_gemm_kernel<2,128><<<dim3(1536/128, NN/128), 256, GS128>>>(
            Ahi_, Alo_, qWh_ + (size_t)l*3*DD*DD, qWl_ + (size_t)l*3*DD*DD,
            qkv_b + (size_t)l*3*DD, nullptr, Qh_, Ql_, 3*DD, DD);
        if (l == 0) {
            // remaining weight conversions overlap attention's PE-join wait
            convW_kernel<<<dim3(512/32,  512/32, LLC),  dim3(32,8)>>>(out_W,  oWh_, oWl_, DD,  DD);
            convW_kernel<<<dim3(2048/32, 512/32, LLC),  dim3(32,8)>>>(ffn_W1, f1h_, f1l_, DD,  DFFC);
            convW_kernel<<<dim3(512/32,  2048/32, LLC), dim3(32,8)>>>(ffn_W2, f2h_, f2l_, DFFC, DD);
            cudaStreamWaitEvent(0, ev_pe, 0);   // join: attention needs pep
        }
        attn_tc_kernel<<<dim3(NN/128, HH, 4), 128, AT_SMEM>>>(Qh_, Ql_, pep_ + (size_t)l*NN*HH, part_, pls_);
        attn_combine_kernel<<<NN, 256>>>(part_, pls_, Ahi_, Alo_);
        mma_gemm_kernel<0,64><<<dim3(DD/128, NN/64), 256, GS64>>>(
            Ahi_, Alo_, oWh_ + (size_t)l*DD*DD, oWl_ + (size_t)l*DD*DD,
            out_b + (size_t)l*DD, o_, nullptr, nullptr, DD, DD);
        ln_kernel<<<NN, 256>>>(x_, o_, ln1_g + (size_t)l*DD, ln1_b + (size_t)l*DD, x1_, Ahi_, Alo_);
        mma_gemm_kernel<3,128><<<dim3(DFFC/128, NN/128), 256, GS128>>>(
            Ahi_, Alo_, f1h_ + (size_t)l*DD*DFFC, f1l_ + (size_t)l*DD*DFFC,
            ffn_b1 + (size_t)l*DFFC, nullptr, Hhi_, Hlo_, DFFC, DD);
        mma_gemm_kernel<0,64><<<dim3(DD/128, NN/64), 256, GS64>>>(
            Hhi_, Hlo_, f2h_ + (size_t)l*DFFC*DD, f2l_ + (size_t)l*DFFC*DD,
            ffn_b2 + (size_t)l*DD, o_, nullptr, nullptr, DD, DFFC);
        float* xout = (l == LLC - 1) ? outp : x_;
        ln_kernel<<<NN, 256>>>(x1_, o_, ln2_g + (size_t)l*DD, ln2_b + (size_t)l*DD, xout, Ahi_, Alo_);
    }
}

// round 8
// speedup vs baseline: 1.0979x; 1.0979x over previous
#include <cuda_runtime.h>
#include <cuda_bf16.h>
#include <math.h>
#include <stdint.h>

#define NN   2048
#define DD   512
#define HH   8
#define DPEC 16
#define WALKC 8
#define LLC  3
#define EEC  32768
#define DFFC 2048
#define MAXD 256

// ============================ PTX helpers (sm_80-baseline ISA only) ============================
__device__ __forceinline__ uint32_t smem_to_u32(const void* p) {
    uint32_t a;
    asm("{ .reg .u64 t; cvta.to.shared.u64 t, %1; cvt.u32.u64 %0, t; }" : "=r"(a) : "l"(p));
    return a;
}
#define CP_ASYNC16(dst, src) \
    asm volatile("cp.async.cg.shared.global [%0], [%1], 16;" :: "r"(dst), "l"(src))
#define CP_COMMIT() asm volatile("cp.async.commit_group;" ::: "memory")
#define CP_WAIT1()  asm volatile("cp.async.wait_group 1;" ::: "memory")
#define CP_WAIT0()  asm volatile("cp.async.wait_group 0;" ::: "memory")

__device__ __forceinline__ void ldsm4(uint32_t* r, uint32_t addr) {
    asm volatile("ldmatrix.sync.aligned.m8n8.x4.shared.b16 {%0,%1,%2,%3}, [%4];"
        : "=r"(r[0]), "=r"(r[1]), "=r"(r[2]), "=r"(r[3]) : "r"(addr));
}
__device__ __forceinline__ void ldsm4t(uint32_t* r, uint32_t addr) {
    asm volatile("ldmatrix.sync.aligned.m8n8.x4.trans.shared.b16 {%0,%1,%2,%3}, [%4];"
        : "=r"(r[0]), "=r"(r[1]), "=r"(r[2]), "=r"(r[3]) : "r"(addr));
}
__device__ __forceinline__ void mma16816(float* c, const uint32_t* a, const uint32_t* b) {
    asm volatile("mma.sync.aligned.m16n8k16.row.col.f32.bf16.bf16.f32 "
        "{%0,%1,%2,%3}, {%4,%5,%6,%7}, {%8,%9}, {%0,%1,%2,%3};"
        : "+f"(c[0]), "+f"(c[1]), "+f"(c[2]), "+f"(c[3])
        : "r"(a[0]), "r"(a[1]), "r"(a[2]), "r"(a[3]), "r"(b[0]), "r"(b[1]));
}

#define ASM_OFF(row, ch) ((uint32_t)((row) * 128 + ((((ch)) ^ ((row) & 7)) << 4)))

// ============================ static device scratch ============================
__device__ uint32_t g_bm[NN*64];
__device__ float g_deg[NN];
__device__ float g_invdeg[NN];
__device__ int   g_nbr[NN*MAXD];
__device__ int   g_cnt[NN];
__device__ __nv_bfloat16 g_T2b[NN*NN];
__device__ __nv_bfloat16 g_T3b[NN*NN];
__device__ __nv_bfloat16 g_T4b[NN*NN];
__device__ float g_rw [NN*WALKC];
__device__ float g_pe [NN*DPEC];
__device__ float g_pep[LLC*NN*HH];
__device__ float g_x   [NN*DD];
__device__ float g_x1  [NN*DD];
__device__ float g_o   [NN*DD];
__device__ __nv_bfloat16 g_Ahi[NN*DD];
__device__ __nv_bfloat16 g_Alo[NN*DD];
__device__ __nv_bfloat16 g_Hhi[NN*DFFC];
__device__ __nv_bfloat16 g_Hlo[NN*DFFC];
__device__ __nv_bfloat16 g_QKVhi[NN*3*DD];
__device__ __nv_bfloat16 g_QKVlo[NN*3*DD];
__device__ __nv_bfloat16 g_qkvW_hi[LLC*3*DD*DD];
__device__ __nv_bfloat16 g_qkvW_lo[LLC*3*DD*DD];
__device__ __nv_bfloat16 g_outW_hi[LLC*DD*DD];
__device__ __nv_bfloat16 g_outW_lo[LLC*DD*DD];
__device__ __nv_bfloat16 g_f1W_hi[LLC*DD*DFFC];
__device__ __nv_bfloat16 g_f1W_lo[LLC*DD*DFFC];
__device__ __nv_bfloat16 g_f2W_hi[LLC*DFFC*DD];
__device__ __nv_bfloat16 g_f2W_lo[LLC*DFFC*DD];
__device__ float g_part [4*HH*NN*64];
__device__ float g_plsum[4*HH*NN];

// ============================ PE pipeline (sparse) ============================
__global__ void zero_bm_kernel() {
    int idx = blockIdx.x * blockDim.x + threadIdx.x;
    if (idx < NN * 64) g_bm[idx] = 0u;
}
__global__ void scatter_bm_kernel(const int* __restrict__ ei) {
    int e = blockIdx.x * blockDim.x + threadIdx.x;
    if (e < EEC) {
        int s = ei[e], t = ei[EEC + e];
        atomicOr(&g_bm[s * 64 + (t >> 5)], 1u << (t & 31));
        atomicOr(&g_bm[t * 64 + (s >> 5)], 1u << (s & 31));
    }
}
__global__ void build_bm_kernel() {
    __shared__ int cnt;
    int i = blockIdx.x, t = threadIdx.x;
    if (t == 0) cnt = 0;
    __syncthreads();
    uint32_t w = g_bm[i * 64 + t];
    int c = __popc(w);
    int pos = (c > 0) ? atomicAdd(&cnt, c) : 0;
    while (w) {
        int b = __ffs(w) - 1;
        w &= w - 1;
        if (pos < MAXD) g_nbr[i * MAXD + pos] = t * 32 + b;
        pos++;
    }
    __syncthreads();
    if (t == 0) {
        int cc = cnt < MAXD ? cnt : MAXD;
        g_cnt[i] = cc;
        float d = cnt < 1 ? 1.f : (float)cnt;
        g_deg[i] = d;
        g_invdeg[i] = 1.f / d;
    }
}
__global__ void __launch_bounds__(256) t2_kernel() {
    __shared__ float rowbuf[NN];
    int i = blockIdx.x, t = threadIdx.x;
    #pragma unroll
    for (int u = 0; u < NN / 256; u++) rowbuf[t + u * 256] = 0.f;
    __syncthreads();
    int cnt = g_cnt[i];
    float inv_i = g_invdeg[i];
    for (int c = t >> 3; c < cnt; c += 32) {
        int j = g_nbr[i * MAXD + c];
        float w = inv_i * g_invdeg[j];
        int cj = g_cnt[j];
        const int* nbj = g_nbr + j * MAXD;
        for (int k = t & 7; k < cj; k += 8) atomicAdd(&rowbuf[nbj[k]], w);
    }
    __syncthreads();
    __nv_bfloat16* out = g_T2b + (size_t)i * NN;
    #pragma unroll
    for (int u = 0; u < NN / 256; u++) {
        int idx = t + u * 256;
        out[idx] = __float2bfloat16_rn(rowbuf[idx]);
    }
}
__global__ void __launch_bounds__(256) spmm_bf_kernel(const __nv_bfloat16* __restrict__ IN,
                                                      __nv_bfloat16* __restrict__ OUT) {
    int i = blockIdx.x, t = threadIdx.x;
    int cnt = g_cnt[i];
    float inv = g_invdeg[i];
    const int* nb = g_nbr + i * MAXD;
    float2 acc[4];
    #pragma unroll
    for (int u = 0; u < 4; u++) acc[u] = make_float2(0.f, 0.f);
    for (int c = 0; c < cnt; c++) {
        const __nv_bfloat162* row = reinterpret_cast<const __nv_bfloat162*>(IN + (size_t)nb[c] * NN);
        #pragma unroll
        for (int u = 0; u < 4; u++) {
            float2 v = __bfloat1622float2(row[t + u * 256]);
            acc[u].x += v.x; acc[u].y += v.y;
        }
    }
    __nv_bfloat162* out = reinterpret_cast<__nv_bfloat162*>(OUT + (size_t)i * NN);
    #pragma unroll
    for (int u = 0; u < 4; u++)
        out[t + u * 256] = __floats2bfloat162_rn(acc[u].x * inv, acc[u].y * inv);
}
__global__ void diag2_kernel() {
    __shared__ float sh[256];
    __shared__ float res[7];
    int i = blockIdx.x, t = threadIdx.x;
    float inv_i = g_invdeg[i], d_i = g_deg[i];
    int cnt = g_cnt[i];
    const __nv_bfloat16* r2 = g_T2b + (size_t)i * NN;
    const __nv_bfloat16* r3 = g_T3b + (size_t)i * NN;
    const __nv_bfloat16* r4 = g_T4b + (size_t)i * NN;
    float s[7] = {};
    for (int c = t; c < cnt; c += 256) {
        int j = g_nbr[i * MAXD + c];
        float wj = g_invdeg[j];
        s[0] += wj;
        s[1] += __bfloat162float(r2[j]) * wj;
    }
    for (int j = t; j < NN; j += 256) {
        float w = g_invdeg[j];
        float t2 = __bfloat162float(r2[j]);
        float t3 = __bfloat162float(r3[j]);
        float t4 = __bfloat162float(r4[j]);
        s[2] += t2 * t2 * w;
        s[3] += t3 * t2 * w;
        s[4] += t3 * t3 * w;
        s[5] += t4 * t3 * w;
        s[6] += t4 * t4 * w;
    }
    for (int v = 0; v < 7; v++) {
        sh[t] = s[v]; __syncthreads();
        for (int k = 128; k > 0; k >>= 1) { if (t < k) sh[t] += sh[t + k]; __syncthreads(); }
        if (t == 0) res[v] = sh[0];
        __syncthreads();
    }
    if (t == 0) {
        bool self = (g_bm[i * 64 + (i >> 5)] >> (i & 31)) & 1u;
        g_rw[i * WALKC + 0] = self ? inv_i : 0.f;
        g_rw[i * WALKC + 1] = inv_i * res[0];
        g_rw[i * WALKC + 2] = res[1];
        g_rw[i * WALKC + 3] = d_i * res[2];
        g_rw[i * WALKC + 4] = d_i * res[3];
        g_rw[i * WALKC + 5] = d_i * res[4];
        g_rw[i * WALKC + 6] = d_i * res[5];
        g_rw[i * WALKC + 7] = d_i * res[6];
    }
}
__global__ void pe_kernel(const float* __restrict__ W, const float* __restrict__ b) {
    int i = blockIdx.x * blockDim.x + threadIdx.x;
    if (i >= NN) return;
    float r[WALKC];
    #pragma unroll
    for (int w = 0; w < WALKC; w++) r[w] = g_rw[i * WALKC + w];
    #pragma unroll
    for (int d = 0; d < DPEC; d++) {
        float s = b[d];
        #pragma unroll
        for (int w = 0; w < WALKC; w++) s += r[w] * W[w * DPEC + d];
        g_pe[i * DPEC + d] = s;
    }
}
__global__ void pep_kernel(const float* __restrict__ W, const float* __restrict__ b) {
    int i = blockIdx.x * blockDim.x + threadIdx.x;
    if (i >= NN) return;
    float p[DPEC];
    #pragma unroll
    for (int d = 0; d < DPEC; d++) p[d] = g_pe[i * DPEC + d];
    for (int l = 0; l < LLC; l++) {
        #pragma unroll
        for (int h = 0; h < HH; h++) {
            float s = b[l * HH + h];
            #pragma unroll
            for (int d = 0; d < DPEC; d++) s += p[d] * W[(l * DPEC + d) * HH + h];
            g_pep[(size_t)l * NN * HH + i * HH + h] = s;
        }
    }
}

// ============================ conversions ============================
__global__ void split_copy_kernel(const float* __restrict__ src) {
    int idx = blockIdx.x * blockDim.x + threadIdx.x;
    if (idx < NN * DD) {
        float v = src[idx];
        g_x[idx] = v;
        __nv_bfloat16 h = __float2bfloat16_rn(v);
        g_Ahi[idx] = h;
        g_Alo[idx] = __float2bfloat16_rn(v - __bfloat162float(h));
    }
}
__global__ void convW_kernel(const float* __restrict__ W, __nv_bfloat16* __restrict__ hi,
                             __nv_bfloat16* __restrict__ lo, int K, int N) {
    __shared__ float tile[32][33];
    size_t lw = (size_t)blockIdx.z * K * N;
    int n0 = blockIdx.x * 32, k0 = blockIdx.y * 32;
    int tx = threadIdx.x, ty = threadIdx.y;
    #pragma unroll
    for (int r = 0; r < 4; r++)
        tile[ty + r * 8][tx] = W[lw + (size_t)(k0 + ty + r * 8) * N + n0 + tx];
    __syncthreads();
    #pragma unroll
    for (int r = 0; r < 4; r++) {
        int ni = ty + r * 8;
        float v = tile[tx][ni];
        __nv_bfloat16 h = __float2bfloat16_rn(v);
        size_t o = lw + (size_t)(n0 + ni) * K + k0 + tx;
        hi[o] = h;
        lo[o] = __float2bfloat16_rn(v - __bfloat162float(h));
    }
}

// ============================ mma.sync bf16x3 GEMM (BK=64, 2-stage, templated TM) ============================
template<int EPI, int TM>  // EPI: 0 fp32 out; 2 bf16 hi/lo out; 3 GELU + bf16 hi/lo out
__global__ void __launch_bounds__(256) mma_gemm_kernel(
    const __nv_bfloat16* __restrict__ Ahi, const __nv_bfloat16* __restrict__ Alo,
    const __nv_bfloat16* __restrict__ Bhi, const __nv_bfloat16* __restrict__ Blo,
    const float* __restrict__ bias, float* __restrict__ C,
    __nv_bfloat16* __restrict__ Chi, __nv_bfloat16* __restrict__ Clo, int N, int K)
{
    constexpr int MBN    = TM / 64;
    constexpr int ABYTES = TM * 128;
    constexpr int STAGE  = 2 * ABYTES + 32768;
    extern __shared__ char smem[];
    const int tid  = threadIdx.x;
    const int lane = tid & 31;
    const int wid  = tid >> 5;
    const int m0 = blockIdx.y * TM, n0 = blockIdx.x * 128;
    const int wrow = (wid >> 1) * (16 * MBN);
    const int wcol = (wid & 1) * 64;
    const uint32_t sbase = smem_to_u32(smem);

    float acc[MBN][8][4];
    #pragma unroll
    for (int a = 0; a < MBN; a++)
        #pragma unroll
        for (int b = 0; b < 8; b++)
            #pragma unroll
            for (int c = 0; c < 4; c++) acc[a][b][c] = 0.f;

    const int nc = K >> 6;

    auto loadChunk = [&](int c) {
        uint32_t sb = sbase + (uint32_t)(c & 1) * STAGE;
        int k0 = c << 6;
        #pragma unroll
        for (int t2 = 0; t2 < 2; t2++) {
            const __nv_bfloat16* s = t2 ? Alo : Ahi;
            #pragma unroll
            for (int it = 0; it < TM / 32; it++) {
                int idx = it * 256 + tid;
                int row = idx >> 3, ch = idx & 7;
                CP_ASYNC16(sb + t2 * ABYTES + ASM_OFF(row, ch),
                           s + (size_t)(m0 + row) * K + k0 + ch * 8);
            }
        }
        #pragma unroll
        for (int t2 = 0; t2 < 2; t2++) {
            const __nv_bfloat16* s = t2 ? Blo : Bhi;
            #pragma unroll
            for (int it = 0; it < 4; it++) {
                int idx = it * 256 + tid;
                int row = idx >> 3, ch = idx & 7;
                CP_ASYNC16(sb + 2 * ABYTES + t2 * 16384 + ASM_OFF(row, ch),
                           s + (size_t)(n0 + row) * K + k0 + ch * 8);
            }
        }
        CP_COMMIT();
    };

    loadChunk(0);
    if (nc > 1) loadChunk(1);

    for (int c = 0; c < nc; c++) {
        if (c + 1 < nc) CP_WAIT1(); else CP_WAIT0();
        __syncthreads();
        uint32_t sb = sbase + (uint32_t)(c & 1) * STAGE;
        uint32_t sAh = sb, sAl = sb + ABYTES, sBh = sb + 2 * ABYTES, sBl = sb + 2 * ABYTES + 16384;
        #pragma unroll
        for (int ks = 0; ks < 4; ks++) {
            uint32_t ah[MBN][4], al[MBN][4], bh[4][4], bl[4][4];
            {
                int sub = lane >> 3;
                int row16 = (lane & 7) + ((sub & 1) << 3);
                int kc = ks * 2 + (sub >> 1);
                #pragma unroll
                for (int mb = 0; mb < MBN; mb++) {
                    int row = wrow + mb * 16 + row16;
                    uint32_t off = ASM_OFF(row, kc);
                    ldsm4(ah[mb], sAh + off);
                    ldsm4(al[mb], sAl + off);
                }
            }
            {
                int sub = lane >> 3;
                int kc = ks * 2 + (sub & 1);
                int nr = ((sub >> 1) << 3) + (lane & 7);
                #pragma unroll
                for (int j = 0; j < 4; j++) {
                    int row = wcol + j * 16 + nr;
                    uint32_t off = ASM_OFF(row, kc);
                    ldsm4(bh[j], sBh + off);
                    ldsm4(bl[j], sBl + off);
                }
            }
            #pragma unroll
            for (int mb = 0; mb < MBN; mb++)
                #pragma unroll
                for (int j = 0; j < 4; j++) {
                    mma16816(acc[mb][2*j],     ah[mb], &bh[j][0]);
                    mma16816(acc[mb][2*j],     ah[mb], &bl[j][0]);
                    mma16816(acc[mb][2*j],     al[mb], &bh[j][0]);
                    mma16816(acc[mb][2*j + 1], ah[mb], &bh[j][2]);
                    mma16816(acc[mb][2*j + 1], ah[mb], &bl[j][2]);
                    mma16816(acc[mb][2*j + 1], al[mb], &bh[j][2]);
                }
        }
        __syncthreads();
        if (c + 2 < nc) loadChunk(c + 2);
    }

    const int r_l = lane >> 2;
    const int c_l = (lane & 3) << 1;
    #pragma unroll
    for (int mb = 0; mb < MBN; mb++) {
        #pragma unroll
        for (int nb = 0; nb < 8; nb++) {
            int row = m0 + wrow + mb * 16 + r_l;
            int col = n0 + wcol + nb * 8 + c_l;
            float b0 = bias[col], b1 = bias[col + 1];
            float v0 = acc[mb][nb][0] + b0;
            float v1 = acc[mb][nb][1] + b1;
            float v2 = acc[mb][nb][2] + b0;
            float v3 = acc[mb][nb][3] + b1;
            if (EPI == 3) {
                v0 = 0.5f * v0 * (1.f + erff(v0 * 0.70710678118654752f));
                v1 = 0.5f * v1 * (1.f + erff(v1 * 0.70710678118654752f));
                v2 = 0.5f * v2 * (1.f + erff(v2 * 0.70710678118654752f));
                v3 = 0.5f * v3 * (1.f + erff(v3 * 0.70710678118654752f));
            }
            if (EPI == 0) {
                *reinterpret_cast<float2*>(C + (size_t)row * N + col)       = make_float2(v0, v1);
                *reinterpret_cast<float2*>(C + (size_t)(row + 8) * N + col) = make_float2(v2, v3);
            } else {
                __nv_bfloat162 h01 = __floats2bfloat162_rn(v0, v1);
                __nv_bfloat162 h23 = __floats2bfloat162_rn(v2, v3);
                __nv_bfloat162 l01 = __floats2bfloat162_rn(v0 - __bfloat162float(h01.x),
                                                           v1 - __bfloat162float(h01.y));
                __nv_bfloat162 l23 = __floats2bfloat162_rn(v2 - __bfloat162float(h23.x),
                                                           v3 - __bfloat162float(h23.y));
                *reinterpret_cast<__nv_bfloat162*>(Chi + (size_t)row * N + col)       = h01;
                *reinterpret_cast<__nv_bfloat162*>(Chi + (size_t)(row + 8) * N + col) = h23;
                *reinterpret_cast<__nv_bfloat162*>(Clo + (size_t)row * N + col)       = l01;
                *reinterpret_cast<__nv_bfloat162*>(Clo + (size_t)(row + 8) * N + col) = l23;
            }
        }
    }
}

// ============================ tensor-core attention (double-buffered K/V) ============================
#define AT_QH   0
#define AT_QL   16384
#define AT_KV   32768
#define AT_BIAS 98304
#define AT_SMEM (98304 + 512)

__global__ void __launch_bounds__(128) attn_tc_kernel(
    const __nv_bfloat16* __restrict__ qh, const __nv_bfloat16* __restrict__ ql,
    const float* __restrict__ pep, float* __restrict__ part, float* __restrict__ plsum)
{
    extern __shared__ char sm[];
    const int h = blockIdx.y, sl = blockIdx.z;
    const int q0 = blockIdx.x * 128;
    const int tid = threadIdx.x, lane = tid & 31, wid = tid >> 5;
    const int wrow = wid * 32;
    const int sub = lane >> 3;
    const uint32_t sb = smem_to_u32(sm);
    float* bias = reinterpret_cast<float*>(sm + AT_BIAS);

    #pragma unroll
    for (int it = 0; it < 8; it++) {
        int idx = it * 128 + tid;
        int row = idx >> 3, ch = idx & 7;
        size_t g = (size_t)(q0 + row) * 1536 + h * 64 + ch * 8;
        uint32_t off = ASM_OFF(row, ch);
        CP_ASYNC16(sb + AT_QH + off, qh + g);
        CP_ASYNC16(sb + AT_QL + off, ql + g);
    }
    {
        const int kk = sl * 512;
        uint32_t stb = sb + AT_KV;
        #pragma unroll
        for (int it = 0; it < 4; it++) {
            int idx = it * 128 + tid;
            int row = idx >> 3, ch = idx & 7;
            size_t gk = (size_t)(kk + row) * 1536 + 512 + h * 64 + ch * 8;
            uint32_t off = ASM_OFF(row, ch);
            CP_ASYNC16(stb + off,         qh + gk);
            CP_ASYNC16(stb + 8192 + off,  ql + gk);
            CP_ASYNC16(stb + 16384 + off, qh + gk + 512);
            CP_ASYNC16(stb + 24576 + off, ql + gk + 512);
        }
        if (tid < 64) bias[tid] = pep[(size_t)(kk + tid) * HH + h];
    }
    CP_COMMIT();

    float O[2][8][4];
    float ls[2][2] = {{0.f, 0.f}, {0.f, 0.f}};
    #pragma unroll
    for (int mb = 0; mb < 2; mb++)
        #pragma unroll
        for (int nb = 0; nb < 8; nb++)
            #pragma unroll
            for (int u = 0; u < 4; u++) O[mb][nb][u] = 0.f;

    for (int c = 0; c < 8; c++) {
        CP_WAIT0();
        __syncthreads();
        if (c < 7) {
            const int kn = sl * 512 + (c + 1) * 64;
            uint32_t stb = sb + AT_KV + (uint32_t)((c + 1) & 1) * 32768;
            #pragma unroll
            for (int it = 0; it < 4; it++) {
                int idx = it * 128 + tid;
                int row = idx >> 3, ch = idx & 7;
                size_t gk = (size_t)(kn + row) * 1536 + 512 + h * 64 + ch * 8;
                uint32_t off = ASM_OFF(row, ch);
                CP_ASYNC16(stb + off,         qh + gk);
                CP_ASYNC16(stb + 8192 + off,  ql + gk);
                CP_ASYNC16(stb + 16384 + off, qh + gk + 512);
                CP_ASYNC16(stb + 24576 + off, ql + gk + 512);
            }
            if (tid < 64) bias[((c + 1) & 1) * 64 + tid] = pep[(size_t)(kn + tid) * HH + h];
            CP_COMMIT();
        }
        const uint32_t stc = sb + AT_KV + (uint32_t)(c & 1) * 32768;
        const uint32_t sKH = stc, sKL = stc + 8192, sVH = stc + 16384, sVL = stc + 24576;
        const float* bs = bias + (c & 1) * 64;

        float S[2][8][4];
        #pragma unroll
        for (int mb = 0; mb < 2; mb++)
            #pragma unroll
            for (int nb = 0; nb < 8; nb++)
                #pragma unroll
                for (int u = 0; u < 4; u++) S[mb][nb][u] = 0.f;
        #pragma unroll
        for (int kb = 0; kb < 4; kb++) {
            uint32_t ah[2][4], al[2][4];
            int r16 = (lane & 7) + ((sub & 1) << 3);
            int chA = kb * 2 + (sub >> 1);
            #pragma unroll
            for (int mb = 0; mb < 2; mb++) {
                int row = wrow + mb * 16 + r16;
                uint32_t off = ASM_OFF(row, chA);
                ldsm4(ah[mb], sb + AT_QH + off);
                ldsm4(al[mb], sb + AT_QL + off);
            }
            int chB = kb * 2 + (sub & 1);
            int nr = ((sub >> 1) << 3) + (lane & 7);
            #pragma unroll
            for (int j = 0; j < 4; j++) {
                uint32_t bh[4], bl[4];
                int row = j * 16 + nr;
                uint32_t off = ASM_OFF(row, chB);
                ldsm4(bh, sKH + off);
                ldsm4(bl, sKL + off);
                #pragma unroll
                for (int mb = 0; mb < 2; mb++) {
                    mma16816(S[mb][2*j],   ah[mb], &bh[0]);
                    mma16816(S[mb][2*j],   al[mb], &bh[0]);
                    mma16816(S[mb][2*j],   ah[mb], &bl[0]);
                    mma16816(S[mb][2*j+1], ah[mb], &bh[2]);
                    mma16816(S[mb][2*j+1], al[mb], &bh[2]);
                    mma16816(S[mb][2*j+1], ah[mb], &bl[2]);
                }
            }
        }

        uint32_t Ph[2][8][2], Pl[2][8][2];
        #pragma unroll
        for (int mb = 0; mb < 2; mb++)
            #pragma unroll
            for (int nb = 0; nb < 8; nb++) {
                int col = nb * 8 + ((lane & 3) << 1);
                float b0 = bs[col], b1 = bs[col + 1];
                float p0 = __expf(fmaf(S[mb][nb][0], 0.125f, -b0));
                float p1 = __expf(fmaf(S[mb][nb][1], 0.125f, -b1));
                float p2 = __expf(fmaf(S[mb][nb][2], 0.125f, -b0));
                float p3 = __expf(fmaf(S[mb][nb][3], 0.125f, -b1));
                ls[mb][0] += p0 + p1;
                ls[mb][1] += p2 + p3;
                __nv_bfloat162 h01 = __floats2bfloat162_rn(p0, p1);
                __nv_bfloat162 h23 = __floats2bfloat162_rn(p2, p3);
                __nv_bfloat162 l01 = __floats2bfloat162_rn(p0 - __bfloat162float(h01.x),
                                                           p1 - __bfloat162float(h01.y));
                __nv_bfloat162 l23 = __floats2bfloat162_rn(p2 - __bfloat162float(h23.x),
                                                           p3 - __bfloat162float(h23.y));
                Ph[mb][nb][0] = *reinterpret_cast<uint32_t*>(&h01);
                Ph[mb][nb][1] = *reinterpret_cast<uint32_t*>(&h23);
                Pl[mb][nb][0] = *reinterpret_cast<uint32_t*>(&l01);
                Pl[mb][nb][1] = *reinterpret_cast<uint32_t*>(&l23);
            }

        #pragma unroll
        for (int kb2 = 0; kb2 < 4; kb2++) {
            int krow = kb2 * 16 + ((sub & 1) << 3) + (lane & 7);
            #pragma unroll
            for (int dI = 0; dI < 4; dI++) {
                uint32_t vh[4], vl[4];
                int ch = dI * 2 + (sub >> 1);
                uint32_t off = ASM_OFF(krow, ch);
                ldsm4t(vh, sVH + off);
                ldsm4t(vl, sVL + off);
                #pragma unroll
                for (int mb = 0; mb < 2; mb++) {
                    uint32_t pa[4] = {Ph[mb][2*kb2][0], Ph[mb][2*kb2][1],
                                      Ph[mb][2*kb2+1][0], Ph[mb][2*kb2+1][1]};
                    uint32_t la[4] = {Pl[mb][2*kb2][0], Pl[mb][2*kb2][1],
                                      Pl[mb][2*kb2+1][0], Pl[mb][2*kb2+1][1]};
                    mma16816(O[mb][2*dI],   pa, &vh[0]);
                    mma16816(O[mb][2*dI],   la, &vh[0]);
                    mma16816(O[mb][2*dI],   pa, &vl[0]);
                    mma16816(O[mb][2*dI+1], pa, &vh[2]);
                    mma16816(O[mb][2*dI+1], la, &vh[2]);
                    mma16816(O[mb][2*dI+1], pa, &vl[2]);
                }
            }
        }
    }

    #pragma unroll
    for (int mb = 0; mb < 2; mb++)
        #pragma unroll
        for (int r = 0; r < 2; r++) {
            float v = ls[mb][r];
            v += __shfl_xor_sync(0xffffffffu, v, 1);
            v += __shfl_xor_sync(0xffffffffu, v, 2);
            ls[mb][r] = v;
        }
    const size_t base = (size_t)(sl * HH + h) * NN;
    #pragma unroll
    for (int mb = 0; mb < 2; mb++) {
        int rowA = q0 + wrow + mb * 16 + (lane >> 2);
        int rowB = rowA + 8;
        if ((lane & 3) == 0) {
            plsum[base + rowA] = ls[mb][0];
            plsum[base + rowB] = ls[mb][1];
        }
        #pragma unroll
        for (int nb = 0; nb < 8; nb++) {
            int col = nb * 8 + ((lane & 3) << 1);
            *reinterpret_cast<float2*>(part + (base + rowA) * 64 + col) = make_float2(O[mb][nb][0], O[mb][nb][1]);
            *reinterpret_cast<float2*>(part + (base + rowB) * 64 + col) = make_float2(O[mb][nb][2], O[mb][nb][3]);
        }
    }
}

__global__ void attn_combine_kernel(const float* __restrict__ part, const float* __restrict__ pls,
                                    __nv_bfloat16* __restrict__ ohi, __nv_bfloat16* __restrict__ olo) {
    int i = blockIdx.x, t = threadIdx.x;
    #pragma unroll
    for (int rep = 0; rep < 2; rep++) {
        int idx = t + rep * 256;
        int h = idx >> 6, d = idx & 63;
        float v = 0.f, l = 0.f;
        #pragma unroll
        for (int s = 0; s < 4; s++) {
            l += pls[(size_t)(s * HH + h) * NN + i];
            v += part[((size_t)(s * HH + h) * NN + i) * 64 + d];
        }
        float r = v / l;
        __nv_bfloat16 hb = __float2bfloat16_rn(r);
        ohi[(size_t)i * DD + idx] = hb;
        olo[(size_t)i * DD + idx] = __float2bfloat16_rn(r - __bfloat162float(hb));
    }
}

// ============================ LN (fp32 out + bf16 hi/lo) ============================
__global__ void ln_kernel(const float* __restrict__ a, const float* __restrict__ b,
                          const float* __restrict__ g, const float* __restrict__ be,
                          float* __restrict__ out,
                          __nv_bfloat16* __restrict__ ohi, __nv_bfloat16* __restrict__ olo) {
    __shared__ float sh[256];
    __shared__ float s_mu, s_r;
    int i = blockIdx.x, t = threadIdx.x;
    float v0 = a[(size_t)i * DD + t]       + b[(size_t)i * DD + t];
    float v1 = a[(size_t)i * DD + 256 + t] + b[(size_t)i * DD + 256 + t];
    sh[t] = v0 + v1; __syncthreads();
    for (int k = 128; k > 0; k >>= 1) { if (t < k) sh[t] += sh[t + k]; __syncthreads(); }
    if (t == 0) s_mu = sh[0] * (1.f / DD);
    __syncthreads();
    float mu = s_mu;
    float d0 = v0 - mu, d1 = v1 - mu;
    sh[t] = d0 * d0 + d1 * d1; __syncthreads();
    for (int k = 128; k > 0; k >>= 1) { if (t < k) sh[t] += sh[t + k]; __syncthreads(); }
    if (t == 0) s_r = rsqrtf(sh[0] * (1.f / DD) + 1e-5f);
    __syncthreads();
    float r = s_r;
    float o0 = d0 * r * g[t]       + be[t];
    float o1 = d1 * r * g[256 + t] + be[256 + t];
    out[(size_t)i * DD + t]       = o0;
    out[(size_t)i * DD + 256 + t] = o1;
    __nv_bfloat16 h0 = __float2bfloat16_rn(o0);
    __nv_bfloat16 h1 = __float2bfloat16_rn(o1);
    ohi[(size_t)i * DD + t]       = h0;
    ohi[(size_t)i * DD + 256 + t] = h1;
    olo[(size_t)i * DD + t]       = __float2bfloat16_rn(o0 - __bfloat162float(h0));
    olo[(size_t)i * DD + 256 + t] = __float2bfloat16_rn(o1 - __bfloat162float(h1));
}

// ============================ launch ============================
extern "C" void kernel_launch(void* const* d_in, const int* in_sizes, int n_in,
                              void* d_out, int out_size) {
    const float* node_features = (const float*)d_in[0];
    const int*   edge_index    = (const int*)  d_in[1];
    const float* pe_proj_W     = (const float*)d_in[2];
    const float* pe_proj_b     = (const float*)d_in[3];
    const float* qkv_W         = (const float*)d_in[4];
    const float* qkv_b         = (const float*)d_in[5];
    const float* peb_W         = (const float*)d_in[6];
    const float* peb_b         = (const float*)d_in[7];
    const float* out_W         = (const float*)d_in[8];
    const float* out_b         = (const float*)d_in[9];
    const float* ffn_W1        = (const float*)d_in[10];
    const float* ffn_b1        = (const float*)d_in[11];
    const float* ffn_W2        = (const float*)d_in[12];
    const float* ffn_b2        = (const float*)d_in[13];
    const float* ln1_g         = (const float*)d_in[14];
    const float* ln1_b         = (const float*)d_in[15];
    const float* ln2_g         = (const float*)d_in[16];
    const float* ln2_b         = (const float*)d_in[17];
    float* outp = (float*)d_out;

    float *x_, *x1_, *o_, *pep_, *part_, *pls_;
    __nv_bfloat16 *Ahi_, *Alo_, *Hhi_, *Hlo_, *Qh_, *Ql_, *T2b_, *T3b_, *T4b_;
    __nv_bfloat16 *qWh_, *qWl_, *oWh_, *oWl_, *f1h_, *f1l_, *f2h_, *f2l_;
    cudaGetSymbolAddress((void**)&x_,   g_x);
    cudaGetSymbolAddress((void**)&x1_,  g_x1);
    cudaGetSymbolAddress((void**)&o_,   g_o);
    cudaGetSymbolAddress((void**)&pep_, g_pep);
    cudaGetSymbolAddress((void**)&part_,g_part);
    cudaGetSymbolAddress((void**)&pls_, g_plsum);
    cudaGetSymbolAddress((void**)&Ahi_, g_Ahi);
    cudaGetSymbolAddress((void**)&Alo_, g_Alo);
    cudaGetSymbolAddress((void**)&Hhi_, g_Hhi);
    cudaGetSymbolAddress((void**)&Hlo_, g_Hlo);
    cudaGetSymbolAddress((void**)&Qh_,  g_QKVhi);
    cudaGetSymbolAddress((void**)&Ql_,  g_QKVlo);
    cudaGetSymbolAddress((void**)&T2b_, g_T2b);
    cudaGetSymbolAddress((void**)&T3b_, g_T3b);
    cudaGetSymbolAddress((void**)&T4b_, g_T4b);
    cudaGetSymbolAddress((void**)&qWh_, g_qkvW_hi);
    cudaGetSymbolAddress((void**)&qWl_, g_qkvW_lo);
    cudaGetSymbolAddress((void**)&oWh_, g_outW_hi);
    cudaGetSymbolAddress((void**)&oWl_, g_outW_lo);
    cudaGetSymbolAddress((void**)&f1h_, g_f1W_hi);
    cudaGetSymbolAddress((void**)&f1l_, g_f1W_lo);
    cudaGetSymbolAddress((void**)&f2h_, g_f2W_hi);
    cudaGetSymbolAddress((void**)&f2l_, g_f2W_lo);

    constexpr int GS64 = 2 * (2 * 64 * 128 + 32768);   // 98304 = 96 KB -> 2 CTA/SM
    cudaFuncSetAttribute(mma_gemm_kernel<2,64>, cudaFuncAttributeMaxDynamicSharedMemorySize, GS64);
    cudaFuncSetAttribute(mma_gemm_kernel<3,64>, cudaFuncAttributeMaxDynamicSharedMemorySize, GS64);
    cudaFuncSetAttribute(mma_gemm_kernel<0,64>, cudaFuncAttributeMaxDynamicSharedMemorySize, GS64);
    cudaFuncSetAttribute(attn_tc_kernel, cudaFuncAttributeMaxDynamicSharedMemorySize, AT_SMEM);

    static cudaStream_t s_side = nullptr;
    static cudaEvent_t  ev_fork = nullptr, ev_pe = nullptr;
    if (s_side == nullptr) {
        cudaStreamCreateWithFlags(&s_side, cudaStreamNonBlocking);
        cudaEventCreateWithFlags(&ev_fork, cudaEventDisableTiming);
        cudaEventCreateWithFlags(&ev_pe,   cudaEventDisableTiming);
    }

    // ---- fork: PE pipeline on side stream ----
    cudaEventRecord(ev_fork, 0);
    cudaStreamWaitEvent(s_side, ev_fork, 0);
    zero_bm_kernel<<<(NN*64)/256, 256, 0, s_side>>>();
    scatter_bm_kernel<<<EEC/256, 256, 0, s_side>>>(edge_index);
    build_bm_kernel<<<NN, 64, 0, s_side>>>();
    t2_kernel<<<NN, 256, 0, s_side>>>();
    spmm_bf_kernel<<<NN, 256, 0, s_side>>>(T2b_, T3b_);
    spmm_bf_kernel<<<NN, 256, 0, s_side>>>(T3b_, T4b_);
    diag2_kernel<<<NN, 256, 0, s_side>>>();
    pe_kernel<<<(NN + 127) / 128, 128, 0, s_side>>>(pe_proj_W, pe_proj_b);
    pep_kernel<<<(NN + 127) / 128, 128, 0, s_side>>>(peb_W, peb_b);
    cudaEventRecord(ev_pe, s_side);

    // ---- main stream: weight conversion + transformer (round-6 order) ----
    convW_kernel<<<dim3(1536/32, 512/32, LLC),  dim3(32,8)>>>(qkv_W,  qWh_, qWl_, DD,  3*DD);
    convW_kernel<<<dim3(512/32,  512/32, LLC),  dim3(32,8)>>>(out_W,  oWh_, oWl_, DD,  DD);
    convW_kernel<<<dim3(2048/32, 512/32, LLC),  dim3(32,8)>>>(ffn_W1, f1h_, f1l_, DD,  DFFC);
    convW_kernel<<<dim3(512/32,  2048/32, LLC), dim3(32,8)>>>(ffn_W2, f2h_, f2l_, DFFC, DD);
    split_copy_kernel<<<(NN*DD)/256, 256>>>(node_features);

    for (int l = 0; l < LLC; l++) {
        mma_gemm_kernel<2,64><<<dim3(1536/128, NN/64), 256, GS64>>>(
            Ahi_, Alo_, qWh_ + (size_t)l*3*DD*DD, qWl_ + (size_t)l*3*DD*DD,
            qkv_b + (size_t)l*3*DD, nullptr, Qh_, Ql_, 3*DD, DD);
        if (l == 0) cudaStreamWaitEvent(0, ev_pe, 0);   // join: attention needs pep
        attn_tc_kernel<<<dim3(NN/128, HH, 4), 128, AT_SMEM>>>(Qh_, Ql_, pep_ + (size_t)l*NN*HH, part_, pls_);
        attn_combine_kernel<<<NN, 256>>>(part_, pls_, Ahi_, Alo_);
        mma_gemm_kernel<0,64><<<dim3(DD/128, NN/64), 256, GS64>>>(
            Ahi_, Alo_, oWh_ + (size_t)l*DD*DD, oWl_ + (size_t)l*DD*DD,
            out_b + (size_t)l*DD, o_, nullptr, nullptr, DD, DD);
        ln_kernel<<<NN, 256>>>(x_, o_, ln1_g + (size_t)l*DD, ln1_b + (size_t)l*DD, x1_, Ahi_, Alo_);
        mma_gemm_kernel<3,64><<<dim3(DFFC/128, NN/64), 256, GS64>>>(
            Ahi_, Alo_, f1h_ + (size_t)l*DD*DFFC, f1l_ + (size_t)l*DD*DFFC,
            ffn_b1 + (size_t)l*DFFC, nullptr, Hhi_, Hlo_, DFFC, DD);
        mma_gemm_kernel<0,64><<<dim3(DD/128, NN/64), 256, GS64>>>(
            Hhi_, Hlo_, f2h_ + (size_t)l*DFFC*DD, f2l_ + (size_t)l*DFFC*DD,
            ffn_b2 + (size_t)l*DD, o_, nullptr, nullptr, DD, DFFC);
        float* xout = (l == LLC - 1) ? outp : x_;
        ln_kernel<<<NN, 256>>>(x1_, o_, ln2_g + (size_t)l*DD, ln2_b + (size_t)l*DD, xout, Ahi_, Alo_);
    }
}

// round 9
// speedup vs baseline: 1.1035x; 1.0051x over previous
#include <cuda_runtime.h>
#include <cuda_bf16.h>
#include <math.h>
#include <stdint.h>

#define NN   2048
#define DD   512
#define HH   8
#define DPEC 16
#define WALKC 8
#define LLC  3
#define EEC  32768
#define DFFC 2048
#define MAXD 256
#define NSL  2          // attention key-slices

// ============================ PTX helpers (sm_80-baseline ISA only) ============================
__device__ __forceinline__ uint32_t smem_to_u32(const void* p) {
    uint32_t a;
    asm("{ .reg .u64 t; cvta.to.shared.u64 t, %1; cvt.u32.u64 %0, t; }" : "=r"(a) : "l"(p));
    return a;
}
#define CP_ASYNC16(dst, src) \
    asm volatile("cp.async.cg.shared.global [%0], [%1], 16;" :: "r"(dst), "l"(src))
#define CP_COMMIT() asm volatile("cp.async.commit_group;" ::: "memory")
#define CP_WAIT1()  asm volatile("cp.async.wait_group 1;" ::: "memory")
#define CP_WAIT0()  asm volatile("cp.async.wait_group 0;" ::: "memory")

__device__ __forceinline__ void ldsm4(uint32_t* r, uint32_t addr) {
    asm volatile("ldmatrix.sync.aligned.m8n8.x4.shared.b16 {%0,%1,%2,%3}, [%4];"
        : "=r"(r[0]), "=r"(r[1]), "=r"(r[2]), "=r"(r[3]) : "r"(addr));
}
__device__ __forceinline__ void ldsm4t(uint32_t* r, uint32_t addr) {
    asm volatile("ldmatrix.sync.aligned.m8n8.x4.trans.shared.b16 {%0,%1,%2,%3}, [%4];"
        : "=r"(r[0]), "=r"(r[1]), "=r"(r[2]), "=r"(r[3]) : "r"(addr));
}
__device__ __forceinline__ void mma16816(float* c, const uint32_t* a, const uint32_t* b) {
    asm volatile("mma.sync.aligned.m16n8k16.row.col.f32.bf16.bf16.f32 "
        "{%0,%1,%2,%3}, {%4,%5,%6,%7}, {%8,%9}, {%0,%1,%2,%3};"
        : "+f"(c[0]), "+f"(c[1]), "+f"(c[2]), "+f"(c[3])
        : "r"(a[0]), "r"(a[1]), "r"(a[2]), "r"(a[3]), "r"(b[0]), "r"(b[1]));
}

#define ASM_OFF(row, ch) ((uint32_t)((row) * 128 + ((((ch)) ^ ((row) & 7)) << 4)))

// ============================ static device scratch ============================
__device__ uint32_t g_bm[NN*64];
__device__ float g_deg[NN];
__device__ float g_invdeg[NN];
__device__ int   g_nbr[NN*MAXD];
__device__ int   g_cnt[NN];
__device__ __nv_bfloat16 g_T2b[NN*NN];
__device__ __nv_bfloat16 g_T3b[NN*NN];
__device__ __nv_bfloat16 g_T4b[NN*NN];
__device__ float g_rw [NN*WALKC];
__device__ float g_pe [NN*DPEC];
__device__ float g_pep[LLC*NN*HH];
__device__ float g_x   [NN*DD];
__device__ float g_x1  [NN*DD];
__device__ float g_o   [NN*DD];
__device__ __nv_bfloat16 g_Ahi[NN*DD];
__device__ __nv_bfloat16 g_Alo[NN*DD];
__device__ __nv_bfloat16 g_Hhi[NN*DFFC];
__device__ __nv_bfloat16 g_Hlo[NN*DFFC];
__device__ __nv_bfloat16 g_QKVhi[NN*3*DD];
__device__ __nv_bfloat16 g_QKVlo[NN*3*DD];
__device__ __nv_bfloat16 g_qkvW_hi[LLC*3*DD*DD];
__device__ __nv_bfloat16 g_qkvW_lo[LLC*3*DD*DD];
__device__ __nv_bfloat16 g_outW_hi[LLC*DD*DD];
__device__ __nv_bfloat16 g_outW_lo[LLC*DD*DD];
__device__ __nv_bfloat16 g_f1W_hi[LLC*DD*DFFC];
__device__ __nv_bfloat16 g_f1W_lo[LLC*DD*DFFC];
__device__ __nv_bfloat16 g_f2W_hi[LLC*DFFC*DD];
__device__ __nv_bfloat16 g_f2W_lo[LLC*DFFC*DD];
__device__ float g_part [NSL*HH*NN*64];
__device__ float g_plsum[NSL*HH*NN];

// ============================ PE pipeline (sparse) ============================
__global__ void zero_bm_kernel() {
    int idx = blockIdx.x * blockDim.x + threadIdx.x;
    if (idx < NN * 64) g_bm[idx] = 0u;
}
__global__ void scatter_bm_kernel(const int* __restrict__ ei) {
    int e = blockIdx.x * blockDim.x + threadIdx.x;
    if (e < EEC) {
        int s = ei[e], t = ei[EEC + e];
        atomicOr(&g_bm[s * 64 + (t >> 5)], 1u << (t & 31));
        atomicOr(&g_bm[t * 64 + (s >> 5)], 1u << (s & 31));
    }
}
__global__ void build_bm_kernel() {
    __shared__ int cnt;
    int i = blockIdx.x, t = threadIdx.x;
    if (t == 0) cnt = 0;
    __syncthreads();
    uint32_t w = g_bm[i * 64 + t];
    int c = __popc(w);
    int pos = (c > 0) ? atomicAdd(&cnt, c) : 0;
    while (w) {
        int b = __ffs(w) - 1;
        w &= w - 1;
        if (pos < MAXD) g_nbr[i * MAXD + pos] = t * 32 + b;
        pos++;
    }
    __syncthreads();
    if (t == 0) {
        int cc = cnt < MAXD ? cnt : MAXD;
        g_cnt[i] = cc;
        float d = cnt < 1 ? 1.f : (float)cnt;
        g_deg[i] = d;
        g_invdeg[i] = 1.f / d;
    }
}
__global__ void __launch_bounds__(256) t2_kernel() {
    __shared__ float rowbuf[NN];
    int i = blockIdx.x, t = threadIdx.x;
    #pragma unroll
    for (int u = 0; u < NN / 256; u++) rowbuf[t + u * 256] = 0.f;
    __syncthreads();
    int cnt = g_cnt[i];
    float inv_i = g_invdeg[i];
    for (int c = t >> 3; c < cnt; c += 32) {
        int j = g_nbr[i * MAXD + c];
        float w = inv_i * g_invdeg[j];
        int cj = g_cnt[j];
        const int* nbj = g_nbr + j * MAXD;
        for (int k = t & 7; k < cj; k += 8) atomicAdd(&rowbuf[nbj[k]], w);
    }
    __syncthreads();
    __nv_bfloat16* out = g_T2b + (size_t)i * NN;
    #pragma unroll
    for (int u = 0; u < NN / 256; u++) {
        int idx = t + u * 256;
        out[idx] = __float2bfloat16_rn(rowbuf[idx]);
    }
}
__global__ void __launch_bounds__(256) spmm_bf_kernel(const __nv_bfloat16* __restrict__ IN,
                                                      __nv_bfloat16* __restrict__ OUT) {
    int i = blockIdx.x, t = threadIdx.x;
    int cnt = g_cnt[i];
    float inv = g_invdeg[i];
    const int* nb = g_nbr + i * MAXD;
    float2 acc[4];
    #pragma unroll
    for (int u = 0; u < 4; u++) acc[u] = make_float2(0.f, 0.f);
    for (int c = 0; c < cnt; c++) {
        const __nv_bfloat162* row = reinterpret_cast<const __nv_bfloat162*>(IN + (size_t)nb[c] * NN);
        #pragma unroll
        for (int u = 0; u < 4; u++) {
            float2 v = __bfloat1622float2(row[t + u * 256]);
            acc[u].x += v.x; acc[u].y += v.y;
        }
    }
    __nv_bfloat162* out = reinterpret_cast<__nv_bfloat162*>(OUT + (size_t)i * NN);
    #pragma unroll
    for (int u = 0; u < 4; u++)
        out[t + u * 256] = __floats2bfloat162_rn(acc[u].x * inv, acc[u].y * inv);
}
__global__ void diag2_kernel() {
    __shared__ float sh[256];
    __shared__ float res[7];
    int i = blockIdx.x, t = threadIdx.x;
    float inv_i = g_invdeg[i], d_i = g_deg[i];
    int cnt = g_cnt[i];
    const __nv_bfloat16* r2 = g_T2b + (size_t)i * NN;
    const __nv_bfloat16* r3 = g_T3b + (size_t)i * NN;
    const __nv_bfloat16* r4 = g_T4b + (size_t)i * NN;
    float s[7] = {};
    for (int c = t; c < cnt; c += 256) {
        int j = g_nbr[i * MAXD + c];
        float wj = g_invdeg[j];
        s[0] += wj;
        s[1] += __bfloat162float(r2[j]) * wj;
    }
    for (int j = t; j < NN; j += 256) {
        float w = g_invdeg[j];
        float t2 = __bfloat162float(r2[j]);
        float t3 = __bfloat162float(r3[j]);
        float t4 = __bfloat162float(r4[j]);
        s[2] += t2 * t2 * w;
        s[3] += t3 * t2 * w;
        s[4] += t3 * t3 * w;
        s[5] += t4 * t3 * w;
        s[6] += t4 * t4 * w;
    }
    for (int v = 0; v < 7; v++) {
        sh[t] = s[v]; __syncthreads();
        for (int k = 128; k > 0; k >>= 1) { if (t < k) sh[t] += sh[t + k]; __syncthreads(); }
        if (t == 0) res[v] = sh[0];
        __syncthreads();
    }
    if (t == 0) {
        bool self = (g_bm[i * 64 + (i >> 5)] >> (i & 31)) & 1u;
        g_rw[i * WALKC + 0] = self ? inv_i : 0.f;
        g_rw[i * WALKC + 1] = inv_i * res[0];
        g_rw[i * WALKC + 2] = res[1];
        g_rw[i * WALKC + 3] = d_i * res[2];
        g_rw[i * WALKC + 4] = d_i * res[3];
        g_rw[i * WALKC + 5] = d_i * res[4];
        g_rw[i * WALKC + 6] = d_i * res[5];
        g_rw[i * WALKC + 7] = d_i * res[6];
    }
}
__global__ void pe_kernel(const float* __restrict__ W, const float* __restrict__ b) {
    int i = blockIdx.x * blockDim.x + threadIdx.x;
    if (i >= NN) return;
    float r[WALKC];
    #pragma unroll
    for (int w = 0; w < WALKC; w++) r[w] = g_rw[i * WALKC + w];
    #pragma unroll
    for (int d = 0; d < DPEC; d++) {
        float s = b[d];
        #pragma unroll
        for (int w = 0; w < WALKC; w++) s += r[w] * W[w * DPEC + d];
        g_pe[i * DPEC + d] = s;
    }
}
__global__ void pep_kernel(const float* __restrict__ W, const float* __restrict__ b) {
    int i = blockIdx.x * blockDim.x + threadIdx.x;
    if (i >= NN) return;
    float p[DPEC];
    #pragma unroll
    for (int d = 0; d < DPEC; d++) p[d] = g_pe[i * DPEC + d];
    for (int l = 0; l < LLC; l++) {
        #pragma unroll
        for (int h = 0; h < HH; h++) {
            float s = b[l * HH + h];
            #pragma unroll
            for (int d = 0; d < DPEC; d++) s += p[d] * W[(l * DPEC + d) * HH + h];
            g_pep[(size_t)l * NN * HH + i * HH + h] = s;
        }
    }
}

// ============================ conversions ============================
__global__ void split_copy_kernel(const float* __restrict__ src) {
    int idx = blockIdx.x * blockDim.x + threadIdx.x;
    if (idx < NN * DD) {
        float v = src[idx];
        g_x[idx] = v;
        __nv_bfloat16 h = __float2bfloat16_rn(v);
        g_Ahi[idx] = h;
        g_Alo[idx] = __float2bfloat16_rn(v - __bfloat162float(h));
    }
}
__global__ void convW_kernel(const float* __restrict__ W, __nv_bfloat16* __restrict__ hi,
                             __nv_bfloat16* __restrict__ lo, int K, int N) {
    __shared__ float tile[32][33];
    size_t lw = (size_t)blockIdx.z * K * N;
    int n0 = blockIdx.x * 32, k0 = blockIdx.y * 32;
    int tx = threadIdx.x, ty = threadIdx.y;
    #pragma unroll
    for (int r = 0; r < 4; r++)
        tile[ty + r * 8][tx] = W[lw + (size_t)(k0 + ty + r * 8) * N + n0 + tx];
    __syncthreads();
    #pragma unroll
    for (int r = 0; r < 4; r++) {
        int ni = ty + r * 8;
        float v = tile[tx][ni];
        __nv_bfloat16 h = __float2bfloat16_rn(v);
        size_t o = lw + (size_t)(n0 + ni) * K + k0 + tx;
        hi[o] = h;
        lo[o] = __float2bfloat16_rn(v - __bfloat162float(h));
    }
}

// ============================ mma.sync bf16x3 GEMM (BK=64, 2-stage, TM=64) ============================
template<int EPI, int TM>  // EPI: 0 fp32 out; 2 bf16 hi/lo out; 3 GELU + bf16 hi/lo out
__global__ void __launch_bounds__(256) mma_gemm_kernel(
    const __nv_bfloat16* __restrict__ Ahi, const __nv_bfloat16* __restrict__ Alo,
    const __nv_bfloat16* __restrict__ Bhi, const __nv_bfloat16* __restrict__ Blo,
    const float* __restrict__ bias, float* __restrict__ C,
    __nv_bfloat16* __restrict__ Chi, __nv_bfloat16* __restrict__ Clo, int N, int K)
{
    constexpr int MBN    = TM / 64;
    constexpr int ABYTES = TM * 128;
    constexpr int STAGE  = 2 * ABYTES + 32768;
    extern __shared__ char smem[];
    const int tid  = threadIdx.x;
    const int lane = tid & 31;
    const int wid  = tid >> 5;
    const int m0 = blockIdx.y * TM, n0 = blockIdx.x * 128;
    const int wrow = (wid >> 1) * (16 * MBN);
    const int wcol = (wid & 1) * 64;
    const uint32_t sbase = smem_to_u32(smem);

    float acc[MBN][8][4];
    #pragma unroll
    for (int a = 0; a < MBN; a++)
        #pragma unroll
        for (int b = 0; b < 8; b++)
            #pragma unroll
            for (int c = 0; c < 4; c++) acc[a][b][c] = 0.f;

    const int nc = K >> 6;

    auto loadChunk = [&](int c) {
        uint32_t sb = sbase + (uint32_t)(c & 1) * STAGE;
        int k0 = c << 6;
        #pragma unroll
        for (int t2 = 0; t2 < 2; t2++) {
            const __nv_bfloat16* s = t2 ? Alo : Ahi;
            #pragma unroll
            for (int it = 0; it < TM / 32; it++) {
                int idx = it * 256 + tid;
                int row = idx >> 3, ch = idx & 7;
                CP_ASYNC16(sb + t2 * ABYTES + ASM_OFF(row, ch),
                           s + (size_t)(m0 + row) * K + k0 + ch * 8);
            }
        }
        #pragma unroll
        for (int t2 = 0; t2 < 2; t2++) {
            const __nv_bfloat16* s = t2 ? Blo : Bhi;
            #pragma unroll
            for (int it = 0; it < 4; it++) {
                int idx = it * 256 + tid;
                int row = idx >> 3, ch = idx & 7;
                CP_ASYNC16(sb + 2 * ABYTES + t2 * 16384 + ASM_OFF(row, ch),
                           s + (size_t)(n0 + row) * K + k0 + ch * 8);
            }
        }
        CP_COMMIT();
    };

    loadChunk(0);
    if (nc > 1) loadChunk(1);

    for (int c = 0; c < nc; c++) {
        if (c + 1 < nc) CP_WAIT1(); else CP_WAIT0();
        __syncthreads();
        uint32_t sb = sbase + (uint32_t)(c & 1) * STAGE;
        uint32_t sAh = sb, sAl = sb + ABYTES, sBh = sb + 2 * ABYTES, sBl = sb + 2 * ABYTES + 16384;
        #pragma unroll
        for (int ks = 0; ks < 4; ks++) {
            uint32_t ah[MBN][4], al[MBN][4], bh[4][4], bl[4][4];
            {
                int sub = lane >> 3;
                int row16 = (lane & 7) + ((sub & 1) << 3);
                int kc = ks * 2 + (sub >> 1);
                #pragma unroll
                for (int mb = 0; mb < MBN; mb++) {
                    int row = wrow + mb * 16 + row16;
                    uint32_t off = ASM_OFF(row, kc);
                    ldsm4(ah[mb], sAh + off);
                    ldsm4(al[mb], sAl + off);
                }
            }
            {
                int sub = lane >> 3;
                int kc = ks * 2 + (sub & 1);
                int nr = ((sub >> 1) << 3) + (lane & 7);
                #pragma unroll
                for (int j = 0; j < 4; j++) {
                    int row = wcol + j * 16 + nr;
                    uint32_t off = ASM_OFF(row, kc);
                    ldsm4(bh[j], sBh + off);
                    ldsm4(bl[j], sBl + off);
                }
            }
            #pragma unroll
            for (int mb = 0; mb < MBN; mb++)
                #pragma unroll
                for (int j = 0; j < 4; j++) {
                    mma16816(acc[mb][2*j],     ah[mb], &bh[j][0]);
                    mma16816(acc[mb][2*j],     ah[mb], &bl[j][0]);
                    mma16816(acc[mb][2*j],     al[mb], &bh[j][0]);
                    mma16816(acc[mb][2*j + 1], ah[mb], &bh[j][2]);
                    mma16816(acc[mb][2*j + 1], ah[mb], &bl[j][2]);
                    mma16816(acc[mb][2*j + 1], al[mb], &bh[j][2]);
                }
        }
        __syncthreads();
        if (c + 2 < nc) loadChunk(c + 2);
    }

    const int r_l = lane >> 2;
    const int c_l = (lane & 3) << 1;
    #pragma unroll
    for (int mb = 0; mb < MBN; mb++) {
        #pragma unroll
        for (int nb = 0; nb < 8; nb++) {
            int row = m0 + wrow + mb * 16 + r_l;
            int col = n0 + wcol + nb * 8 + c_l;
            float b0 = bias[col], b1 = bias[col + 1];
            float v0 = acc[mb][nb][0] + b0;
            float v1 = acc[mb][nb][1] + b1;
            float v2 = acc[mb][nb][2] + b0;
            float v3 = acc[mb][nb][3] + b1;
            if (EPI == 3) {
                v0 = 0.5f * v0 * (1.f + erff(v0 * 0.70710678118654752f));
                v1 = 0.5f * v1 * (1.f + erff(v1 * 0.70710678118654752f));
                v2 = 0.5f * v2 * (1.f + erff(v2 * 0.70710678118654752f));
                v3 = 0.5f * v3 * (1.f + erff(v3 * 0.70710678118654752f));
            }
            if (EPI == 0) {
                *reinterpret_cast<float2*>(C + (size_t)row * N + col)       = make_float2(v0, v1);
                *reinterpret_cast<float2*>(C + (size_t)(row + 8) * N + col) = make_float2(v2, v3);
            } else {
                __nv_bfloat162 h01 = __floats2bfloat162_rn(v0, v1);
                __nv_bfloat162 h23 = __floats2bfloat162_rn(v2, v3);
                __nv_bfloat162 l01 = __floats2bfloat162_rn(v0 - __bfloat162float(h01.x),
                                                           v1 - __bfloat162float(h01.y));
                __nv_bfloat162 l23 = __floats2bfloat162_rn(v2 - __bfloat162float(h23.x),
                                                           v3 - __bfloat162float(h23.y));
                *reinterpret_cast<__nv_bfloat162*>(Chi + (size_t)row * N + col)       = h01;
                *reinterpret_cast<__nv_bfloat162*>(Chi + (size_t)(row + 8) * N + col) = h23;
                *reinterpret_cast<__nv_bfloat162*>(Clo + (size_t)row * N + col)       = l01;
                *reinterpret_cast<__nv_bfloat162*>(Clo + (size_t)(row + 8) * N + col) = l23;
            }
        }
    }
}

// ============================ tensor-core attention (double-buffered K/V, NSL=2 slices) ============================
#define AT_QH   0
#define AT_QL   16384
#define AT_KV   32768
#define AT_BIAS 98304
#define AT_SMEM (98304 + 512)
#define NCHUNK  (NN / NSL / 64)   // 16 K/V chunks per block

__global__ void __launch_bounds__(128) attn_tc_kernel(
    const __nv_bfloat16* __restrict__ qh, const __nv_bfloat16* __restrict__ ql,
    const float* __restrict__ pep, float* __restrict__ part, float* __restrict__ plsum)
{
    extern __shared__ char sm[];
    const int h = blockIdx.y, sl = blockIdx.z;
    const int q0 = blockIdx.x * 128;
    const int tid = threadIdx.x, lane = tid & 31, wid = tid >> 5;
    const int wrow = wid * 32;
    const int sub = lane >> 3;
    const uint32_t sb = smem_to_u32(sm);
    float* bias = reinterpret_cast<float*>(sm + AT_BIAS);

    #pragma unroll
    for (int it = 0; it < 8; it++) {
        int idx = it * 128 + tid;
        int row = idx >> 3, ch = idx & 7;
        size_t g = (size_t)(q0 + row) * 1536 + h * 64 + ch * 8;
        uint32_t off = ASM_OFF(row, ch);
        CP_ASYNC16(sb + AT_QH + off, qh + g);
        CP_ASYNC16(sb + AT_QL + off, ql + g);
    }
    {
        const int kk = sl * (NN / NSL);
        uint32_t stb = sb + AT_KV;
        #pragma unroll
        for (int it = 0; it < 4; it++) {
            int idx = it * 128 + tid;
            int row = idx >> 3, ch = idx & 7;
            size_t gk = (size_t)(kk + row) * 1536 + 512 + h * 64 + ch * 8;
            uint32_t off = ASM_OFF(row, ch);
            CP_ASYNC16(stb + off,         qh + gk);
            CP_ASYNC16(stb + 8192 + off,  ql + gk);
            CP_ASYNC16(stb + 16384 + off, qh + gk + 512);
            CP_ASYNC16(stb + 24576 + off, ql + gk + 512);
        }
        if (tid < 64) bias[tid] = pep[(size_t)(kk + tid) * HH + h];
    }
    CP_COMMIT();

    float O[2][8][4];
    float ls[2][2] = {{0.f, 0.f}, {0.f, 0.f}};
    #pragma unroll
    for (int mb = 0; mb < 2; mb++)
        #pragma unroll
        for (int nb = 0; nb < 8; nb++)
            #pragma unroll
            for (int u = 0; u < 4; u++) O[mb][nb][u] = 0.f;

    for (int c = 0; c < NCHUNK; c++) {
        CP_WAIT0();
        __syncthreads();
        if (c < NCHUNK - 1) {
            const int kn = sl * (NN / NSL) + (c + 1) * 64;
            uint32_t stb = sb + AT_KV + (uint32_t)((c + 1) & 1) * 32768;
            #pragma unroll
            for (int it = 0; it < 4; it++) {
                int idx = it * 128 + tid;
                int row = idx >> 3, ch = idx & 7;
                size_t gk = (size_t)(kn + row) * 1536 + 512 + h * 64 + ch * 8;
                uint32_t off = ASM_OFF(row, ch);
                CP_ASYNC16(stb + off,         qh + gk);
                CP_ASYNC16(stb + 8192 + off,  ql + gk);
                CP_ASYNC16(stb + 16384 + off, qh + gk + 512);
                CP_ASYNC16(stb + 24576 + off, ql + gk + 512);
            }
            if (tid < 64) bias[((c + 1) & 1) * 64 + tid] = pep[(size_t)(kn + tid) * HH + h];
            CP_COMMIT();
        }
        const uint32_t stc = sb + AT_KV + (uint32_t)(c & 1) * 32768;
        const uint32_t sKH = stc, sKL = stc + 8192, sVH = stc + 16384, sVL = stc + 24576;
        const float* bs = bias + (c & 1) * 64;

        float S[2][8][4];
        #pragma unroll
        for (int mb = 0; mb < 2; mb++)
            #pragma unroll
            for (int nb = 0; nb < 8; nb++)
                #pragma unroll
                for (int u = 0; u < 4; u++) S[mb][nb][u] = 0.f;
        #pragma unroll
        for (int kb = 0; kb < 4; kb++) {
            uint32_t ah[2][4], al[2][4];
            int r16 = (lane & 7) + ((sub & 1) << 3);
            int chA = kb * 2 + (sub >> 1);
            #pragma unroll
            for (int mb = 0; mb < 2; mb++) {
                int row = wrow + mb * 16 + r16;
                uint32_t off = ASM_OFF(row, chA);
                ldsm4(ah[mb], sb + AT_QH + off);
                ldsm4(al[mb], sb + AT_QL + off);
            }
            int chB = kb * 2 + (sub & 1);
            int nr = ((sub >> 1) << 3) + (lane & 7);
            #pragma unroll
            for (int j = 0; j < 4; j++) {
                uint32_t bh[4], bl[4];
                int row = j * 16 + nr;
                uint32_t off = ASM_OFF(row, chB);
                ldsm4(bh, sKH + off);
                ldsm4(bl, sKL + off);
                #pragma unroll
                for (int mb = 0; mb < 2; mb++) {
                    mma16816(S[mb][2*j],   ah[mb], &bh[0]);
                    mma16816(S[mb][2*j],   al[mb], &bh[0]);
                    mma16816(S[mb][2*j],   ah[mb], &bl[0]);
                    mma16816(S[mb][2*j+1], ah[mb], &bh[2]);
                    mma16816(S[mb][2*j+1], al[mb], &bh[2]);
                    mma16816(S[mb][2*j+1], ah[mb], &bl[2]);
                }
            }
        }

        uint32_t Ph[2][8][2], Pl[2][8][2];
        #pragma unroll
        for (int mb = 0; mb < 2; mb++)
            #pragma unroll
            for (int nb = 0; nb < 8; nb++) {
                int col = nb * 8 + ((lane & 3) << 1);
                float b0 = bs[col], b1 = bs[col + 1];
                float p0 = __expf(fmaf(S[mb][nb][0], 0.125f, -b0));
                float p1 = __expf(fmaf(S[mb][nb][1], 0.125f, -b1));
                float p2 = __expf(fmaf(S[mb][nb][2], 0.125f, -b0));
                float p3 = __expf(fmaf(S[mb][nb][3], 0.125f, -b1));
                ls[mb][0] += p0 + p1;
                ls[mb][1] += p2 + p3;
                __nv_bfloat162 h01 = __floats2bfloat162_rn(p0, p1);
                __nv_bfloat162 h23 = __floats2bfloat162_rn(p2, p3);
                __nv_bfloat162 l01 = __floats2bfloat162_rn(p0 - __bfloat162float(h01.x),
                                                           p1 - __bfloat162float(h01.y));
                __nv_bfloat162 l23 = __floats2bfloat162_rn(p2 - __bfloat162float(h23.x),
                                                           p3 - __bfloat162float(h23.y));
                Ph[mb][nb][0] = *reinterpret_cast<uint32_t*>(&h01);
                Ph[mb][nb][1] = *reinterpret_cast<uint32_t*>(&h23);
                Pl[mb][nb][0] = *reinterpret_cast<uint32_t*>(&l01);
                Pl[mb][nb][1] = *reinterpret_cast<uint32_t*>(&l23);
            }

        #pragma unroll
        for (int kb2 = 0; kb2 < 4; kb2++) {
            int krow = kb2 * 16 + ((sub & 1) << 3) + (lane & 7);
            #pragma unroll
            for (int dI = 0; dI < 4; dI++) {
                uint32_t vh[4], vl[4];
                int ch = dI * 2 + (sub >> 1);
                uint32_t off = ASM_OFF(krow, ch);
                ldsm4t(vh, sVH + off);
                ldsm4t(vl, sVL + off);
                #pragma unroll
                for (int mb = 0; mb < 2; mb++) {
                    uint32_t pa[4] = {Ph[mb][2*kb2][0], Ph[mb][2*kb2][1],
                                      Ph[mb][2*kb2+1][0], Ph[mb][2*kb2+1][1]};
                    uint32_t la[4] = {Pl[mb][2*kb2][0], Pl[mb][2*kb2][1],
                                      Pl[mb][2*kb2+1][0], Pl[mb][2*kb2+1][1]};
                    mma16816(O[mb][2*dI],   pa, &vh[0]);
                    mma16816(O[mb][2*dI],   la, &vh[0]);
                    mma16816(O[mb][2*dI],   pa, &vl[0]);
                    mma16816(O[mb][2*dI+1], pa, &vh[2]);
                    mma16816(O[mb][2*dI+1], la, &vh[2]);
                    mma16816(O[mb][2*dI+1], pa, &vl[2]);
                }
            }
        }
    }

    #pragma unroll
    for (int mb = 0; mb < 2; mb++)
        #pragma unroll
        for (int r = 0; r < 2; r++) {
            float v = ls[mb][r];
            v += __shfl_xor_sync(0xffffffffu, v, 1);
            v += __shfl_xor_sync(0xffffffffu, v, 2);
            ls[mb][r] = v;
        }
    const size_t base = (size_t)(sl * HH + h) * NN;
    #pragma unroll
    for (int mb = 0; mb < 2; mb++) {
        int rowA = q0 + wrow + mb * 16 + (lane >> 2);
        int rowB = rowA + 8;
        if ((lane & 3) == 0) {
            plsum[base + rowA] = ls[mb][0];
            plsum[base + rowB] = ls[mb][1];
        }
        #pragma unroll
        for (int nb = 0; nb < 8; nb++) {
            int col = nb * 8 + ((lane & 3) << 1);
            *reinterpret_cast<float2*>(part + (base + rowA) * 64 + col) = make_float2(O[mb][nb][0], O[mb][nb][1]);
            *reinterpret_cast<float2*>(part + (base + rowB) * 64 + col) = make_float2(O[mb][nb][2], O[mb][nb][3]);
        }
    }
}

__global__ void attn_combine_kernel(const float* __restrict__ part, const float* __restrict__ pls,
                                    __nv_bfloat16* __restrict__ ohi, __nv_bfloat16* __restrict__ olo) {
    int i = blockIdx.x, t = threadIdx.x;
    #pragma unroll
    for (int rep = 0; rep < 2; rep++) {
        int idx = t + rep * 256;
        int h = idx >> 6, d = idx & 63;
        float v = 0.f, l = 0.f;
        #pragma unroll
        for (int s = 0; s < NSL; s++) {
            l += pls[(size_t)(s * HH + h) * NN + i];
            v += part[((size_t)(s * HH + h) * NN + i) * 64 + d];
        }
        float r = v / l;
        __nv_bfloat16 hb = __float2bfloat16_rn(r);
        ohi[(size_t)i * DD + idx] = hb;
        olo[(size_t)i * DD + idx] = __float2bfloat16_rn(r - __bfloat162float(hb));
    }
}

// ============================ LN (fp32 out + bf16 hi/lo) ============================
__global__ void ln_kernel(const float* __restrict__ a, const float* __restrict__ b,
                          const float* __restrict__ g, const float* __restrict__ be,
                          float* __restrict__ out,
                          __nv_bfloat16* __restrict__ ohi, __nv_bfloat16* __restrict__ olo) {
    __shared__ float sh[256];
    __shared__ float s_mu, s_r;
    int i = blockIdx.x, t = threadIdx.x;
    float v0 = a[(size_t)i * DD + t]       + b[(size_t)i * DD + t];
    float v1 = a[(size_t)i * DD + 256 + t] + b[(size_t)i * DD + 256 + t];
    sh[t] = v0 + v1; __syncthreads();
    for (int k = 128; k > 0; k >>= 1) { if (t < k) sh[t] += sh[t + k]; __syncthreads(); }
    if (t == 0) s_mu = sh[0] * (1.f / DD);
    __syncthreads();
    float mu = s_mu;
    float d0 = v0 - mu, d1 = v1 - mu;
    sh[t] = d0 * d0 + d1 * d1; __syncthreads();
    for (int k = 128; k > 0; k >>= 1) { if (t < k) sh[t] += sh[t + k]; __syncthreads(); }
    if (t == 0) s_r = rsqrtf(sh[0] * (1.f / DD) + 1e-5f);
    __syncthreads();
    float r = s_r;
    float o0 = d0 * r * g[t]       + be[t];
    float o1 = d1 * r * g[256 + t] + be[256 + t];
    out[(size_t)i * DD + t]       = o0;
    out[(size_t)i * DD + 256 + t] = o1;
    __nv_bfloat16 h0 = __float2bfloat16_rn(o0);
    __nv_bfloat16 h1 = __float2bfloat16_rn(o1);
    ohi[(size_t)i * DD + t]       = h0;
    ohi[(size_t)i * DD + 256 + t] = h1;
    olo[(size_t)i * DD + t]       = __float2bfloat16_rn(o0 - __bfloat162float(h0));
    olo[(size_t)i * DD + 256 + t] = __float2bfloat16_rn(o1 - __bfloat162float(h1));
}

// ============================ launch ============================
extern "C" void kernel_launch(void* const* d_in, const int* in_sizes, int n_in,
                              void* d_out, int out_size) {
    const float* node_features = (const float*)d_in[0];
    const int*   edge_index    = (const int*)  d_in[1];
    const float* pe_proj_W     = (const float*)d_in[2];
    const float* pe_proj_b     = (const float*)d_in[3];
    const float* qkv_W         = (const float*)d_in[4];
    const float* qkv_b         = (const float*)d_in[5];
    const float* peb_W         = (const float*)d_in[6];
    const float* peb_b         = (const float*)d_in[7];
    const float* out_W         = (const float*)d_in[8];
    const float* out_b         = (const float*)d_in[9];
    const float* ffn_W1        = (const float*)d_in[10];
    const float* ffn_b1        = (const float*)d_in[11];
    const float* ffn_W2        = (const float*)d_in[12];
    const float* ffn_b2        = (const float*)d_in[13];
    const float* ln1_g         = (const float*)d_in[14];
    const float* ln1_b         = (const float*)d_in[15];
    const float* ln2_g         = (const float*)d_in[16];
    const float* ln2_b         = (const float*)d_in[17];
    float* outp = (float*)d_out;

    float *x_, *x1_, *o_, *pep_, *part_, *pls_;
    __nv_bfloat16 *Ahi_, *Alo_, *Hhi_, *Hlo_, *Qh_, *Ql_, *T2b_, *T3b_, *T4b_;
    __nv_bfloat16 *qWh_, *qWl_, *oWh_, *oWl_, *f1h_, *f1l_, *f2h_, *f2l_;
    cudaGetSymbolAddress((void**)&x_,   g_x);
    cudaGetSymbolAddress((void**)&x1_,  g_x1);
    cudaGetSymbolAddress((void**)&o_,   g_o);
    cudaGetSymbolAddress((void**)&pep_, g_pep);
    cudaGetSymbolAddress((void**)&part_,g_part);
    cudaGetSymbolAddress((void**)&pls_, g_plsum);
    cudaGetSymbolAddress((void**)&Ahi_, g_Ahi);
    cudaGetSymbolAddress((void**)&Alo_, g_Alo);
    cudaGetSymbolAddress((void**)&Hhi_, g_Hhi);
    cudaGetSymbolAddress((void**)&Hlo_, g_Hlo);
    cudaGetSymbolAddress((void**)&Qh_,  g_QKVhi);
    cudaGetSymbolAddress((void**)&Ql_,  g_QKVlo);
    cudaGetSymbolAddress((void**)&T2b_, g_T2b);
    cudaGetSymbolAddress((void**)&T3b_, g_T3b);
    cudaGetSymbolAddress((void**)&T4b_, g_T4b);
    cudaGetSymbolAddress((void**)&qWh_, g_qkvW_hi);
    cudaGetSymbolAddress((void**)&qWl_, g_qkvW_lo);
    cudaGetSymbolAddress((void**)&oWh_, g_outW_hi);
    cudaGetSymbolAddress((void**)&oWl_, g_outW_lo);
    cudaGetSymbolAddress((void**)&f1h_, g_f1W_hi);
    cudaGetSymbolAddress((void**)&f1l_, g_f1W_lo);
    cudaGetSymbolAddress((void**)&f2h_, g_f2W_hi);
    cudaGetSymbolAddress((void**)&f2l_, g_f2W_lo);

    constexpr int GS64 = 2 * (2 * 64 * 128 + 32768);   // 96 KB -> 2 CTA/SM
    cudaFuncSetAttribute(mma_gemm_kernel<2,64>, cudaFuncAttributeMaxDynamicSharedMemorySize, GS64);
    cudaFuncSetAttribute(mma_gemm_kernel<3,64>, cudaFuncAttributeMaxDynamicSharedMemorySize, GS64);
    cudaFuncSetAttribute(mma_gemm_kernel<0,64>, cudaFuncAttributeMaxDynamicSharedMemorySize, GS64);
    cudaFuncSetAttribute(attn_tc_kernel, cudaFuncAttributeMaxDynamicSharedMemorySize, AT_SMEM);

    static cudaStream_t s_side = nullptr;
    static cudaEvent_t  ev_fork = nullptr, ev_pe = nullptr;
    if (s_side == nullptr) {
        cudaStreamCreateWithFlags(&s_side, cudaStreamNonBlocking);
        cudaEventCreateWithFlags(&ev_fork, cudaEventDisableTiming);
        cudaEventCreateWithFlags(&ev_pe,   cudaEventDisableTiming);
    }

    // ---- fork: PE pipeline on side stream ----
    cudaEventRecord(ev_fork, 0);
    cudaStreamWaitEvent(s_side, ev_fork, 0);
    zero_bm_kernel<<<(NN*64)/256, 256, 0, s_side>>>();
    scatter_bm_kernel<<<EEC/256, 256, 0, s_side>>>(edge_index);
    build_bm_kernel<<<NN, 64, 0, s_side>>>();
    t2_kernel<<<NN, 256, 0, s_side>>>();
    spmm_bf_kernel<<<NN, 256, 0, s_side>>>(T2b_, T3b_);
    spmm_bf_kernel<<<NN, 256, 0, s_side>>>(T3b_, T4b_);
    diag2_kernel<<<NN, 256, 0, s_side>>>();
    pe_kernel<<<(NN + 127) / 128, 128, 0, s_side>>>(pe_proj_W, pe_proj_b);
    pep_kernel<<<(NN + 127) / 128, 128, 0, s_side>>>(peb_W, peb_b);
    cudaEventRecord(ev_pe, s_side);

    // ---- main stream ----
    convW_kernel<<<dim3(1536/32, 512/32, LLC),  dim3(32,8)>>>(qkv_W,  qWh_, qWl_, DD,  3*DD);
    convW_kernel<<<dim3(512/32,  512/32, LLC),  dim3(32,8)>>>(out_W,  oWh_, oWl_, DD,  DD);
    convW_kernel<<<dim3(2048/32, 512/32, LLC),  dim3(32,8)>>>(ffn_W1, f1h_, f1l_, DD,  DFFC);
    convW_kernel<<<dim3(512/32,  2048/32, LLC), dim3(32,8)>>>(ffn_W2, f2h_, f2l_, DFFC, DD);
    split_copy_kernel<<<(NN*DD)/256, 256>>>(node_features);

    for (int l = 0; l < LLC; l++) {
        mma_gemm_kernel<2,64><<<dim3(1536/128, NN/64), 256, GS64>>>(
            Ahi_, Alo_, qWh_ + (size_t)l*3*DD*DD, qWl_ + (size_t)l*3*DD*DD,
            qkv_b + (size_t)l*3*DD, nullptr, Qh_, Ql_, 3*DD, DD);
        if (l == 0) cudaStreamWaitEvent(0, ev_pe, 0);   // join: attention needs pep
        attn_tc_kernel<<<dim3(NN/128, HH, NSL), 128, AT_SMEM>>>(Qh_, Ql_, pep_ + (size_t)l*NN*HH, part_, pls_);
        attn_combine_kernel<<<NN, 256>>>(part_, pls_, Ahi_, Alo_);
        mma_gemm_kernel<0,64><<<dim3(DD/128, NN/64), 256, GS64>>>(
            Ahi_, Alo_, oWh_ + (size_t)l*DD*DD, oWl_ + (size_t)l*DD*DD,
            out_b + (size_t)l*DD, o_, nullptr, nullptr, DD, DD);
        ln_kernel<<<NN, 256>>>(x_, o_, ln1_g + (size_t)l*DD, ln1_b + (size_t)l*DD, x1_, Ahi_, Alo_);
        mma_gemm_kernel<3,64><<<dim3(DFFC/128, NN/64), 256, GS64>>>(
            Ahi_, Alo_, f1h_ + (size_t)l*DD*DFFC, f1l_ + (size_t)l*DD*DFFC,
            ffn_b1 + (size_t)l*DFFC, nullptr, Hhi_, Hlo_, DFFC, DD);
        mma_gemm_kernel<0,64><<<dim3(DD/128, NN/64), 256, GS64>>>(
            Hhi_, Hlo_, f2h_ + (size_t)l*DFFC*DD, f2l_ + (size_t)l*DFFC*DD,
            ffn_b2 + (size_t)l*DD, o_, nullptr, nullptr, DD, DFFC);
        float* xout = (l == LLC - 1) ? outp : x_;
        ln_kernel<<<NN, 256>>>(x1_, o_, ln2_g + (size_t)l*DD, ln2_b + (size_t)l*DD, xout, Ahi_, Alo_);
    }
}

// round 10
// speedup vs baseline: 1.1199x; 1.0149x over previous
#include <cuda_runtime.h>
#include <cuda_bf16.h>
#include <math.h>
#include <stdint.h>

#define NN   2048
#define DD   512
#define HH   8
#define DPEC 16
#define WALKC 8
#define LLC  3
#define EEC  32768
#define DFFC 2048
#define MAXD 256
#define NSL  2          // attention key-slices

// ============================ PTX helpers (sm_80-baseline ISA only) ============================
__device__ __forceinline__ uint32_t smem_to_u32(const void* p) {
    uint32_t a;
    asm("{ .reg .u64 t; cvta.to.shared.u64 t, %1; cvt.u32.u64 %0, t; }" : "=r"(a) : "l"(p));
    return a;
}
#define CP_ASYNC16(dst, src) \
    asm volatile("cp.async.cg.shared.global [%0], [%1], 16;" :: "r"(dst), "l"(src))
#define CP_COMMIT() asm volatile("cp.async.commit_group;" ::: "memory")
#define CP_WAIT1()  asm volatile("cp.async.wait_group 1;" ::: "memory")
#define CP_WAIT0()  asm volatile("cp.async.wait_group 0;" ::: "memory")

__device__ __forceinline__ void ldsm4(uint32_t* r, uint32_t addr) {
    asm volatile("ldmatrix.sync.aligned.m8n8.x4.shared.b16 {%0,%1,%2,%3}, [%4];"
        : "=r"(r[0]), "=r"(r[1]), "=r"(r[2]), "=r"(r[3]) : "r"(addr));
}
__device__ __forceinline__ void ldsm4t(uint32_t* r, uint32_t addr) {
    asm volatile("ldmatrix.sync.aligned.m8n8.x4.trans.shared.b16 {%0,%1,%2,%3}, [%4];"
        : "=r"(r[0]), "=r"(r[1]), "=r"(r[2]), "=r"(r[3]) : "r"(addr));
}
__device__ __forceinline__ void mma16816(float* c, const uint32_t* a, const uint32_t* b) {
    asm volatile("mma.sync.aligned.m16n8k16.row.col.f32.bf16.bf16.f32 "
        "{%0,%1,%2,%3}, {%4,%5,%6,%7}, {%8,%9}, {%0,%1,%2,%3};"
        : "+f"(c[0]), "+f"(c[1]), "+f"(c[2]), "+f"(c[3])
        : "r"(a[0]), "r"(a[1]), "r"(a[2]), "r"(a[3]), "r"(b[0]), "r"(b[1]));
}

#define ASM_OFF(row, ch) ((uint32_t)((row) * 128 + ((((ch)) ^ ((row) & 7)) << 4)))

// ============================ static device scratch ============================
__device__ uint32_t g_bm[NN*64];
__device__ float g_deg[NN];
__device__ float g_invdeg[NN];
__device__ int   g_nbr[NN*MAXD];
__device__ int   g_cnt[NN];
__device__ __nv_bfloat16 g_T2b[NN*NN];
__device__ __nv_bfloat16 g_T3b[NN*NN];
__device__ __nv_bfloat16 g_T4b[NN*NN];
__device__ float g_rw [NN*WALKC];
__device__ float g_pe [NN*DPEC];
__device__ float g_pep[LLC*NN*HH];
__device__ float g_x   [NN*DD];
__device__ float g_x1  [NN*DD];
__device__ float g_o   [2*NN*DD];     // split-K partials
__device__ __nv_bfloat16 g_Ahi[NN*DD];
__device__ __nv_bfloat16 g_Alo[NN*DD];
__device__ __nv_bfloat16 g_Hhi[NN*DFFC];
__device__ __nv_bfloat16 g_Hlo[NN*DFFC];
__device__ __nv_bfloat16 g_QKVhi[NN*3*DD];
__device__ __nv_bfloat16 g_QKVlo[NN*3*DD];
__device__ __nv_bfloat16 g_qkvW_hi[LLC*3*DD*DD];
__device__ __nv_bfloat16 g_qkvW_lo[LLC*3*DD*DD];
__device__ __nv_bfloat16 g_outW_hi[LLC*DD*DD];
__device__ __nv_bfloat16 g_outW_lo[LLC*DD*DD];
__device__ __nv_bfloat16 g_f1W_hi[LLC*DD*DFFC];
__device__ __nv_bfloat16 g_f1W_lo[LLC*DD*DFFC];
__device__ __nv_bfloat16 g_f2W_hi[LLC*DFFC*DD];
__device__ __nv_bfloat16 g_f2W_lo[LLC*DFFC*DD];
__device__ float g_part [NSL*HH*NN*64];
__device__ float g_plsum[NSL*HH*NN];

// ============================ PE pipeline (sparse) ============================
__global__ void zero_bm_kernel() {
    int idx = blockIdx.x * blockDim.x + threadIdx.x;
    if (idx < NN * 64) g_bm[idx] = 0u;
}
__global__ void scatter_bm_kernel(const int* __restrict__ ei) {
    int e = blockIdx.x * blockDim.x + threadIdx.x;
    if (e < EEC) {
        int s = ei[e], t = ei[EEC + e];
        atomicOr(&g_bm[s * 64 + (t >> 5)], 1u << (t & 31));
        atomicOr(&g_bm[t * 64 + (s >> 5)], 1u << (s & 31));
    }
}
__global__ void build_bm_kernel() {
    __shared__ int cnt;
    int i = blockIdx.x, t = threadIdx.x;
    if (t == 0) cnt = 0;
    __syncthreads();
    uint32_t w = g_bm[i * 64 + t];
    int c = __popc(w);
    int pos = (c > 0) ? atomicAdd(&cnt, c) : 0;
    while (w) {
        int b = __ffs(w) - 1;
        w &= w - 1;
        if (pos < MAXD) g_nbr[i * MAXD + pos] = t * 32 + b;
        pos++;
    }
    __syncthreads();
    if (t == 0) {
        int cc = cnt < MAXD ? cnt : MAXD;
        g_cnt[i] = cc;
        float d = cnt < 1 ? 1.f : (float)cnt;
        g_deg[i] = d;
        g_invdeg[i] = 1.f / d;
    }
}
__global__ void __launch_bounds__(256) t2_kernel() {
    __shared__ float rowbuf[NN];
    int i = blockIdx.x, t = threadIdx.x;
    #pragma unroll
    for (int u = 0; u < NN / 256; u++) rowbuf[t + u * 256] = 0.f;
    __syncthreads();
    int cnt = g_cnt[i];
    float inv_i = g_invdeg[i];
    for (int c = t >> 3; c < cnt; c += 32) {
        int j = g_nbr[i * MAXD + c];
        float w = inv_i * g_invdeg[j];
        int cj = g_cnt[j];
        const int* nbj = g_nbr + j * MAXD;
        for (int k = t & 7; k < cj; k += 8) atomicAdd(&rowbuf[nbj[k]], w);
    }
    __syncthreads();
    __nv_bfloat16* out = g_T2b + (size_t)i * NN;
    #pragma unroll
    for (int u = 0; u < NN / 256; u++) {
        int idx = t + u * 256;
        out[idx] = __float2bfloat16_rn(rowbuf[idx]);
    }
}
__global__ void __launch_bounds__(256) spmm_bf_kernel(const __nv_bfloat16* __restrict__ IN,
                                                      __nv_bfloat16* __restrict__ OUT) {
    int i = blockIdx.x, t = threadIdx.x;
    int cnt = g_cnt[i];
    float inv = g_invdeg[i];
    const int* nb = g_nbr + i * MAXD;
    float2 acc[4];
    #pragma unroll
    for (int u = 0; u < 4; u++) acc[u] = make_float2(0.f, 0.f);
    for (int c = 0; c < cnt; c++) {
        const __nv_bfloat162* row = reinterpret_cast<const __nv_bfloat162*>(IN + (size_t)nb[c] * NN);
        #pragma unroll
        for (int u = 0; u < 4; u++) {
            float2 v = __bfloat1622float2(row[t + u * 256]);
            acc[u].x += v.x; acc[u].y += v.y;
        }
    }
    __nv_bfloat162* out = reinterpret_cast<__nv_bfloat162*>(OUT + (size_t)i * NN);
    #pragma unroll
    for (int u = 0; u < 4; u++)
        out[t + u * 256] = __floats2bfloat162_rn(acc[u].x * inv, acc[u].y * inv);
}
__global__ void diag2_kernel() {
    __shared__ float sh[256];
    __shared__ float res[7];
    int i = blockIdx.x, t = threadIdx.x;
    float inv_i = g_invdeg[i], d_i = g_deg[i];
    int cnt = g_cnt[i];
    const __nv_bfloat16* r2 = g_T2b + (size_t)i * NN;
    const __nv_bfloat16* r3 = g_T3b + (size_t)i * NN;
    const __nv_bfloat16* r4 = g_T4b + (size_t)i * NN;
    float s[7] = {};
    for (int c = t; c < cnt; c += 256) {
        int j = g_nbr[i * MAXD + c];
        float wj = g_invdeg[j];
        s[0] += wj;
        s[1] += __bfloat162float(r2[j]) * wj;
    }
    for (int j = t; j < NN; j += 256) {
        float w = g_invdeg[j];
        float t2 = __bfloat162float(r2[j]);
        float t3 = __bfloat162float(r3[j]);
        float t4 = __bfloat162float(r4[j]);
        s[2] += t2 * t2 * w;
        s[3] += t3 * t2 * w;
        s[4] += t3 * t3 * w;
        s[5] += t4 * t3 * w;
        s[6] += t4 * t4 * w;
    }
    for (int v = 0; v < 7; v++) {
        sh[t] = s[v]; __syncthreads();
        for (int k = 128; k > 0; k >>= 1) { if (t < k) sh[t] += sh[t + k]; __syncthreads(); }
        if (t == 0) res[v] = sh[0];
        __syncthreads();
    }
    if (t == 0) {
        bool self = (g_bm[i * 64 + (i >> 5)] >> (i & 31)) & 1u;
        g_rw[i * WALKC + 0] = self ? inv_i : 0.f;
        g_rw[i * WALKC + 1] = inv_i * res[0];
        g_rw[i * WALKC + 2] = res[1];
        g_rw[i * WALKC + 3] = d_i * res[2];
        g_rw[i * WALKC + 4] = d_i * res[3];
        g_rw[i * WALKC + 5] = d_i * res[4];
        g_rw[i * WALKC + 6] = d_i * res[5];
        g_rw[i * WALKC + 7] = d_i * res[6];
    }
}
__global__ void pe_kernel(const float* __restrict__ W, const float* __restrict__ b) {
    int i = blockIdx.x * blockDim.x + threadIdx.x;
    if (i >= NN) return;
    float r[WALKC];
    #pragma unroll
    for (int w = 0; w < WALKC; w++) r[w] = g_rw[i * WALKC + w];
    #pragma unroll
    for (int d = 0; d < DPEC; d++) {
        float s = b[d];
        #pragma unroll
        for (int w = 0; w < WALKC; w++) s += r[w] * W[w * DPEC + d];
        g_pe[i * DPEC + d] = s;
    }
}
__global__ void pep_kernel(const float* __restrict__ W, const float* __restrict__ b) {
    int i = blockIdx.x * blockDim.x + threadIdx.x;
    if (i >= NN) return;
    float p[DPEC];
    #pragma unroll
    for (int d = 0; d < DPEC; d++) p[d] = g_pe[i * DPEC + d];
    for (int l = 0; l < LLC; l++) {
        #pragma unroll
        for (int h = 0; h < HH; h++) {
            float s = b[l * HH + h];
            #pragma unroll
            for (int d = 0; d < DPEC; d++) s += p[d] * W[(l * DPEC + d) * HH + h];
            g_pep[(size_t)l * NN * HH + i * HH + h] = s;
        }
    }
}

// ============================ conversions ============================
__global__ void split_copy_kernel(const float* __restrict__ src) {
    int idx = blockIdx.x * blockDim.x + threadIdx.x;
    if (idx < NN * DD) {
        float v = src[idx];
        g_x[idx] = v;
        __nv_bfloat16 h = __float2bfloat16_rn(v);
        g_Ahi[idx] = h;
        g_Alo[idx] = __float2bfloat16_rn(v - __bfloat162float(h));
    }
}
__global__ void convW_kernel(const float* __restrict__ W, __nv_bfloat16* __restrict__ hi,
                             __nv_bfloat16* __restrict__ lo, int K, int N) {
    __shared__ float tile[32][33];
    size_t lw = (size_t)blockIdx.z * K * N;
    int n0 = blockIdx.x * 32, k0 = blockIdx.y * 32;
    int tx = threadIdx.x, ty = threadIdx.y;
    #pragma unroll
    for (int r = 0; r < 4; r++)
        tile[ty + r * 8][tx] = W[lw + (size_t)(k0 + ty + r * 8) * N + n0 + tx];
    __syncthreads();
    #pragma unroll
    for (int r = 0; r < 4; r++) {
        int ni = ty + r * 8;
        float v = tile[tx][ni];
        __nv_bfloat16 h = __float2bfloat16_rn(v);
        size_t o = lw + (size_t)(n0 + ni) * K + k0 + tx;
        hi[o] = h;
        lo[o] = __float2bfloat16_rn(v - __bfloat162float(h));
    }
}

// ============================ mma.sync bf16x3 GEMM (BK=64, 2-stage, TM=64, optional split-K) ============================
template<int EPI, int TM, int SPLITK>  // EPI: 0 fp32 out; 2 bf16 hi/lo out; 3 GELU + bf16 hi/lo out
__global__ void __launch_bounds__(256) mma_gemm_kernel(
    const __nv_bfloat16* __restrict__ Ahi, const __nv_bfloat16* __restrict__ Alo,
    const __nv_bfloat16* __restrict__ Bhi, const __nv_bfloat16* __restrict__ Blo,
    const float* __restrict__ bias, float* __restrict__ C,
    __nv_bfloat16* __restrict__ Chi, __nv_bfloat16* __restrict__ Clo, int N, int K)
{
    constexpr int MBN    = TM / 64;
    constexpr int ABYTES = TM * 128;
    constexpr int STAGE  = 2 * ABYTES + 32768;
    extern __shared__ char smem[];
    const int tid  = threadIdx.x;
    const int lane = tid & 31;
    const int wid  = tid >> 5;
    const int m0 = blockIdx.y * TM, n0 = blockIdx.x * 128;
    const int wrow = (wid >> 1) * (16 * MBN);
    const int wcol = (wid & 1) * 64;
    const uint32_t sbase = smem_to_u32(smem);
    const int kseg = K / SPLITK;
    const int koff = (SPLITK > 1) ? blockIdx.z * kseg : 0;

    float acc[MBN][8][4];
    #pragma unroll
    for (int a = 0; a < MBN; a++)
        #pragma unroll
        for (int b = 0; b < 8; b++)
            #pragma unroll
            for (int c = 0; c < 4; c++) acc[a][b][c] = 0.f;

    const int nc = kseg >> 6;

    auto loadChunk = [&](int c) {
        uint32_t sb = sbase + (uint32_t)(c & 1) * STAGE;
        int k0 = koff + (c << 6);
        #pragma unroll
        for (int t2 = 0; t2 < 2; t2++) {
            const __nv_bfloat16* s = t2 ? Alo : Ahi;
            #pragma unroll
            for (int it = 0; it < TM / 32; it++) {
                int idx = it * 256 + tid;
                int row = idx >> 3, ch = idx & 7;
                CP_ASYNC16(sb + t2 * ABYTES + ASM_OFF(row, ch),
                           s + (size_t)(m0 + row) * K + k0 + ch * 8);
            }
        }
        #pragma unroll
        for (int t2 = 0; t2 < 2; t2++) {
            const __nv_bfloat16* s = t2 ? Blo : Bhi;
            #pragma unroll
            for (int it = 0; it < 4; it++) {
                int idx = it * 256 + tid;
                int row = idx >> 3, ch = idx & 7;
                CP_ASYNC16(sb + 2 * ABYTES + t2 * 16384 + ASM_OFF(row, ch),
                           s + (size_t)(n0 + row) * K + k0 + ch * 8);
            }
        }
        CP_COMMIT();
    };

    loadChunk(0);
    if (nc > 1) loadChunk(1);

    for (int c = 0; c < nc; c++) {
        if (c + 1 < nc) CP_WAIT1(); else CP_WAIT0();
        __syncthreads();
        uint32_t sb = sbase + (uint32_t)(c & 1) * STAGE;
        uint32_t sAh = sb, sAl = sb + ABYTES, sBh = sb + 2 * ABYTES, sBl = sb + 2 * ABYTES + 16384;
        #pragma unroll
        for (int ks = 0; ks < 4; ks++) {
            uint32_t ah[MBN][4], al[MBN][4], bh[4][4], bl[4][4];
            {
                int sub = lane >> 3;
                int row16 = (lane & 7) + ((sub & 1) << 3);
                int kc = ks * 2 + (sub >> 1);
                #pragma unroll
                for (int mb = 0; mb < MBN; mb++) {
                    int row = wrow + mb * 16 + row16;
                    uint32_t off = ASM_OFF(row, kc);
                    ldsm4(ah[mb], sAh + off);
                    ldsm4(al[mb], sAl + off);
                }
            }
            {
                int sub = lane >> 3;
                int kc = ks * 2 + (sub & 1);
                int nr = ((sub >> 1) << 3) + (lane & 7);
                #pragma unroll
                for (int j = 0; j < 4; j++) {
                    int row = wcol + j * 16 + nr;
                    uint32_t off = ASM_OFF(row, kc);
                    ldsm4(bh[j], sBh + off);
                    ldsm4(bl[j], sBl + off);
                }
            }
            #pragma unroll
            for (int mb = 0; mb < MBN; mb++)
                #pragma unroll
                for (int j = 0; j < 4; j++) {
                    mma16816(acc[mb][2*j],     ah[mb], &bh[j][0]);
                    mma16816(acc[mb][2*j],     ah[mb], &bl[j][0]);
                    mma16816(acc[mb][2*j],     al[mb], &bh[j][0]);
                    mma16816(acc[mb][2*j + 1], ah[mb], &bh[j][2]);
                    mma16816(acc[mb][2*j + 1], ah[mb], &bl[j][2]);
                    mma16816(acc[mb][2*j + 1], al[mb], &bh[j][2]);
                }
        }
        __syncthreads();
        if (c + 2 < nc) loadChunk(c + 2);
    }

    const int r_l = lane >> 2;
    const int c_l = (lane & 3) << 1;
    float* Cz = C;
    if (SPLITK > 1) Cz = C + (size_t)blockIdx.z * NN * N;
    const bool useBias = (SPLITK == 1) || (blockIdx.z == 0);
    #pragma unroll
    for (int mb = 0; mb < MBN; mb++) {
        #pragma unroll
        for (int nb = 0; nb < 8; nb++) {
            int row = m0 + wrow + mb * 16 + r_l;
            int col = n0 + wcol + nb * 8 + c_l;
            float b0 = useBias ? bias[col]     : 0.f;
            float b1 = useBias ? bias[col + 1] : 0.f;
            float v0 = acc[mb][nb][0] + b0;
            float v1 = acc[mb][nb][1] + b1;
            float v2 = acc[mb][nb][2] + b0;
            float v3 = acc[mb][nb][3] + b1;
            if (EPI == 3) {
                v0 = 0.5f * v0 * (1.f + erff(v0 * 0.70710678118654752f));
                v1 = 0.5f * v1 * (1.f + erff(v1 * 0.70710678118654752f));
                v2 = 0.5f * v2 * (1.f + erff(v2 * 0.70710678118654752f));
                v3 = 0.5f * v3 * (1.f + erff(v3 * 0.70710678118654752f));
            }
            if (EPI == 0) {
                *reinterpret_cast<float2*>(Cz + (size_t)row * N + col)       = make_float2(v0, v1);
                *reinterpret_cast<float2*>(Cz + (size_t)(row + 8) * N + col) = make_float2(v2, v3);
            } else {
                __nv_bfloat162 h01 = __floats2bfloat162_rn(v0, v1);
                __nv_bfloat162 h23 = __floats2bfloat162_rn(v2, v3);
                __nv_bfloat162 l01 = __floats2bfloat162_rn(v0 - __bfloat162float(h01.x),
                                                           v1 - __bfloat162float(h01.y));
                __nv_bfloat162 l23 = __floats2bfloat162_rn(v2 - __bfloat162float(h23.x),
                                                           v3 - __bfloat162float(h23.y));
                *reinterpret_cast<__nv_bfloat162*>(Chi + (size_t)row * N + col)       = h01;
                *reinterpret_cast<__nv_bfloat162*>(Chi + (size_t)(row + 8) * N + col) = h23;
                *reinterpret_cast<__nv_bfloat162*>(Clo + (size_t)row * N + col)       = l01;
                *reinterpret_cast<__nv_bfloat162*>(Clo + (size_t)(row + 8) * N + col) = l23;
            }
        }
    }
}

// ============================ tensor-core attention (double-buffered K/V, NSL=2 slices) ============================
#define AT_QH   0
#define AT_QL   16384
#define AT_KV   32768
#define AT_BIAS 98304
#define AT_SMEM (98304 + 512)
#define NCHUNK  (NN / NSL / 64)

__global__ void __launch_bounds__(128) attn_tc_kernel(
    const __nv_bfloat16* __restrict__ qh, const __nv_bfloat16* __restrict__ ql,
    const float* __restrict__ pep, float* __restrict__ part, float* __restrict__ plsum)
{
    extern __shared__ char sm[];
    const int h = blockIdx.y, sl = blockIdx.z;
    const int q0 = blockIdx.x * 128;
    const int tid = threadIdx.x, lane = tid & 31, wid = tid >> 5;
    const int wrow = wid * 32;
    const int sub = lane >> 3;
    const uint32_t sb = smem_to_u32(sm);
    float* bias = reinterpret_cast<float*>(sm + AT_BIAS);

    #pragma unroll
    for (int it = 0; it < 8; it++) {
        int idx = it * 128 + tid;
        int row = idx >> 3, ch = idx & 7;
        size_t g = (size_t)(q0 + row) * 1536 + h * 64 + ch * 8;
        uint32_t off = ASM_OFF(row, ch);
        CP_ASYNC16(sb + AT_QH + off, qh + g);
        CP_ASYNC16(sb + AT_QL + off, ql + g);
    }
    {
        const int kk = sl * (NN / NSL);
        uint32_t stb = sb + AT_KV;
        #pragma unroll
        for (int it = 0; it < 4; it++) {
            int idx = it * 128 + tid;
            int row = idx >> 3, ch = idx & 7;
            size_t gk = (size_t)(kk + row) * 1536 + 512 + h * 64 + ch * 8;
            uint32_t off = ASM_OFF(row, ch);
            CP_ASYNC16(stb + off,         qh + gk);
            CP_ASYNC16(stb + 8192 + off,  ql + gk);
            CP_ASYNC16(stb + 16384 + off, qh + gk + 512);
            CP_ASYNC16(stb + 24576 + off, ql + gk + 512);
        }
        if (tid < 64) bias[tid] = pep[(size_t)(kk + tid) * HH + h];
    }
    CP_COMMIT();

    float O[2][8][4];
    float ls[2][2] = {{0.f, 0.f}, {0.f, 0.f}};
    #pragma unroll
    for (int mb = 0; mb < 2; mb++)
        #pragma unroll
        for (int nb = 0; nb < 8; nb++)
            #pragma unroll
            for (int u = 0; u < 4; u++) O[mb][nb][u] = 0.f;

    for (int c = 0; c < NCHUNK; c++) {
        CP_WAIT0();
        __syncthreads();
        if (c < NCHUNK - 1) {
            const int kn = sl * (NN / NSL) + (c + 1) * 64;
            uint32_t stb = sb + AT_KV + (uint32_t)((c + 1) & 1) * 32768;
            #pragma unroll
            for (int it = 0; it < 4; it++) {
                int idx = it * 128 + tid;
                int row = idx >> 3, ch = idx & 7;
                size_t gk = (size_t)(kn + row) * 1536 + 512 + h * 64 + ch * 8;
                uint32_t off = ASM_OFF(row, ch);
                CP_ASYNC16(stb + off,         qh + gk);
                CP_ASYNC16(stb + 8192 + off,  ql + gk);
                CP_ASYNC16(stb + 16384 + off, qh + gk + 512);
                CP_ASYNC16(stb + 24576 + off, ql + gk + 512);
            }
            if (tid < 64) bias[((c + 1) & 1) * 64 + tid] = pep[(size_t)(kn + tid) * HH + h];
            CP_COMMIT();
        }
        const uint32_t stc = sb + AT_KV + (uint32_t)(c & 1) * 32768;
        const uint32_t sKH = stc, sKL = stc + 8192, sVH = stc + 16384, sVL = stc + 24576;
        const float* bs = bias + (c & 1) * 64;

        float S[2][8][4];
        #pragma unroll
        for (int mb = 0; mb < 2; mb++)
            #pragma unroll
            for (int nb = 0; nb < 8; nb++)
                #pragma unroll
                for (int u = 0; u < 4; u++) S[mb][nb][u] = 0.f;
        #pragma unroll
        for (int kb = 0; kb < 4; kb++) {
            uint32_t ah[2][4], al[2][4];
            int r16 = (lane & 7) + ((sub & 1) << 3);
            int chA = kb * 2 + (sub >> 1);
            #pragma unroll
            for (int mb = 0; mb < 2; mb++) {
                int row = wrow + mb * 16 + r16;
                uint32_t off = ASM_OFF(row, chA);
                ldsm4(ah[mb], sb + AT_QH + off);
                ldsm4(al[mb], sb + AT_QL + off);
            }
            int chB = kb * 2 + (sub & 1);
            int nr = ((sub >> 1) << 3) + (lane & 7);
            #pragma unroll
            for (int j = 0; j < 4; j++) {
                uint32_t bh[4], bl[4];
                int row = j * 16 + nr;
                uint32_t off = ASM_OFF(row, chB);
                ldsm4(bh, sKH + off);
                ldsm4(bl, sKL + off);
                #pragma unroll
                for (int mb = 0; mb < 2; mb++) {
                    mma16816(S[mb][2*j],   ah[mb], &bh[0]);
                    mma16816(S[mb][2*j],   al[mb], &bh[0]);
                    mma16816(S[mb][2*j],   ah[mb], &bl[0]);
                    mma16816(S[mb][2*j+1], ah[mb], &bh[2]);
                    mma16816(S[mb][2*j+1], al[mb], &bh[2]);
                    mma16816(S[mb][2*j+1], ah[mb], &bl[2]);
                }
            }
        }

        uint32_t Ph[2][8][2], Pl[2][8][2];
        #pragma unroll
        for (int mb = 0; mb < 2; mb++)
            #pragma unroll
            for (int nb = 0; nb < 8; nb++) {
                int col = nb * 8 + ((lane & 3) << 1);
                float b0 = bs[col], b1 = bs[col + 1];
                float p0 = __expf(fmaf(S[mb][nb][0], 0.125f, -b0));
                float p1 = __expf(fmaf(S[mb][nb][1], 0.125f, -b1));
                float p2 = __expf(fmaf(S[mb][nb][2], 0.125f, -b0));
                float p3 = __expf(fmaf(S[mb][nb][3], 0.125f, -b1));
                ls[mb][0] += p0 + p1;
                ls[mb][1] += p2 + p3;
                __nv_bfloat162 h01 = __floats2bfloat162_rn(p0, p1);
                __nv_bfloat162 h23 = __floats2bfloat162_rn(p2, p3);
                __nv_bfloat162 l01 = __floats2bfloat162_rn(p0 - __bfloat162float(h01.x),
                                                           p1 - __bfloat162float(h01.y));
                __nv_bfloat162 l23 = __floats2bfloat162_rn(p2 - __bfloat162float(h23.x),
                                                           p3 - __bfloat162float(h23.y));
                Ph[mb][nb][0] = *reinterpret_cast<uint32_t*>(&h01);
                Ph[mb][nb][1] = *reinterpret_cast<uint32_t*>(&h23);
                Pl[mb][nb][0] = *reinterpret_cast<uint32_t*>(&l01);
                Pl[mb][nb][1] = *reinterpret_cast<uint32_t*>(&l23);
            }

        #pragma unroll
        for (int kb2 = 0; kb2 < 4; kb2++) {
            int krow = kb2 * 16 + ((sub & 1) << 3) + (lane & 7);
            #pragma unroll
            for (int dI = 0; dI < 4; dI++) {
                uint32_t vh[4], vl[4];
                int ch = dI * 2 + (sub >> 1);
                uint32_t off = ASM_OFF(krow, ch);
                ldsm4t(vh, sVH + off);
                ldsm4t(vl, sVL + off);
                #pragma unroll
                for (int mb = 0; mb < 2; mb++) {
                    uint32_t pa[4] = {Ph[mb][2*kb2][0], Ph[mb][2*kb2][1],
                                      Ph[mb][2*kb2+1][0], Ph[mb][2*kb2+1][1]};
                    uint32_t la[4] = {Pl[mb][2*kb2][0], Pl[mb][2*kb2][1],
                                      Pl[mb][2*kb2+1][0], Pl[mb][2*kb2+1][1]};
                    mma16816(O[mb][2*dI],   pa, &vh[0]);
                    mma16816(O[mb][2*dI],   la, &vh[0]);
                    mma16816(O[mb][2*dI],   pa, &vl[0]);
                    mma16816(O[mb][2*dI+1], pa, &vh[2]);
                    mma16816(O[mb][2*dI+1], la, &vh[2]);
                    mma16816(O[mb][2*dI+1], pa, &vl[2]);
                }
            }
        }
    }

    #pragma unroll
    for (int mb = 0; mb < 2; mb++)
        #pragma unroll
        for (int r = 0; r < 2; r++) {
            float v = ls[mb][r];
            v += __shfl_xor_sync(0xffffffffu, v, 1);
            v += __shfl_xor_sync(0xffffffffu, v, 2);
            ls[mb][r] = v;
        }
    const size_t base = (size_t)(sl * HH + h) * NN;
    #pragma unroll
    for (int mb = 0; mb < 2; mb++) {
        int rowA = q0 + wrow + mb * 16 + (lane >> 2);
        int rowB = rowA + 8;
        if ((lane & 3) == 0) {
            plsum[base + rowA] = ls[mb][0];
            plsum[base + rowB] = ls[mb][1];
        }
        #pragma unroll
        for (int nb = 0; nb < 8; nb++) {
            int col = nb * 8 + ((lane & 3) << 1);
            *reinterpret_cast<float2*>(part + (base + rowA) * 64 + col) = make_float2(O[mb][nb][0], O[mb][nb][1]);
            *reinterpret_cast<float2*>(part + (base + rowB) * 64 + col) = make_float2(O[mb][nb][2], O[mb][nb][3]);
        }
    }
}

__global__ void attn_combine_kernel(const float* __restrict__ part, const float* __restrict__ pls,
                                    __nv_bfloat16* __restrict__ ohi, __nv_bfloat16* __restrict__ olo) {
    int i = blockIdx.x, t = threadIdx.x;
    #pragma unroll
    for (int rep = 0; rep < 2; rep++) {
        int idx = t + rep * 256;
        int h = idx >> 6, d = idx & 63;
        float v = 0.f, l = 0.f;
        #pragma unroll
        for (int s = 0; s < NSL; s++) {
            l += pls[(size_t)(s * HH + h) * NN + i];
            v += part[((size_t)(s * HH + h) * NN + i) * 64 + d];
        }
        float r = v / l;
        __nv_bfloat16 hb = __float2bfloat16_rn(r);
        ohi[(size_t)i * DD + idx] = hb;
        olo[(size_t)i * DD + idx] = __float2bfloat16_rn(r - __bfloat162float(hb));
    }
}

// ============================ LN over (a + p0 + p1) -> fp32 out + bf16 hi/lo ============================
__global__ void ln3_kernel(const float* __restrict__ a, const float* __restrict__ b,
                           const float* __restrict__ b2,
                           const float* __restrict__ g, const float* __restrict__ be,
                           float* __restrict__ out,
                           __nv_bfloat16* __restrict__ ohi, __nv_bfloat16* __restrict__ olo) {
    __shared__ float sh[256];
    __shared__ float s_mu, s_r;
    int i = blockIdx.x, t = threadIdx.x;
    float v0 = a[(size_t)i * DD + t]       + b[(size_t)i * DD + t]       + b2[(size_t)i * DD + t];
    float v1 = a[(size_t)i * DD + 256 + t] + b[(size_t)i * DD + 256 + t] + b2[(size_t)i * DD + 256 + t];
    sh[t] = v0 + v1; __syncthreads();
    for (int k = 128; k > 0; k >>= 1) { if (t < k) sh[t] += sh[t + k]; __syncthreads(); }
    if (t == 0) s_mu = sh[0] * (1.f / DD);
    __syncthreads();
    float mu = s_mu;
    float d0 = v0 - mu, d1 = v1 - mu;
    sh[t] = d0 * d0 + d1 * d1; __syncthreads();
    for (int k = 128; k > 0; k >>= 1) { if (t < k) sh[t] += sh[t + k]; __syncthreads(); }
    if (t == 0) s_r = rsqrtf(sh[0] * (1.f / DD) + 1e-5f);
    __syncthreads();
    float r = s_r;
    float o0 = d0 * r * g[t]       + be[t];
    float o1 = d1 * r * g[256 + t] + be[256 + t];
    out[(size_t)i * DD + t]       = o0;
    out[(size_t)i * DD + 256 + t] = o1;
    __nv_bfloat16 h0 = __float2bfloat16_rn(o0);
    __nv_bfloat16 h1 = __float2bfloat16_rn(o1);
    ohi[(size_t)i * DD + t]       = h0;
    ohi[(size_t)i * DD + 256 + t] = h1;
    olo[(size_t)i * DD + t]       = __float2bfloat16_rn(o0 - __bfloat162float(h0));
    olo[(size_t)i * DD + 256 + t] = __float2bfloat16_rn(o1 - __bfloat162float(h1));
}

// ============================ launch ============================
extern "C" void kernel_launch(void* const* d_in, const int* in_sizes, int n_in,
                              void* d_out, int out_size) {
    const float* node_features = (const float*)d_in[0];
    const int*   edge_index    = (const int*)  d_in[1];
    const float* pe_proj_W     = (const float*)d_in[2];
    const float* pe_proj_b     = (const float*)d_in[3];
    const float* qkv_W         = (const float*)d_in[4];
    const float* qkv_b         = (const float*)d_in[5];
    const float* peb_W         = (const float*)d_in[6];
    const float* peb_b         = (const float*)d_in[7];
    const float* out_W         = (const float*)d_in[8];
    const float* out_b         = (const float*)d_in[9];
    const float* ffn_W1        = (const float*)d_in[10];
    const float* ffn_b1        = (const float*)d_in[11];
    const float* ffn_W2        = (const float*)d_in[12];
    const float* ffn_b2        = (const float*)d_in[13];
    const float* ln1_g         = (const float*)d_in[14];
    const float* ln1_b         = (const float*)d_in[15];
    const float* ln2_g         = (const float*)d_in[16];
    const float* ln2_b         = (const float*)d_in[17];
    float* outp = (float*)d_out;

    float *x_, *x1_, *o_, *pep_, *part_, *pls_;
    __nv_bfloat16 *Ahi_, *Alo_, *Hhi_, *Hlo_, *Qh_, *Ql_, *T2b_, *T3b_, *T4b_;
    __nv_bfloat16 *qWh_, *qWl_, *oWh_, *oWl_, *f1h_, *f1l_, *f2h_, *f2l_;
    cudaGetSymbolAddress((void**)&x_,   g_x);
    cudaGetSymbolAddress((void**)&x1_,  g_x1);
    cudaGetSymbolAddress((void**)&o_,   g_o);
    cudaGetSymbolAddress((void**)&pep_, g_pep);
    cudaGetSymbolAddress((void**)&part_,g_part);
    cudaGetSymbolAddress((void**)&pls_, g_plsum);
    cudaGetSymbolAddress((void**)&Ahi_, g_Ahi);
    cudaGetSymbolAddress((void**)&Alo_, g_Alo);
    cudaGetSymbolAddress((void**)&Hhi_, g_Hhi);
    cudaGetSymbolAddress((void**)&Hlo_, g_Hlo);
    cudaGetSymbolAddress((void**)&Qh_,  g_QKVhi);
    cudaGetSymbolAddress((void**)&Ql_,  g_QKVlo);
    cudaGetSymbolAddress((void**)&T2b_, g_T2b);
    cudaGetSymbolAddress((void**)&T3b_, g_T3b);
    cudaGetSymbolAddress((void**)&T4b_, g_T4b);
    cudaGetSymbolAddress((void**)&qWh_, g_qkvW_hi);
    cudaGetSymbolAddress((void**)&qWl_, g_qkvW_lo);
    cudaGetSymbolAddress((void**)&oWh_, g_outW_hi);
    cudaGetSymbolAddress((void**)&oWl_, g_outW_lo);
    cudaGetSymbolAddress((void**)&f1h_, g_f1W_hi);
    cudaGetSymbolAddress((void**)&f1l_, g_f1W_lo);
    cudaGetSymbolAddress((void**)&f2h_, g_f2W_hi);
    cudaGetSymbolAddress((void**)&f2l_, g_f2W_lo);

    constexpr int GS64 = 2 * (2 * 64 * 128 + 32768);   // 96 KB -> 2 CTA/SM
    cudaFuncSetAttribute((const void*)mma_gemm_kernel<2,64,1>, cudaFuncAttributeMaxDynamicSharedMemorySize, GS64);
    cudaFuncSetAttribute((const void*)mma_gemm_kernel<3,64,1>, cudaFuncAttributeMaxDynamicSharedMemorySize, GS64);
    cudaFuncSetAttribute((const void*)mma_gemm_kernel<0,64,2>, cudaFuncAttributeMaxDynamicSharedMemorySize, GS64);
    cudaFuncSetAttribute(attn_tc_kernel, cudaFuncAttributeMaxDynamicSharedMemorySize, AT_SMEM);

    static cudaStream_t s_side = nullptr;
    static cudaEvent_t  ev_fork = nullptr, ev_pe = nullptr;
    if (s_side == nullptr) {
        cudaStreamCreateWithFlags(&s_side, cudaStreamNonBlocking);
        cudaEventCreateWithFlags(&ev_fork, cudaEventDisableTiming);
        cudaEventCreateWithFlags(&ev_pe,   cudaEventDisableTiming);
    }

    // ---- fork: PE pipeline on side stream ----
    cudaEventRecord(ev_fork, 0);
    cudaStreamWaitEvent(s_side, ev_fork, 0);
    zero_bm_kernel<<<(NN*64)/256, 256, 0, s_side>>>();
    scatter_bm_kernel<<<EEC/256, 256, 0, s_side>>>(edge_index);
    build_bm_kernel<<<NN, 64, 0, s_side>>>();
    t2_kernel<<<NN, 256, 0, s_side>>>();
    spmm_bf_kernel<<<NN, 256, 0, s_side>>>(T2b_, T3b_);
    spmm_bf_kernel<<<NN, 256, 0, s_side>>>(T3b_, T4b_);
    diag2_kernel<<<NN, 256, 0, s_side>>>();
    pe_kernel<<<(NN + 127) / 128, 128, 0, s_side>>>(pe_proj_W, pe_proj_b);
    pep_kernel<<<(NN + 127) / 128, 128, 0, s_side>>>(peb_W, peb_b);
    cudaEventRecord(ev_pe, s_side);

    // ---- main stream ----
    convW_kernel<<<dim3(1536/32, 512/32, LLC),  dim3(32,8)>>>(qkv_W,  qWh_, qWl_, DD,  3*DD);
    convW_kernel<<<dim3(512/32,  512/32, LLC),  dim3(32,8)>>>(out_W,  oWh_, oWl_, DD,  DD);
    convW_kernel<<<dim3(2048/32, 512/32, LLC),  dim3(32,8)>>>(ffn_W1, f1h_, f1l_, DD,  DFFC);
    convW_kernel<<<dim3(512/32,  2048/32, LLC), dim3(32,8)>>>(ffn_W2, f2h_, f2l_, DFFC, DD);
    split_copy_kernel<<<(NN*DD)/256, 256>>>(node_features);

    float* o2_ = o_ + (size_t)NN * DD;
    for (int l = 0; l < LLC; l++) {
        mma_gemm_kernel<2,64,1><<<dim3(1536/128, NN/64), 256, GS64>>>(
            Ahi_, Alo_, qWh_ + (size_t)l*3*DD*DD, qWl_ + (size_t)l*3*DD*DD,
            qkv_b + (size_t)l*3*DD, nullptr, Qh_, Ql_, 3*DD, DD);
        if (l == 0) cudaStreamWaitEvent(0, ev_pe, 0);   // join: attention needs pep
        attn_tc_kernel<<<dim3(NN/128, HH, NSL), 128, AT_SMEM>>>(Qh_, Ql_, pep_ + (size_t)l*NN*HH, part_, pls_);
        attn_combine_kernel<<<NN, 256>>>(part_, pls_, Ahi_, Alo_);
        // out-proj: split-K=2 -> partials o_[0], o_[1]
        mma_gemm_kernel<0,64,2><<<dim3(DD/128, NN/64, 2), 256, GS64>>>(
            Ahi_, Alo_, oWh_ + (size_t)l*DD*DD, oWl_ + (size_t)l*DD*DD,
            out_b + (size_t)l*DD, o_, nullptr, nullptr, DD, DD);
        ln3_kernel<<<NN, 256>>>(x_, o_, o2_, ln1_g + (size_t)l*DD, ln1_b + (size_t)l*DD, x1_, Ahi_, Alo_);
        mma_gemm_kernel<3,64,1><<<dim3(DFFC/128, NN/64), 256, GS64>>>(
            Ahi_, Alo_, f1h_ + (size_t)l*DD*DFFC, f1l_ + (size_t)l*DD*DFFC,
            ffn_b1 + (size_t)l*DFFC, nullptr, Hhi_, Hlo_, DFFC, DD);
        // ffn2: split-K=2
        mma_gemm_kernel<0,64,2><<<dim3(DD/128, NN/64, 2), 256, GS64>>>(
            Hhi_, Hlo_, f2h_ + (size_t)l*DFFC*DD, f2l_ + (size_t)l*DFFC*DD,
            ffn_b2 + (size_t)l*DD, o_, nullptr, nullptr, DD, DFFC);
        float* xout = (l == LLC - 1) ? outp : x_;
        ln3_kernel<<<NN, 256>>>(x1_, o_, o2_, ln2_g + (size_t)l*DD, ln2_b + (size_t)l*DD, xout, Ahi_, Alo_);
    }
}

// round 11
// speedup vs baseline: 1.1257x; 1.0052x over previous
#include <cuda_runtime.h>
#include <cuda_bf16.h>
#include <math.h>
#include <stdint.h>

#define NN   2048
#define DD   512
#define HH   8
#define DPEC 16
#define WALKC 8
#define LLC  3
#define EEC  32768
#define DFFC 2048
#define MAXD 256
#define NSL  2          // attention key-slices

// ============================ PTX helpers (sm_80-baseline ISA only) ============================
__device__ __forceinline__ uint32_t smem_to_u32(const void* p) {
    uint32_t a;
    asm("{ .reg .u64 t; cvta.to.shared.u64 t, %1; cvt.u32.u64 %0, t; }" : "=r"(a) : "l"(p));
    return a;
}
#define CP_ASYNC16(dst, src) \
    asm volatile("cp.async.cg.shared.global [%0], [%1], 16;" :: "r"(dst), "l"(src))
#define CP_COMMIT() asm volatile("cp.async.commit_group;" ::: "memory")
#define CP_WAIT1()  asm volatile("cp.async.wait_group 1;" ::: "memory")
#define CP_WAIT0()  asm volatile("cp.async.wait_group 0;" ::: "memory")

__device__ __forceinline__ void ldsm4(uint32_t* r, uint32_t addr) {
    asm volatile("ldmatrix.sync.aligned.m8n8.x4.shared.b16 {%0,%1,%2,%3}, [%4];"
        : "=r"(r[0]), "=r"(r[1]), "=r"(r[2]), "=r"(r[3]) : "r"(addr));
}
__device__ __forceinline__ void ldsm4t(uint32_t* r, uint32_t addr) {
    asm volatile("ldmatrix.sync.aligned.m8n8.x4.trans.shared.b16 {%0,%1,%2,%3}, [%4];"
        : "=r"(r[0]), "=r"(r[1]), "=r"(r[2]), "=r"(r[3]) : "r"(addr));
}
__device__ __forceinline__ void mma16816(float* c, const uint32_t* a, const uint32_t* b) {
    asm volatile("mma.sync.aligned.m16n8k16.row.col.f32.bf16.bf16.f32 "
        "{%0,%1,%2,%3}, {%4,%5,%6,%7}, {%8,%9}, {%0,%1,%2,%3};"
        : "+f"(c[0]), "+f"(c[1]), "+f"(c[2]), "+f"(c[3])
        : "r"(a[0]), "r"(a[1]), "r"(a[2]), "r"(a[3]), "r"(b[0]), "r"(b[1]));
}

#define ASM_OFF(row, ch) ((uint32_t)((row) * 128 + ((((ch)) ^ ((row) & 7)) << 4)))

// ============================ static device scratch ============================
__device__ uint32_t g_bm[NN*64];
__device__ float g_deg[NN];
__device__ float g_invdeg[NN];
__device__ int   g_nbr[NN*MAXD];
__device__ int   g_cnt[NN];
__device__ __nv_bfloat16 g_T2b[NN*NN];
__device__ __nv_bfloat16 g_T3b[NN*NN];
__device__ __nv_bfloat16 g_T4b[NN*NN];
__device__ float g_rw [NN*WALKC];
__device__ float g_pe [NN*DPEC];
__device__ float g_pep[LLC*NN*HH];
__device__ float g_x   [NN*DD];
__device__ float g_x1  [NN*DD];
__device__ float g_o   [2*NN*DD];     // split-K partials
__device__ __nv_bfloat16 g_Ahi[NN*DD];
__device__ __nv_bfloat16 g_Alo[NN*DD];
__device__ __nv_bfloat16 g_Hhi[NN*DFFC];
__device__ __nv_bfloat16 g_Hlo[NN*DFFC];
__device__ __nv_bfloat16 g_QKVhi[NN*3*DD];
__device__ __nv_bfloat16 g_QKVlo[NN*3*DD];
__device__ __nv_bfloat16 g_qkvW_hi[LLC*3*DD*DD];
__device__ __nv_bfloat16 g_qkvW_lo[LLC*3*DD*DD];
__device__ __nv_bfloat16 g_outW_hi[LLC*DD*DD];
__device__ __nv_bfloat16 g_outW_lo[LLC*DD*DD];
__device__ __nv_bfloat16 g_f1W_hi[LLC*DD*DFFC];
__device__ __nv_bfloat16 g_f1W_lo[LLC*DD*DFFC];
__device__ __nv_bfloat16 g_f2W_hi[LLC*DFFC*DD];
__device__ __nv_bfloat16 g_f2W_lo[LLC*DFFC*DD];
__device__ float g_part [NSL*HH*NN*64];
__device__ float g_plsum[NSL*HH*NN];

// ============================ PE pipeline (sparse) ============================
__global__ void zero_bm_kernel() {
    int idx = blockIdx.x * blockDim.x + threadIdx.x;
    if (idx < NN * 64) g_bm[idx] = 0u;
}
__global__ void scatter_bm_kernel(const int* __restrict__ ei) {
    int e = blockIdx.x * blockDim.x + threadIdx.x;
    if (e < EEC) {
        int s = ei[e], t = ei[EEC + e];
        atomicOr(&g_bm[s * 64 + (t >> 5)], 1u << (t & 31));
        atomicOr(&g_bm[t * 64 + (s >> 5)], 1u << (s & 31));
    }
}
__global__ void build_bm_kernel() {
    __shared__ int cnt;
    int i = blockIdx.x, t = threadIdx.x;
    if (t == 0) cnt = 0;
    __syncthreads();
    uint32_t w = g_bm[i * 64 + t];
    int c = __popc(w);
    int pos = (c > 0) ? atomicAdd(&cnt, c) : 0;
    while (w) {
        int b = __ffs(w) - 1;
        w &= w - 1;
        if (pos < MAXD) g_nbr[i * MAXD + pos] = t * 32 + b;
        pos++;
    }
    __syncthreads();
    if (t == 0) {
        int cc = cnt < MAXD ? cnt : MAXD;
        g_cnt[i] = cc;
        float d = cnt < 1 ? 1.f : (float)cnt;
        g_deg[i] = d;
        g_invdeg[i] = 1.f / d;
    }
}
__global__ void __launch_bounds__(256) t2_kernel() {
    __shared__ float rowbuf[NN];
    int i = blockIdx.x, t = threadIdx.x;
    #pragma unroll
    for (int u = 0; u < NN / 256; u++) rowbuf[t + u * 256] = 0.f;
    __syncthreads();
    int cnt = g_cnt[i];
    float inv_i = g_invdeg[i];
    for (int c = t >> 3; c < cnt; c += 32) {
        int j = g_nbr[i * MAXD + c];
        float w = inv_i * g_invdeg[j];
        int cj = g_cnt[j];
        const int* nbj = g_nbr + j * MAXD;
        for (int k = t & 7; k < cj; k += 8) atomicAdd(&rowbuf[nbj[k]], w);
    }
    __syncthreads();
    __nv_bfloat16* out = g_T2b + (size_t)i * NN;
    #pragma unroll
    for (int u = 0; u < NN / 256; u++) {
        int idx = t + u * 256;
        out[idx] = __float2bfloat16_rn(rowbuf[idx]);
    }
}
__global__ void __launch_bounds__(256) spmm_bf_kernel(const __nv_bfloat16* __restrict__ IN,
                                                      __nv_bfloat16* __restrict__ OUT) {
    int i = blockIdx.x, t = threadIdx.x;
    int cnt = g_cnt[i];
    float inv = g_invdeg[i];
    const int* nb = g_nbr + i * MAXD;
    float2 acc[4];
    #pragma unroll
    for (int u = 0; u < 4; u++) acc[u] = make_float2(0.f, 0.f);
    for (int c = 0; c < cnt; c++) {
        const __nv_bfloat162* row = reinterpret_cast<const __nv_bfloat162*>(IN + (size_t)nb[c] * NN);
        #pragma unroll
        for (int u = 0; u < 4; u++) {
            float2 v = __bfloat1622float2(row[t + u * 256]);
            acc[u].x += v.x; acc[u].y += v.y;
        }
    }
    __nv_bfloat162* out = reinterpret_cast<__nv_bfloat162*>(OUT + (size_t)i * NN);
    #pragma unroll
    for (int u = 0; u < 4; u++)
        out[t + u * 256] = __floats2bfloat162_rn(acc[u].x * inv, acc[u].y * inv);
}
__global__ void diag2_kernel() {
    __shared__ float sh[256];
    __shared__ float res[7];
    int i = blockIdx.x, t = threadIdx.x;
    float inv_i = g_invdeg[i], d_i = g_deg[i];
    int cnt = g_cnt[i];
    const __nv_bfloat16* r2 = g_T2b + (size_t)i * NN;
    const __nv_bfloat16* r3 = g_T3b + (size_t)i * NN;
    const __nv_bfloat16* r4 = g_T4b + (size_t)i * NN;
    float s[7] = {};
    for (int c = t; c < cnt; c += 256) {
        int j = g_nbr[i * MAXD + c];
        float wj = g_invdeg[j];
        s[0] += wj;
        s[1] += __bfloat162float(r2[j]) * wj;
    }
    for (int j = t; j < NN; j += 256) {
        float w = g_invdeg[j];
        float t2 = __bfloat162float(r2[j]);
        float t3 = __bfloat162float(r3[j]);
        float t4 = __bfloat162float(r4[j]);
        s[2] += t2 * t2 * w;
        s[3] += t3 * t2 * w;
        s[4] += t3 * t3 * w;
        s[5] += t4 * t3 * w;
        s[6] += t4 * t4 * w;
    }
    for (int v = 0; v < 7; v++) {
        sh[t] = s[v]; __syncthreads();
        for (int k = 128; k > 0; k >>= 1) { if (t < k) sh[t] += sh[t + k]; __syncthreads(); }
        if (t == 0) res[v] = sh[0];
        __syncthreads();
    }
    if (t == 0) {
        bool self = (g_bm[i * 64 + (i >> 5)] >> (i & 31)) & 1u;
        g_rw[i * WALKC + 0] = self ? inv_i : 0.f;
        g_rw[i * WALKC + 1] = inv_i * res[0];
        g_rw[i * WALKC + 2] = res[1];
        g_rw[i * WALKC + 3] = d_i * res[2];
        g_rw[i * WALKC + 4] = d_i * res[3];
        g_rw[i * WALKC + 5] = d_i * res[4];
        g_rw[i * WALKC + 6] = d_i * res[5];
        g_rw[i * WALKC + 7] = d_i * res[6];
    }
}
__global__ void pe_kernel(const float* __restrict__ W, const float* __restrict__ b) {
    int i = blockIdx.x * blockDim.x + threadIdx.x;
    if (i >= NN) return;
    float r[WALKC];
    #pragma unroll
    for (int w = 0; w < WALKC; w++) r[w] = g_rw[i * WALKC + w];
    #pragma unroll
    for (int d = 0; d < DPEC; d++) {
        float s = b[d];
        #pragma unroll
        for (int w = 0; w < WALKC; w++) s += r[w] * W[w * DPEC + d];
        g_pe[i * DPEC + d] = s;
    }
}
__global__ void pep_kernel(const float* __restrict__ W, const float* __restrict__ b) {
    int i = blockIdx.x * blockDim.x + threadIdx.x;
    if (i >= NN) return;
    float p[DPEC];
    #pragma unroll
    for (int d = 0; d < DPEC; d++) p[d] = g_pe[i * DPEC + d];
    for (int l = 0; l < LLC; l++) {
        #pragma unroll
        for (int h = 0; h < HH; h++) {
            float s = b[l * HH + h];
            #pragma unroll
            for (int d = 0; d < DPEC; d++) s += p[d] * W[(l * DPEC + d) * HH + h];
            g_pep[(size_t)l * NN * HH + i * HH + h] = s;
        }
    }
}

// ============================ conversions ============================
__global__ void split_copy_kernel(const float* __restrict__ src) {
    int idx = blockIdx.x * blockDim.x + threadIdx.x;
    if (idx < NN * DD) {
        float v = src[idx];
        g_x[idx] = v;
        __nv_bfloat16 h = __float2bfloat16_rn(v);
        g_Ahi[idx] = h;
        g_Alo[idx] = __float2bfloat16_rn(v - __bfloat162float(h));
    }
}
__global__ void convW_kernel(const float* __restrict__ W, __nv_bfloat16* __restrict__ hi,
                             __nv_bfloat16* __restrict__ lo, int K, int N) {
    __shared__ float tile[32][33];
    size_t lw = (size_t)blockIdx.z * K * N;
    int n0 = blockIdx.x * 32, k0 = blockIdx.y * 32;
    int tx = threadIdx.x, ty = threadIdx.y;
    #pragma unroll
    for (int r = 0; r < 4; r++)
        tile[ty + r * 8][tx] = W[lw + (size_t)(k0 + ty + r * 8) * N + n0 + tx];
    __syncthreads();
    #pragma unroll
    for (int r = 0; r < 4; r++) {
        int ni = ty + r * 8;
        float v = tile[tx][ni];
        __nv_bfloat16 h = __float2bfloat16_rn(v);
        size_t o = lw + (size_t)(n0 + ni) * K + k0 + tx;
        hi[o] = h;
        lo[o] = __float2bfloat16_rn(v - __bfloat162float(h));
    }
}

// ============================ mma.sync bf16x3 GEMM (BK=64, 2-stage, TM=64, optional split-K) ============================
template<int EPI, int TM, int SPLITK>  // EPI: 0 fp32 out; 2 bf16 hi/lo out; 3 GELU + bf16 hi/lo out
__global__ void __launch_bounds__(256) mma_gemm_kernel(
    const __nv_bfloat16* __restrict__ Ahi, const __nv_bfloat16* __restrict__ Alo,
    const __nv_bfloat16* __restrict__ Bhi, const __nv_bfloat16* __restrict__ Blo,
    const float* __restrict__ bias, float* __restrict__ C,
    __nv_bfloat16* __restrict__ Chi, __nv_bfloat16* __restrict__ Clo, int N, int K)
{
    constexpr int MBN    = TM / 64;
    constexpr int ABYTES = TM * 128;
    constexpr int STAGE  = 2 * ABYTES + 32768;
    extern __shared__ char smem[];
    const int tid  = threadIdx.x;
    const int lane = tid & 31;
    const int wid  = tid >> 5;
    const int m0 = blockIdx.y * TM, n0 = blockIdx.x * 128;
    const int wrow = (wid >> 1) * (16 * MBN);
    const int wcol = (wid & 1) * 64;
    const uint32_t sbase = smem_to_u32(smem);
    const int kseg = K / SPLITK;
    const int koff = (SPLITK > 1) ? blockIdx.z * kseg : 0;

    float acc[MBN][8][4];
    #pragma unroll
    for (int a = 0; a < MBN; a++)
        #pragma unroll
        for (int b = 0; b < 8; b++)
            #pragma unroll
            for (int c = 0; c < 4; c++) acc[a][b][c] = 0.f;

    const int nc = kseg >> 6;

    auto loadChunk = [&](int c) {
        uint32_t sb = sbase + (uint32_t)(c & 1) * STAGE;
        int k0 = koff + (c << 6);
        #pragma unroll
        for (int t2 = 0; t2 < 2; t2++) {
            const __nv_bfloat16* s = t2 ? Alo : Ahi;
            #pragma unroll
            for (int it = 0; it < TM / 32; it++) {
                int idx = it * 256 + tid;
                int row = idx >> 3, ch = idx & 7;
                CP_ASYNC16(sb + t2 * ABYTES + ASM_OFF(row, ch),
                           s + (size_t)(m0 + row) * K + k0 + ch * 8);
            }
        }
        #pragma unroll
        for (int t2 = 0; t2 < 2; t2++) {
            const __nv_bfloat16* s = t2 ? Blo : Bhi;
            #pragma unroll
            for (int it = 0; it < 4; it++) {
                int idx = it * 256 + tid;
                int row = idx >> 3, ch = idx & 7;
                CP_ASYNC16(sb + 2 * ABYTES + t2 * 16384 + ASM_OFF(row, ch),
                           s + (size_t)(n0 + row) * K + k0 + ch * 8);
            }
        }
        CP_COMMIT();
    };

    loadChunk(0);
    if (nc > 1) loadChunk(1);

    for (int c = 0; c < nc; c++) {
        if (c + 1 < nc) CP_WAIT1(); else CP_WAIT0();
        __syncthreads();
        uint32_t sb = sbase + (uint32_t)(c & 1) * STAGE;
        uint32_t sAh = sb, sAl = sb + ABYTES, sBh = sb + 2 * ABYTES, sBl = sb + 2 * ABYTES + 16384;
        #pragma unroll
        for (int ks = 0; ks < 4; ks++) {
            uint32_t ah[MBN][4], al[MBN][4], bh[4][4], bl[4][4];
            {
                int sub = lane >> 3;
                int row16 = (lane & 7) + ((sub & 1) << 3);
                int kc = ks * 2 + (sub >> 1);
                #pragma unroll
                for (int mb = 0; mb < MBN; mb++) {
                    int row = wrow + mb * 16 + row16;
                    uint32_t off = ASM_OFF(row, kc);
                    ldsm4(ah[mb], sAh + off);
                    ldsm4(al[mb], sAl + off);
                }
            }
            {
                int sub = lane >> 3;
                int kc = ks * 2 + (sub & 1);
                int nr = ((sub >> 1) << 3) + (lane & 7);
                #pragma unroll
                for (int j = 0; j < 4; j++) {
                    int row = wcol + j * 16 + nr;
                    uint32_t off = ASM_OFF(row, kc);
                    ldsm4(bh[j], sBh + off);
                    ldsm4(bl[j], sBl + off);
                }
            }
            #pragma unroll
            for (int mb = 0; mb < MBN; mb++)
                #pragma unroll
                for (int j = 0; j < 4; j++) {
                    mma16816(acc[mb][2*j],     ah[mb], &bh[j][0]);
                    mma16816(acc[mb][2*j],     ah[mb], &bl[j][0]);
                    mma16816(acc[mb][2*j],     al[mb], &bh[j][0]);
                    mma16816(acc[mb][2*j + 1], ah[mb], &bh[j][2]);
                    mma16816(acc[mb][2*j + 1], ah[mb], &bl[j][2]);
                    mma16816(acc[mb][2*j + 1], al[mb], &bh[j][2]);
                }
        }
        __syncthreads();
        if (c + 2 < nc) loadChunk(c + 2);
    }

    const int r_l = lane >> 2;
    const int c_l = (lane & 3) << 1;
    float* Cz = C;
    if (SPLITK > 1) Cz = C + (size_t)blockIdx.z * NN * N;
    const bool useBias = (SPLITK == 1) || (blockIdx.z == 0);
    #pragma unroll
    for (int mb = 0; mb < MBN; mb++) {
        #pragma unroll
        for (int nb = 0; nb < 8; nb++) {
            int row = m0 + wrow + mb * 16 + r_l;
            int col = n0 + wcol + nb * 8 + c_l;
            float b0 = useBias ? bias[col]     : 0.f;
            float b1 = useBias ? bias[col + 1] : 0.f;
            float v0 = acc[mb][nb][0] + b0;
            float v1 = acc[mb][nb][1] + b1;
            float v2 = acc[mb][nb][2] + b0;
            float v3 = acc[mb][nb][3] + b1;
            if (EPI == 3) {
                v0 = 0.5f * v0 * (1.f + erff(v0 * 0.70710678118654752f));
                v1 = 0.5f * v1 * (1.f + erff(v1 * 0.70710678118654752f));
                v2 = 0.5f * v2 * (1.f + erff(v2 * 0.70710678118654752f));
                v3 = 0.5f * v3 * (1.f + erff(v3 * 0.70710678118654752f));
            }
            if (EPI == 0) {
                *reinterpret_cast<float2*>(Cz + (size_t)row * N + col)       = make_float2(v0, v1);
                *reinterpret_cast<float2*>(Cz + (size_t)(row + 8) * N + col) = make_float2(v2, v3);
            } else {
                __nv_bfloat162 h01 = __floats2bfloat162_rn(v0, v1);
                __nv_bfloat162 h23 = __floats2bfloat162_rn(v2, v3);
                __nv_bfloat162 l01 = __floats2bfloat162_rn(v0 - __bfloat162float(h01.x),
                                                           v1 - __bfloat162float(h01.y));
                __nv_bfloat162 l23 = __floats2bfloat162_rn(v2 - __bfloat162float(h23.x),
                                                           v3 - __bfloat162float(h23.y));
                *reinterpret_cast<__nv_bfloat162*>(Chi + (size_t)row * N + col)       = h01;
                *reinterpret_cast<__nv_bfloat162*>(Chi + (size_t)(row + 8) * N + col) = h23;
                *reinterpret_cast<__nv_bfloat162*>(Clo + (size_t)row * N + col)       = l01;
                *reinterpret_cast<__nv_bfloat162*>(Clo + (size_t)(row + 8) * N + col) = l23;
            }
        }
    }
}

// ============================ tensor-core attention (double-buffered K/V, NSL=2 slices) ============================
#define AT_QH   0
#define AT_QL   16384
#define AT_KV   32768
#define AT_BIAS 98304
#define AT_SMEM (98304 + 512)
#define NCHUNK  (NN / NSL / 64)

__global__ void __launch_bounds__(128) attn_tc_kernel(
    const __nv_bfloat16* __restrict__ qh, const __nv_bfloat16* __restrict__ ql,
    const float* __restrict__ pep, float* __restrict__ part, float* __restrict__ plsum)
{
    extern __shared__ char sm[];
    const int h = blockIdx.y, sl = blockIdx.z;
    const int q0 = blockIdx.x * 128;
    const int tid = threadIdx.x, lane = tid & 31, wid = tid >> 5;
    const int wrow = wid * 32;
    const int sub = lane >> 3;
    const uint32_t sb = smem_to_u32(sm);
    float* bias = reinterpret_cast<float*>(sm + AT_BIAS);

    #pragma unroll
    for (int it = 0; it < 8; it++) {
        int idx = it * 128 + tid;
        int row = idx >> 3, ch = idx & 7;
        size_t g = (size_t)(q0 + row) * 1536 + h * 64 + ch * 8;
        uint32_t off = ASM_OFF(row, ch);
        CP_ASYNC16(sb + AT_QH + off, qh + g);
        CP_ASYNC16(sb + AT_QL + off, ql + g);
    }
    {
        const int kk = sl * (NN / NSL);
        uint32_t stb = sb + AT_KV;
        #pragma unroll
        for (int it = 0; it < 4; it++) {
            int idx = it * 128 + tid;
            int row = idx >> 3, ch = idx & 7;
            size_t gk = (size_t)(kk + row) * 1536 + 512 + h * 64 + ch * 8;
            uint32_t off = ASM_OFF(row, ch);
            CP_ASYNC16(stb + off,         qh + gk);
            CP_ASYNC16(stb + 8192 + off,  ql + gk);
            CP_ASYNC16(stb + 16384 + off, qh + gk + 512);
            CP_ASYNC16(stb + 24576 + off, ql + gk + 512);
        }
        if (tid < 64) bias[tid] = pep[(size_t)(kk + tid) * HH + h];
    }
    CP_COMMIT();

    float O[2][8][4];
    float ls[2][2] = {{0.f, 0.f}, {0.f, 0.f}};
    #pragma unroll
    for (int mb = 0; mb < 2; mb++)
        #pragma unroll
        for (int nb = 0; nb < 8; nb++)
            #pragma unroll
            for (int u = 0; u < 4; u++) O[mb][nb][u] = 0.f;

    for (int c = 0; c < NCHUNK; c++) {
        CP_WAIT0();
        __syncthreads();
        if (c < NCHUNK - 1) {
            const int kn = sl * (NN / NSL) + (c + 1) * 64;
            uint32_t stb = sb + AT_KV + (uint32_t)((c + 1) & 1) * 32768;
            #pragma unroll
            for (int it = 0; it < 4; it++) {
                int idx = it * 128 + tid;
                int row = idx >> 3, ch = idx & 7;
                size_t gk = (size_t)(kn + row) * 1536 + 512 + h * 64 + ch * 8;
                uint32_t off = ASM_OFF(row, ch);
                CP_ASYNC16(stb + off,         qh + gk);
                CP_ASYNC16(stb + 8192 + off,  ql + gk);
                CP_ASYNC16(stb + 16384 + off, qh + gk + 512);
                CP_ASYNC16(stb + 24576 + off, ql + gk + 512);
            }
            if (tid < 64) bias[((c + 1) & 1) * 64 + tid] = pep[(size_t)(kn + tid) * HH + h];
            CP_COMMIT();
        }
        const uint32_t stc = sb + AT_KV + (uint32_t)(c & 1) * 32768;
        const uint32_t sKH = stc, sKL = stc + 8192, sVH = stc + 16384, sVL = stc + 24576;
        const float* bs = bias + (c & 1) * 64;

        float S[2][8][4];
        #pragma unroll
        for (int mb = 0; mb < 2; mb++)
            #pragma unroll
            for (int nb = 0; nb < 8; nb++)
                #pragma unroll
                for (int u = 0; u < 4; u++) S[mb][nb][u] = 0.f;
        #pragma unroll
        for (int kb = 0; kb < 4; kb++) {
            uint32_t ah[2][4], al[2][4];
            int r16 = (lane & 7) + ((sub & 1) << 3);
            int chA = kb * 2 + (sub >> 1);
            #pragma unroll
            for (int mb = 0; mb < 2; mb++) {
                int row = wrow + mb * 16 + r16;
                uint32_t off = ASM_OFF(row, chA);
                ldsm4(ah[mb], sb + AT_QH + off);
                ldsm4(al[mb], sb + AT_QL + off);
            }
            int chB = kb * 2 + (sub & 1);
            int nr = ((sub >> 1) << 3) + (lane & 7);
            #pragma unroll
            for (int j = 0; j < 4; j++) {
                uint32_t bh[4], bl[4];
                int row = j * 16 + nr;
                uint32_t off = ASM_OFF(row, chB);
                ldsm4(bh, sKH + off);
                ldsm4(bl, sKL + off);
                #pragma unroll
                for (int mb = 0; mb < 2; mb++) {
                    mma16816(S[mb][2*j],   ah[mb], &bh[0]);
                    mma16816(S[mb][2*j],   al[mb], &bh[0]);
                    mma16816(S[mb][2*j],   ah[mb], &bl[0]);
                    mma16816(S[mb][2*j+1], ah[mb], &bh[2]);
                    mma16816(S[mb][2*j+1], al[mb], &bh[2]);
                    mma16816(S[mb][2*j+1], ah[mb], &bl[2]);
                }
            }
        }

        uint32_t Ph[2][8][2], Pl[2][8][2];
        #pragma unroll
        for (int mb = 0; mb < 2; mb++)
            #pragma unroll
            for (int nb = 0; nb < 8; nb++) {
                int col = nb * 8 + ((lane & 3) << 1);
                float b0 = bs[col], b1 = bs[col + 1];
                float p0 = __expf(fmaf(S[mb][nb][0], 0.125f, -b0));
                float p1 = __expf(fmaf(S[mb][nb][1], 0.125f, -b1));
                float p2 = __expf(fmaf(S[mb][nb][2], 0.125f, -b0));
                float p3 = __expf(fmaf(S[mb][nb][3], 0.125f, -b1));
                ls[mb][0] += p0 + p1;
                ls[mb][1] += p2 + p3;
                __nv_bfloat162 h01 = __floats2bfloat162_rn(p0, p1);
                __nv_bfloat162 h23 = __floats2bfloat162_rn(p2, p3);
                __nv_bfloat162 l01 = __floats2bfloat162_rn(p0 - __bfloat162float(h01.x),
                                                           p1 - __bfloat162float(h01.y));
                __nv_bfloat162 l23 = __floats2bfloat162_rn(p2 - __bfloat162float(h23.x),
                                                           p3 - __bfloat162float(h23.y));
                Ph[mb][nb][0] = *reinterpret_cast<uint32_t*>(&h01);
                Ph[mb][nb][1] = *reinterpret_cast<uint32_t*>(&h23);
                Pl[mb][nb][0] = *reinterpret_cast<uint32_t*>(&l01);
                Pl[mb][nb][1] = *reinterpret_cast<uint32_t*>(&l23);
            }

        #pragma unroll
        for (int kb2 = 0; kb2 < 4; kb2++) {
            int krow = kb2 * 16 + ((sub & 1) << 3) + (lane & 7);
            #pragma unroll
            for (int dI = 0; dI < 4; dI++) {
                uint32_t vh[4], vl[4];
                int ch = dI * 2 + (sub >> 1);
                uint32_t off = ASM_OFF(krow, ch);
                ldsm4t(vh, sVH + off);
                ldsm4t(vl, sVL + off);
                #pragma unroll
                for (int mb = 0; mb < 2; mb++) {
                    uint32_t pa[4] = {Ph[mb][2*kb2][0], Ph[mb][2*kb2][1],
                                      Ph[mb][2*kb2+1][0], Ph[mb][2*kb2+1][1]};
                    uint32_t la[4] = {Pl[mb][2*kb2][0], Pl[mb][2*kb2][1],
                                      Pl[mb][2*kb2+1][0], Pl[mb][2*kb2+1][1]};
                    mma16816(O[mb][2*dI],   pa, &vh[0]);
                    mma16816(O[mb][2*dI],   la, &vh[0]);
                    mma16816(O[mb][2*dI],   pa, &vl[0]);
                    mma16816(O[mb][2*dI+1], pa, &vh[2]);
                    mma16816(O[mb][2*dI+1], la, &vh[2]);
                    mma16816(O[mb][2*dI+1], pa, &vl[2]);
                }
            }
        }
    }

    #pragma unroll
    for (int mb = 0; mb < 2; mb++)
        #pragma unroll
        for (int r = 0; r < 2; r++) {
            float v = ls[mb][r];
            v += __shfl_xor_sync(0xffffffffu, v, 1);
            v += __shfl_xor_sync(0xffffffffu, v, 2);
            ls[mb][r] = v;
        }
    const size_t base = (size_t)(sl * HH + h) * NN;
    #pragma unroll
    for (int mb = 0; mb < 2; mb++) {
        int rowA = q0 + wrow + mb * 16 + (lane >> 2);
        int rowB = rowA + 8;
        if ((lane & 3) == 0) {
            plsum[base + rowA] = ls[mb][0];
            plsum[base + rowB] = ls[mb][1];
        }
        #pragma unroll
        for (int nb = 0; nb < 8; nb++) {
            int col = nb * 8 + ((lane & 3) << 1);
            *reinterpret_cast<float2*>(part + (base + rowA) * 64 + col) = make_float2(O[mb][nb][0], O[mb][nb][1]);
            *reinterpret_cast<float2*>(part + (base + rowB) * 64 + col) = make_float2(O[mb][nb][2], O[mb][nb][3]);
        }
    }
}

__global__ void __launch_bounds__(512) attn_combine_kernel(const float* __restrict__ part, const float* __restrict__ pls,
                                                           __nv_bfloat16* __restrict__ ohi, __nv_bfloat16* __restrict__ olo) {
    int i = blockIdx.x, idx = threadIdx.x;
    int h = idx >> 6, d = idx & 63;
    float v = 0.f, l = 0.f;
    #pragma unroll
    for (int s = 0; s < NSL; s++) {
        l += pls[(size_t)(s * HH + h) * NN + i];
        v += part[((size_t)(s * HH + h) * NN + i) * 64 + d];
    }
    float r = v / l;
    __nv_bfloat16 hb = __float2bfloat16_rn(r);
    ohi[(size_t)i * DD + idx] = hb;
    olo[(size_t)i * DD + idx] = __float2bfloat16_rn(r - __bfloat162float(hb));
}

// ============================ LN over (a + p0 + p1) -> fp32 out + bf16 hi/lo (warp-shuffle reduce) ============================
__global__ void ln3_kernel(const float* __restrict__ a, const float* __restrict__ b,
                           const float* __restrict__ b2,
                           const float* __restrict__ g, const float* __restrict__ be,
                           float* __restrict__ out,
                           __nv_bfloat16* __restrict__ ohi, __nv_bfloat16* __restrict__ olo) {
    __shared__ float wsum[8];
    __shared__ float s_mu, s_r;
    int i = blockIdx.x, t = threadIdx.x;
    int lane = t & 31, wid = t >> 5;
    float v0 = a[(size_t)i * DD + t]       + b[(size_t)i * DD + t]       + b2[(size_t)i * DD + t];
    float v1 = a[(size_t)i * DD + 256 + t] + b[(size_t)i * DD + 256 + t] + b2[(size_t)i * DD + 256 + t];
    // mean
    float s = v0 + v1;
    #pragma unroll
    for (int o = 16; o > 0; o >>= 1) s += __shfl_xor_sync(0xffffffffu, s, o);
    if (lane == 0) wsum[wid] = s;
    __syncthreads();
    if (t < 8) {
        float w = wsum[t];
        #pragma unroll
        for (int o = 4; o > 0; o >>= 1) w += __shfl_xor_sync(0xffu, w, o);
        if (t == 0) s_mu = w * (1.f / DD);
    }
    __syncthreads();
    float mu = s_mu;
    float d0 = v0 - mu, d1 = v1 - mu;
    // variance
    float q = d0 * d0 + d1 * d1;
    #pragma unroll
    for (int o = 16; o > 0; o >>= 1) q += __shfl_xor_sync(0xffffffffu, q, o);
    if (lane == 0) wsum[wid] = q;
    __syncthreads();
    if (t < 8) {
        float w = wsum[t];
        #pragma unroll
        for (int o = 4; o > 0; o >>= 1) w += __shfl_xor_sync(0xffu, w, o);
        if (t == 0) s_r = rsqrtf(w * (1.f / DD) + 1e-5f);
    }
    __syncthreads();
    float r = s_r;
    float o0 = d0 * r * g[t]       + be[t];
    float o1 = d1 * r * g[256 + t] + be[256 + t];
    out[(size_t)i * DD + t]       = o0;
    out[(size_t)i * DD + 256 + t] = o1;
    __nv_bfloat16 h0 = __float2bfloat16_rn(o0);
    __nv_bfloat16 h1 = __float2bfloat16_rn(o1);
    ohi[(size_t)i * DD + t]       = h0;
    ohi[(size_t)i * DD + 256 + t] = h1;
    olo[(size_t)i * DD + t]       = __float2bfloat16_rn(o0 - __bfloat162float(h0));
    olo[(size_t)i * DD + 256 + t] = __float2bfloat16_rn(o1 - __bfloat162float(h1));
}

// ============================ launch ============================
extern "C" void kernel_launch(void* const* d_in, const int* in_sizes, int n_in,
                              void* d_out, int out_size) {
    const float* node_features = (const float*)d_in[0];
    const int*   edge_index    = (const int*)  d_in[1];
    const float* pe_proj_W     = (const float*)d_in[2];
    const float* pe_proj_b     = (const float*)d_in[3];
    const float* qkv_W         = (const float*)d_in[4];
    const float* qkv_b         = (const float*)d_in[5];
    const float* peb_W         = (const float*)d_in[6];
    const float* peb_b         = (const float*)d_in[7];
    const float* out_W         = (const float*)d_in[8];
    const float* out_b         = (const float*)d_in[9];
    const float* ffn_W1        = (const float*)d_in[10];
    const float* ffn_b1        = (const float*)d_in[11];
    const float* ffn_W2        = (const float*)d_in[12];
    const float* ffn_b2        = (const float*)d_in[13];
    const float* ln1_g         = (const float*)d_in[14];
    const float* ln1_b         = (const float*)d_in[15];
    const float* ln2_g         = (const float*)d_in[16];
    const float* ln2_b         = (const float*)d_in[17];
    float* outp = (float*)d_out;

    float *x_, *x1_, *o_, *pep_, *part_, *pls_;
    __nv_bfloat16 *Ahi_, *Alo_, *Hhi_, *Hlo_, *Qh_, *Ql_, *T2b_, *T3b_, *T4b_;
    __nv_bfloat16 *qWh_, *qWl_, *oWh_, *oWl_, *f1h_, *f1l_, *f2h_, *f2l_;
    cudaGetSymbolAddress((void**)&x_,   g_x);
    cudaGetSymbolAddress((void**)&x1_,  g_x1);
    cudaGetSymbolAddress((void**)&o_,   g_o);
    cudaGetSymbolAddress((void**)&pep_, g_pep);
    cudaGetSymbolAddress((void**)&part_,g_part);
    cudaGetSymbolAddress((void**)&pls_, g_plsum);
    cudaGetSymbolAddress((void**)&Ahi_, g_Ahi);
    cudaGetSymbolAddress((void**)&Alo_, g_Alo);
    cudaGetSymbolAddress((void**)&Hhi_, g_Hhi);
    cudaGetSymbolAddress((void**)&Hlo_, g_Hlo);
    cudaGetSymbolAddress((void**)&Qh_,  g_QKVhi);
    cudaGetSymbolAddress((void**)&Ql_,  g_QKVlo);
    cudaGetSymbolAddress((void**)&T2b_, g_T2b);
    cudaGetSymbolAddress((void**)&T3b_, g_T3b);
    cudaGetSymbolAddress((void**)&T4b_, g_T4b);
    cudaGetSymbolAddress((void**)&qWh_, g_qkvW_hi);
    cudaGetSymbolAddress((void**)&qWl_, g_qkvW_lo);
    cudaGetSymbolAddress((void**)&oWh_, g_outW_hi);
    cudaGetSymbolAddress((void**)&oWl_, g_outW_lo);
    cudaGetSymbolAddress((void**)&f1h_, g_f1W_hi);
    cudaGetSymbolAddress((void**)&f1l_, g_f1W_lo);
    cudaGetSymbolAddress((void**)&f2h_, g_f2W_hi);
    cudaGetSymbolAddress((void**)&f2l_, g_f2W_lo);

    constexpr int GS64 = 2 * (2 * 64 * 128 + 32768);   // 96 KB -> 2 CTA/SM
    cudaFuncSetAttribute((const void*)mma_gemm_kernel<2,64,1>, cudaFuncAttributeMaxDynamicSharedMemorySize, GS64);
    cudaFuncSetAttribute((const void*)mma_gemm_kernel<3,64,1>, cudaFuncAttributeMaxDynamicSharedMemorySize, GS64);
    cudaFuncSetAttribute((const void*)mma_gemm_kernel<0,64,2>, cudaFuncAttributeMaxDynamicSharedMemorySize, GS64);
    cudaFuncSetAttribute(attn_tc_kernel, cudaFuncAttributeMaxDynamicSharedMemorySize, AT_SMEM);

    static cudaStream_t s_side = nullptr;
    static cudaEvent_t  ev_fork = nullptr, ev_pe = nullptr;
    if (s_side == nullptr) {
        cudaStreamCreateWithFlags(&s_side, cudaStreamNonBlocking);
        cudaEventCreateWithFlags(&ev_fork, cudaEventDisableTiming);
        cudaEventCreateWithFlags(&ev_pe,   cudaEventDisableTiming);
    }

    // ---- fork: PE pipeline on side stream ----
    cudaEventRecord(ev_fork, 0);
    cudaStreamWaitEvent(s_side, ev_fork, 0);
    zero_bm_kernel<<<(NN*64)/256, 256, 0, s_side>>>();
    scatter_bm_kernel<<<EEC/256, 256, 0, s_side>>>(edge_index);
    build_bm_kernel<<<NN, 64, 0, s_side>>>();
    t2_kernel<<<NN, 256, 0, s_side>>>();
    spmm_bf_kernel<<<NN, 256, 0, s_side>>>(T2b_, T3b_);
    spmm_bf_kernel<<<NN, 256, 0, s_side>>>(T3b_, T4b_);
    diag2_kernel<<<NN, 256, 0, s_side>>>();
    pe_kernel<<<(NN + 127) / 128, 128, 0, s_side>>>(pe_proj_W, pe_proj_b);
    pep_kernel<<<(NN + 127) / 128, 128, 0, s_side>>>(peb_W, peb_b);
    cudaEventRecord(ev_pe, s_side);

    // ---- main stream: only qkv prerequisites before the first GEMM ----
    convW_kernel<<<dim3(1536/32, 512/32, LLC),  dim3(32,8)>>>(qkv_W,  qWh_, qWl_, DD,  3*DD);
    split_copy_kernel<<<(NN*DD)/256, 256>>>(node_features);

    float* o2_ = o_ + (size_t)NN * DD;
    for (int l = 0; l < LLC; l++) {
        mma_gemm_kernel<2,64,1><<<dim3(1536/128, NN/64), 256, GS64>>>(
            Ahi_, Alo_, qWh_ + (size_t)l*3*DD*DD, qWl_ + (size_t)l*3*DD*DD,
            qkv_b + (size_t)l*3*DD, nullptr, Qh_, Ql_, 3*DD, DD);
        if (l == 0) {
            // remaining weight conversions fill the PE-join bubble
            convW_kernel<<<dim3(512/32,  512/32, LLC),  dim3(32,8)>>>(out_W,  oWh_, oWl_, DD,  DD);
            convW_kernel<<<dim3(2048/32, 512/32, LLC),  dim3(32,8)>>>(ffn_W1, f1h_, f1l_, DD,  DFFC);
            convW_kernel<<<dim3(512/32,  2048/32, LLC), dim3(32,8)>>>(ffn_W2, f2h_, f2l_, DFFC, DD);
            cudaStreamWaitEvent(0, ev_pe, 0);   // join: attention needs pep
        }
        attn_tc_kernel<<<dim3(NN/128, HH, NSL), 128, AT_SMEM>>>(Qh_, Ql_, pep_ + (size_t)l*NN*HH, part_, pls_);
        attn_combine_kernel<<<NN, 512>>>(part_, pls_, Ahi_, Alo_);
        mma_gemm_kernel<0,64,2><<<dim3(DD/128, NN/64, 2), 256, GS64>>>(
            Ahi_, Alo_, oWh_ + (size_t)l*DD*DD, oWl_ + (size_t)l*DD*DD,
            out_b + (size_t)l*DD, o_, nullptr, nullptr, DD, DD);
        ln3_kernel<<<NN, 256>>>(x_, o_, o2_, ln1_g + (size_t)l*DD, ln1_b + (size_t)l*DD, x1_, Ahi_, Alo_);
        mma_gemm_kernel<3,64,1><<<dim3(DFFC/128, NN/64), 256, GS64>>>(
            Ahi_, Alo_, f1h_ + (size_t)l*DD*DFFC, f1l_ + (size_t)l*DD*DFFC,
            ffn_b1 + (size_t)l*DFFC, nullptr, Hhi_, Hlo_, DFFC, DD);
        mma_gemm_kernel<0,64,2><<<dim3(DD/128, NN/64, 2), 256, GS64>>>(
            Hhi_, Hlo_, f2h_ + (size_t)l*DFFC*DD, f2l_ + (size_t)l*DFFC*DD,
            ffn_b2 + (size_t)l*DD, o_, nullptr, nullptr, DD, DFFC);
        float* xout = (l == LLC - 1) ? outp : x_;
        ln3_kernel<<<NN, 256>>>(x1_, o_, o2_, ln2_g + (size_t)l*DD, ln2_b + (size_t)l*DD, xout, Ahi_, Alo_);
    }
}

// round 12
// speedup vs baseline: 1.2216x; 1.0852x over previous
#include <cuda_runtime.h>
#include <cuda_bf16.h>
#include <math.h>
#include <stdint.h>

#define NN   2048
#define DD   512
#define HH   8
#define DPEC 16
#define WALKC 8
#define LLC  3
#define EEC  32768
#define DFFC 2048
#define MAXD 256
#define NSL  2          // attention key-slices

// ============================ PTX helpers (sm_80-baseline ISA only) ============================
__device__ __forceinline__ uint32_t smem_to_u32(const void* p) {
    uint32_t a;
    asm("{ .reg .u64 t; cvta.to.shared.u64 t, %1; cvt.u32.u64 %0, t; }" : "=r"(a) : "l"(p));
    return a;
}
#define CP_ASYNC16(dst, src) \
    asm volatile("cp.async.cg.shared.global [%0], [%1], 16;" :: "r"(dst), "l"(src))
#define CP_COMMIT() asm volatile("cp.async.commit_group;" ::: "memory")
#define CP_WAIT1()  asm volatile("cp.async.wait_group 1;" ::: "memory")
#define CP_WAIT0()  asm volatile("cp.async.wait_group 0;" ::: "memory")

__device__ __forceinline__ void ldsm4(uint32_t* r, uint32_t addr) {
    asm volatile("ldmatrix.sync.aligned.m8n8.x4.shared.b16 {%0,%1,%2,%3}, [%4];"
        : "=r"(r[0]), "=r"(r[1]), "=r"(r[2]), "=r"(r[3]) : "r"(addr));
}
__device__ __forceinline__ void ldsm4t(uint32_t* r, uint32_t addr) {
    asm volatile("ldmatrix.sync.aligned.m8n8.x4.trans.shared.b16 {%0,%1,%2,%3}, [%4];"
        : "=r"(r[0]), "=r"(r[1]), "=r"(r[2]), "=r"(r[3]) : "r"(addr));
}
__device__ __forceinline__ void mma16816(float* c, const uint32_t* a, const uint32_t* b) {
    asm volatile("mma.sync.aligned.m16n8k16.row.col.f32.bf16.bf16.f32 "
        "{%0,%1,%2,%3}, {%4,%5,%6,%7}, {%8,%9}, {%0,%1,%2,%3};"
        : "+f"(c[0]), "+f"(c[1]), "+f"(c[2]), "+f"(c[3])
        : "r"(a[0]), "r"(a[1]), "r"(a[2]), "r"(a[3]), "r"(b[0]), "r"(b[1]));
}

#define ASM_OFF(row, ch) ((uint32_t)((row) * 128 + ((((ch)) ^ ((row) & 7)) << 4)))

// ============================ static device scratch ============================
__device__ uint32_t g_bm[NN*64];
__device__ float g_deg[NN];
__device__ float g_invdeg[NN];
__device__ int   g_nbr[NN*MAXD];
__device__ int   g_cnt[NN];
__device__ __nv_bfloat16 g_T2b[NN*NN];
__device__ __nv_bfloat16 g_T3b[NN*NN];
__device__ __nv_bfloat16 g_T4b[NN*NN];
__device__ float g_rw [NN*WALKC];
__device__ float g_pe [NN*DPEC];
__device__ float g_pep[LLC*NN*HH];
__device__ float g_x   [NN*DD];
__device__ float g_x1  [NN*DD];
__device__ float g_o   [2*NN*DD];     // split-K partials
__device__ __nv_bfloat16 g_Ahi[NN*DD];
__device__ __nv_bfloat16 g_Alo[NN*DD];
__device__ __nv_bfloat16 g_Hhi[NN*DFFC];
__device__ __nv_bfloat16 g_Hlo[NN*DFFC];
__device__ __nv_bfloat16 g_QKVhi[NN*3*DD];
__device__ __nv_bfloat16 g_QKVlo[NN*3*DD];
__device__ __nv_bfloat16 g_qkvW_hi[LLC*3*DD*DD];
__device__ __nv_bfloat16 g_qkvW_lo[LLC*3*DD*DD];
__device__ __nv_bfloat16 g_outW_hi[LLC*DD*DD];
__device__ __nv_bfloat16 g_outW_lo[LLC*DD*DD];
__device__ __nv_bfloat16 g_f1W_hi[LLC*DD*DFFC];
__device__ __nv_bfloat16 g_f1W_lo[LLC*DD*DFFC];
__device__ __nv_bfloat16 g_f2W_hi[LLC*DFFC*DD];
__device__ __nv_bfloat16 g_f2W_lo[LLC*DFFC*DD];
__device__ float g_part [NSL*HH*NN*64];
__device__ float g_plsum[NSL*HH*NN];

// ============================ PE pipeline (sparse) ============================
__global__ void zero_bm_kernel() {
    int idx = blockIdx.x * blockDim.x + threadIdx.x;
    if (idx < NN * 64) g_bm[idx] = 0u;
}
__global__ void scatter_bm_kernel(const int* __restrict__ ei) {
    int e = blockIdx.x * blockDim.x + threadIdx.x;
    if (e < EEC) {
        int s = ei[e], t = ei[EEC + e];
        atomicOr(&g_bm[s * 64 + (t >> 5)], 1u << (t & 31));
        atomicOr(&g_bm[t * 64 + (s >> 5)], 1u << (s & 31));
    }
}
__global__ void build_bm_kernel() {
    __shared__ int cnt;
    int i = blockIdx.x, t = threadIdx.x;
    if (t == 0) cnt = 0;
    __syncthreads();
    uint32_t w = g_bm[i * 64 + t];
    int c = __popc(w);
    int pos = (c > 0) ? atomicAdd(&cnt, c) : 0;
    while (w) {
        int b = __ffs(w) - 1;
        w &= w - 1;
        if (pos < MAXD) g_nbr[i * MAXD + pos] = t * 32 + b;
        pos++;
    }
    __syncthreads();
    if (t == 0) {
        int cc = cnt < MAXD ? cnt : MAXD;
        g_cnt[i] = cc;
        float d = cnt < 1 ? 1.f : (float)cnt;
        g_deg[i] = d;
        g_invdeg[i] = 1.f / d;
    }
}
__global__ void __launch_bounds__(256) t2_kernel() {
    __shared__ float rowbuf[NN];
    int i = blockIdx.x, t = threadIdx.x;
    #pragma unroll
    for (int u = 0; u < NN / 256; u++) rowbuf[t + u * 256] = 0.f;
    __syncthreads();
    int cnt = g_cnt[i];
    float inv_i = g_invdeg[i];
    for (int c = t >> 3; c < cnt; c += 32) {
        int j = g_nbr[i * MAXD + c];
        float w = inv_i * g_invdeg[j];
        int cj = g_cnt[j];
        const int* nbj = g_nbr + j * MAXD;
        for (int k = t & 7; k < cj; k += 8) atomicAdd(&rowbuf[nbj[k]], w);
    }
    __syncthreads();
    __nv_bfloat16* out = g_T2b + (size_t)i * NN;
    #pragma unroll
    for (int u = 0; u < NN / 256; u++) {
        int idx = t + u * 256;
        out[idx] = __float2bfloat16_rn(rowbuf[idx]);
    }
}
__global__ void __launch_bounds__(256) spmm_bf_kernel(const __nv_bfloat16* __restrict__ IN,
                                                      __nv_bfloat16* __restrict__ OUT) {
    int i = blockIdx.x, t = threadIdx.x;
    int cnt = g_cnt[i];
    float inv = g_invdeg[i];
    const int* nb = g_nbr + i * MAXD;
    float2 acc[4];
    #pragma unroll
    for (int u = 0; u < 4; u++) acc[u] = make_float2(0.f, 0.f);
    for (int c = 0; c < cnt; c++) {
        const __nv_bfloat162* row = reinterpret_cast<const __nv_bfloat162*>(IN + (size_t)nb[c] * NN);
        #pragma unroll
        for (int u = 0; u < 4; u++) {
            float2 v = __bfloat1622float2(row[t + u * 256]);
            acc[u].x += v.x; acc[u].y += v.y;
        }
    }
    __nv_bfloat162* out = reinterpret_cast<__nv_bfloat162*>(OUT + (size_t)i * NN);
    #pragma unroll
    for (int u = 0; u < 4; u++)
        out[t + u * 256] = __floats2bfloat162_rn(acc[u].x * inv, acc[u].y * inv);
}
__global__ void diag2_kernel() {
    __shared__ float sh[256];
    __shared__ float res[7];
    int i = blockIdx.x, t = threadIdx.x;
    float inv_i = g_invdeg[i], d_i = g_deg[i];
    int cnt = g_cnt[i];
    const __nv_bfloat16* r2 = g_T2b + (size_t)i * NN;
    const __nv_bfloat16* r3 = g_T3b + (size_t)i * NN;
    const __nv_bfloat16* r4 = g_T4b + (size_t)i * NN;
    float s[7] = {};
    for (int c = t; c < cnt; c += 256) {
        int j = g_nbr[i * MAXD + c];
        float wj = g_invdeg[j];
        s[0] += wj;
        s[1] += __bfloat162float(r2[j]) * wj;
    }
    for (int j = t; j < NN; j += 256) {
        float w = g_invdeg[j];
        float t2 = __bfloat162float(r2[j]);
        float t3 = __bfloat162float(r3[j]);
        float t4 = __bfloat162float(r4[j]);
        s[2] += t2 * t2 * w;
        s[3] += t3 * t2 * w;
        s[4] += t3 * t3 * w;
        s[5] += t4 * t3 * w;
        s[6] += t4 * t4 * w;
    }
    for (int v = 0; v < 7; v++) {
        sh[t] = s[v]; __syncthreads();
        for (int k = 128; k > 0; k >>= 1) { if (t < k) sh[t] += sh[t + k]; __syncthreads(); }
        if (t == 0) res[v] = sh[0];
        __syncthreads();
    }
    if (t == 0) {
        bool self = (g_bm[i * 64 + (i >> 5)] >> (i & 31)) & 1u;
        g_rw[i * WALKC + 0] = self ? inv_i : 0.f;
        g_rw[i * WALKC + 1] = inv_i * res[0];
        g_rw[i * WALKC + 2] = res[1];
        g_rw[i * WALKC + 3] = d_i * res[2];
        g_rw[i * WALKC + 4] = d_i * res[3];
        g_rw[i * WALKC + 5] = d_i * res[4];
        g_rw[i * WALKC + 6] = d_i * res[5];
        g_rw[i * WALKC + 7] = d_i * res[6];
    }
}
__global__ void pe_kernel(const float* __restrict__ W, const float* __restrict__ b) {
    int i = blockIdx.x * blockDim.x + threadIdx.x;
    if (i >= NN) return;
    float r[WALKC];
    #pragma unroll
    for (int w = 0; w < WALKC; w++) r[w] = g_rw[i * WALKC + w];
    #pragma unroll
    for (int d = 0; d < DPEC; d++) {
        float s = b[d];
        #pragma unroll
        for (int w = 0; w < WALKC; w++) s += r[w] * W[w * DPEC + d];
        g_pe[i * DPEC + d] = s;
    }
}
__global__ void pep_kernel(const float* __restrict__ W, const float* __restrict__ b) {
    int i = blockIdx.x * blockDim.x + threadIdx.x;
    if (i >= NN) return;
    float p[DPEC];
    #pragma unroll
    for (int d = 0; d < DPEC; d++) p[d] = g_pe[i * DPEC + d];
    for (int l = 0; l < LLC; l++) {
        #pragma unroll
        for (int h = 0; h < HH; h++) {
            float s = b[l * HH + h];
            #pragma unroll
            for (int d = 0; d < DPEC; d++) s += p[d] * W[(l * DPEC + d) * HH + h];
            g_pep[(size_t)l * NN * HH + i * HH + h] = s;
        }
    }
}

// ============================ conversions ============================
__global__ void split_copy_kernel(const float* __restrict__ src) {
    int idx = blockIdx.x * blockDim.x + threadIdx.x;
    if (idx < NN * DD) {
        float v = src[idx];
        g_x[idx] = v;
        __nv_bfloat16 h = __float2bfloat16_rn(v);
        g_Ahi[idx] = h;
        g_Alo[idx] = __float2bfloat16_rn(v - __bfloat162float(h));
    }
}
__global__ void convW_kernel(const float* __restrict__ W, __nv_bfloat16* __restrict__ hi,
                             __nv_bfloat16* __restrict__ lo, int K, int N) {
    __shared__ float tile[32][33];
    size_t lw = (size_t)blockIdx.z * K * N;
    int n0 = blockIdx.x * 32, k0 = blockIdx.y * 32;
    int tx = threadIdx.x, ty = threadIdx.y;
    #pragma unroll
    for (int r = 0; r < 4; r++)
        tile[ty + r * 8][tx] = W[lw + (size_t)(k0 + ty + r * 8) * N + n0 + tx];
    __syncthreads();
    #pragma unroll
    for (int r = 0; r < 4; r++) {
        int ni = ty + r * 8;
        float v = tile[tx][ni];
        __nv_bfloat16 h = __float2bfloat16_rn(v);
        size_t o = lw + (size_t)(n0 + ni) * K + k0 + tx;
        hi[o] = h;
        lo[o] = __float2bfloat16_rn(v - __bfloat162float(h));
    }
}

// ============================ mma.sync bf16x3 GEMM (BK=64, 2-stage, TM=64, optional split-K) ============================
template<int EPI, int TM, int SPLITK>  // EPI: 0 fp32 out; 2 bf16 hi/lo out; 3 GELU + bf16 hi/lo out
__global__ void __launch_bounds__(256) mma_gemm_kernel(
    const __nv_bfloat16* __restrict__ Ahi, const __nv_bfloat16* __restrict__ Alo,
    const __nv_bfloat16* __restrict__ Bhi, const __nv_bfloat16* __restrict__ Blo,
    const float* __restrict__ bias, float* __restrict__ C,
    __nv_bfloat16* __restrict__ Chi, __nv_bfloat16* __restrict__ Clo, int N, int K)
{
    constexpr int MBN    = TM / 64;
    constexpr int ABYTES = TM * 128;
    constexpr int STAGE  = 2 * ABYTES + 32768;
    extern __shared__ char smem[];
    const int tid  = threadIdx.x;
    const int lane = tid & 31;
    const int wid  = tid >> 5;
    const int m0 = blockIdx.y * TM, n0 = blockIdx.x * 128;
    const int wrow = (wid >> 1) * (16 * MBN);
    const int wcol = (wid & 1) * 64;
    const uint32_t sbase = smem_to_u32(smem);
    const int kseg = K / SPLITK;
    const int koff = (SPLITK > 1) ? blockIdx.z * kseg : 0;

    float acc[MBN][8][4];
    #pragma unroll
    for (int a = 0; a < MBN; a++)
        #pragma unroll
        for (int b = 0; b < 8; b++)
            #pragma unroll
            for (int c = 0; c < 4; c++) acc[a][b][c] = 0.f;

    const int nc = kseg >> 6;

    auto loadChunk = [&](int c) {
        uint32_t sb = sbase + (uint32_t)(c & 1) * STAGE;
        int k0 = koff + (c << 6);
        #pragma unroll
        for (int t2 = 0; t2 < 2; t2++) {
            const __nv_bfloat16* s = t2 ? Alo : Ahi;
            #pragma unroll
            for (int it = 0; it < TM / 32; it++) {
                int idx = it * 256 + tid;
                int row = idx >> 3, ch = idx & 7;
                CP_ASYNC16(sb + t2 * ABYTES + ASM_OFF(row, ch),
                           s + (size_t)(m0 + row) * K + k0 + ch * 8);
            }
        }
        #pragma unroll
        for (int t2 = 0; t2 < 2; t2++) {
            const __nv_bfloat16* s = t2 ? Blo : Bhi;
            #pragma unroll
            for (int it = 0; it < 4; it++) {
                int idx = it * 256 + tid;
                int row = idx >> 3, ch = idx & 7;
                CP_ASYNC16(sb + 2 * ABYTES + t2 * 16384 + ASM_OFF(row, ch),
                           s + (size_t)(n0 + row) * K + k0 + ch * 8);
            }
        }
        CP_COMMIT();
    };

    loadChunk(0);
    if (nc > 1) loadChunk(1);

    for (int c = 0; c < nc; c++) {
        if (c + 1 < nc) CP_WAIT1(); else CP_WAIT0();
        __syncthreads();
        uint32_t sb = sbase + (uint32_t)(c & 1) * STAGE;
        uint32_t sAh = sb, sAl = sb + ABYTES, sBh = sb + 2 * ABYTES, sBl = sb + 2 * ABYTES + 16384;
        #pragma unroll
        for (int ks = 0; ks < 4; ks++) {
            uint32_t ah[MBN][4], al[MBN][4], bh[4][4], bl[4][4];
            {
                int sub = lane >> 3;
                int row16 = (lane & 7) + ((sub & 1) << 3);
                int kc = ks * 2 + (sub >> 1);
                #pragma unroll
                for (int mb = 0; mb < MBN; mb++) {
                    int row = wrow + mb * 16 + row16;
                    uint32_t off = ASM_OFF(row, kc);
                    ldsm4(ah[mb], sAh + off);
                    ldsm4(al[mb], sAl + off);
                }
            }
            {
                int sub = lane >> 3;
                int kc = ks * 2 + (sub & 1);
                int nr = ((sub >> 1) << 3) + (lane & 7);
                #pragma unroll
                for (int j = 0; j < 4; j++) {
                    int row = wcol + j * 16 + nr;
                    uint32_t off = ASM_OFF(row, kc);
                    ldsm4(bh[j], sBh + off);
                    ldsm4(bl[j], sBl + off);
                }
            }
            #pragma unroll
            for (int mb = 0; mb < MBN; mb++)
                #pragma unroll
                for (int j = 0; j < 4; j++) {
                    mma16816(acc[mb][2*j],     ah[mb], &bh[j][0]);
                    mma16816(acc[mb][2*j],     ah[mb], &bl[j][0]);
                    mma16816(acc[mb][2*j],     al[mb], &bh[j][0]);
                    mma16816(acc[mb][2*j + 1], ah[mb], &bh[j][2]);
                    mma16816(acc[mb][2*j + 1], ah[mb], &bl[j][2]);
                    mma16816(acc[mb][2*j + 1], al[mb], &bh[j][2]);
                }
        }
        __syncthreads();
        if (c + 2 < nc) loadChunk(c + 2);
    }

    const int r_l = lane >> 2;
    const int c_l = (lane & 3) << 1;
    float* Cz = C;
    if (SPLITK > 1) Cz = C + (size_t)blockIdx.z * NN * N;
    const bool useBias = (SPLITK == 1) || (blockIdx.z == 0);
    #pragma unroll
    for (int mb = 0; mb < MBN; mb++) {
        #pragma unroll
        for (int nb = 0; nb < 8; nb++) {
            int row = m0 + wrow + mb * 16 + r_l;
            int col = n0 + wcol + nb * 8 + c_l;
            float b0 = useBias ? bias[col]     : 0.f;
            float b1 = useBias ? bias[col + 1] : 0.f;
            float v0 = acc[mb][nb][0] + b0;
            float v1 = acc[mb][nb][1] + b1;
            float v2 = acc[mb][nb][2] + b0;
            float v3 = acc[mb][nb][3] + b1;
            if (EPI == 3) {
                v0 = 0.5f * v0 * (1.f + erff(v0 * 0.70710678118654752f));
                v1 = 0.5f * v1 * (1.f + erff(v1 * 0.70710678118654752f));
                v2 = 0.5f * v2 * (1.f + erff(v2 * 0.70710678118654752f));
                v3 = 0.5f * v3 * (1.f + erff(v3 * 0.70710678118654752f));
            }
            if (EPI == 0) {
                *reinterpret_cast<float2*>(Cz + (size_t)row * N + col)       = make_float2(v0, v1);
                *reinterpret_cast<float2*>(Cz + (size_t)(row + 8) * N + col) = make_float2(v2, v3);
            } else {
                __nv_bfloat162 h01 = __floats2bfloat162_rn(v0, v1);
                __nv_bfloat162 h23 = __floats2bfloat162_rn(v2, v3);
                __nv_bfloat162 l01 = __floats2bfloat162_rn(v0 - __bfloat162float(h01.x),
                                                           v1 - __bfloat162float(h01.y));
                __nv_bfloat162 l23 = __floats2bfloat162_rn(v2 - __bfloat162float(h23.x),
                                                           v3 - __bfloat162float(h23.y));
                *reinterpret_cast<__nv_bfloat162*>(Chi + (size_t)row * N + col)       = h01;
                *reinterpret_cast<__nv_bfloat162*>(Chi + (size_t)(row + 8) * N + col) = h23;
                *reinterpret_cast<__nv_bfloat162*>(Clo + (size_t)row * N + col)       = l01;
                *reinterpret_cast<__nv_bfloat162*>(Clo + (size_t)(row + 8) * N + col) = l23;
            }
        }
    }
}

// ============================ tensor-core attention ============================
// S = Qh·Kh only (score error ~3e-4 absolute, provably safe under softmax);
// P·V keeps the full 3-term scheme. Q-lo/K-lo never loaded.
// smem: QH 16K; KV stages (KH 8K, VH 8K, VL 8K = 24K) x2; bias. 64.5KB -> 3 CTA/SM.
#define AT_QH   0
#define AT_KV   16384
#define AT_KVST 24576
#define AT_BIAS (16384 + 2 * 24576)
#define AT_SMEM (AT_BIAS + 512)
#define NCHUNK  (NN / NSL / 64)

__global__ void __launch_bounds__(128) attn_tc_kernel(
    const __nv_bfloat16* __restrict__ qh, const __nv_bfloat16* __restrict__ ql,
    const float* __restrict__ pep, float* __restrict__ part, float* __restrict__ plsum)
{
    extern __shared__ char sm[];
    const int h = blockIdx.y, sl = blockIdx.z;
    const int q0 = blockIdx.x * 128;
    const int tid = threadIdx.x, lane = tid & 31, wid = tid >> 5;
    const int wrow = wid * 32;
    const int sub = lane >> 3;
    const uint32_t sb = smem_to_u32(sm);
    float* bias = reinterpret_cast<float*>(sm + AT_BIAS);

    // Q hi tile only
    #pragma unroll
    for (int it = 0; it < 8; it++) {
        int idx = it * 128 + tid;
        int row = idx >> 3, ch = idx & 7;
        size_t g = (size_t)(q0 + row) * 1536 + h * 64 + ch * 8;
        CP_ASYNC16(sb + AT_QH + ASM_OFF(row, ch), qh + g);
    }
    {
        const int kk = sl * (NN / NSL);
        uint32_t stb = sb + AT_KV;
        #pragma unroll
        for (int it = 0; it < 4; it++) {
            int idx = it * 128 + tid;
            int row = idx >> 3, ch = idx & 7;
            size_t gk = (size_t)(kk + row) * 1536 + 512 + h * 64 + ch * 8;
            uint32_t off = ASM_OFF(row, ch);
            CP_ASYNC16(stb + off,         qh + gk);            // K hi
            CP_ASYNC16(stb + 8192 + off,  qh + gk + 512);      // V hi
            CP_ASYNC16(stb + 16384 + off, ql + gk + 512);      // V lo
        }
        if (tid < 64) bias[tid] = pep[(size_t)(kk + tid) * HH + h];
    }
    CP_COMMIT();

    float O[2][8][4];
    float ls[2][2] = {{0.f, 0.f}, {0.f, 0.f}};
    #pragma unroll
    for (int mb = 0; mb < 2; mb++)
        #pragma unroll
        for (int nb = 0; nb < 8; nb++)
            #pragma unroll
            for (int u = 0; u < 4; u++) O[mb][nb][u] = 0.f;

    for (int c = 0; c < NCHUNK; c++) {
        CP_WAIT0();
        __syncthreads();
        if (c < NCHUNK - 1) {
            const int kn = sl * (NN / NSL) + (c + 1) * 64;
            uint32_t stb = sb + AT_KV + (uint32_t)((c + 1) & 1) * AT_KVST;
            #pragma unroll
            for (int it = 0; it < 4; it++) {
                int idx = it * 128 + tid;
                int row = idx >> 3, ch = idx & 7;
                size_t gk = (size_t)(kn + row) * 1536 + 512 + h * 64 + ch * 8;
                uint32_t off = ASM_OFF(row, ch);
                CP_ASYNC16(stb + off,         qh + gk);
                CP_ASYNC16(stb + 8192 + off,  qh + gk + 512);
                CP_ASYNC16(stb + 16384 + off, ql + gk + 512);
            }
            if (tid < 64) bias[((c + 1) & 1) * 64 + tid] = pep[(size_t)(kn + tid) * HH + h];
            CP_COMMIT();
        }
        const uint32_t stc = sb + AT_KV + (uint32_t)(c & 1) * AT_KVST;
        const uint32_t sKH = stc, sVH = stc + 8192, sVL = stc + 16384;
        const float* bs = bias + (c & 1) * 64;

        // ---- S = Qh Kh^T (single MMA per tile) ----
        float S[2][8][4];
        #pragma unroll
        for (int mb = 0; mb < 2; mb++)
            #pragma unroll
            for (int nb = 0; nb < 8; nb++)
                #pragma unroll
                for (int u = 0; u < 4; u++) S[mb][nb][u] = 0.f;
        #pragma unroll
        for (int kb = 0; kb < 4; kb++) {
            uint32_t ah[2][4];
            int r16 = (lane & 7) + ((sub & 1) << 3);
            int chA = kb * 2 + (sub >> 1);
            #pragma unroll
            for (int mb = 0; mb < 2; mb++) {
                int row = wrow + mb * 16 + r16;
                ldsm4(ah[mb], sb + AT_QH + ASM_OFF(row, chA));
            }
            int chB = kb * 2 + (sub & 1);
            int nr = ((sub >> 1) << 3) + (lane & 7);
            #pragma unroll
            for (int j = 0; j < 4; j++) {
                uint32_t bh[4];
                int row = j * 16 + nr;
                ldsm4(bh, sKH + ASM_OFF(row, chB));
                #pragma unroll
                for (int mb = 0; mb < 2; mb++) {
                    mma16816(S[mb][2*j],   ah[mb], &bh[0]);
                    mma16816(S[mb][2*j+1], ah[mb], &bh[2]);
                }
            }
        }

        // ---- softmax (fixed m=0) + in-register bf16 hi/lo pack of P ----
        uint32_t Ph[2][8][2], Pl[2][8][2];
        #pragma unroll
        for (int mb = 0; mb < 2; mb++)
            #pragma unroll
            for (int nb = 0; nb < 8; nb++) {
                int col = nb * 8 + ((lane & 3) << 1);
                float b0 = bs[col], b1 = bs[col + 1];
                float p0 = __expf(fmaf(S[mb][nb][0], 0.125f, -b0));
                float p1 = __expf(fmaf(S[mb][nb][1], 0.125f, -b1));
                float p2 = __expf(fmaf(S[mb][nb][2], 0.125f, -b0));
                float p3 = __expf(fmaf(S[mb][nb][3], 0.125f, -b1));
                ls[mb][0] += p0 + p1;
                ls[mb][1] += p2 + p3;
                __nv_bfloat162 h01 = __floats2bfloat162_rn(p0, p1);
                __nv_bfloat162 h23 = __floats2bfloat162_rn(p2, p3);
                __nv_bfloat162 l01 = __floats2bfloat162_rn(p0 - __bfloat162float(h01.x),
                                                           p1 - __bfloat162float(h01.y));
                __nv_bfloat162 l23 = __floats2bfloat162_rn(p2 - __bfloat162float(h23.x),
                                                           p3 - __bfloat162float(h23.y));
                Ph[mb][nb][0] = *reinterpret_cast<uint32_t*>(&h01);
                Ph[mb][nb][1] = *reinterpret_cast<uint32_t*>(&h23);
                Pl[mb][nb][0] = *reinterpret_cast<uint32_t*>(&l01);
                Pl[mb][nb][1] = *reinterpret_cast<uint32_t*>(&l23);
            }

        // ---- O += P V (full 3-term) ----
        #pragma unroll
        for (int kb2 = 0; kb2 < 4; kb2++) {
            int krow = kb2 * 16 + ((sub & 1) << 3) + (lane & 7);
            #pragma unroll
            for (int dI = 0; dI < 4; dI++) {
                uint32_t vh[4], vl[4];
                int ch = dI * 2 + (sub >> 1);
                uint32_t off = ASM_OFF(krow, ch);
                ldsm4t(vh, sVH + off);
                ldsm4t(vl, sVL + off);
                #pragma unroll
                for (int mb = 0; mb < 2; mb++) {
                    uint32_t pa[4] = {Ph[mb][2*kb2][0], Ph[mb][2*kb2][1],
                                      Ph[mb][2*kb2+1][0], Ph[mb][2*kb2+1][1]};
                    uint32_t la[4] = {Pl[mb][2*kb2][0], Pl[mb][2*kb2][1],
                                      Pl[mb][2*kb2+1][0], Pl[mb][2*kb2+1][1]};
                    mma16816(O[mb][2*dI],   pa, &vh[0]);
                    mma16816(O[mb][2*dI],   la, &vh[0]);
                    mma16816(O[mb][2*dI],   pa, &vl[0]);
                    mma16816(O[mb][2*dI+1], pa, &vh[2]);
                    mma16816(O[mb][2*dI+1], la, &vh[2]);
                    mma16816(O[mb][2*dI+1], pa, &vl[2]);
                }
            }
        }
    }

    #pragma unroll
    for (int mb = 0; mb < 2; mb++)
        #pragma unroll
        for (int r = 0; r < 2; r++) {
            float v = ls[mb][r];
            v += __shfl_xor_sync(0xffffffffu, v, 1);
            v += __shfl_xor_sync(0xffffffffu, v, 2);
            ls[mb][r] = v;
        }
    const size_t base = (size_t)(sl * HH + h) * NN;
    #pragma unroll
    for (int mb = 0; mb < 2; mb++) {
        int rowA = q0 + wrow + mb * 16 + (lane >> 2);
        int rowB = rowA + 8;
        if ((lane & 3) == 0) {
            plsum[base + rowA] = ls[mb][0];
            plsum[base + rowB] = ls[mb][1];
        }
        #pragma unroll
        for (int nb = 0; nb < 8; nb++) {
            int col = nb * 8 + ((lane & 3) << 1);
            *reinterpret_cast<float2*>(part + (base + rowA) * 64 + col) = make_float2(O[mb][nb][0], O[mb][nb][1]);
            *reinterpret_cast<float2*>(part + (base + rowB) * 64 + col) = make_float2(O[mb][nb][2], O[mb][nb][3]);
        }
    }
}

__global__ void __launch_bounds__(512) attn_combine_kernel(const float* __restrict__ part, const float* __restrict__ pls,
                                                           __nv_bfloat16* __restrict__ ohi, __nv_bfloat16* __restrict__ olo) {
    int i = blockIdx.x, idx = threadIdx.x;
    int h = idx >> 6, d = idx & 63;
    float v = 0.f, l = 0.f;
    #pragma unroll
    for (int s = 0; s < NSL; s++) {
        l += pls[(size_t)(s * HH + h) * NN + i];
        v += part[((size_t)(s * HH + h) * NN + i) * 64 + d];
    }
    float r = v / l;
    __nv_bfloat16 hb = __float2bfloat16_rn(r);
    ohi[(size_t)i * DD + idx] = hb;
    olo[(size_t)i * DD + idx] = __float2bfloat16_rn(r - __bfloat162float(hb));
}

// ============================ LN over (a + p0 + p1) -> fp32 out + bf16 hi/lo (warp-shuffle reduce) ============================
__global__ void ln3_kernel(const float* __restrict__ a, const float* __restrict__ b,
                           const float* __restrict__ b2,
                           const float* __restrict__ g, const float* __restrict__ be,
                           float* __restrict__ out,
                           __nv_bfloat16* __restrict__ ohi, __nv_bfloat16* __restrict__ olo) {
    __shared__ float wsum[8];
    __shared__ float s_mu, s_r;
    int i = blockIdx.x, t = threadIdx.x;
    int lane = t & 31, wid = t >> 5;
    float v0 = a[(size_t)i * DD + t]       + b[(size_t)i * DD + t]       + b2[(size_t)i * DD + t];
    float v1 = a[(size_t)i * DD + 256 + t] + b[(size_t)i * DD + 256 + t] + b2[(size_t)i * DD + 256 + t];
    float s = v0 + v1;
    #pragma unroll
    for (int o = 16; o > 0; o >>= 1) s += __shfl_xor_sync(0xffffffffu, s, o);
    if (lane == 0) wsum[wid] = s;
    __syncthreads();
    if (t < 8) {
        float w = wsum[t];
        #pragma unroll
        for (int o = 4; o > 0; o >>= 1) w += __shfl_xor_sync(0xffu, w, o);
        if (t == 0) s_mu = w * (1.f / DD);
    }
    __syncthreads();
    float mu = s_mu;
    float d0 = v0 - mu, d1 = v1 - mu;
    float q = d0 * d0 + d1 * d1;
    #pragma unroll
    for (int o = 16; o > 0; o >>= 1) q += __shfl_xor_sync(0xffffffffu, q, o);
    if (lane == 0) wsum[wid] = q;
    __syncthreads();
    if (t < 8) {
        float w = wsum[t];
        #pragma unroll
        for (int o = 4; o > 0; o >>= 1) w += __shfl_xor_sync(0xffu, w, o);
        if (t == 0) s_r = rsqrtf(w * (1.f / DD) + 1e-5f);
    }
    __syncthreads();
    float r = s_r;
    float o0 = d0 * r * g[t]       + be[t];
    float o1 = d1 * r * g[256 + t] + be[256 + t];
    out[(size_t)i * DD + t]       = o0;
    out[(size_t)i * DD + 256 + t] = o1;
    __nv_bfloat16 h0 = __float2bfloat16_rn(o0);
    __nv_bfloat16 h1 = __float2bfloat16_rn(o1);
    ohi[(size_t)i * DD + t]       = h0;
    ohi[(size_t)i * DD + 256 + t] = h1;
    olo[(size_t)i * DD + t]       = __float2bfloat16_rn(o0 - __bfloat162float(h0));
    olo[(size_t)i * DD + 256 + t] = __float2bfloat16_rn(o1 - __bfloat162float(h1));
}

// ============================ launch ============================
extern "C" void kernel_launch(void* const* d_in, const int* in_sizes, int n_in,
                              void* d_out, int out_size) {
    const float* node_features = (const float*)d_in[0];
    const int*   edge_index    = (const int*)  d_in[1];
    const float* pe_proj_W     = (const float*)d_in[2];
    const float* pe_proj_b     = (const float*)d_in[3];
    const float* qkv_W         = (const float*)d_in[4];
    const float* qkv_b         = (const float*)d_in[5];
    const float* peb_W         = (const float*)d_in[6];
    const float* peb_b         = (const float*)d_in[7];
    const float* out_W         = (const float*)d_in[8];
    const float* out_b         = (const float*)d_in[9];
    const float* ffn_W1        = (const float*)d_in[10];
    const float* ffn_b1        = (const float*)d_in[11];
    const float* ffn_W2        = (const float*)d_in[12];
    const float* ffn_b2        = (const float*)d_in[13];
    const float* ln1_g         = (const float*)d_in[14];
    const float* ln1_b         = (const float*)d_in[15];
    const float* ln2_g         = (const float*)d_in[16];
    const float* ln2_b         = (const float*)d_in[17];
    float* outp = (float*)d_out;

    float *x_, *x1_, *o_, *pep_, *part_, *pls_;
    __nv_bfloat16 *Ahi_, *Alo_, *Hhi_, *Hlo_, *Qh_, *Ql_, *T2b_, *T3b_, *T4b_;
    __nv_bfloat16 *qWh_, *qWl_, *oWh_, *oWl_, *f1h_, *f1l_, *f2h_, *f2l_;
    cudaGetSymbolAddress((void**)&x_,   g_x);
    cudaGetSymbolAddress((void**)&x1_,  g_x1);
    cudaGetSymbolAddress((void**)&o_,   g_o);
    cudaGetSymbolAddress((void**)&pep_, g_pep);
    cudaGetSymbolAddress((void**)&part_,g_part);
    cudaGetSymbolAddress((void**)&pls_, g_plsum);
    cudaGetSymbolAddress((void**)&Ahi_, g_Ahi);
    cudaGetSymbolAddress((void**)&Alo_, g_Alo);
    cudaGetSymbolAddress((void**)&Hhi_, g_Hhi);
    cudaGetSymbolAddress((void**)&Hlo_, g_Hlo);
    cudaGetSymbolAddress((void**)&Qh_,  g_QKVhi);
    cudaGetSymbolAddress((void**)&Ql_,  g_QKVlo);
    cudaGetSymbolAddress((void**)&T2b_, g_T2b);
    cudaGetSymbolAddress((void**)&T3b_, g_T3b);
    cudaGetSymbolAddress((void**)&T4b_, g_T4b);
    cudaGetSymbolAddress((void**)&qWh_, g_qkvW_hi);
    cudaGetSymbolAddress((void**)&qWl_, g_qkvW_lo);
    cudaGetSymbolAddress((void**)&oWh_, g_outW_hi);
    cudaGetSymbolAddress((void**)&oWl_, g_outW_lo);
    cudaGetSymbolAddress((void**)&f1h_, g_f1W_hi);
    cudaGetSymbolAddress((void**)&f1l_, g_f1W_lo);
    cudaGetSymbolAddress((void**)&f2h_, g_f2W_hi);
    cudaGetSymbolAddress((void**)&f2l_, g_f2W_lo);

    constexpr int GS64 = 2 * (2 * 64 * 128 + 32768);   // 96 KB -> 2 CTA/SM
    cudaFuncSetAttribute((const void*)mma_gemm_kernel<2,64,1>, cudaFuncAttributeMaxDynamicSharedMemorySize, GS64);
    cudaFuncSetAttribute((const void*)mma_gemm_kernel<3,64,1>, cudaFuncAttributeMaxDynamicSharedMemorySize, GS64);
    cudaFuncSetAttribute((const void*)mma_gemm_kernel<0,64,2>, cudaFuncAttributeMaxDynamicSharedMemorySize, GS64);
    cudaFuncSetAttribute(attn_tc_kernel, cudaFuncAttributeMaxDynamicSharedMemorySize, AT_SMEM);

    static cudaStream_t s_side = nullptr;
    static cudaEvent_t  ev_fork = nullptr, ev_pe = nullptr;
    if (s_side == nullptr) {
        cudaStreamCreateWithFlags(&s_side, cudaStreamNonBlocking);
        cudaEventCreateWithFlags(&ev_fork, cudaEventDisableTiming);
        cudaEventCreateWithFlags(&ev_pe,   cudaEventDisableTiming);
    }

    // ---- fork: PE pipeline on side stream ----
    cudaEventRecord(ev_fork, 0);
    cudaStreamWaitEvent(s_side, ev_fork, 0);
    zero_bm_kernel<<<(NN*64)/256, 256, 0, s_side>>>();
    scatter_bm_kernel<<<EEC/256, 256, 0, s_side>>>(edge_index);
    build_bm_kernel<<<NN, 64, 0, s_side>>>();
    t2_kernel<<<NN, 256, 0, s_side>>>();
    spmm_bf_kernel<<<NN, 256, 0, s_side>>>(T2b_, T3b_);
    spmm_bf_kernel<<<NN, 256, 0, s_side>>>(T3b_, T4b_);
    diag2_kernel<<<NN, 256, 0, s_side>>>();
    pe_kernel<<<(NN + 127) / 128, 128, 0, s_side>>>(pe_proj_W, pe_proj_b);
    pep_kernel<<<(NN + 127) / 128, 128, 0, s_side>>>(peb_W, peb_b);
    cudaEventRecord(ev_pe, s_side);

    // ---- main stream: only qkv prerequisites before the first GEMM ----
    convW_kernel<<<dim3(1536/32, 512/32, LLC),  dim3(32,8)>>>(qkv_W,  qWh_, qWl_, DD,  3*DD);
    split_copy_kernel<<<(NN*DD)/256, 256>>>(node_features);

    float* o2_ = o_ + (size_t)NN * DD;
    for (int l = 0; l < LLC; l++) {
        mma_gemm_kernel<2,64,1><<<dim3(1536/128, NN/64), 256, GS64>>>(
            Ahi_, Alo_, qWh_ + (size_t)l*3*DD*DD, qWl_ + (size_t)l*3*DD*DD,
            qkv_b + (size_t)l*3*DD, nullptr, Qh_, Ql_, 3*DD, DD);
        if (l == 0) {
            convW_kernel<<<dim3(512/32,  512/32, LLC),  dim3(32,8)>>>(out_W,  oWh_, oWl_, DD,  DD);
            convW_kernel<<<dim3(2048/32, 512/32, LLC),  dim3(32,8)>>>(ffn_W1, f1h_, f1l_, DD,  DFFC);
            convW_kernel<<<dim3(512/32,  2048/32, LLC), dim3(32,8)>>>(ffn_W2, f2h_, f2l_, DFFC, DD);
            cudaStreamWaitEvent(0, ev_pe, 0);   // join: attention needs pep
        }
        attn_tc_kernel<<<dim3(NN/128, HH, NSL), 128, AT_SMEM>>>(Qh_, Ql_, pep_ + (size_t)l*NN*HH, part_, pls_);
        attn_combine_kernel<<<NN, 512>>>(part_, pls_, Ahi_, Alo_);
        mma_gemm_kernel<0,64,2><<<dim3(DD/128, NN/64, 2), 256, GS64>>>(
            Ahi_, Alo_, oWh_ + (size_t)l*DD*DD, oWl_ + (size_t)l*DD*DD,
            out_b + (size_t)l*DD, o_, nullptr, nullptr, DD, DD);
        ln3_kernel<<<NN, 256>>>(x_, o_, o2_, ln1_g + (size_t)l*DD, ln1_b + (size_t)l*DD, x1_, Ahi_, Alo_);
        mma_gemm_kernel<3,64,1><<<dim3(DFFC/128, NN/64), 256, GS64>>>(
            Ahi_, Alo_, f1h_ + (size_t)l*DD*DFFC, f1l_ + (size_t)l*DD*DFFC,
            ffn_b1 + (size_t)l*DFFC, nullptr, Hhi_, Hlo_, DFFC, DD);
        mma_gemm_kernel<0,64,2><<<dim3(DD/128, NN/64, 2), 256, GS64>>>(
            Hhi_, Hlo_, f2h_ + (size_t)l*DFFC*DD, f2l_ + (size_t)l*DFFC*DD,
            ffn_b2 + (size_t)l*DD, o_, nullptr, nullptr, DD, DFFC);
        float* xout = (l == LLC - 1) ? outp : x_;
        ln3_kernel<<<NN, 256>>>(x1_, o_, o2_, ln2_g + (size_t)l*DD, ln2_b + (size_t)l*DD, xout, Ahi_, Alo_);
    }
}

// round 13
// speedup vs baseline: 1.3423x; 1.0988x over previous
#include <cuda_runtime.h>
#include <cuda_bf16.h>
#include <math.h>
#include <stdint.h>

#define NN   2048
#define DD   512
#define HH   8
#define DPEC 16
#define WALKC 8
#define LLC  3
#define EEC  32768
#define DFFC 2048
#define MAXD 256
#define NSL  2          // attention key-slices

// ============================ PTX helpers (sm_80-baseline ISA only) ============================
__device__ __forceinline__ uint32_t smem_to_u32(const void* p) {
    uint32_t a;
    asm("{ .reg .u64 t; cvta.to.shared.u64 t, %1; cvt.u32.u64 %0, t; }" : "=r"(a) : "l"(p));
    return a;
}
#define CP_ASYNC16(dst, src) \
    asm volatile("cp.async.cg.shared.global [%0], [%1], 16;" :: "r"(dst), "l"(src))
#define CP_COMMIT() asm volatile("cp.async.commit_group;" ::: "memory")
#define CP_WAIT1()  asm volatile("cp.async.wait_group 1;" ::: "memory")
#define CP_WAIT0()  asm volatile("cp.async.wait_group 0;" ::: "memory")

__device__ __forceinline__ void ldsm4(uint32_t* r, uint32_t addr) {
    asm volatile("ldmatrix.sync.aligned.m8n8.x4.shared.b16 {%0,%1,%2,%3}, [%4];"
        : "=r"(r[0]), "=r"(r[1]), "=r"(r[2]), "=r"(r[3]) : "r"(addr));
}
__device__ __forceinline__ void ldsm4t(uint32_t* r, uint32_t addr) {
    asm volatile("ldmatrix.sync.aligned.m8n8.x4.trans.shared.b16 {%0,%1,%2,%3}, [%4];"
        : "=r"(r[0]), "=r"(r[1]), "=r"(r[2]), "=r"(r[3]) : "r"(addr));
}
__device__ __forceinline__ void mma16816(float* c, const uint32_t* a, const uint32_t* b) {
    asm volatile("mma.sync.aligned.m16n8k16.row.col.f32.bf16.bf16.f32 "
        "{%0,%1,%2,%3}, {%4,%5,%6,%7}, {%8,%9}, {%0,%1,%2,%3};"
        : "+f"(c[0]), "+f"(c[1]), "+f"(c[2]), "+f"(c[3])
        : "r"(a[0]), "r"(a[1]), "r"(a[2]), "r"(a[3]), "r"(b[0]), "r"(b[1]));
}

#define ASM_OFF(row, ch) ((uint32_t)((row) * 128 + ((((ch)) ^ ((row) & 7)) << 4)))

// ============================ static device scratch ============================
__device__ uint32_t g_bm[NN*64];
__device__ float g_deg[NN];
__device__ float g_invdeg[NN];
__device__ int   g_nbr[NN*MAXD];
__device__ int   g_cnt[NN];
__device__ __nv_bfloat16 g_T2b[NN*NN];
__device__ __nv_bfloat16 g_T3b[NN*NN];
__device__ __nv_bfloat16 g_T4b[NN*NN];
__device__ float g_rw [NN*WALKC];
__device__ float g_pe [NN*DPEC];
__device__ float g_pep[LLC*NN*HH];
__device__ float g_x   [NN*DD];
__device__ float g_x1  [NN*DD];
__device__ float g_o   [2*NN*DD];     // split-K partials
__device__ __nv_bfloat16 g_Ahi[NN*DD];
__device__ __nv_bfloat16 g_Alo[NN*DD];
__device__ __nv_bfloat16 g_Hhi[NN*DFFC];
__device__ __nv_bfloat16 g_Hlo[NN*DFFC];
__device__ __nv_bfloat16 g_QKVhi[NN*3*DD];
__device__ __nv_bfloat16 g_QKVlo[NN*3*DD];
__device__ __nv_bfloat16 g_qkvW_hi[LLC*3*DD*DD];
__device__ __nv_bfloat16 g_qkvW_lo[LLC*3*DD*DD];
__device__ __nv_bfloat16 g_outW_hi[LLC*DD*DD];
__device__ __nv_bfloat16 g_outW_lo[LLC*DD*DD];
__device__ __nv_bfloat16 g_f1W_hi[LLC*DD*DFFC];
__device__ __nv_bfloat16 g_f1W_lo[LLC*DD*DFFC];
__device__ __nv_bfloat16 g_f2W_hi[LLC*DFFC*DD];
__device__ __nv_bfloat16 g_f2W_lo[LLC*DFFC*DD];
__device__ float g_part [NSL*HH*NN*64];
__device__ float g_plsum[NSL*HH*NN];

// ============================ PE pipeline (sparse) ============================
__global__ void zero_bm_kernel() {
    int idx = blockIdx.x * blockDim.x + threadIdx.x;
    if (idx < NN * 64) g_bm[idx] = 0u;
}
__global__ void scatter_bm_kernel(const int* __restrict__ ei) {
    int e = blockIdx.x * blockDim.x + threadIdx.x;
    if (e < EEC) {
        int s = ei[e], t = ei[EEC + e];
        atomicOr(&g_bm[s * 64 + (t >> 5)], 1u << (t & 31));
        atomicOr(&g_bm[t * 64 + (s >> 5)], 1u << (s & 31));
    }
}
__global__ void build_bm_kernel() {
    __shared__ int cnt;
    int i = blockIdx.x, t = threadIdx.x;
    if (t == 0) cnt = 0;
    __syncthreads();
    uint32_t w = g_bm[i * 64 + t];
    int c = __popc(w);
    int pos = (c > 0) ? atomicAdd(&cnt, c) : 0;
    while (w) {
        int b = __ffs(w) - 1;
        w &= w - 1;
        if (pos < MAXD) g_nbr[i * MAXD + pos] = t * 32 + b;
        pos++;
    }
    __syncthreads();
    if (t == 0) {
        int cc = cnt < MAXD ? cnt : MAXD;
        g_cnt[i] = cc;
        float d = cnt < 1 ? 1.f : (float)cnt;
        g_deg[i] = d;
        g_invdeg[i] = 1.f / d;
    }
}
__global__ void __launch_bounds__(256) t2_kernel() {
    __shared__ float rowbuf[NN];
    int i = blockIdx.x, t = threadIdx.x;
    #pragma unroll
    for (int u = 0; u < NN / 256; u++) rowbuf[t + u * 256] = 0.f;
    __syncthreads();
    int cnt = g_cnt[i];
    float inv_i = g_invdeg[i];
    for (int c = t >> 3; c < cnt; c += 32) {
        int j = g_nbr[i * MAXD + c];
        float w = inv_i * g_invdeg[j];
        int cj = g_cnt[j];
        const int* nbj = g_nbr + j * MAXD;
        for (int k = t & 7; k < cj; k += 8) atomicAdd(&rowbuf[nbj[k]], w);
    }
    __syncthreads();
    __nv_bfloat16* out = g_T2b + (size_t)i * NN;
    #pragma unroll
    for (int u = 0; u < NN / 256; u++) {
        int idx = t + u * 256;
        out[idx] = __float2bfloat16_rn(rowbuf[idx]);
    }
}
__global__ void __launch_bounds__(256) spmm_bf_kernel(const __nv_bfloat16* __restrict__ IN,
                                                      __nv_bfloat16* __restrict__ OUT) {
    int i = blockIdx.x, t = threadIdx.x;
    int cnt = g_cnt[i];
    float inv = g_invdeg[i];
    const int* nb = g_nbr + i * MAXD;
    float2 acc[4];
    #pragma unroll
    for (int u = 0; u < 4; u++) acc[u] = make_float2(0.f, 0.f);
    for (int c = 0; c < cnt; c++) {
        const __nv_bfloat162* row = reinterpret_cast<const __nv_bfloat162*>(IN + (size_t)nb[c] * NN);
        #pragma unroll
        for (int u = 0; u < 4; u++) {
            float2 v = __bfloat1622float2(row[t + u * 256]);
            acc[u].x += v.x; acc[u].y += v.y;
        }
    }
    __nv_bfloat162* out = reinterpret_cast<__nv_bfloat162*>(OUT + (size_t)i * NN);
    #pragma unroll
    for (int u = 0; u < 4; u++)
        out[t + u * 256] = __floats2bfloat162_rn(acc[u].x * inv, acc[u].y * inv);
}
__global__ void diag2_kernel() {
    __shared__ float sh[256];
    __shared__ float res[7];
    int i = blockIdx.x, t = threadIdx.x;
    float inv_i = g_invdeg[i], d_i = g_deg[i];
    int cnt = g_cnt[i];
    const __nv_bfloat16* r2 = g_T2b + (size_t)i * NN;
    const __nv_bfloat16* r3 = g_T3b + (size_t)i * NN;
    const __nv_bfloat16* r4 = g_T4b + (size_t)i * NN;
    float s[7] = {};
    for (int c = t; c < cnt; c += 256) {
        int j = g_nbr[i * MAXD + c];
        float wj = g_invdeg[j];
        s[0] += wj;
        s[1] += __bfloat162float(r2[j]) * wj;
    }
    for (int j = t; j < NN; j += 256) {
        float w = g_invdeg[j];
        float t2 = __bfloat162float(r2[j]);
        float t3 = __bfloat162float(r3[j]);
        float t4 = __bfloat162float(r4[j]);
        s[2] += t2 * t2 * w;
        s[3] += t3 * t2 * w;
        s[4] += t3 * t3 * w;
        s[5] += t4 * t3 * w;
        s[6] += t4 * t4 * w;
    }
    for (int v = 0; v < 7; v++) {
        sh[t] = s[v]; __syncthreads();
        for (int k = 128; k > 0; k >>= 1) { if (t < k) sh[t] += sh[t + k]; __syncthreads(); }
        if (t == 0) res[v] = sh[0];
        __syncthreads();
    }
    if (t == 0) {
        bool self = (g_bm[i * 64 + (i >> 5)] >> (i & 31)) & 1u;
        g_rw[i * WALKC + 0] = self ? inv_i : 0.f;
        g_rw[i * WALKC + 1] = inv_i * res[0];
        g_rw[i * WALKC + 2] = res[1];
        g_rw[i * WALKC + 3] = d_i * res[2];
        g_rw[i * WALKC + 4] = d_i * res[3];
        g_rw[i * WALKC + 5] = d_i * res[4];
        g_rw[i * WALKC + 6] = d_i * res[5];
        g_rw[i * WALKC + 7] = d_i * res[6];
    }
}
__global__ void pe_kernel(const float* __restrict__ W, const float* __restrict__ b) {
    int i = blockIdx.x * blockDim.x + threadIdx.x;
    if (i >= NN) return;
    float r[WALKC];
    #pragma unroll
    for (int w = 0; w < WALKC; w++) r[w] = g_rw[i * WALKC + w];
    #pragma unroll
    for (int d = 0; d < DPEC; d++) {
        float s = b[d];
        #pragma unroll
        for (int w = 0; w < WALKC; w++) s += r[w] * W[w * DPEC + d];
        g_pe[i * DPEC + d] = s;
    }
}
__global__ void pep_kernel(const float* __restrict__ W, const float* __restrict__ b) {
    int i = blockIdx.x * blockDim.x + threadIdx.x;
    if (i >= NN) return;
    float p[DPEC];
    #pragma unroll
    for (int d = 0; d < DPEC; d++) p[d] = g_pe[i * DPEC + d];
    for (int l = 0; l < LLC; l++) {
        #pragma unroll
        for (int h = 0; h < HH; h++) {
            float s = b[l * HH + h];
            #pragma unroll
            for (int d = 0; d < DPEC; d++) s += p[d] * W[(l * DPEC + d) * HH + h];
            g_pep[(size_t)l * NN * HH + i * HH + h] = s;
        }
    }
}

// ============================ conversions ============================
__global__ void split_copy_kernel(const float* __restrict__ src) {
    int idx = blockIdx.x * blockDim.x + threadIdx.x;
    if (idx < NN * DD) {
        float v = src[idx];
        g_x[idx] = v;
        __nv_bfloat16 h = __float2bfloat16_rn(v);
        g_Ahi[idx] = h;
        g_Alo[idx] = __float2bfloat16_rn(v - __bfloat162float(h));
    }
}
__global__ void convW_kernel(const float* __restrict__ W, __nv_bfloat16* __restrict__ hi,
                             __nv_bfloat16* __restrict__ lo, int K, int N) {
    __shared__ float tile[32][33];
    size_t lw = (size_t)blockIdx.z * K * N;
    int n0 = blockIdx.x * 32, k0 = blockIdx.y * 32;
    int tx = threadIdx.x, ty = threadIdx.y;
    #pragma unroll
    for (int r = 0; r < 4; r++)
        tile[ty + r * 8][tx] = W[lw + (size_t)(k0 + ty + r * 8) * N + n0 + tx];
    __syncthreads();
    #pragma unroll
    for (int r = 0; r < 4; r++) {
        int ni = ty + r * 8;
        float v = tile[tx][ni];
        __nv_bfloat16 h = __float2bfloat16_rn(v);
        size_t o = lw + (size_t)(n0 + ni) * K + k0 + tx;
        hi[o] = h;
        lo[o] = __float2bfloat16_rn(v - __bfloat162float(h));
    }
}

// ============================ mma.sync bf16x3 GEMM (BK=64, 2-stage, TM=64, optional split-K) ============================
template<int EPI, int TM, int SPLITK>  // EPI: 0 fp32 out; 2 bf16 hi/lo out; 3 GELU + bf16 hi/lo out
__global__ void __launch_bounds__(256) mma_gemm_kernel(
    const __nv_bfloat16* __restrict__ Ahi, const __nv_bfloat16* __restrict__ Alo,
    const __nv_bfloat16* __restrict__ Bhi, const __nv_bfloat16* __restrict__ Blo,
    const float* __restrict__ bias, float* __restrict__ C,
    __nv_bfloat16* __restrict__ Chi, __nv_bfloat16* __restrict__ Clo, int N, int K)
{
    constexpr int MBN    = TM / 64;
    constexpr int ABYTES = TM * 128;
    constexpr int STAGE  = 2 * ABYTES + 32768;
    extern __shared__ char smem[];
    const int tid  = threadIdx.x;
    const int lane = tid & 31;
    const int wid  = tid >> 5;
    const int m0 = blockIdx.y * TM, n0 = blockIdx.x * 128;
    const int wrow = (wid >> 1) * (16 * MBN);
    const int wcol = (wid & 1) * 64;
    const uint32_t sbase = smem_to_u32(smem);
    const int kseg = K / SPLITK;
    const int koff = (SPLITK > 1) ? blockIdx.z * kseg : 0;

    float acc[MBN][8][4];
    #pragma unroll
    for (int a = 0; a < MBN; a++)
        #pragma unroll
        for (int b = 0; b < 8; b++)
            #pragma unroll
            for (int c = 0; c < 4; c++) acc[a][b][c] = 0.f;

    const int nc = kseg >> 6;

    auto loadChunk = [&](int c) {
        uint32_t sb = sbase + (uint32_t)(c & 1) * STAGE;
        int k0 = koff + (c << 6);
        #pragma unroll
        for (int t2 = 0; t2 < 2; t2++) {
            const __nv_bfloat16* s = t2 ? Alo : Ahi;
            #pragma unroll
            for (int it = 0; it < TM / 32; it++) {
                int idx = it * 256 + tid;
                int row = idx >> 3, ch = idx & 7;
                CP_ASYNC16(sb + t2 * ABYTES + ASM_OFF(row, ch),
                           s + (size_t)(m0 + row) * K + k0 + ch * 8);
            }
        }
        #pragma unroll
        for (int t2 = 0; t2 < 2; t2++) {
            const __nv_bfloat16* s = t2 ? Blo : Bhi;
            #pragma unroll
            for (int it = 0; it < 4; it++) {
                int idx = it * 256 + tid;
                int row = idx >> 3, ch = idx & 7;
                CP_ASYNC16(sb + 2 * ABYTES + t2 * 16384 + ASM_OFF(row, ch),
                           s + (size_t)(n0 + row) * K + k0 + ch * 8);
            }
        }
        CP_COMMIT();
    };

    loadChunk(0);
    if (nc > 1) loadChunk(1);

    for (int c = 0; c < nc; c++) {
        if (c + 1 < nc) CP_WAIT1(); else CP_WAIT0();
        __syncthreads();
        uint32_t sb = sbase + (uint32_t)(c & 1) * STAGE;
        uint32_t sAh = sb, sAl = sb + ABYTES, sBh = sb + 2 * ABYTES, sBl = sb + 2 * ABYTES + 16384;
        #pragma unroll
        for (int ks = 0; ks < 4; ks++) {
            uint32_t ah[MBN][4], al[MBN][4], bh[4][4], bl[4][4];
            {
                int sub = lane >> 3;
                int row16 = (lane & 7) + ((sub & 1) << 3);
                int kc = ks * 2 + (sub >> 1);
                #pragma unroll
                for (int mb = 0; mb < MBN; mb++) {
                    int row = wrow + mb * 16 + row16;
                    uint32_t off = ASM_OFF(row, kc);
                    ldsm4(ah[mb], sAh + off);
                    ldsm4(al[mb], sAl + off);
                }
            }
            {
                int sub = lane >> 3;
                int kc = ks * 2 + (sub & 1);
                int nr = ((sub >> 1) << 3) + (lane & 7);
                #pragma unroll
                for (int j = 0; j < 4; j++) {
                    int row = wcol + j * 16 + nr;
                    uint32_t off = ASM_OFF(row, kc);
                    ldsm4(bh[j], sBh + off);
                    ldsm4(bl[j], sBl + off);
                }
            }
            #pragma unroll
            for (int mb = 0; mb < MBN; mb++)
                #pragma unroll
                for (int j = 0; j < 4; j++) {
                    mma16816(acc[mb][2*j],     ah[mb], &bh[j][0]);
                    mma16816(acc[mb][2*j],     ah[mb], &bl[j][0]);
                    mma16816(acc[mb][2*j],     al[mb], &bh[j][0]);
                    mma16816(acc[mb][2*j + 1], ah[mb], &bh[j][2]);
                    mma16816(acc[mb][2*j + 1], ah[mb], &bl[j][2]);
                    mma16816(acc[mb][2*j + 1], al[mb], &bh[j][2]);
                }
        }
        __syncthreads();
        if (c + 2 < nc) loadChunk(c + 2);
    }

    const int r_l = lane >> 2;
    const int c_l = (lane & 3) << 1;
    float* Cz = C;
    if (SPLITK > 1) Cz = C + (size_t)blockIdx.z * NN * N;
    const bool useBias = (SPLITK == 1) || (blockIdx.z == 0);
    #pragma unroll
    for (int mb = 0; mb < MBN; mb++) {
        #pragma unroll
        for (int nb = 0; nb < 8; nb++) {
            int row = m0 + wrow + mb * 16 + r_l;
            int col = n0 + wcol + nb * 8 + c_l;
            float b0 = useBias ? bias[col]     : 0.f;
            float b1 = useBias ? bias[col + 1] : 0.f;
            float v0 = acc[mb][nb][0] + b0;
            float v1 = acc[mb][nb][1] + b1;
            float v2 = acc[mb][nb][2] + b0;
            float v3 = acc[mb][nb][3] + b1;
            if (EPI == 3) {
                v0 = 0.5f * v0 * (1.f + erff(v0 * 0.70710678118654752f));
                v1 = 0.5f * v1 * (1.f + erff(v1 * 0.70710678118654752f));
                v2 = 0.5f * v2 * (1.f + erff(v2 * 0.70710678118654752f));
                v3 = 0.5f * v3 * (1.f + erff(v3 * 0.70710678118654752f));
            }
            if (EPI == 0) {
                *reinterpret_cast<float2*>(Cz + (size_t)row * N + col)       = make_float2(v0, v1);
                *reinterpret_cast<float2*>(Cz + (size_t)(row + 8) * N + col) = make_float2(v2, v3);
            } else {
                __nv_bfloat162 h01 = __floats2bfloat162_rn(v0, v1);
                __nv_bfloat162 h23 = __floats2bfloat162_rn(v2, v3);
                __nv_bfloat162 l01 = __floats2bfloat162_rn(v0 - __bfloat162float(h01.x),
                                                           v1 - __bfloat162float(h01.y));
                __nv_bfloat162 l23 = __floats2bfloat162_rn(v2 - __bfloat162float(h23.x),
                                                           v3 - __bfloat162float(h23.y));
                *reinterpret_cast<__nv_bfloat162*>(Chi + (size_t)row * N + col)       = h01;
                *reinterpret_cast<__nv_bfloat162*>(Chi + (size_t)(row + 8) * N + col) = h23;
                *reinterpret_cast<__nv_bfloat162*>(Clo + (size_t)row * N + col)       = l01;
                *reinterpret_cast<__nv_bfloat162*>(Clo + (size_t)(row + 8) * N + col) = l23;
            }
        }
    }
}

// ============================ tensor-core attention (hi-only S and P·V) ============================
// S = Qh·Kh; O += Ph·Vh. All dropped terms are random-signed bf16 residuals that
// average down by ~sqrt(N_eff≈2048) under the near-uniform softmax (round-12 validated).
// smem: QH 16K; KV stages (KH 8K, VH 8K) x2; bias. 48.5 KB.
#define AT_QH   0
#define AT_KV   16384
#define AT_KVST 16384
#define AT_BIAS (16384 + 2 * 16384)
#define AT_SMEM (AT_BIAS + 512)
#define NCHUNK  (NN / NSL / 64)

__global__ void __launch_bounds__(128) attn_tc_kernel(
    const __nv_bfloat16* __restrict__ qh,
    const float* __restrict__ pep, float* __restrict__ part, float* __restrict__ plsum)
{
    extern __shared__ char sm[];
    const int h = blockIdx.y, sl = blockIdx.z;
    const int q0 = blockIdx.x * 128;
    const int tid = threadIdx.x, lane = tid & 31, wid = tid >> 5;
    const int wrow = wid * 32;
    const int sub = lane >> 3;
    const uint32_t sb = smem_to_u32(sm);
    float* bias = reinterpret_cast<float*>(sm + AT_BIAS);

    // Q hi tile
    #pragma unroll
    for (int it = 0; it < 8; it++) {
        int idx = it * 128 + tid;
        int row = idx >> 3, ch = idx & 7;
        size_t g = (size_t)(q0 + row) * 1536 + h * 64 + ch * 8;
        CP_ASYNC16(sb + AT_QH + ASM_OFF(row, ch), qh + g);
    }
    {
        const int kk = sl * (NN / NSL);
        uint32_t stb = sb + AT_KV;
        #pragma unroll
        for (int it = 0; it < 4; it++) {
            int idx = it * 128 + tid;
            int row = idx >> 3, ch = idx & 7;
            size_t gk = (size_t)(kk + row) * 1536 + 512 + h * 64 + ch * 8;
            uint32_t off = ASM_OFF(row, ch);
            CP_ASYNC16(stb + off,        qh + gk);         // K hi
            CP_ASYNC16(stb + 8192 + off, qh + gk + 512);   // V hi
        }
        if (tid < 64) bias[tid] = pep[(size_t)(kk + tid) * HH + h];
    }
    CP_COMMIT();

    float O[2][8][4];
    float ls[2][2] = {{0.f, 0.f}, {0.f, 0.f}};
    #pragma unroll
    for (int mb = 0; mb < 2; mb++)
        #pragma unroll
        for (int nb = 0; nb < 8; nb++)
            #pragma unroll
            for (int u = 0; u < 4; u++) O[mb][nb][u] = 0.f;

    for (int c = 0; c < NCHUNK; c++) {
        CP_WAIT0();
        __syncthreads();
        if (c < NCHUNK - 1) {
            const int kn = sl * (NN / NSL) + (c + 1) * 64;
            uint32_t stb = sb + AT_KV + (uint32_t)((c + 1) & 1) * AT_KVST;
            #pragma unroll
            for (int it = 0; it < 4; it++) {
                int idx = it * 128 + tid;
                int row = idx >> 3, ch = idx & 7;
                size_t gk = (size_t)(kn + row) * 1536 + 512 + h * 64 + ch * 8;
                uint32_t off = ASM_OFF(row, ch);
                CP_ASYNC16(stb + off,        qh + gk);
                CP_ASYNC16(stb + 8192 + off, qh + gk + 512);
            }
            if (tid < 64) bias[((c + 1) & 1) * 64 + tid] = pep[(size_t)(kn + tid) * HH + h];
            CP_COMMIT();
        }
        const uint32_t stc = sb + AT_KV + (uint32_t)(c & 1) * AT_KVST;
        const uint32_t sKH = stc, sVH = stc + 8192;
        const float* bs = bias + (c & 1) * 64;

        // ---- S = Qh Kh^T ----
        float S[2][8][4];
        #pragma unroll
        for (int mb = 0; mb < 2; mb++)
            #pragma unroll
            for (int nb = 0; nb < 8; nb++)
                #pragma unroll
                for (int u = 0; u < 4; u++) S[mb][nb][u] = 0.f;
        #pragma unroll
        for (int kb = 0; kb < 4; kb++) {
            uint32_t ah[2][4];
            int r16 = (lane & 7) + ((sub & 1) << 3);
            int chA = kb * 2 + (sub >> 1);
            #pragma unroll
            for (int mb = 0; mb < 2; mb++) {
                int row = wrow + mb * 16 + r16;
                ldsm4(ah[mb], sb + AT_QH + ASM_OFF(row, chA));
            }
            int chB = kb * 2 + (sub & 1);
            int nr = ((sub >> 1) << 3) + (lane & 7);
            #pragma unroll
            for (int j = 0; j < 4; j++) {
                uint32_t bh[4];
                int row = j * 16 + nr;
                ldsm4(bh, sKH + ASM_OFF(row, chB));
                #pragma unroll
                for (int mb = 0; mb < 2; mb++) {
                    mma16816(S[mb][2*j],   ah[mb], &bh[0]);
                    mma16816(S[mb][2*j+1], ah[mb], &bh[2]);
                }
            }
        }

        // ---- softmax (fixed m=0) + bf16 pack of P (hi only) ----
        uint32_t Ph[2][8][2];
        #pragma unroll
        for (int mb = 0; mb < 2; mb++)
            #pragma unroll
            for (int nb = 0; nb < 8; nb++) {
                int col = nb * 8 + ((lane & 3) << 1);
                float b0 = bs[col], b1 = bs[col + 1];
                float p0 = __expf(fmaf(S[mb][nb][0], 0.125f, -b0));
                float p1 = __expf(fmaf(S[mb][nb][1], 0.125f, -b1));
                float p2 = __expf(fmaf(S[mb][nb][2], 0.125f, -b0));
                float p3 = __expf(fmaf(S[mb][nb][3], 0.125f, -b1));
                ls[mb][0] += p0 + p1;
                ls[mb][1] += p2 + p3;
                __nv_bfloat162 h01 = __floats2bfloat162_rn(p0, p1);
                __nv_bfloat162 h23 = __floats2bfloat162_rn(p2, p3);
                Ph[mb][nb][0] = *reinterpret_cast<uint32_t*>(&h01);
                Ph[mb][nb][1] = *reinterpret_cast<uint32_t*>(&h23);
            }

        // ---- O += Ph Vh ----
        #pragma unroll
        for (int kb2 = 0; kb2 < 4; kb2++) {
            int krow = kb2 * 16 + ((sub & 1) << 3) + (lane & 7);
            #pragma unroll
            for (int dI = 0; dI < 4; dI++) {
                uint32_t vh[4];
                int ch = dI * 2 + (sub >> 1);
                ldsm4t(vh, sVH + ASM_OFF(krow, ch));
                #pragma unroll
                for (int mb = 0; mb < 2; mb++) {
                    uint32_t pa[4] = {Ph[mb][2*kb2][0], Ph[mb][2*kb2][1],
                                      Ph[mb][2*kb2+1][0], Ph[mb][2*kb2+1][1]};
                    mma16816(O[mb][2*dI],   pa, &vh[0]);
                    mma16816(O[mb][2*dI+1], pa, &vh[2]);
                }
            }
        }
    }

    #pragma unroll
    for (int mb = 0; mb < 2; mb++)
        #pragma unroll
        for (int r = 0; r < 2; r++) {
            float v = ls[mb][r];
            v += __shfl_xor_sync(0xffffffffu, v, 1);
            v += __shfl_xor_sync(0xffffffffu, v, 2);
            ls[mb][r] = v;
        }
    const size_t base = (size_t)(sl * HH + h) * NN;
    #pragma unroll
    for (int mb = 0; mb < 2; mb++) {
        int rowA = q0 + wrow + mb * 16 + (lane >> 2);
        int rowB = rowA + 8;
        if ((lane & 3) == 0) {
            plsum[base + rowA] = ls[mb][0];
            plsum[base + rowB] = ls[mb][1];
        }
        #pragma unroll
        for (int nb = 0; nb < 8; nb++) {
            int col = nb * 8 + ((lane & 3) << 1);
            *reinterpret_cast<float2*>(part + (base + rowA) * 64 + col) = make_float2(O[mb][nb][0], O[mb][nb][1]);
            *reinterpret_cast<float2*>(part + (base + rowB) * 64 + col) = make_float2(O[mb][nb][2], O[mb][nb][3]);
        }
    }
}

__global__ void __launch_bounds__(512) attn_combine_kernel(const float* __restrict__ part, const float* __restrict__ pls,
                                                           __nv_bfloat16* __restrict__ ohi, __nv_bfloat16* __restrict__ olo) {
    int i = blockIdx.x, idx = threadIdx.x;
    int h = idx >> 6, d = idx & 63;
    float v = 0.f, l = 0.f;
    #pragma unroll
    for (int s = 0; s < NSL; s++) {
        l += pls[(size_t)(s * HH + h) * NN + i];
        v += part[((size_t)(s * HH + h) * NN + i) * 64 + d];
    }
    float r = v / l;
    __nv_bfloat16 hb = __float2bfloat16_rn(r);
    ohi[(size_t)i * DD + idx] = hb;
    olo[(size_t)i * DD + idx] = __float2bfloat16_rn(r - __bfloat162float(hb));
}

// ============================ LN over (a + p0 + p1) -> fp32 out + bf16 hi/lo (warp-shuffle reduce) ============================
__global__ void ln3_kernel(const float* __restrict__ a, const float* __restrict__ b,
                           const float* __restrict__ b2,
                           const float* __restrict__ g, const float* __restrict__ be,
                           float* __restrict__ out,
                           __nv_bfloat16* __restrict__ ohi, __nv_bfloat16* __restrict__ olo) {
    __shared__ float wsum[8];
    __shared__ float s_mu, s_r;
    int i = blockIdx.x, t = threadIdx.x;
    int lane = t & 31, wid = t >> 5;
    float v0 = a[(size_t)i * DD + t]       + b[(size_t)i * DD + t]       + b2[(size_t)i * DD + t];
    float v1 = a[(size_t)i * DD + 256 + t] + b[(size_t)i * DD + 256 + t] + b2[(size_t)i * DD + 256 + t];
    float s = v0 + v1;
    #pragma unroll
    for (int o = 16; o > 0; o >>= 1) s += __shfl_xor_sync(0xffffffffu, s, o);
    if (lane == 0) wsum[wid] = s;
    __syncthreads();
    if (t < 8) {
        float w = wsum[t];
        #pragma unroll
        for (int o = 4; o > 0; o >>= 1) w += __shfl_xor_sync(0xffu, w, o);
        if (t == 0) s_mu = w * (1.f / DD);
    }
    __syncthreads();
    float mu = s_mu;
    float d0 = v0 - mu, d1 = v1 - mu;
    float q = d0 * d0 + d1 * d1;
    #pragma unroll
    for (int o = 16; o > 0; o >>= 1) q += __shfl_xor_sync(0xffffffffu, q, o);
    if (lane == 0) wsum[wid] = q;
    __syncthreads();
    if (t < 8) {
        float w = wsum[t];
        #pragma unroll
        for (int o = 4; o > 0; o >>= 1) w += __shfl_xor_sync(0xffu, w, o);
        if (t == 0) s_r = rsqrtf(w * (1.f / DD) + 1e-5f);
    }
    __syncthreads();
    float r = s_r;
    float o0 = d0 * r * g[t]       + be[t];
    float o1 = d1 * r * g[256 + t] + be[256 + t];
    out[(size_t)i * DD + t]       = o0;
    out[(size_t)i * DD + 256 + t] = o1;
    __nv_bfloat16 h0 = __float2bfloat16_rn(o0);
    __nv_bfloat16 h1 = __float2bfloat16_rn(o1);
    ohi[(size_t)i * DD + t]       = h0;
    ohi[(size_t)i * DD + 256 + t] = h1;
    olo[(size_t)i * DD + t]       = __float2bfloat16_rn(o0 - __bfloat162float(h0));
    olo[(size_t)i * DD + 256 + t] = __float2bfloat16_rn(o1 - __bfloat162float(h1));
}

// ============================ launch ============================
extern "C" void kernel_launch(void* const* d_in, const int* in_sizes, int n_in,
                              void* d_out, int out_size) {
    const float* node_features = (const float*)d_in[0];
    const int*   edge_index    = (const int*)  d_in[1];
    const float* pe_proj_W     = (const float*)d_in[2];
    const float* pe_proj_b     = (const float*)d_in[3];
    const float* qkv_W         = (const float*)d_in[4];
    const float* qkv_b         = (const float*)d_in[5];
    const float* peb_W         = (const float*)d_in[6];
    const float* peb_b         = (const float*)d_in[7];
    const float* out_W         = (const float*)d_in[8];
    const float* out_b         = (const float*)d_in[9];
    const float* ffn_W1        = (const float*)d_in[10];
    const float* ffn_b1        = (const float*)d_in[11];
    const float* ffn_W2        = (const float*)d_in[12];
    const float* ffn_b2        = (const float*)d_in[13];
    const float* ln1_g         = (const float*)d_in[14];
    const float* ln1_b         = (const float*)d_in[15];
    const float* ln2_g         = (const float*)d_in[16];
    const float* ln2_b         = (const float*)d_in[17];
    float* outp = (float*)d_out;

    float *x_, *x1_, *o_, *pep_, *part_, *pls_;
    __nv_bfloat16 *Ahi_, *Alo_, *Hhi_, *Hlo_, *Qh_, *Ql_, *T2b_, *T3b_, *T4b_;
    __nv_bfloat16 *qWh_, *qWl_, *oWh_, *oWl_, *f1h_, *f1l_, *f2h_, *f2l_;
    cudaGetSymbolAddress((void**)&x_,   g_x);
    cudaGetSymbolAddress((void**)&x1_,  g_x1);
    cudaGetSymbolAddress((void**)&o_,   g_o);
    cudaGetSymbolAddress((void**)&pep_, g_pep);
    cudaGetSymbolAddress((void**)&part_,g_part);
    cudaGetSymbolAddress((void**)&pls_, g_plsum);
    cudaGetSymbolAddress((void**)&Ahi_, g_Ahi);
    cudaGetSymbolAddress((void**)&Alo_, g_Alo);
    cudaGetSymbolAddress((void**)&Hhi_, g_Hhi);
    cudaGetSymbolAddress((void**)&Hlo_, g_Hlo);
    cudaGetSymbolAddress((void**)&Qh_,  g_QKVhi);
    cudaGetSymbolAddress((void**)&Ql_,  g_QKVlo);
    cudaGetSymbolAddress((void**)&T2b_, g_T2b);
    cudaGetSymbolAddress((void**)&T3b_, g_T3b);
    cudaGetSymbolAddress((void**)&T4b_, g_T4b);
    cudaGetSymbolAddress((void**)&qWh_, g_qkvW_hi);
    cudaGetSymbolAddress((void**)&qWl_, g_qkvW_lo);
    cudaGetSymbolAddress((void**)&oWh_, g_outW_hi);
    cudaGetSymbolAddress((void**)&oWl_, g_outW_lo);
    cudaGetSymbolAddress((void**)&f1h_, g_f1W_hi);
    cudaGetSymbolAddress((void**)&f1l_, g_f1W_lo);
    cudaGetSymbolAddress((void**)&f2h_, g_f2W_hi);
    cudaGetSymbolAddress((void**)&f2l_, g_f2W_lo);

    constexpr int GS64 = 2 * (2 * 64 * 128 + 32768);   // 96 KB -> 2 CTA/SM
    cudaFuncSetAttribute((const void*)mma_gemm_kernel<2,64,1>, cudaFuncAttributeMaxDynamicSharedMemorySize, GS64);
    cudaFuncSetAttribute((const void*)mma_gemm_kernel<3,64,1>, cudaFuncAttributeMaxDynamicSharedMemorySize, GS64);
    cudaFuncSetAttribute((const void*)mma_gemm_kernel<0,64,2>, cudaFuncAttributeMaxDynamicSharedMemorySize, GS64);
    cudaFuncSetAttribute(attn_tc_kernel, cudaFuncAttributeMaxDynamicSharedMemorySize, AT_SMEM);

    static cudaStream_t s_side = nullptr;
    static cudaEvent_t  ev_fork = nullptr, ev_pe = nullptr;
    if (s_side == nullptr) {
        cudaStreamCreateWithFlags(&s_side, cudaStreamNonBlocking);
        cudaEventCreateWithFlags(&ev_fork, cudaEventDisableTiming);
        cudaEventCreateWithFlags(&ev_pe,   cudaEventDisableTiming);
    }

    // ---- fork: PE pipeline on side stream ----
    cudaEventRecord(ev_fork, 0);
    cudaStreamWaitEvent(s_side, ev_fork, 0);
    zero_bm_kernel<<<(NN*64)/256, 256, 0, s_side>>>();
    scatter_bm_kernel<<<EEC/256, 256, 0, s_side>>>(edge_index);
    build_bm_kernel<<<NN, 64, 0, s_side>>>();
    t2_kernel<<<NN, 256, 0, s_side>>>();
    spmm_bf_kernel<<<NN, 256, 0, s_side>>>(T2b_, T3b_);
    spmm_bf_kernel<<<NN, 256, 0, s_side>>>(T3b_, T4b_);
    diag2_kernel<<<NN, 256, 0, s_side>>>();
    pe_kernel<<<(NN + 127) / 128, 128, 0, s_side>>>(pe_proj_W, pe_proj_b);
    pep_kernel<<<(NN + 127) / 128, 128, 0, s_side>>>(peb_W, peb_b);
    cudaEventRecord(ev_pe, s_side);

    // ---- main stream: only qkv prerequisites before the first GEMM ----
    convW_kernel<<<dim3(1536/32, 512/32, LLC),  dim3(32,8)>>>(qkv_W,  qWh_, qWl_, DD,  3*DD);
    split_copy_kernel<<<(NN*DD)/256, 256>>>(node_features);

    float* o2_ = o_ + (size_t)NN * DD;
    for (int l = 0; l < LLC; l++) {
        mma_gemm_kernel<2,64,1><<<dim3(1536/128, NN/64), 256, GS64>>>(
            Ahi_, Alo_, qWh_ + (size_t)l*3*DD*DD, qWl_ + (size_t)l*3*DD*DD,
            qkv_b + (size_t)l*3*DD, nullptr, Qh_, Ql_, 3*DD, DD);
        if (l == 0) {
            convW_kernel<<<dim3(512/32,  512/32, LLC),  dim3(32,8)>>>(out_W,  oWh_, oWl_, DD,  DD);
            convW_kernel<<<dim3(2048/32, 512/32, LLC),  dim3(32,8)>>>(ffn_W1, f1h_, f1l_, DD,  DFFC);
            convW_kernel<<<dim3(512/32,  2048/32, LLC), dim3(32,8)>>>(ffn_W2, f2h_, f2l_, DFFC, DD);
            cudaStreamWaitEvent(0, ev_pe, 0);   // join: attention needs pep
        }
        attn_tc_kernel<<<dim3(NN/128, HH, NSL), 128, AT_SMEM>>>(Qh_, pep_ + (size_t)l*NN*HH, part_, pls_);
        attn_combine_kernel<<<NN, 512>>>(part_, pls_, Ahi_, Alo_);
        mma_gemm_kernel<0,64,2><<<dim3(DD/128, NN/64, 2), 256, GS64>>>(
            Ahi_, Alo_, oWh_ + (size_t)l*DD*DD, oWl_ + (size_t)l*DD*DD,
            out_b + (size_t)l*DD, o_, nullptr, nullptr, DD, DD);
        ln3_kernel<<<NN, 256>>>(x_, o_, o2_, ln1_g + (size_t)l*DD, ln1_b + (size_t)l*DD, x1_, Ahi_, Alo_);
        mma_gemm_kernel<3,64,1><<<dim3(DFFC/128, NN/64), 256, GS64>>>(
            Ahi_, Alo_, f1h_ + (size_t)l*DD*DFFC, f1l_ + (size_t)l*DD*DFFC,
            ffn_b1 + (size_t)l*DFFC, nullptr, Hhi_, Hlo_, DFFC, DD);
        mma_gemm_kernel<0,64,2><<<dim3(DD/128, NN/64, 2), 256, GS64>>>(
            Hhi_, Hlo_, f2h_ + (size_t)l*DFFC*DD, f2l_ + (size_t)l*DFFC*DD,
            ffn_b2 + (size_t)l*DD, o_, nullptr, nullptr, DD, DFFC);
        float* xout = (l == LLC - 1) ? outp : x_;
        ln3_kernel<<<NN, 256>>>(x1_, o_, o2_, ln2_g + (size_t)l*DD, ln2_b + (size_t)l*DD, xout, Ahi_, Alo_);
    }
}

// round 14
// speedup vs baseline: 1.4510x; 1.0810x over previous
#include <cuda_runtime.h>
#include <cuda_bf16.h>
#include <math.h>
#include <stdint.h>

#define NN   2048
#define DD   512
#define HH   8
#define DPEC 16
#define WALKC 8
#define LLC  3
#define EEC  32768
#define DFFC 2048
#define MAXD 256
#define NSL  2          // attention key-slices

// ============================ PTX helpers (sm_80-baseline ISA only) ============================
__device__ __forceinline__ uint32_t smem_to_u32(const void* p) {
    uint32_t a;
    asm("{ .reg .u64 t; cvta.to.shared.u64 t, %1; cvt.u32.u64 %0, t; }" : "=r"(a) : "l"(p));
    return a;
}
#define CP_ASYNC16(dst, src) \
    asm volatile("cp.async.cg.shared.global [%0], [%1], 16;" :: "r"(dst), "l"(src))
#define CP_COMMIT() asm volatile("cp.async.commit_group;" ::: "memory")
#define CP_WAIT1()  asm volatile("cp.async.wait_group 1;" ::: "memory")
#define CP_WAIT0()  asm volatile("cp.async.wait_group 0;" ::: "memory")

__device__ __forceinline__ void ldsm4(uint32_t* r, uint32_t addr) {
    asm volatile("ldmatrix.sync.aligned.m8n8.x4.shared.b16 {%0,%1,%2,%3}, [%4];"
        : "=r"(r[0]), "=r"(r[1]), "=r"(r[2]), "=r"(r[3]) : "r"(addr));
}
__device__ __forceinline__ void ldsm4t(uint32_t* r, uint32_t addr) {
    asm volatile("ldmatrix.sync.aligned.m8n8.x4.trans.shared.b16 {%0,%1,%2,%3}, [%4];"
        : "=r"(r[0]), "=r"(r[1]), "=r"(r[2]), "=r"(r[3]) : "r"(addr));
}
__device__ __forceinline__ void mma16816(float* c, const uint32_t* a, const uint32_t* b) {
    asm volatile("mma.sync.aligned.m16n8k16.row.col.f32.bf16.bf16.f32 "
        "{%0,%1,%2,%3}, {%4,%5,%6,%7}, {%8,%9}, {%0,%1,%2,%3};"
        : "+f"(c[0]), "+f"(c[1]), "+f"(c[2]), "+f"(c[3])
        : "r"(a[0]), "r"(a[1]), "r"(a[2]), "r"(a[3]), "r"(b[0]), "r"(b[1]));
}

#define ASM_OFF(row, ch) ((uint32_t)((row) * 128 + ((((ch)) ^ ((row) & 7)) << 4)))

// ============================ static device scratch ============================
__device__ uint32_t g_bm[NN*64];
__device__ float g_deg[NN];
__device__ float g_invdeg[NN];
__device__ int   g_nbr[NN*MAXD];
__device__ int   g_cnt[NN];
__device__ __nv_bfloat16 g_T2b[NN*NN];
__device__ __nv_bfloat16 g_T3b[NN*NN];
__device__ __nv_bfloat16 g_T4b[NN*NN];
__device__ float g_rw [NN*WALKC];
__device__ float g_pe [NN*DPEC];
__device__ float g_pep[LLC*NN*HH];
__device__ float g_x   [NN*DD];
__device__ float g_x1  [NN*DD];
__device__ float g_o   [2*NN*DD];     // split-K partials
__device__ __nv_bfloat16 g_Ahi[NN*DD];
__device__ __nv_bfloat16 g_Alo[NN*DD];
__device__ __nv_bfloat16 g_Hhi[NN*DFFC];
__device__ __nv_bfloat16 g_Hlo[NN*DFFC];
__device__ __nv_bfloat16 g_QKVhi[NN*3*DD];
__device__ __nv_bfloat16 g_qkvW_hi[LLC*3*DD*DD];
__device__ __nv_bfloat16 g_qkvW_lo[LLC*3*DD*DD];
__device__ __nv_bfloat16 g_outW_hi[LLC*DD*DD];
__device__ __nv_bfloat16 g_outW_lo[LLC*DD*DD];
__device__ __nv_bfloat16 g_f1W_hi[LLC*DD*DFFC];
__device__ __nv_bfloat16 g_f1W_lo[LLC*DD*DFFC];
__device__ __nv_bfloat16 g_f2W_hi[LLC*DFFC*DD];
__device__ __nv_bfloat16 g_f2W_lo[LLC*DFFC*DD];
__device__ float g_part [NSL*HH*NN*64];
__device__ float g_plsum[NSL*HH*NN];

// ============================ PE pipeline (sparse) ============================
__global__ void zero_bm_kernel() {
    int idx = blockIdx.x * blockDim.x + threadIdx.x;
    if (idx < NN * 64) g_bm[idx] = 0u;
}
__global__ void scatter_bm_kernel(const int* __restrict__ ei) {
    int e = blockIdx.x * blockDim.x + threadIdx.x;
    if (e < EEC) {
        int s = ei[e], t = ei[EEC + e];
        atomicOr(&g_bm[s * 64 + (t >> 5)], 1u << (t & 31));
        atomicOr(&g_bm[t * 64 + (s >> 5)], 1u << (s & 31));
    }
}
__global__ void build_bm_kernel() {
    __shared__ int cnt;
    int i = blockIdx.x, t = threadIdx.x;
    if (t == 0) cnt = 0;
    __syncthreads();
    uint32_t w = g_bm[i * 64 + t];
    int c = __popc(w);
    int pos = (c > 0) ? atomicAdd(&cnt, c) : 0;
    while (w) {
        int b = __ffs(w) - 1;
        w &= w - 1;
        if (pos < MAXD) g_nbr[i * MAXD + pos] = t * 32 + b;
        pos++;
    }
    __syncthreads();
    if (t == 0) {
        int cc = cnt < MAXD ? cnt : MAXD;
        g_cnt[i] = cc;
        float d = cnt < 1 ? 1.f : (float)cnt;
        g_deg[i] = d;
        g_invdeg[i] = 1.f / d;
    }
}
__global__ void __launch_bounds__(256) t2_kernel() {
    __shared__ float rowbuf[NN];
    int i = blockIdx.x, t = threadIdx.x;
    #pragma unroll
    for (int u = 0; u < NN / 256; u++) rowbuf[t + u * 256] = 0.f;
    __syncthreads();
    int cnt = g_cnt[i];
    float inv_i = g_invdeg[i];
    for (int c = t >> 3; c < cnt; c += 32) {
        int j = g_nbr[i * MAXD + c];
        float w = inv_i * g_invdeg[j];
        int cj = g_cnt[j];
        const int* nbj = g_nbr + j * MAXD;
        for (int k = t & 7; k < cj; k += 8) atomicAdd(&rowbuf[nbj[k]], w);
    }
    __syncthreads();
    __nv_bfloat16* out = g_T2b + (size_t)i * NN;
    #pragma unroll
    for (int u = 0; u < NN / 256; u++) {
        int idx = t + u * 256;
        out[idx] = __float2bfloat16_rn(rowbuf[idx]);
    }
}
__global__ void __launch_bounds__(256) spmm_bf_kernel(const __nv_bfloat16* __restrict__ IN,
                                                      __nv_bfloat16* __restrict__ OUT) {
    int i = blockIdx.x, t = threadIdx.x;
    int cnt = g_cnt[i];
    float inv = g_invdeg[i];
    const int* nb = g_nbr + i * MAXD;
    float2 acc[4];
    #pragma unroll
    for (int u = 0; u < 4; u++) acc[u] = make_float2(0.f, 0.f);
    for (int c = 0; c < cnt; c++) {
        const __nv_bfloat162* row = reinterpret_cast<const __nv_bfloat162*>(IN + (size_t)nb[c] * NN);
        #pragma unroll
        for (int u = 0; u < 4; u++) {
            float2 v = __bfloat1622float2(row[t + u * 256]);
            acc[u].x += v.x; acc[u].y += v.y;
        }
    }
    __nv_bfloat162* out = reinterpret_cast<__nv_bfloat162*>(OUT + (size_t)i * NN);
    #pragma unroll
    for (int u = 0; u < 4; u++)
        out[t + u * 256] = __floats2bfloat162_rn(acc[u].x * inv, acc[u].y * inv);
}
__global__ void diag2_kernel() {
    __shared__ float sh[256];
    __shared__ float res[7];
    int i = blockIdx.x, t = threadIdx.x;
    float inv_i = g_invdeg[i], d_i = g_deg[i];
    int cnt = g_cnt[i];
    const __nv_bfloat16* r2 = g_T2b + (size_t)i * NN;
    const __nv_bfloat16* r3 = g_T3b + (size_t)i * NN;
    const __nv_bfloat16* r4 = g_T4b + (size_t)i * NN;
    float s[7] = {};
    for (int c = t; c < cnt; c += 256) {
        int j = g_nbr[i * MAXD + c];
        float wj = g_invdeg[j];
        s[0] += wj;
        s[1] += __bfloat162float(r2[j]) * wj;
    }
    for (int j = t; j < NN; j += 256) {
        float w = g_invdeg[j];
        float t2 = __bfloat162float(r2[j]);
        float t3 = __bfloat162float(r3[j]);
        float t4 = __bfloat162float(r4[j]);
        s[2] += t2 * t2 * w;
        s[3] += t3 * t2 * w;
        s[4] += t3 * t3 * w;
        s[5] += t4 * t3 * w;
        s[6] += t4 * t4 * w;
    }
    for (int v = 0; v < 7; v++) {
        sh[t] = s[v]; __syncthreads();
        for (int k = 128; k > 0; k >>= 1) { if (t < k) sh[t] += sh[t + k]; __syncthreads(); }
        if (t == 0) res[v] = sh[0];
        __syncthreads();
    }
    if (t == 0) {
        bool self = (g_bm[i * 64 + (i >> 5)] >> (i & 31)) & 1u;
        g_rw[i * WALKC + 0] = self ? inv_i : 0.f;
        g_rw[i * WALKC + 1] = inv_i * res[0];
        g_rw[i * WALKC + 2] = res[1];
        g_rw[i * WALKC + 3] = d_i * res[2];
        g_rw[i * WALKC + 4] = d_i * res[3];
        g_rw[i * WALKC + 5] = d_i * res[4];
        g_rw[i * WALKC + 6] = d_i * res[5];
        g_rw[i * WALKC + 7] = d_i * res[6];
    }
}
__global__ void pe_kernel(const float* __restrict__ W, const float* __restrict__ b) {
    int i = blockIdx.x * blockDim.x + threadIdx.x;
    if (i >= NN) return;
    float r[WALKC];
    #pragma unroll
    for (int w = 0; w < WALKC; w++) r[w] = g_rw[i * WALKC + w];
    #pragma unroll
    for (int d = 0; d < DPEC; d++) {
        float s = b[d];
        #pragma unroll
        for (int w = 0; w < WALKC; w++) s += r[w] * W[w * DPEC + d];
        g_pe[i * DPEC + d] = s;
    }
}
__global__ void pep_kernel(const float* __restrict__ W, const float* __restrict__ b) {
    int i = blockIdx.x * blockDim.x + threadIdx.x;
    if (i >= NN) return;
    float p[DPEC];
    #pragma unroll
    for (int d = 0; d < DPEC; d++) p[d] = g_pe[i * DPEC + d];
    for (int l = 0; l < LLC; l++) {
        #pragma unroll
        for (int h = 0; h < HH; h++) {
            float s = b[l * HH + h];
            #pragma unroll
            for (int d = 0; d < DPEC; d++) s += p[d] * W[(l * DPEC + d) * HH + h];
            g_pep[(size_t)l * NN * HH + i * HH + h] = s;
        }
    }
}

// ============================ conversions ============================
__global__ void split_copy_kernel(const float* __restrict__ src) {
    int idx = blockIdx.x * blockDim.x + threadIdx.x;
    if (idx < NN * DD) {
        float v = src[idx];
        g_x[idx] = v;
        __nv_bfloat16 h = __float2bfloat16_rn(v);
        g_Ahi[idx] = h;
        g_Alo[idx] = __float2bfloat16_rn(v - __bfloat162float(h));
    }
}
__global__ void convW_kernel(const float* __restrict__ W, __nv_bfloat16* __restrict__ hi,
                             __nv_bfloat16* __restrict__ lo, int K, int N) {
    __shared__ float tile[32][33];
    size_t lw = (size_t)blockIdx.z * K * N;
    int n0 = blockIdx.x * 32, k0 = blockIdx.y * 32;
    int tx = threadIdx.x, ty = threadIdx.y;
    #pragma unroll
    for (int r = 0; r < 4; r++)
        tile[ty + r * 8][tx] = W[lw + (size_t)(k0 + ty + r * 8) * N + n0 + tx];
    __syncthreads();
    #pragma unroll
    for (int r = 0; r < 4; r++) {
        int ni = ty + r * 8;
        float v = tile[tx][ni];
        __nv_bfloat16 h = __float2bfloat16_rn(v);
        size_t o = lw + (size_t)(n0 + ni) * K + k0 + tx;
        hi[o] = h;
        lo[o] = __float2bfloat16_rn(v - __bfloat162float(h));
    }
}

// ============================ mma.sync GEMM (BK=64, 2-stage, TM=64, split-K, TERMS) ============================
// EPI: 0 fp32 out; 2 bf16 hi/lo out; 3 GELU + bf16 hi/lo out; 4 bf16 hi-only out
// TERMS: 3 = bf16x3 (hi.hi + hi.lo + lo.hi); 1 = hi.hi only (A-lo/B-lo never loaded)
template<int EPI, int TM, int SPLITK, int TERMS>
__global__ void __launch_bounds__(256) mma_gemm_kernel(
    const __nv_bfloat16* __restrict__ Ahi, const __nv_bfloat16* __restrict__ Alo,
    const __nv_bfloat16* __restrict__ Bhi, const __nv_bfloat16* __restrict__ Blo,
    const float* __restrict__ bias, float* __restrict__ C,
    __nv_bfloat16* __restrict__ Chi, __nv_bfloat16* __restrict__ Clo, int N, int K)
{
    constexpr int MBN    = TM / 64;
    constexpr int ABYTES = TM * 128;
    constexpr int STAGE  = (TERMS == 3) ? (2 * ABYTES + 32768) : (ABYTES + 16384);
    extern __shared__ char smem[];
    const int tid  = threadIdx.x;
    const int lane = tid & 31;
    const int wid  = tid >> 5;
    const int m0 = blockIdx.y * TM, n0 = blockIdx.x * 128;
    const int wrow = (wid >> 1) * (16 * MBN);
    const int wcol = (wid & 1) * 64;
    const uint32_t sbase = smem_to_u32(smem);
    const int kseg = K / SPLITK;
    const int koff = (SPLITK > 1) ? blockIdx.z * kseg : 0;

    float acc[MBN][8][4];
    #pragma unroll
    for (int a = 0; a < MBN; a++)
        #pragma unroll
        for (int b = 0; b < 8; b++)
            #pragma unroll
            for (int c = 0; c < 4; c++) acc[a][b][c] = 0.f;

    const int nc = kseg >> 6;
    constexpr uint32_t BOFF = (TERMS == 3) ? (2 * ABYTES) : ABYTES;

    auto loadChunk = [&](int c) {
        uint32_t sb = sbase + (uint32_t)(c & 1) * STAGE;
        int k0 = koff + (c << 6);
        #pragma unroll
        for (int t2 = 0; t2 < (TERMS == 3 ? 2 : 1); t2++) {
            const __nv_bfloat16* s = t2 ? Alo : Ahi;
            #pragma unroll
            for (int it = 0; it < TM / 32; it++) {
                int idx = it * 256 + tid;
                int row = idx >> 3, ch = idx & 7;
                CP_ASYNC16(sb + t2 * ABYTES + ASM_OFF(row, ch),
                           s + (size_t)(m0 + row) * K + k0 + ch * 8);
            }
        }
        #pragma unroll
        for (int t2 = 0; t2 < (TERMS == 3 ? 2 : 1); t2++) {
            const __nv_bfloat16* s = t2 ? Blo : Bhi;
            #pragma unroll
            for (int it = 0; it < 4; it++) {
                int idx = it * 256 + tid;
                int row = idx >> 3, ch = idx & 7;
                CP_ASYNC16(sb + BOFF + t2 * 16384 + ASM_OFF(row, ch),
                           s + (size_t)(n0 + row) * K + k0 + ch * 8);
            }
        }
        CP_COMMIT();
    };

    loadChunk(0);
    if (nc > 1) loadChunk(1);

    for (int c = 0; c < nc; c++) {
        if (c + 1 < nc) CP_WAIT1(); else CP_WAIT0();
        __syncthreads();
        uint32_t sb = sbase + (uint32_t)(c & 1) * STAGE;
        uint32_t sAh = sb, sAl = sb + ABYTES, sBh = sb + BOFF, sBl = sb + BOFF + 16384;
        #pragma unroll
        for (int ks = 0; ks < 4; ks++) {
            uint32_t ah[MBN][4], al[MBN][4], bh[4][4], bl[4][4];
            {
                int sub = lane >> 3;
                int row16 = (lane & 7) + ((sub & 1) << 3);
                int kc = ks * 2 + (sub >> 1);
                #pragma unroll
                for (int mb = 0; mb < MBN; mb++) {
                    int row = wrow + mb * 16 + row16;
                    uint32_t off = ASM_OFF(row, kc);
                    ldsm4(ah[mb], sAh + off);
                    if (TERMS == 3) ldsm4(al[mb], sAl + off);
                }
            }
            {
                int sub = lane >> 3;
                int kc = ks * 2 + (sub & 1);
                int nr = ((sub >> 1) << 3) + (lane & 7);
                #pragma unroll
                for (int j = 0; j < 4; j++) {
                    int row = wcol + j * 16 + nr;
                    uint32_t off = ASM_OFF(row, kc);
                    ldsm4(bh[j], sBh + off);
                    if (TERMS == 3) ldsm4(bl[j], sBl + off);
                }
            }
            #pragma unroll
            for (int mb = 0; mb < MBN; mb++)
                #pragma unroll
                for (int j = 0; j < 4; j++) {
                    mma16816(acc[mb][2*j],     ah[mb], &bh[j][0]);
                    mma16816(acc[mb][2*j + 1], ah[mb], &bh[j][2]);
                    if (TERMS == 3) {
                        mma16816(acc[mb][2*j],     ah[mb], &bl[j][0]);
                        mma16816(acc[mb][2*j],     al[mb], &bh[j][0]);
                        mma16816(acc[mb][2*j + 1], ah[mb], &bl[j][2]);
                        mma16816(acc[mb][2*j + 1], al[mb], &bh[j][2]);
                    }
                }
        }
        __syncthreads();
        if (c + 2 < nc) loadChunk(c + 2);
    }

    const int r_l = lane >> 2;
    const int c_l = (lane & 3) << 1;
    float* Cz = C;
    if (SPLITK > 1) Cz = C + (size_t)blockIdx.z * NN * N;
    const bool useBias = (SPLITK == 1) || (blockIdx.z == 0);
    #pragma unroll
    for (int mb = 0; mb < MBN; mb++) {
        #pragma unroll
        for (int nb = 0; nb < 8; nb++) {
            int row = m0 + wrow + mb * 16 + r_l;
            int col = n0 + wcol + nb * 8 + c_l;
            float b0 = useBias ? bias[col]     : 0.f;
            float b1 = useBias ? bias[col + 1] : 0.f;
            float v0 = acc[mb][nb][0] + b0;
            float v1 = acc[mb][nb][1] + b1;
            float v2 = acc[mb][nb][2] + b0;
            float v3 = acc[mb][nb][3] + b1;
            if (EPI == 3) {
                v0 = 0.5f * v0 * (1.f + erff(v0 * 0.70710678118654752f));
                v1 = 0.5f * v1 * (1.f + erff(v1 * 0.70710678118654752f));
                v2 = 0.5f * v2 * (1.f + erff(v2 * 0.70710678118654752f));
                v3 = 0.5f * v3 * (1.f + erff(v3 * 0.70710678118654752f));
            }
            if (EPI == 0) {
                *reinterpret_cast<float2*>(Cz + (size_t)row * N + col)       = make_float2(v0, v1);
                *reinterpret_cast<float2*>(Cz + (size_t)(row + 8) * N + col) = make_float2(v2, v3);
            } else if (EPI == 4) {
                *reinterpret_cast<__nv_bfloat162*>(Chi + (size_t)row * N + col)       = __floats2bfloat162_rn(v0, v1);
                *reinterpret_cast<__nv_bfloat162*>(Chi + (size_t)(row + 8) * N + col) = __floats2bfloat162_rn(v2, v3);
            } else {
                __nv_bfloat162 h01 = __floats2bfloat162_rn(v0, v1);
                __nv_bfloat162 h23 = __floats2bfloat162_rn(v2, v3);
                __nv_bfloat162 l01 = __floats2bfloat162_rn(v0 - __bfloat162float(h01.x),
                                                           v1 - __bfloat162float(h01.y));
                __nv_bfloat162 l23 = __floats2bfloat162_rn(v2 - __bfloat162float(h23.x),
                                                           v3 - __bfloat162float(h23.y));
                *reinterpret_cast<__nv_bfloat162*>(Chi + (size_t)row * N + col)       = h01;
                *reinterpret_cast<__nv_bfloat162*>(Chi + (size_t)(row + 8) * N + col) = h23;
                *reinterpret_cast<__nv_bfloat162*>(Clo + (size_t)row * N + col)       = l01;
                *reinterpret_cast<__nv_bfloat162*>(Clo + (size_t)(row + 8) * N + col) = l23;
            }
        }
    }
}

// ============================ tensor-core attention (hi-only S and P·V) ============================
#define AT_QH   0
#define AT_KV   16384
#define AT_KVST 16384
#define AT_BIAS (16384 + 2 * 16384)
#define AT_SMEM (AT_BIAS + 512)
#define NCHUNK  (NN / NSL / 64)

__global__ void __launch_bounds__(128) attn_tc_kernel(
    const __nv_bfloat16* __restrict__ qh,
    const float* __restrict__ pep, float* __restrict__ part, float* __restrict__ plsum)
{
    extern __shared__ char sm[];
    const int h = blockIdx.y, sl = blockIdx.z;
    const int q0 = blockIdx.x * 128;
    const int tid = threadIdx.x, lane = tid & 31, wid = tid >> 5;
    const int wrow = wid * 32;
    const int sub = lane >> 3;
    const uint32_t sb = smem_to_u32(sm);
    float* bias = reinterpret_cast<float*>(sm + AT_BIAS);

    #pragma unroll
    for (int it = 0; it < 8; it++) {
        int idx = it * 128 + tid;
        int row = idx >> 3, ch = idx & 7;
        size_t g = (size_t)(q0 + row) * 1536 + h * 64 + ch * 8;
        CP_ASYNC16(sb + AT_QH + ASM_OFF(row, ch), qh + g);
    }
    {
        const int kk = sl * (NN / NSL);
        uint32_t stb = sb + AT_KV;
        #pragma unroll
        for (int it = 0; it < 4; it++) {
            int idx = it * 128 + tid;
            int row = idx >> 3, ch = idx & 7;
            size_t gk = (size_t)(kk + row) * 1536 + 512 + h * 64 + ch * 8;
            uint32_t off = ASM_OFF(row, ch);
            CP_ASYNC16(stb + off,        qh + gk);
            CP_ASYNC16(stb + 8192 + off, qh + gk + 512);
        }
        if (tid < 64) bias[tid] = pep[(size_t)(kk + tid) * HH + h];
    }
    CP_COMMIT();

    float O[2][8][4];
    float ls[2][2] = {{0.f, 0.f}, {0.f, 0.f}};
    #pragma unroll
    for (int mb = 0; mb < 2; mb++)
        #pragma unroll
        for (int nb = 0; nb < 8; nb++)
            #pragma unroll
            for (int u = 0; u < 4; u++) O[mb][nb][u] = 0.f;

    for (int c = 0; c < NCHUNK; c++) {
        CP_WAIT0();
        __syncthreads();
        if (c < NCHUNK - 1) {
            const int kn = sl * (NN / NSL) + (c + 1) * 64;
            uint32_t stb = sb + AT_KV + (uint32_t)((c + 1) & 1) * AT_KVST;
            #pragma unroll
            for (int it = 0; it < 4; it++) {
                int idx = it * 128 + tid;
                int row = idx >> 3, ch = idx & 7;
                size_t gk = (size_t)(kn + row) * 1536 + 512 + h * 64 + ch * 8;
                uint32_t off = ASM_OFF(row, ch);
                CP_ASYNC16(stb + off,        qh + gk);
                CP_ASYNC16(stb + 8192 + off, qh + gk + 512);
            }
            if (tid < 64) bias[((c + 1) & 1) * 64 + tid] = pep[(size_t)(kn + tid) * HH + h];
            CP_COMMIT();
        }
        const uint32_t stc = sb + AT_KV + (uint32_t)(c & 1) * AT_KVST;
        const uint32_t sKH = stc, sVH = stc + 8192;
        const float* bs = bias + (c & 1) * 64;

        float S[2][8][4];
        #pragma unroll
        for (int mb = 0; mb < 2; mb++)
            #pragma unroll
            for (int nb = 0; nb < 8; nb++)
                #pragma unroll
                for (int u = 0; u < 4; u++) S[mb][nb][u] = 0.f;
        #pragma unroll
        for (int kb = 0; kb < 4; kb++) {
            uint32_t ah[2][4];
            int r16 = (lane & 7) + ((sub & 1) << 3);
            int chA = kb * 2 + (sub >> 1);
            #pragma unroll
            for (int mb = 0; mb < 2; mb++) {
                int row = wrow + mb * 16 + r16;
                ldsm4(ah[mb], sb + AT_QH + ASM_OFF(row, chA));
            }
            int chB = kb * 2 + (sub & 1);
            int nr = ((sub >> 1) << 3) + (lane & 7);
            #pragma unroll
            for (int j = 0; j < 4; j++) {
                uint32_t bh[4];
                int row = j * 16 + nr;
                ldsm4(bh, sKH + ASM_OFF(row, chB));
                #pragma unroll
                for (int mb = 0; mb < 2; mb++) {
                    mma16816(S[mb][2*j],   ah[mb], &bh[0]);
                    mma16816(S[mb][2*j+1], ah[mb], &bh[2]);
                }
            }
        }

        uint32_t Ph[2][8][2];
        #pragma unroll
        for (int mb = 0; mb < 2; mb++)
            #pragma unroll
            for (int nb = 0; nb < 8; nb++) {
                int col = nb * 8 + ((lane & 3) << 1);
                float b0 = bs[col], b1 = bs[col + 1];
                float p0 = __expf(fmaf(S[mb][nb][0], 0.125f, -b0));
                float p1 = __expf(fmaf(S[mb][nb][1], 0.125f, -b1));
                float p2 = __expf(fmaf(S[mb][nb][2], 0.125f, -b0));
                float p3 = __expf(fmaf(S[mb][nb][3], 0.125f, -b1));
                ls[mb][0] += p0 + p1;
                ls[mb][1] += p2 + p3;
                __nv_bfloat162 h01 = __floats2bfloat162_rn(p0, p1);
                __nv_bfloat162 h23 = __floats2bfloat162_rn(p2, p3);
                Ph[mb][nb][0] = *reinterpret_cast<uint32_t*>(&h01);
                Ph[mb][nb][1] = *reinterpret_cast<uint32_t*>(&h23);
            }

        #pragma unroll
        for (int kb2 = 0; kb2 < 4; kb2++) {
            int krow = kb2 * 16 + ((sub & 1) << 3) + (lane & 7);
            #pragma unroll
            for (int dI = 0; dI < 4; dI++) {
                uint32_t vh[4];
                int ch = dI * 2 + (sub >> 1);
                ldsm4t(vh, sVH + ASM_OFF(krow, ch));
                #pragma unroll
                for (int mb = 0; mb < 2; mb++) {
                    uint32_t pa[4] = {Ph[mb][2*kb2][0], Ph[mb][2*kb2][1],
                                      Ph[mb][2*kb2+1][0], Ph[mb][2*kb2+1][1]};
                    mma16816(O[mb][2*dI],   pa, &vh[0]);
                    mma16816(O[mb][2*dI+1], pa, &vh[2]);
                }
            }
        }
    }

    #pragma unroll
    for (int mb = 0; mb < 2; mb++)
        #pragma unroll
        for (int r = 0; r < 2; r++) {
            float v = ls[mb][r];
            v += __shfl_xor_sync(0xffffffffu, v, 1);
            v += __shfl_xor_sync(0xffffffffu, v, 2);
            ls[mb][r] = v;
        }
    const size_t base = (size_t)(sl * HH + h) * NN;
    #pragma unroll
    for (int mb = 0; mb < 2; mb++) {
        int rowA = q0 + wrow + mb * 16 + (lane >> 2);
        int rowB = rowA + 8;
        if ((lane & 3) == 0) {
            plsum[base + rowA] = ls[mb][0];
            plsum[base + rowB] = ls[mb][1];
        }
        #pragma unroll
        for (int nb = 0; nb < 8; nb++) {
            int col = nb * 8 + ((lane & 3) << 1);
            *reinterpret_cast<float2*>(part + (base + rowA) * 64 + col) = make_float2(O[mb][nb][0], O[mb][nb][1]);
            *reinterpret_cast<float2*>(part + (base + rowB) * 64 + col) = make_float2(O[mb][nb][2], O[mb][nb][3]);
        }
    }
}

__global__ void __launch_bounds__(512) attn_combine_kernel(const float* __restrict__ part, const float* __restrict__ pls,
                                                           __nv_bfloat16* __restrict__ ohi, __nv_bfloat16* __restrict__ olo) {
    int i = blockIdx.x, idx = threadIdx.x;
    int h = idx >> 6, d = idx & 63;
    float v = 0.f, l = 0.f;
    #pragma unroll
    for (int s = 0; s < NSL; s++) {
        l += pls[(size_t)(s * HH + h) * NN + i];
        v += part[((size_t)(s * HH + h) * NN + i) * 64 + d];
    }
    float r = v / l;
    __nv_bfloat16 hb = __float2bfloat16_rn(r);
    ohi[(size_t)i * DD + idx] = hb;
    olo[(size_t)i * DD + idx] = __float2bfloat16_rn(r - __bfloat162float(hb));
}

// ============================ LN over (a + p0 + p1) -> fp32 out + bf16 hi/lo ============================
__global__ void ln3_kernel(const float* __restrict__ a, const float* __restrict__ b,
                           const float* __restrict__ b2,
                           const float* __restrict__ g, const float* __restrict__ be,
                           float* __restrict__ out,
                           __nv_bfloat16* __restrict__ ohi, __nv_bfloat16* __restrict__ olo) {
    __shared__ float wsum[8];
    __shared__ float s_mu, s_r;
    int i = blockIdx.x, t = threadIdx.x;
    int lane = t & 31, wid = t >> 5;
    float v0 = a[(size_t)i * DD + t]       + b[(size_t)i * DD + t]       + b2[(size_t)i * DD + t];
    float v1 = a[(size_t)i * DD + 256 + t] + b[(size_t)i * DD + 256 + t] + b2[(size_t)i * DD + 256 + t];
    float s = v0 + v1;
    #pragma unroll
    for (int o = 16; o > 0; o >>= 1) s += __shfl_xor_sync(0xffffffffu, s, o);
    if (lane == 0) wsum[wid] = s;
    __syncthreads();
    if (t < 8) {
        float w = wsum[t];
        #pragma unroll
        for (int o = 4; o > 0; o >>= 1) w += __shfl_xor_sync(0xffu, w, o);
        if (t == 0) s_mu = w * (1.f / DD);
    }
    __syncthreads();
    float mu = s_mu;
    float d0 = v0 - mu, d1 = v1 - mu;
    float q = d0 * d0 + d1 * d1;
    #pragma unroll
    for (int o = 16; o > 0; o >>= 1) q += __shfl_xor_sync(0xffffffffu, q, o);
    if (lane == 0) wsum[wid] = q;
    __syncthreads();
    if (t < 8) {
        float w = wsum[t];
        #pragma unroll
        for (int o = 4; o > 0; o >>= 1) w += __shfl_xor_sync(0xffu, w, o);
        if (t == 0) s_r = rsqrtf(w * (1.f / DD) + 1e-5f);
    }
    __syncthreads();
    float r = s_r;
    float o0 = d0 * r * g[t]       + be[t];
    float o1 = d1 * r * g[256 + t] + be[256 + t];
    out[(size_t)i * DD + t]       = o0;
    out[(size_t)i * DD + 256 + t] = o1;
    __nv_bfloat16 h0 = __float2bfloat16_rn(o0);
    __nv_bfloat16 h1 = __float2bfloat16_rn(o1);
    ohi[(size_t)i * DD + t]       = h0;
    ohi[(size_t)i * DD + 256 + t] = h1;
    olo[(size_t)i * DD + t]       = __float2bfloat16_rn(o0 - __bfloat162float(h0));
    olo[(size_t)i * DD + 256 + t] = __float2bfloat16_rn(o1 - __bfloat162float(h1));
}

// ============================ launch ============================
extern "C" void kernel_launch(void* const* d_in, const int* in_sizes, int n_in,
                              void* d_out, int out_size) {
    const float* node_features = (const float*)d_in[0];
    const int*   edge_index    = (const int*)  d_in[1];
    const float* pe_proj_W     = (const float*)d_in[2];
    const float* pe_proj_b     = (const float*)d_in[3];
    const float* qkv_W         = (const float*)d_in[4];
    const float* qkv_b         = (const float*)d_in[5];
    const float* peb_W         = (const float*)d_in[6];
    const float* peb_b         = (const float*)d_in[7];
    const float* out_W         = (const float*)d_in[8];
    const float* out_b         = (const float*)d_in[9];
    const float* ffn_W1        = (const float*)d_in[10];
    const float* ffn_b1        = (const float*)d_in[11];
    const float* ffn_W2        = (const float*)d_in[12];
    const float* ffn_b2        = (const float*)d_in[13];
    const float* ln1_g         = (const float*)d_in[14];
    const float* ln1_b         = (const float*)d_in[15];
    const float* ln2_g         = (const float*)d_in[16];
    const float* ln2_b         = (const float*)d_in[17];
    float* outp = (float*)d_out;

    float *x_, *x1_, *o_, *pep_, *part_, *pls_;
    __nv_bfloat16 *Ahi_, *Alo_, *Hhi_, *Hlo_, *Qh_, *T2b_, *T3b_, *T4b_;
    __nv_bfloat16 *qWh_, *qWl_, *oWh_, *oWl_, *f1h_, *f1l_, *f2h_, *f2l_;
    cudaGetSymbolAddress((void**)&x_,   g_x);
    cudaGetSymbolAddress((void**)&x1_,  g_x1);
    cudaGetSymbolAddress((void**)&o_,   g_o);
    cudaGetSymbolAddress((void**)&pep_, g_pep);
    cudaGetSymbolAddress((void**)&part_,g_part);
    cudaGetSymbolAddress((void**)&pls_, g_plsum);
    cudaGetSymbolAddress((void**)&Ahi_, g_Ahi);
    cudaGetSymbolAddress((void**)&Alo_, g_Alo);
    cudaGetSymbolAddress((void**)&Hhi_, g_Hhi);
    cudaGetSymbolAddress((void**)&Hlo_, g_Hlo);
    cudaGetSymbolAddress((void**)&Qh_,  g_QKVhi);
    cudaGetSymbolAddress((void**)&T2b_, g_T2b);
    cudaGetSymbolAddress((void**)&T3b_, g_T3b);
    cudaGetSymbolAddress((void**)&T4b_, g_T4b);
    cudaGetSymbolAddress((void**)&qWh_, g_qkvW_hi);
    cudaGetSymbolAddress((void**)&qWl_, g_qkvW_lo);
    cudaGetSymbolAddress((void**)&oWh_, g_outW_hi);
    cudaGetSymbolAddress((void**)&oWl_, g_outW_lo);
    cudaGetSymbolAddress((void**)&f1h_, g_f1W_hi);
    cudaGetSymbolAddress((void**)&f1l_, g_f1W_lo);
    cudaGetSymbolAddress((void**)&f2h_, g_f2W_hi);
    cudaGetSymbolAddress((void**)&f2l_, g_f2W_lo);

    constexpr int GS64 = 2 * (2 * 64 * 128 + 32768);   // 96 KB (3-term)
    constexpr int GS1  = 2 * (64 * 128 + 16384);       // 48 KB (1-term) -> 4 CTA/SM
    cudaFuncSetAttribute((const void*)mma_gemm_kernel<4,64,1,1>, cudaFuncAttributeMaxDynamicSharedMemorySize, GS1);
    cudaFuncSetAttribute((const void*)mma_gemm_kernel<3,64,1,3>, cudaFuncAttributeMaxDynamicSharedMemorySize, GS64);
    cudaFuncSetAttribute((const void*)mma_gemm_kernel<0,64,2,3>, cudaFuncAttributeMaxDynamicSharedMemorySize, GS64);
    cudaFuncSetAttribute(attn_tc_kernel, cudaFuncAttributeMaxDynamicSharedMemorySize, AT_SMEM);

    static cudaStream_t s_side = nullptr;
    static cudaEvent_t  ev_fork = nullptr, ev_pe = nullptr;
    if (s_side == nullptr) {
        cudaStreamCreateWithFlags(&s_side, cudaStreamNonBlocking);
        cudaEventCreateWithFlags(&ev_fork, cudaEventDisableTiming);
        cudaEventCreateWithFlags(&ev_pe,   cudaEventDisableTiming);
    }

    // ---- fork: PE pipeline on side stream ----
    cudaEventRecord(ev_fork, 0);
    cudaStreamWaitEvent(s_side, ev_fork, 0);
    zero_bm_kernel<<<(NN*64)/256, 256, 0, s_side>>>();
    scatter_bm_kernel<<<EEC/256, 256, 0, s_side>>>(edge_index);
    build_bm_kernel<<<NN, 64, 0, s_side>>>();
    t2_kernel<<<NN, 256, 0, s_side>>>();
    spmm_bf_kernel<<<NN, 256, 0, s_side>>>(T2b_, T3b_);
    spmm_bf_kernel<<<NN, 256, 0, s_side>>>(T3b_, T4b_);
    diag2_kernel<<<NN, 256, 0, s_side>>>();
    pe_kernel<<<(NN + 127) / 128, 128, 0, s_side>>>(pe_proj_W, pe_proj_b);
    pep_kernel<<<(NN + 127) / 128, 128, 0, s_side>>>(peb_W, peb_b);
    cudaEventRecord(ev_pe, s_side);

    // ---- main stream: only qkv prerequisites before the first GEMM ----
    convW_kernel<<<dim3(1536/32, 512/32, LLC),  dim3(32,8)>>>(qkv_W,  qWh_, qWl_, DD,  3*DD);
    split_copy_kernel<<<(NN*DD)/256, 256>>>(node_features);

    float* o2_ = o_ + (size_t)NN * DD;
    for (int l = 0; l < LLC; l++) {
        // qkv: hi.hi only, hi-only output (q/k/v are bf16-rounded before use anyway)
        mma_gemm_kernel<4,64,1,1><<<dim3(1536/128, NN/64), 256, GS1>>>(
            Ahi_, Alo_, qWh_ + (size_t)l*3*DD*DD, qWl_ + (size_t)l*3*DD*DD,
            qkv_b + (size_t)l*3*DD, nullptr, Qh_, nullptr, 3*DD, DD);
        if (l == 0) {
            convW_kernel<<<dim3(512/32,  512/32, LLC),  dim3(32,8)>>>(out_W,  oWh_, oWl_, DD,  DD);
            convW_kernel<<<dim3(2048/32, 512/32, LLC),  dim3(32,8)>>>(ffn_W1, f1h_, f1l_, DD,  DFFC);
            convW_kernel<<<dim3(512/32,  2048/32, LLC), dim3(32,8)>>>(ffn_W2, f2h_, f2l_, DFFC, DD);
            cudaStreamWaitEvent(0, ev_pe, 0);   // join: attention needs pep
        }
        attn_tc_kernel<<<dim3(NN/128, HH, NSL), 128, AT_SMEM>>>(Qh_, pep_ + (size_t)l*NN*HH, part_, pls_);
        attn_combine_kernel<<<NN, 512>>>(part_, pls_, Ahi_, Alo_);
        mma_gemm_kernel<0,64,2,3><<<dim3(DD/128, NN/64, 2), 256, GS64>>>(
            Ahi_, Alo_, oWh_ + (size_t)l*DD*DD, oWl_ + (size_t)l*DD*DD,
            out_b + (size_t)l*DD, o_, nullptr, nullptr, DD, DD);
        ln3_kernel<<<NN, 256>>>(x_, o_, o2_, ln1_g + (size_t)l*DD, ln1_b + (size_t)l*DD, x1_, Ahi_, Alo_);
        mma_gemm_kernel<3,64,1,3><<<dim3(DFFC/128, NN/64), 256, GS64>>>(
            Ahi_, Alo_, f1h_ + (size_t)l*DD*DFFC, f1l_ + (size_t)l*DD*DFFC,
            ffn_b1 + (size_t)l*DFFC, nullptr, Hhi_, Hlo_, DFFC, DD);
        mma_gemm_kernel<0,64,2,3><<<dim3(DD/128, NN/64, 2), 256, GS64>>>(
            Hhi_, Hlo_, f2h_ + (size_t)l*DFFC*DD, f2l_ + (size_t)l*DFFC*DD,
            ffn_b2 + (size_t)l*DD, o_, nullptr, nullptr, DD, DFFC);
        float* xout = (l == LLC - 1) ? outp : x_;
        ln3_kernel<<<NN, 256>>>(x1_, o_, o2_, ln2_g + (size_t)l*DD, ln2_b + (size_t)l*DD, xout, Ahi_, Alo_);
    }
}

// round 15
// speedup vs baseline: 1.5160x; 1.0448x over previous
#include <cuda_runtime.h>
#include <cuda_bf16.h>
#include <math.h>
#include <stdint.h>

#define NN   2048
#define DD   512
#define HH   8
#define DPEC 16
#define WALKC 8
#define LLC  3
#define EEC  32768
#define DFFC 2048
#define MAXD 256
#define NSL  2          // attention key-slices

// ============================ PTX helpers (sm_80-baseline ISA only) ============================
__device__ __forceinline__ uint32_t smem_to_u32(const void* p) {
    uint32_t a;
    asm("{ .reg .u64 t; cvta.to.shared.u64 t, %1; cvt.u32.u64 %0, t; }" : "=r"(a) : "l"(p));
    return a;
}
#define CP_ASYNC16(dst, src) \
    asm volatile("cp.async.cg.shared.global [%0], [%1], 16;" :: "r"(dst), "l"(src))
#define CP_COMMIT() asm volatile("cp.async.commit_group;" ::: "memory")
#define CP_WAIT1()  asm volatile("cp.async.wait_group 1;" ::: "memory")
#define CP_WAIT0()  asm volatile("cp.async.wait_group 0;" ::: "memory")

__device__ __forceinline__ void ldsm4(uint32_t* r, uint32_t addr) {
    asm volatile("ldmatrix.sync.aligned.m8n8.x4.shared.b16 {%0,%1,%2,%3}, [%4];"
        : "=r"(r[0]), "=r"(r[1]), "=r"(r[2]), "=r"(r[3]) : "r"(addr));
}
__device__ __forceinline__ void ldsm4t(uint32_t* r, uint32_t addr) {
    asm volatile("ldmatrix.sync.aligned.m8n8.x4.trans.shared.b16 {%0,%1,%2,%3}, [%4];"
        : "=r"(r[0]), "=r"(r[1]), "=r"(r[2]), "=r"(r[3]) : "r"(addr));
}
__device__ __forceinline__ void mma16816(float* c, const uint32_t* a, const uint32_t* b) {
    asm volatile("mma.sync.aligned.m16n8k16.row.col.f32.bf16.bf16.f32 "
        "{%0,%1,%2,%3}, {%4,%5,%6,%7}, {%8,%9}, {%0,%1,%2,%3};"
        : "+f"(c[0]), "+f"(c[1]), "+f"(c[2]), "+f"(c[3])
        : "r"(a[0]), "r"(a[1]), "r"(a[2]), "r"(a[3]), "r"(b[0]), "r"(b[1]));
}

#define ASM_OFF(row, ch) ((uint32_t)((row) * 128 + ((((ch)) ^ ((row) & 7)) << 4)))

// ============================ static device scratch ============================
__device__ uint32_t g_bm[NN*64];
__device__ float g_deg[NN];
__device__ float g_invdeg[NN];
__device__ int   g_nbr[NN*MAXD];
__device__ int   g_cnt[NN];
__device__ __nv_bfloat16 g_T2b[NN*NN];
__device__ __nv_bfloat16 g_T3b[NN*NN];
__device__ float g_rw [NN*WALKC];
__device__ float g_pe [NN*DPEC];
__device__ float g_pep[LLC*NN*HH];
__device__ float g_x   [NN*DD];
__device__ float g_x1  [NN*DD];
__device__ float g_o   [2*NN*DD];     // split-K partials
__device__ __nv_bfloat16 g_Ahi[NN*DD];
__device__ __nv_bfloat16 g_Alo[NN*DD];
__device__ __nv_bfloat16 g_Hhi[NN*DFFC];
__device__ __nv_bfloat16 g_Hlo[NN*DFFC];
__device__ __nv_bfloat16 g_QKVhi[NN*3*DD];
__device__ __nv_bfloat16 g_qkvW_hi[LLC*3*DD*DD];
__device__ __nv_bfloat16 g_outW_hi[LLC*DD*DD];
__device__ __nv_bfloat16 g_outW_lo[LLC*DD*DD];
__device__ __nv_bfloat16 g_f1W_hi[LLC*DD*DFFC];
__device__ __nv_bfloat16 g_f1W_lo[LLC*DD*DFFC];
__device__ __nv_bfloat16 g_f2W_hi[LLC*DFFC*DD];
__device__ __nv_bfloat16 g_f2W_lo[LLC*DFFC*DD];
__device__ float g_part [NSL*HH*NN*64];
__device__ float g_plsum[NSL*HH*NN];

// ============================ PE pipeline (sparse) ============================
__global__ void zero_bm_kernel() {
    int idx = blockIdx.x * blockDim.x + threadIdx.x;
    if (idx < NN * 64) g_bm[idx] = 0u;
}
__global__ void scatter_bm_kernel(const int* __restrict__ ei) {
    int e = blockIdx.x * blockDim.x + threadIdx.x;
    if (e < EEC) {
        int s = ei[e], t = ei[EEC + e];
        atomicOr(&g_bm[s * 64 + (t >> 5)], 1u << (t & 31));
        atomicOr(&g_bm[t * 64 + (s >> 5)], 1u << (s & 31));
    }
}
__global__ void build_bm_kernel() {
    __shared__ int cnt;
    int i = blockIdx.x, t = threadIdx.x;
    if (t == 0) cnt = 0;
    __syncthreads();
    uint32_t w = g_bm[i * 64 + t];
    int c = __popc(w);
    int pos = (c > 0) ? atomicAdd(&cnt, c) : 0;
    while (w) {
        int b = __ffs(w) - 1;
        w &= w - 1;
        if (pos < MAXD) g_nbr[i * MAXD + pos] = t * 32 + b;
        pos++;
    }
    __syncthreads();
    if (t == 0) {
        int cc = cnt < MAXD ? cnt : MAXD;
        g_cnt[i] = cc;
        float d = cnt < 1 ? 1.f : (float)cnt;
        g_deg[i] = d;
        g_invdeg[i] = 1.f / d;
    }
}
__global__ void __launch_bounds__(256) t2_kernel() {
    __shared__ float rowbuf[NN];
    int i = blockIdx.x, t = threadIdx.x;
    #pragma unroll
    for (int u = 0; u < NN / 256; u++) rowbuf[t + u * 256] = 0.f;
    __syncthreads();
    int cnt = g_cnt[i];
    float inv_i = g_invdeg[i];
    for (int c = t >> 3; c < cnt; c += 32) {
        int j = g_nbr[i * MAXD + c];
        float w = inv_i * g_invdeg[j];
        int cj = g_cnt[j];
        const int* nbj = g_nbr + j * MAXD;
        for (int k = t & 7; k < cj; k += 8) atomicAdd(&rowbuf[nbj[k]], w);
    }
    __syncthreads();
    __nv_bfloat16* out = g_T2b + (size_t)i * NN;
    #pragma unroll
    for (int u = 0; u < NN / 256; u++) {
        int idx = t + u * 256;
        out[idx] = __float2bfloat16_rn(rowbuf[idx]);
    }
}
// T3 = T @ T2 with bf16x2 accumulation (entry-level ~2% error, invisible in pep bias)
__global__ void __launch_bounds__(256) spmm_bf_kernel(const __nv_bfloat16* __restrict__ IN,
                                                      __nv_bfloat16* __restrict__ OUT) {
    int i = blockIdx.x, t = threadIdx.x;
    int cnt = g_cnt[i];
    __nv_bfloat16 invb = __float2bfloat16_rn(g_invdeg[i]);
    __nv_bfloat162 inv2 = __nv_bfloat162(invb, invb);
    const int* nb = g_nbr + i * MAXD;
    __nv_bfloat162 acc2[4];
    #pragma unroll
    for (int u = 0; u < 4; u++) acc2[u] = __nv_bfloat162(__float2bfloat16_rn(0.f), __float2bfloat16_rn(0.f));
    for (int c = 0; c < cnt; c++) {
        const __nv_bfloat162* row = reinterpret_cast<const __nv_bfloat162*>(IN + (size_t)nb[c] * NN);
        #pragma unroll
        for (int u = 0; u < 4; u++) acc2[u] = __hadd2(acc2[u], row[t + u * 256]);
    }
    __nv_bfloat162* out = reinterpret_cast<__nv_bfloat162*>(OUT + (size_t)i * NN);
    #pragma unroll
    for (int u = 0; u < 4; u++) out[t + u * 256] = __hmul2(acc2[u], inv2);
}
// Fused: T4 row (registers, bf16x2) = T @ T3, consumed in-place for diagonals.
// Produces rw[0..7] exactly as the old spmm(T4)+diag2 pair (modulo bf16 T4 accumulation).
__global__ void __launch_bounds__(256) spmm_diag_kernel() {
    __shared__ float sh[256];
    __shared__ float res[7];
    int i = blockIdx.x, t = threadIdx.x;
    float inv_i = g_invdeg[i], d_i = g_deg[i];
    int cnt = g_cnt[i];
    const int* nb = g_nbr + i * MAXD;
    const __nv_bfloat16* r2 = g_T2b + (size_t)i * NN;
    const __nv_bfloat16* r3 = g_T3b + (size_t)i * NN;

    // T4 row pairs (columns 2*(t+u*256), 2*(t+u*256)+1)
    __nv_bfloat162 acc2[4];
    #pragma unroll
    for (int u = 0; u < 4; u++) acc2[u] = __nv_bfloat162(__float2bfloat16_rn(0.f), __float2bfloat16_rn(0.f));
    for (int c = 0; c < cnt; c++) {
        const __nv_bfloat162* row = reinterpret_cast<const __nv_bfloat162*>(g_T3b + (size_t)nb[c] * NN);
        #pragma unroll
        for (int u = 0; u < 4; u++) acc2[u] = __hadd2(acc2[u], row[t + u * 256]);
    }

    float s[7] = {};
    // neighbor terms: diag T2 (sum w_j) and diag T3 (sum T2_ij w_j)
    for (int c = t; c < cnt; c += 256) {
        int j = nb[c];
        float wj = g_invdeg[j];
        s[0] += wj;
        s[1] += __bfloat162float(r2[j]) * wj;
    }
    // dense terms over all columns (pairs)
    const __nv_bfloat162* r2p = reinterpret_cast<const __nv_bfloat162*>(r2);
    const __nv_bfloat162* r3p = reinterpret_cast<const __nv_bfloat162*>(r3);
    const float2* wp = reinterpret_cast<const float2*>(g_invdeg);
    #pragma unroll
    for (int u = 0; u < 4; u++) {
        int p = t + u * 256;
        float2 w2  = wp[p];
        float2 t2v = __bfloat1622float2(r2p[p]);
        float2 t3v = __bfloat1622float2(r3p[p]);
        float2 t4v = __bfloat1622float2(acc2[u]);
        t4v.x *= inv_i; t4v.y *= inv_i;
        s[2] += t2v.x * t2v.x * w2.x + t2v.y * t2v.y * w2.y;   // diag T4
        s[3] += t3v.x * t2v.x * w2.x + t3v.y * t2v.y * w2.y;   // diag T5
        s[4] += t3v.x * t3v.x * w2.x + t3v.y * t3v.y * w2.y;   // diag T6
        s[5] += t4v.x * t3v.x * w2.x + t4v.y * t3v.y * w2.y;   // diag T7
        s[6] += t4v.x * t4v.x * w2.x + t4v.y * t4v.y * w2.y;   // diag T8
    }
    for (int v = 0; v < 7; v++) {
        sh[t] = s[v]; __syncthreads();
        for (int k = 128; k > 0; k >>= 1) { if (t < k) sh[t] += sh[t + k]; __syncthreads(); }
        if (t == 0) res[v] = sh[0];
        __syncthreads();
    }
    if (t == 0) {
        bool self = (g_bm[i * 64 + (i >> 5)] >> (i & 31)) & 1u;
        g_rw[i * WALKC + 0] = self ? inv_i : 0.f;
        g_rw[i * WALKC + 1] = inv_i * res[0];
        g_rw[i * WALKC + 2] = res[1];
        g_rw[i * WALKC + 3] = d_i * res[2];
        g_rw[i * WALKC + 4] = d_i * res[3];
        g_rw[i * WALKC + 5] = d_i * res[4];
        g_rw[i * WALKC + 6] = d_i * res[5];
        g_rw[i * WALKC + 7] = d_i * res[6];
    }
}
__global__ void pe_kernel(const float* __restrict__ W, const float* __restrict__ b) {
    int i = blockIdx.x * blockDim.x + threadIdx.x;
    if (i >= NN) return;
    float r[WALKC];
    #pragma unroll
    for (int w = 0; w < WALKC; w++) r[w] = g_rw[i * WALKC + w];
    #pragma unroll
    for (int d = 0; d < DPEC; d++) {
        float s = b[d];
        #pragma unroll
        for (int w = 0; w < WALKC; w++) s += r[w] * W[w * DPEC + d];
        g_pe[i * DPEC + d] = s;
    }
}
__global__ void pep_kernel(const float* __restrict__ W, const float* __restrict__ b) {
    int i = blockIdx.x * blockDim.x + threadIdx.x;
    if (i >= NN) return;
    float p[DPEC];
    #pragma unroll
    for (int d = 0; d < DPEC; d++) p[d] = g_pe[i * DPEC + d];
    for (int l = 0; l < LLC; l++) {
        #pragma unroll
        for (int h = 0; h < HH; h++) {
            float s = b[l * HH + h];
            #pragma unroll
            for (int d = 0; d < DPEC; d++) s += p[d] * W[(l * DPEC + d) * HH + h];
            g_pep[(size_t)l * NN * HH + i * HH + h] = s;
        }
    }
}

// ============================ conversions ============================
// bf16 hi/lo split of node features (fp32 residual read directly from input at layer 0)
__global__ void split_copy_kernel(const float* __restrict__ src) {
    int idx = blockIdx.x * blockDim.x + threadIdx.x;
    if (idx < NN * DD) {
        float v = src[idx];
        __nv_bfloat16 h = __float2bfloat16_rn(v);
        g_Ahi[idx] = h;
        g_Alo[idx] = __float2bfloat16_rn(v - __bfloat162float(h));
    }
}
__global__ void convW_kernel(const float* __restrict__ W, __nv_bfloat16* __restrict__ hi,
                             __nv_bfloat16* __restrict__ lo, int K, int N) {
    __shared__ float tile[32][33];
    size_t lw = (size_t)blockIdx.z * K * N;
    int n0 = blockIdx.x * 32, k0 = blockIdx.y * 32;
    int tx = threadIdx.x, ty = threadIdx.y;
    #pragma unroll
    for (int r = 0; r < 4; r++)
        tile[ty + r * 8][tx] = W[lw + (size_t)(k0 + ty + r * 8) * N + n0 + tx];
    __syncthreads();
    #pragma unroll
    for (int r = 0; r < 4; r++) {
        int ni = ty + r * 8;
        float v = tile[tx][ni];
        __nv_bfloat16 h = __float2bfloat16_rn(v);
        size_t o = lw + (size_t)(n0 + ni) * K + k0 + tx;
        hi[o] = h;
        lo[o] = __float2bfloat16_rn(v - __bfloat162float(h));
    }
}
// hi-only transpose (qkv weights: lo never consumed)
__global__ void convW_hi_kernel(const float* __restrict__ W, __nv_bfloat16* __restrict__ hi,
                                int K, int N) {
    __shared__ float tile[32][33];
    size_t lw = (size_t)blockIdx.z * K * N;
    int n0 = blockIdx.x * 32, k0 = blockIdx.y * 32;
    int tx = threadIdx.x, ty = threadIdx.y;
    #pragma unroll
    for (int r = 0; r < 4; r++)
        tile[ty + r * 8][tx] = W[lw + (size_t)(k0 + ty + r * 8) * N + n0 + tx];
    __syncthreads();
    #pragma unroll
    for (int r = 0; r < 4; r++) {
        int ni = ty + r * 8;
        hi[lw + (size_t)(n0 + ni) * K + k0 + tx] = __float2bfloat16_rn(tile[tx][ni]);
    }
}

// ============================ mma.sync GEMM (BK=64, 2-stage, TM=64, split-K, TERMS) ============================
// EPI: 0 fp32 out; 2 bf16 hi/lo out; 3 GELU + bf16 hi/lo out; 4 bf16 hi-only out
// TERMS: 3 = bf16x3 (hi.hi + hi.lo + lo.hi); 1 = hi.hi only (A-lo/B-lo never loaded)
template<int EPI, int TM, int SPLITK, int TERMS>
__global__ void __launch_bounds__(256) mma_gemm_kernel(
    const __nv_bfloat16* __restrict__ Ahi, const __nv_bfloat16* __restrict__ Alo,
    const __nv_bfloat16* __restrict__ Bhi, const __nv_bfloat16* __restrict__ Blo,
    const float* __restrict__ bias, float* __restrict__ C,
    __nv_bfloat16* __restrict__ Chi, __nv_bfloat16* __restrict__ Clo, int N, int K)
{
    constexpr int MBN    = TM / 64;
    constexpr int ABYTES = TM * 128;
    constexpr int STAGE  = (TERMS == 3) ? (2 * ABYTES + 32768) : (ABYTES + 16384);
    extern __shared__ char smem[];
    const int tid  = threadIdx.x;
    const int lane = tid & 31;
    const int wid  = tid >> 5;
    const int m0 = blockIdx.y * TM, n0 = blockIdx.x * 128;
    const int wrow = (wid >> 1) * (16 * MBN);
    const int wcol = (wid & 1) * 64;
    const uint32_t sbase = smem_to_u32(smem);
    const int kseg = K / SPLITK;
    const int koff = (SPLITK > 1) ? blockIdx.z * kseg : 0;

    float acc[MBN][8][4];
    #pragma unroll
    for (int a = 0; a < MBN; a++)
        #pragma unroll
        for (int b = 0; b < 8; b++)
            #pragma unroll
            for (int c = 0; c < 4; c++) acc[a][b][c] = 0.f;

    const int nc = kseg >> 6;
    constexpr uint32_t BOFF = (TERMS == 3) ? (2 * ABYTES) : ABYTES;

    auto loadChunk = [&](int c) {
        uint32_t sb = sbase + (uint32_t)(c & 1) * STAGE;
        int k0 = koff + (c << 6);
        #pragma unroll
        for (int t2 = 0; t2 < (TERMS == 3 ? 2 : 1); t2++) {
            const __nv_bfloat16* s = t2 ? Alo : Ahi;
            #pragma unroll
            for (int it = 0; it < TM / 32; it++) {
                int idx = it * 256 + tid;
                int row = idx >> 3, ch = idx & 7;
                CP_ASYNC16(sb + t2 * ABYTES + ASM_OFF(row, ch),
                           s + (size_t)(m0 + row) * K + k0 + ch * 8);
            }
        }
        #pragma unroll
        for (int t2 = 0; t2 < (TERMS == 3 ? 2 : 1); t2++) {
            const __nv_bfloat16* s = t2 ? Blo : Bhi;
            #pragma unroll
            for (int it = 0; it < 4; it++) {
                int idx = it * 256 + tid;
                int row = idx >> 3, ch = idx & 7;
                CP_ASYNC16(sb + BOFF + t2 * 16384 + ASM_OFF(row, ch),
                           s + (size_t)(n0 + row) * K + k0 + ch * 8);
            }
        }
        CP_COMMIT();
    };

    loadChunk(0);
    if (nc > 1) loadChunk(1);

    for (int c = 0; c < nc; c++) {
        if (c + 1 < nc) CP_WAIT1(); else CP_WAIT0();
        __syncthreads();
        uint32_t sb = sbase + (uint32_t)(c & 1) * STAGE;
        uint32_t sAh = sb, sAl = sb + ABYTES, sBh = sb + BOFF, sBl = sb + BOFF + 16384;
        #pragma unroll
        for (int ks = 0; ks < 4; ks++) {
            uint32_t ah[MBN][4], al[MBN][4], bh[4][4], bl[4][4];
            {
                int sub = lane >> 3;
                int row16 = (lane & 7) + ((sub & 1) << 3);
                int kc = ks * 2 + (sub >> 1);
                #pragma unroll
                for (int mb = 0; mb < MBN; mb++) {
                    int row = wrow + mb * 16 + row16;
                    uint32_t off = ASM_OFF(row, kc);
                    ldsm4(ah[mb], sAh + off);
                    if (TERMS == 3) ldsm4(al[mb], sAl + off);
                }
            }
            {
                int sub = lane >> 3;
                int kc = ks * 2 + (sub & 1);
                int nr = ((sub >> 1) << 3) + (lane & 7);
                #pragma unroll
                for (int j = 0; j < 4; j++) {
                    int row = wcol + j * 16 + nr;
                    uint32_t off = ASM_OFF(row, kc);
                    ldsm4(bh[j], sBh + off);
                    if (TERMS == 3) ldsm4(bl[j], sBl + off);
                }
            }
            #pragma unroll
            for (int mb = 0; mb < MBN; mb++)
                #pragma unroll
                for (int j = 0; j < 4; j++) {
                    mma16816(acc[mb][2*j],     ah[mb], &bh[j][0]);
                    mma16816(acc[mb][2*j + 1], ah[mb], &bh[j][2]);
                    if (TERMS == 3) {
                        mma16816(acc[mb][2*j],     ah[mb], &bl[j][0]);
                        mma16816(acc[mb][2*j],     al[mb], &bh[j][0]);
                        mma16816(acc[mb][2*j + 1], ah[mb], &bl[j][2]);
                        mma16816(acc[mb][2*j + 1], al[mb], &bh[j][2]);
                    }
                }
        }
        __syncthreads();
        if (c + 2 < nc) loadChunk(c + 2);
    }

    const int r_l = lane >> 2;
    const int c_l = (lane & 3) << 1;
    float* Cz = C;
    if (SPLITK > 1) Cz = C + (size_t)blockIdx.z * NN * N;
    const bool useBias = (SPLITK == 1) || (blockIdx.z == 0);
    #pragma unroll
    for (int mb = 0; mb < MBN; mb++) {
        #pragma unroll
        for (int nb = 0; nb < 8; nb++) {
            int row = m0 + wrow + mb * 16 + r_l;
            int col = n0 + wcol + nb * 8 + c_l;
            float b0 = useBias ? bias[col]     : 0.f;
            float b1 = useBias ? bias[col + 1] : 0.f;
            float v0 = acc[mb][nb][0] + b0;
            float v1 = acc[mb][nb][1] + b1;
            float v2 = acc[mb][nb][2] + b0;
            float v3 = acc[mb][nb][3] + b1;
            if (EPI == 3) {
                v0 = 0.5f * v0 * (1.f + erff(v0 * 0.70710678118654752f));
                v1 = 0.5f * v1 * (1.f + erff(v1 * 0.70710678118654752f));
                v2 = 0.5f * v2 * (1.f + erff(v2 * 0.70710678118654752f));
                v3 = 0.5f * v3 * (1.f + erff(v3 * 0.70710678118654752f));
            }
            if (EPI == 0) {
                *reinterpret_cast<float2*>(Cz + (size_t)row * N + col)       = make_float2(v0, v1);
                *reinterpret_cast<float2*>(Cz + (size_t)(row + 8) * N + col) = make_float2(v2, v3);
            } else if (EPI == 4) {
                *reinterpret_cast<__nv_bfloat162*>(Chi + (size_t)row * N + col)       = __floats2bfloat162_rn(v0, v1);
                *reinterpret_cast<__nv_bfloat162*>(Chi + (size_t)(row + 8) * N + col) = __floats2bfloat162_rn(v2, v3);
            } else {
                __nv_bfloat162 h01 = __floats2bfloat162_rn(v0, v1);
                __nv_bfloat162 h23 = __floats2bfloat162_rn(v2, v3);
                __nv_bfloat162 l01 = __floats2bfloat162_rn(v0 - __bfloat162float(h01.x),
                                                           v1 - __bfloat162float(h01.y));
                __nv_bfloat162 l23 = __floats2bfloat162_rn(v2 - __bfloat162float(h23.x),
                                                           v3 - __bfloat162float(h23.y));
                *reinterpret_cast<__nv_bfloat162*>(Chi + (size_t)row * N + col)       = h01;
                *reinterpret_cast<__nv_bfloat162*>(Chi + (size_t)(row + 8) * N + col) = h23;
                *reinterpret_cast<__nv_bfloat162*>(Clo + (size_t)row * N + col)       = l01;
                *reinterpret_cast<__nv_bfloat162*>(Clo + (size_t)(row + 8) * N + col) = l23;
            }
        }
    }
}

// ============================ tensor-core attention (hi-only S and P·V) ============================
#define AT_QH   0
#define AT_KV   16384
#define AT_KVST 16384
#define AT_BIAS (16384 + 2 * 16384)
#define AT_SMEM (AT_BIAS + 512)
#define NCHUNK  (NN / NSL / 64)

__global__ void __launch_bounds__(128) attn_tc_kernel(
    const __nv_bfloat16* __restrict__ qh,
    const float* __restrict__ pep, float* __restrict__ part, float* __restrict__ plsum)
{
    extern __shared__ char sm[];
    const int h = blockIdx.y, sl = blockIdx.z;
    const int q0 = blockIdx.x * 128;
    const int tid = threadIdx.x, lane = tid & 31, wid = tid >> 5;
    const int wrow = wid * 32;
    const int sub = lane >> 3;
    const uint32_t sb = smem_to_u32(sm);
    float* bias = reinterpret_cast<float*>(sm + AT_BIAS);

    #pragma unroll
    for (int it = 0; it < 8; it++) {
        int idx = it * 128 + tid;
        int row = idx >> 3, ch = idx & 7;
        size_t g = (size_t)(q0 + row) * 1536 + h * 64 + ch * 8;
        CP_ASYNC16(sb + AT_QH + ASM_OFF(row, ch), qh + g);
    }
    {
        const int kk = sl * (NN / NSL);
        uint32_t stb = sb + AT_KV;
        #pragma unroll
        for (int it = 0; it < 4; it++) {
            int idx = it * 128 + tid;
            int row = idx >> 3, ch = idx & 7;
            size_t gk = (size_t)(kk + row) * 1536 + 512 + h * 64 + ch * 8;
            uint32_t off = ASM_OFF(row, ch);
            CP_ASYNC16(stb + off,        qh + gk);
            CP_ASYNC16(stb + 8192 + off, qh + gk + 512);
        }
        if (tid < 64) bias[tid] = pep[(size_t)(kk + tid) * HH + h];
    }
    CP_COMMIT();

    float O[2][8][4];
    float ls[2][2] = {{0.f, 0.f}, {0.f, 0.f}};
    #pragma unroll
    for (int mb = 0; mb < 2; mb++)
        #pragma unroll
        for (int nb = 0; nb < 8; nb++)
            #pragma unroll
            for (int u = 0; u < 4; u++) O[mb][nb][u] = 0.f;

    for (int c = 0; c < NCHUNK; c++) {
        CP_WAIT0();
        __syncthreads();
        if (c < NCHUNK - 1) {
            const int kn = sl * (NN / NSL) + (c + 1) * 64;
            uint32_t stb = sb + AT_KV + (uint32_t)((c + 1) & 1) * AT_KVST;
            #pragma unroll
            for (int it = 0; it < 4; it++) {
                int idx = it * 128 + tid;
                int row = idx >> 3, ch = idx & 7;
                size_t gk = (size_t)(kn + row) * 1536 + 512 + h * 64 + ch * 8;
                uint32_t off = ASM_OFF(row, ch);
                CP_ASYNC16(stb + off,        qh + gk);
                CP_ASYNC16(stb + 8192 + off, qh + gk + 512);
            }
            if (tid < 64) bias[((c + 1) & 1) * 64 + tid] = pep[(size_t)(kn + tid) * HH + h];
            CP_COMMIT();
        }
        const uint32_t stc = sb + AT_KV + (uint32_t)(c & 1) * AT_KVST;
        const uint32_t sKH = stc, sVH = stc + 8192;
        const float* bs = bias + (c & 1) * 64;

        float S[2][8][4];
        #pragma unroll
        for (int mb = 0; mb < 2; mb++)
            #pragma unroll
            for (int nb = 0; nb < 8; nb++)
                #pragma unroll
                for (int u = 0; u < 4; u++) S[mb][nb][u] = 0.f;
        #pragma unroll
        for (int kb = 0; kb < 4; kb++) {
            uint32_t ah[2][4];
            int r16 = (lane & 7) + ((sub & 1) << 3);
            int chA = kb * 2 + (sub >> 1);
            #pragma unroll
            for (int mb = 0; mb < 2; mb++) {
                int row = wrow + mb * 16 + r16;
                ldsm4(ah[mb], sb + AT_QH + ASM_OFF(row, chA));
            }
            int chB = kb * 2 + (sub & 1);
            int nr = ((sub >> 1) << 3) + (lane & 7);
            #pragma unroll
            for (int j = 0; j < 4; j++) {
                uint32_t bh[4];
                int row = j * 16 + nr;
                ldsm4(bh, sKH + ASM_OFF(row, chB));
                #pragma unroll
                for (int mb = 0; mb < 2; mb++) {
                    mma16816(S[mb][2*j],   ah[mb], &bh[0]);
                    mma16816(S[mb][2*j+1], ah[mb], &bh[2]);
                }
            }
        }

        uint32_t Ph[2][8][2];
        #pragma unroll
        for (int mb = 0; mb < 2; mb++)
            #pragma unroll
            for (int nb = 0; nb < 8; nb++) {
                int col = nb * 8 + ((lane & 3) << 1);
                float b0 = bs[col], b1 = bs[col + 1];
                float p0 = __expf(fmaf(S[mb][nb][0], 0.125f, -b0));
                float p1 = __expf(fmaf(S[mb][nb][1], 0.125f, -b1));
                float p2 = __expf(fmaf(S[mb][nb][2], 0.125f, -b0));
                float p3 = __expf(fmaf(S[mb][nb][3], 0.125f, -b1));
                ls[mb][0] += p0 + p1;
                ls[mb][1] += p2 + p3;
                __nv_bfloat162 h01 = __floats2bfloat162_rn(p0, p1);
                __nv_bfloat162 h23 = __floats2bfloat162_rn(p2, p3);
                Ph[mb][nb][0] = *reinterpret_cast<uint32_t*>(&h01);
                Ph[mb][nb][1] = *reinterpret_cast<uint32_t*>(&h23);
            }

        #pragma unroll
        for (int kb2 = 0; kb2 < 4; kb2++) {
            int krow = kb2 * 16 + ((sub & 1) << 3) + (lane & 7);
            #pragma unroll
            for (int dI = 0; dI < 4; dI++) {
                uint32_t vh[4];
                int ch = dI * 2 + (sub >> 1);
                ldsm4t(vh, sVH + ASM_OFF(krow, ch));
                #pragma unroll
                for (int mb = 0; mb < 2; mb++) {
                    uint32_t pa[4] = {Ph[mb][2*kb2][0], Ph[mb][2*kb2][1],
                                      Ph[mb][2*kb2+1][0], Ph[mb][2*kb2+1][1]};
                    mma16816(O[mb][2*dI],   pa, &vh[0]);
                    mma16816(O[mb][2*dI+1], pa, &vh[2]);
                }
            }
        }
    }

    #pragma unroll
    for (int mb = 0; mb < 2; mb++)
        #pragma unroll
        for (int r = 0; r < 2; r++) {
            float v = ls[mb][r];
            v += __shfl_xor_sync(0xffffffffu, v, 1);
            v += __shfl_xor_sync(0xffffffffu, v, 2);
            ls[mb][r] = v;
        }
    const size_t base = (size_t)(sl * HH + h) * NN;
    #pragma unroll
    for (int mb = 0; mb < 2; mb++) {
        int rowA = q0 + wrow + mb * 16 + (lane >> 2);
        int rowB = rowA + 8;
        if ((lane & 3) == 0) {
            plsum[base + rowA] = ls[mb][0];
            plsum[base + rowB] = ls[mb][1];
        }
        #pragma unroll
        for (int nb = 0; nb < 8; nb++) {
            int col = nb * 8 + ((lane & 3) << 1);
            *reinterpret_cast<float2*>(part + (base + rowA) * 64 + col) = make_float2(O[mb][nb][0], O[mb][nb][1]);
            *reinterpret_cast<float2*>(part + (base + rowB) * 64 + col) = make_float2(O[mb][nb][2], O[mb][nb][3]);
        }
    }
}

__global__ void __launch_bounds__(512) attn_combine_kernel(const float* __restrict__ part, const float* __restrict__ pls,
                                                           __nv_bfloat16* __restrict__ ohi, __nv_bfloat16* __restrict__ olo) {
    int i = blockIdx.x, idx = threadIdx.x;
    int h = idx >> 6, d = idx & 63;
    float v = 0.f, l = 0.f;
    #pragma unroll
    for (int s = 0; s < NSL; s++) {
        l += pls[(size_t)(s * HH + h) * NN + i];
        v += part[((size_t)(s * HH + h) * NN + i) * 64 + d];
    }
    float r = v / l;
    __nv_bfloat16 hb = __float2bfloat16_rn(r);
    ohi[(size_t)i * DD + idx] = hb;
    olo[(size_t)i * DD + idx] = __float2bfloat16_rn(r - __bfloat162float(hb));
}

// ============================ LN over (a + p0 + p1) -> fp32 out + bf16 hi/lo ============================
__global__ void ln3_kernel(const float* __restrict__ a, const float* __restrict__ b,
                           const float* __restrict__ b2,
                           const float* __restrict__ g, const float* __restrict__ be,
                           float* __restrict__ out,
                           __nv_bfloat16* __restrict__ ohi, __nv_bfloat16* __restrict__ olo) {
    __shared__ float wsum[8];
    __shared__ float s_mu, s_r;
    int i = blockIdx.x, t = threadIdx.x;
    int lane = t & 31, wid = t >> 5;
    float v0 = a[(size_t)i * DD + t]       + b[(size_t)i * DD + t]       + b2[(size_t)i * DD + t];
    float v1 = a[(size_t)i * DD + 256 + t] + b[(size_t)i * DD + 256 + t] + b2[(size_t)i * DD + 256 + t];
    float s = v0 + v1;
    #pragma unroll
    for (int o = 16; o > 0; o >>= 1) s += __shfl_xor_sync(0xffffffffu, s, o);
    if (lane == 0) wsum[wid] = s;
    __syncthreads();
    if (t < 8) {
        float w = wsum[t];
        #pragma unroll
        for (int o = 4; o > 0; o >>= 1) w += __shfl_xor_sync(0xffu, w, o);
        if (t == 0) s_mu = w * (1.f / DD);
    }
    __syncthreads();
    float mu = s_mu;
    float d0 = v0 - mu, d1 = v1 - mu;
    float q = d0 * d0 + d1 * d1;
    #pragma unroll
    for (int o = 16; o > 0; o >>= 1) q += __shfl_xor_sync(0xffffffffu, q, o);
    if (lane == 0) wsum[wid] = q;
    __syncthreads();
    if (t < 8) {
        float w = wsum[t];
        #pragma unroll
        for (int o = 4; o > 0; o >>= 1) w += __shfl_xor_sync(0xffu, w, o);
        if (t == 0) s_r = rsqrtf(w * (1.f / DD) + 1e-5f);
    }
    __syncthreads();
    float r = s_r;
    float o0 = d0 * r * g[t]       + be[t];
    float o1 = d1 * r * g[256 + t] + be[256 + t];
    out[(size_t)i * DD + t]       = o0;
    out[(size_t)i * DD + 256 + t] = o1;
    __nv_bfloat16 h0 = __float2bfloat16_rn(o0);
    __nv_bfloat16 h1 = __float2bfloat16_rn(o1);
    ohi[(size_t)i * DD + t]       = h0;
    ohi[(size_t)i * DD + 256 + t] = h1;
    olo[(size_t)i * DD + t]       = __float2bfloat16_rn(o0 - __bfloat162float(h0));
    olo[(size_t)i * DD + 256 + t] = __float2bfloat16_rn(o1 - __bfloat162float(h1));
}

// ============================ launch ============================
extern "C" void kernel_launch(void* const* d_in, const int* in_sizes, int n_in,
                              void* d_out, int out_size) {
    const float* node_features = (const float*)d_in[0];
    const int*   edge_index    = (const int*)  d_in[1];
    const float* pe_proj_W     = (const float*)d_in[2];
    const float* pe_proj_b     = (const float*)d_in[3];
    const float* qkv_W         = (const float*)d_in[4];
    const float* qkv_b         = (const float*)d_in[5];
    const float* peb_W         = (const float*)d_in[6];
    const float* peb_b         = (const float*)d_in[7];
    const float* out_W         = (const float*)d_in[8];
    const float* out_b         = (const float*)d_in[9];
    const float* ffn_W1        = (const float*)d_in[10];
    const float* ffn_b1        = (const float*)d_in[11];
    const float* ffn_W2        = (const float*)d_in[12];
    const float* ffn_b2        = (const float*)d_in[13];
    const float* ln1_g         = (const float*)d_in[14];
    const float* ln1_b         = (const float*)d_in[15];
    const float* ln2_g         = (const float*)d_in[16];
    const float* ln2_b         = (const float*)d_in[17];
    float* outp = (float*)d_out;

    float *x_, *x1_, *o_, *pep_, *part_, *pls_;
    __nv_bfloat16 *Ahi_, *Alo_, *Hhi_, *Hlo_, *Qh_, *T2b_, *T3b_;
    __nv_bfloat16 *qWh_, *oWh_, *oWl_, *f1h_, *f1l_, *f2h_, *f2l_;
    cudaGetSymbolAddress((void**)&x_,   g_x);
    cudaGetSymbolAddress((void**)&x1_,  g_x1);
    cudaGetSymbolAddress((void**)&o_,   g_o);
    cudaGetSymbolAddress((void**)&pep_, g_pep);
    cudaGetSymbolAddress((void**)&part_,g_part);
    cudaGetSymbolAddress((void**)&pls_, g_plsum);
    cudaGetSymbolAddress((void**)&Ahi_, g_Ahi);
    cudaGetSymbolAddress((void**)&Alo_, g_Alo);
    cudaGetSymbolAddress((void**)&Hhi_, g_Hhi);
    cudaGetSymbolAddress((void**)&Hlo_, g_Hlo);
    cudaGetSymbolAddress((void**)&Qh_,  g_QKVhi);
    cudaGetSymbolAddress((void**)&T2b_, g_T2b);
    cudaGetSymbolAddress((void**)&T3b_, g_T3b);
    cudaGetSymbolAddress((void**)&qWh_, g_qkvW_hi);
    cudaGetSymbolAddress((void**)&oWh_, g_outW_hi);
    cudaGetSymbolAddress((void**)&oWl_, g_outW_lo);
    cudaGetSymbolAddress((void**)&f1h_, g_f1W_hi);
    cudaGetSymbolAddress((void**)&f1l_, g_f1W_lo);
    cudaGetSymbolAddress((void**)&f2h_, g_f2W_hi);
    cudaGetSymbolAddress((void**)&f2l_, g_f2W_lo);

    constexpr int GS64 = 2 * (2 * 64 * 128 + 32768);   // 96 KB (3-term)
    constexpr int GS1  = 2 * (64 * 128 + 16384);       // 48 KB (1-term) -> 4 CTA/SM
    cudaFuncSetAttribute((const void*)mma_gemm_kernel<4,64,1,1>, cudaFuncAttributeMaxDynamicSharedMemorySize, GS1);
    cudaFuncSetAttribute((const void*)mma_gemm_kernel<3,64,1,3>, cudaFuncAttributeMaxDynamicSharedMemorySize, GS64);
    cudaFuncSetAttribute((const void*)mma_gemm_kernel<0,64,2,3>, cudaFuncAttributeMaxDynamicSharedMemorySize, GS64);
    cudaFuncSetAttribute(attn_tc_kernel, cudaFuncAttributeMaxDynamicSharedMemorySize, AT_SMEM);

    static cudaStream_t s_side = nullptr;
    static cudaEvent_t  ev_fork = nullptr, ev_pe = nullptr;
    if (s_side == nullptr) {
        cudaStreamCreateWithFlags(&s_side, cudaStreamNonBlocking);
        cudaEventCreateWithFlags(&ev_fork, cudaEventDisableTiming);
        cudaEventCreateWithFlags(&ev_pe,   cudaEventDisableTiming);
    }

    // ---- fork: PE pipeline on side stream ----
    cudaEventRecord(ev_fork, 0);
    cudaStreamWaitEvent(s_side, ev_fork, 0);
    zero_bm_kernel<<<(NN*64)/256, 256, 0, s_side>>>();
    scatter_bm_kernel<<<EEC/256, 256, 0, s_side>>>(edge_index);
    build_bm_kernel<<<NN, 64, 0, s_side>>>();
    t2_kernel<<<NN, 256, 0, s_side>>>();
    spmm_bf_kernel<<<NN, 256, 0, s_side>>>(T2b_, T3b_);
    spmm_diag_kernel<<<NN, 256, 0, s_side>>>();
    pe_kernel<<<(NN + 127) / 128, 128, 0, s_side>>>(pe_proj_W, pe_proj_b);
    pep_kernel<<<(NN + 127) / 128, 128, 0, s_side>>>(peb_W, peb_b);
    cudaEventRecord(ev_pe, s_side);

    // ---- main stream: only qkv prerequisites before the first GEMM ----
    convW_hi_kernel<<<dim3(1536/32, 512/32, LLC), dim3(32,8)>>>(qkv_W, qWh_, DD, 3*DD);
    split_copy_kernel<<<(NN*DD)/256, 256>>>(node_features);

    float* o2_ = o_ + (size_t)NN * DD;
    for (int l = 0; l < LLC; l++) {
        mma_gemm_kernel<4,64,1,1><<<dim3(1536/128, NN/64), 256, GS1>>>(
            Ahi_, Alo_, qWh_ + (size_t)l*3*DD*DD, nullptr,
            qkv_b + (size_t)l*3*DD, nullptr, Qh_, nullptr, 3*DD, DD);
        if (l == 0) {
            convW_kernel<<<dim3(512/32,  512/32, LLC),  dim3(32,8)>>>(out_W,  oWh_, oWl_, DD,  DD);
            convW_kernel<<<dim3(2048/32, 512/32, LLC),  dim3(32,8)>>>(ffn_W1, f1h_, f1l_, DD,  DFFC);
            convW_kernel<<<dim3(512/32,  2048/32, LLC), dim3(32,8)>>>(ffn_W2, f2h_, f2l_, DFFC, DD);
            cudaStreamWaitEvent(0, ev_pe, 0);   // join: attention needs pep
        }
        attn_tc_kernel<<<dim3(NN/128, HH, NSL), 128, AT_SMEM>>>(Qh_, pep_ + (size_t)l*NN*HH, part_, pls_);
        attn_combine_kernel<<<NN, 512>>>(part_, pls_, Ahi_, Alo_);
        mma_gemm_kernel<0,64,2,3><<<dim3(DD/128, NN/64, 2), 256, GS64>>>(
            Ahi_, Alo_, oWh_ + (size_t)l*DD*DD, oWl_ + (size_t)l*DD*DD,
            out_b + (size_t)l*DD, o_, nullptr, nullptr, DD, DD);
        const float* resid1 = (l == 0) ? node_features : x_;
        ln3_kernel<<<NN, 256>>>(resid1, o_, o2_, ln1_g + (size_t)l*DD, ln1_b + (size_t)l*DD, x1_, Ahi_, Alo_);
        mma_gemm_kernel<3,64,1,3><<<dim3(DFFC/128, NN/64), 256, GS64>>>(
            Ahi_, Alo_, f1h_ + (size_t)l*DD*DFFC, f1l_ + (size_t)l*DD*DFFC,
            ffn_b1 + (size_t)l*DFFC, nullptr, Hhi_, Hlo_, DFFC, DD);
        mma_gemm_kernel<0,64,2,3><<<dim3(DD/128, NN/64, 2), 256, GS64>>>(
            Hhi_, Hlo_, f2h_ + (size_t)l*DFFC*DD, f2l_ + (size_t)l*DFFC*DD,
            ffn_b2 + (size_t)l*DD, o_, nullptr, nullptr, DD, DFFC);
        float* xout = (l == LLC - 1) ? outp : x_;
        ln3_kernel<<<NN, 256>>>(x1_, o_, o2_, ln2_g + (size_t)l*DD, ln2_b + (size_t)l*DD, xout, Ahi_, Alo_);
    }
}

// round 16
// speedup vs baseline: 1.5510x; 1.0231x over previous
#include <cuda_runtime.h>
#include <cuda_bf16.h>
#include <math.h>
#include <stdint.h>

#define NN   2048
#define DD   512
#define HH   8
#define DPEC 16
#define WALKC 8
#define LLC  3
#define EEC  32768
#define DFFC 2048
#define MAXD 256
#define NSL  2          // attention key-slices

// ============================ PTX helpers (sm_80-baseline ISA only) ============================
__device__ __forceinline__ uint32_t smem_to_u32(const void* p) {
    uint32_t a;
    asm("{ .reg .u64 t; cvta.to.shared.u64 t, %1; cvt.u32.u64 %0, t; }" : "=r"(a) : "l"(p));
    return a;
}
#define CP_ASYNC16(dst, src) \
    asm volatile("cp.async.cg.shared.global [%0], [%1], 16;" :: "r"(dst), "l"(src))
#define CP_COMMIT() asm volatile("cp.async.commit_group;" ::: "memory")
#define CP_WAIT1()  asm volatile("cp.async.wait_group 1;" ::: "memory")
#define CP_WAIT0()  asm volatile("cp.async.wait_group 0;" ::: "memory")

__device__ __forceinline__ void ldsm4(uint32_t* r, uint32_t addr) {
    asm volatile("ldmatrix.sync.aligned.m8n8.x4.shared.b16 {%0,%1,%2,%3}, [%4];"
        : "=r"(r[0]), "=r"(r[1]), "=r"(r[2]), "=r"(r[3]) : "r"(addr));
}
__device__ __forceinline__ void ldsm4t(uint32_t* r, uint32_t addr) {
    asm volatile("ldmatrix.sync.aligned.m8n8.x4.trans.shared.b16 {%0,%1,%2,%3}, [%4];"
        : "=r"(r[0]), "=r"(r[1]), "=r"(r[2]), "=r"(r[3]) : "r"(addr));
}
__device__ __forceinline__ void mma16816(float* c, const uint32_t* a, const uint32_t* b) {
    asm volatile("mma.sync.aligned.m16n8k16.row.col.f32.bf16.bf16.f32 "
        "{%0,%1,%2,%3}, {%4,%5,%6,%7}, {%8,%9}, {%0,%1,%2,%3};"
        : "+f"(c[0]), "+f"(c[1]), "+f"(c[2]), "+f"(c[3])
        : "r"(a[0]), "r"(a[1]), "r"(a[2]), "r"(a[3]), "r"(b[0]), "r"(b[1]));
}

#define ASM_OFF(row, ch) ((uint32_t)((row) * 128 + ((((ch)) ^ ((row) & 7)) << 4)))

// ============================ static device scratch ============================
__device__ uint32_t g_bm[NN*64];
__device__ float g_deg[NN];
__device__ float g_invdeg[NN];
__device__ int   g_nbr[NN*MAXD];
__device__ int   g_cnt[NN];
__device__ __nv_bfloat16 g_T2b[NN*NN];
__device__ __nv_bfloat16 g_T3b[NN*NN];
__device__ float g_rw [NN*WALKC];
__device__ float g_pe [NN*DPEC];
__device__ float g_pep[LLC*NN*HH];
__device__ float g_x   [NN*DD];
__device__ float g_x1  [NN*DD];
__device__ float g_o   [2*NN*DD];     // split-K partials
__device__ __nv_bfloat16 g_Ahi[NN*DD];
__device__ __nv_bfloat16 g_Alo[NN*DD];
__device__ __nv_bfloat16 g_Hhi[NN*DFFC];
__device__ __nv_bfloat16 g_Hlo[NN*DFFC];
__device__ __nv_bfloat16 g_QKVhi[NN*3*DD];
__device__ __nv_bfloat16 g_qkvW_hi[LLC*3*DD*DD];
__device__ __nv_bfloat16 g_outW_hi[LLC*DD*DD];
__device__ __nv_bfloat16 g_f1W_hi[LLC*DD*DFFC];
__device__ __nv_bfloat16 g_f1W_lo[LLC*DD*DFFC];
__device__ __nv_bfloat16 g_f2W_hi[LLC*DFFC*DD];
__device__ __nv_bfloat16 g_f2W_lo[LLC*DFFC*DD];
__device__ float g_part [NSL*HH*NN*64];
__device__ float g_plsum[NSL*HH*NN];

// ============================ PE pipeline (sparse) ============================
__global__ void zero_bm_kernel() {
    int idx = blockIdx.x * blockDim.x + threadIdx.x;
    if (idx < NN * 64) g_bm[idx] = 0u;
}
__global__ void scatter_bm_kernel(const int* __restrict__ ei) {
    int e = blockIdx.x * blockDim.x + threadIdx.x;
    if (e < EEC) {
        int s = ei[e], t = ei[EEC + e];
        atomicOr(&g_bm[s * 64 + (t >> 5)], 1u << (t & 31));
        atomicOr(&g_bm[t * 64 + (s >> 5)], 1u << (s & 31));
    }
}
__global__ void build_bm_kernel() {
    __shared__ int cnt;
    int i = blockIdx.x, t = threadIdx.x;
    if (t == 0) cnt = 0;
    __syncthreads();
    uint32_t w = g_bm[i * 64 + t];
    int c = __popc(w);
    int pos = (c > 0) ? atomicAdd(&cnt, c) : 0;
    while (w) {
        int b = __ffs(w) - 1;
        w &= w - 1;
        if (pos < MAXD) g_nbr[i * MAXD + pos] = t * 32 + b;
        pos++;
    }
    __syncthreads();
    if (t == 0) {
        int cc = cnt < MAXD ? cnt : MAXD;
        g_cnt[i] = cc;
        float d = cnt < 1 ? 1.f : (float)cnt;
        g_deg[i] = d;
        g_invdeg[i] = 1.f / d;
    }
}
__global__ void __launch_bounds__(256) t2_kernel() {
    __shared__ float rowbuf[NN];
    int i = blockIdx.x, t = threadIdx.x;
    #pragma unroll
    for (int u = 0; u < NN / 256; u++) rowbuf[t + u * 256] = 0.f;
    __syncthreads();
    int cnt = g_cnt[i];
    float inv_i = g_invdeg[i];
    for (int c = t >> 3; c < cnt; c += 32) {
        int j = g_nbr[i * MAXD + c];
        float w = inv_i * g_invdeg[j];
        int cj = g_cnt[j];
        const int* nbj = g_nbr + j * MAXD;
        for (int k = t & 7; k < cj; k += 8) atomicAdd(&rowbuf[nbj[k]], w);
    }
    __syncthreads();
    __nv_bfloat16* out = g_T2b + (size_t)i * NN;
    #pragma unroll
    for (int u = 0; u < NN / 256; u++) {
        int idx = t + u * 256;
        out[idx] = __float2bfloat16_rn(rowbuf[idx]);
    }
}
__global__ void __launch_bounds__(256) spmm_bf_kernel(const __nv_bfloat16* __restrict__ IN,
                                                      __nv_bfloat16* __restrict__ OUT) {
    int i = blockIdx.x, t = threadIdx.x;
    int cnt = g_cnt[i];
    __nv_bfloat16 invb = __float2bfloat16_rn(g_invdeg[i]);
    __nv_bfloat162 inv2 = __nv_bfloat162(invb, invb);
    const int* nb = g_nbr + i * MAXD;
    __nv_bfloat162 acc2[4];
    #pragma unroll
    for (int u = 0; u < 4; u++) acc2[u] = __nv_bfloat162(__float2bfloat16_rn(0.f), __float2bfloat16_rn(0.f));
    for (int c = 0; c < cnt; c++) {
        const __nv_bfloat162* row = reinterpret_cast<const __nv_bfloat162*>(IN + (size_t)nb[c] * NN);
        #pragma unroll
        for (int u = 0; u < 4; u++) acc2[u] = __hadd2(acc2[u], row[t + u * 256]);
    }
    __nv_bfloat162* out = reinterpret_cast<__nv_bfloat162*>(OUT + (size_t)i * NN);
    #pragma unroll
    for (int u = 0; u < 4; u++) out[t + u * 256] = __hmul2(acc2[u], inv2);
}
__global__ void __launch_bounds__(256) spmm_diag_kernel() {
    __shared__ float sh[256];
    __shared__ float res[7];
    int i = blockIdx.x, t = threadIdx.x;
    float inv_i = g_invdeg[i], d_i = g_deg[i];
    int cnt = g_cnt[i];
    const int* nb = g_nbr + i * MAXD;
    const __nv_bfloat16* r2 = g_T2b + (size_t)i * NN;
    const __nv_bfloat16* r3 = g_T3b + (size_t)i * NN;

    __nv_bfloat162 acc2[4];
    #pragma unroll
    for (int u = 0; u < 4; u++) acc2[u] = __nv_bfloat162(__float2bfloat16_rn(0.f), __float2bfloat16_rn(0.f));
    for (int c = 0; c < cnt; c++) {
        const __nv_bfloat162* row = reinterpret_cast<const __nv_bfloat162*>(g_T3b + (size_t)nb[c] * NN);
        #pragma unroll
        for (int u = 0; u < 4; u++) acc2[u] = __hadd2(acc2[u], row[t + u * 256]);
    }

    float s[7] = {};
    for (int c = t; c < cnt; c += 256) {
        int j = nb[c];
        float wj = g_invdeg[j];
        s[0] += wj;
        s[1] += __bfloat162float(r2[j]) * wj;
    }
    const __nv_bfloat162* r2p = reinterpret_cast<const __nv_bfloat162*>(r2);
    const __nv_bfloat162* r3p = reinterpret_cast<const __nv_bfloat162*>(r3);
    const float2* wp = reinterpret_cast<const float2*>(g_invdeg);
    #pragma unroll
    for (int u = 0; u < 4; u++) {
        int p = t + u * 256;
        float2 w2  = wp[p];
        float2 t2v = __bfloat1622float2(r2p[p]);
        float2 t3v = __bfloat1622float2(r3p[p]);
        float2 t4v = __bfloat1622float2(acc2[u]);
        t4v.x *= inv_i; t4v.y *= inv_i;
        s[2] += t2v.x * t2v.x * w2.x + t2v.y * t2v.y * w2.y;
        s[3] += t3v.x * t2v.x * w2.x + t3v.y * t2v.y * w2.y;
        s[4] += t3v.x * t3v.x * w2.x + t3v.y * t3v.y * w2.y;
        s[5] += t4v.x * t3v.x * w2.x + t4v.y * t3v.y * w2.y;
        s[6] += t4v.x * t4v.x * w2.x + t4v.y * t4v.y * w2.y;
    }
    for (int v = 0; v < 7; v++) {
        sh[t] = s[v]; __syncthreads();
        for (int k = 128; k > 0; k >>= 1) { if (t < k) sh[t] += sh[t + k]; __syncthreads(); }
        if (t == 0) res[v] = sh[0];
        __syncthreads();
    }
    if (t == 0) {
        bool self = (g_bm[i * 64 + (i >> 5)] >> (i & 31)) & 1u;
        g_rw[i * WALKC + 0] = self ? inv_i : 0.f;
        g_rw[i * WALKC + 1] = inv_i * res[0];
        g_rw[i * WALKC + 2] = res[1];
        g_rw[i * WALKC + 3] = d_i * res[2];
        g_rw[i * WALKC + 4] = d_i * res[3];
        g_rw[i * WALKC + 5] = d_i * res[4];
        g_rw[i * WALKC + 6] = d_i * res[5];
        g_rw[i * WALKC + 7] = d_i * res[6];
    }
}
__global__ void pe_kernel(const float* __restrict__ W, const float* __restrict__ b) {
    int i = blockIdx.x * blockDim.x + threadIdx.x;
    if (i >= NN) return;
    float r[WALKC];
    #pragma unroll
    for (int w = 0; w < WALKC; w++) r[w] = g_rw[i * WALKC + w];
    #pragma unroll
    for (int d = 0; d < DPEC; d++) {
        float s = b[d];
        #pragma unroll
        for (int w = 0; w < WALKC; w++) s += r[w] * W[w * DPEC + d];
        g_pe[i * DPEC + d] = s;
    }
}
__global__ void pep_kernel(const float* __restrict__ W, const float* __restrict__ b) {
    int i = blockIdx.x * blockDim.x + threadIdx.x;
    if (i >= NN) return;
    float p[DPEC];
    #pragma unroll
    for (int d = 0; d < DPEC; d++) p[d] = g_pe[i * DPEC + d];
    for (int l = 0; l < LLC; l++) {
        #pragma unroll
        for (int h = 0; h < HH; h++) {
            float s = b[l * HH + h];
            #pragma unroll
            for (int d = 0; d < DPEC; d++) s += p[d] * W[(l * DPEC + d) * HH + h];
            g_pep[(size_t)l * NN * HH + i * HH + h] = s;
        }
    }
}

// ============================ conversions ============================
__global__ void split_copy_kernel(const float* __restrict__ src) {
    int idx = blockIdx.x * blockDim.x + threadIdx.x;
    if (idx < NN * DD) {
        float v = src[idx];
        __nv_bfloat16 h = __float2bfloat16_rn(v);
        g_Ahi[idx] = h;
        g_Alo[idx] = __float2bfloat16_rn(v - __bfloat162float(h));
    }
}
__global__ void convW_kernel(const float* __restrict__ W, __nv_bfloat16* __restrict__ hi,
                             __nv_bfloat16* __restrict__ lo, int K, int N) {
    __shared__ float tile[32][33];
    size_t lw = (size_t)blockIdx.z * K * N;
    int n0 = blockIdx.x * 32, k0 = blockIdx.y * 32;
    int tx = threadIdx.x, ty = threadIdx.y;
    #pragma unroll
    for (int r = 0; r < 4; r++)
        tile[ty + r * 8][tx] = W[lw + (size_t)(k0 + ty + r * 8) * N + n0 + tx];
    __syncthreads();
    #pragma unroll
    for (int r = 0; r < 4; r++) {
        int ni = ty + r * 8;
        float v = tile[tx][ni];
        __nv_bfloat16 h = __float2bfloat16_rn(v);
        size_t o = lw + (size_t)(n0 + ni) * K + k0 + tx;
        hi[o] = h;
        lo[o] = __float2bfloat16_rn(v - __bfloat162float(h));
    }
}
__global__ void convW_hi_kernel(const float* __restrict__ W, __nv_bfloat16* __restrict__ hi,
                                int K, int N) {
    __shared__ float tile[32][33];
    size_t lw = (size_t)blockIdx.z * K * N;
    int n0 = blockIdx.x * 32, k0 = blockIdx.y * 32;
    int tx = threadIdx.x, ty = threadIdx.y;
    #pragma unroll
    for (int r = 0; r < 4; r++)
        tile[ty + r * 8][tx] = W[lw + (size_t)(k0 + ty + r * 8) * N + n0 + tx];
    __syncthreads();
    #pragma unroll
    for (int r = 0; r < 4; r++) {
        int ni = ty + r * 8;
        hi[lw + (size_t)(n0 + ni) * K + k0 + tx] = __float2bfloat16_rn(tile[tx][ni]);
    }
}

// ============================ mma.sync GEMM (BK=64, 2-stage, TM=64, split-K, TERMS) ============================
// EPI: 0 fp32 out; 2 bf16 hi/lo out; 3 GELU + bf16 hi/lo out; 4 bf16 hi-only out
// TERMS: 3 = bf16x3 (hi.hi + hi.lo + lo.hi); 1 = hi.hi only (A-lo/B-lo never loaded)
template<int EPI, int TM, int SPLITK, int TERMS>
__global__ void __launch_bounds__(256) mma_gemm_kernel(
    const __nv_bfloat16* __restrict__ Ahi, const __nv_bfloat16* __restrict__ Alo,
    const __nv_bfloat16* __restrict__ Bhi, const __nv_bfloat16* __restrict__ Blo,
    const float* __restrict__ bias, float* __restrict__ C,
    __nv_bfloat16* __restrict__ Chi, __nv_bfloat16* __restrict__ Clo, int N, int K)
{
    constexpr int MBN    = TM / 64;
    constexpr int ABYTES = TM * 128;
    constexpr int STAGE  = (TERMS == 3) ? (2 * ABYTES + 32768) : (ABYTES + 16384);
    extern __shared__ char smem[];
    const int tid  = threadIdx.x;
    const int lane = tid & 31;
    const int wid  = tid >> 5;
    const int m0 = blockIdx.y * TM, n0 = blockIdx.x * 128;
    const int wrow = (wid >> 1) * (16 * MBN);
    const int wcol = (wid & 1) * 64;
    const uint32_t sbase = smem_to_u32(smem);
    const int kseg = K / SPLITK;
    const int koff = (SPLITK > 1) ? blockIdx.z * kseg : 0;

    float acc[MBN][8][4];
    #pragma unroll
    for (int a = 0; a < MBN; a++)
        #pragma unroll
        for (int b = 0; b < 8; b++)
            #pragma unroll
            for (int c = 0; c < 4; c++) acc[a][b][c] = 0.f;

    const int nc = kseg >> 6;
    constexpr uint32_t BOFF = (TERMS == 3) ? (2 * ABYTES) : ABYTES;

    auto loadChunk = [&](int c) {
        uint32_t sb = sbase + (uint32_t)(c & 1) * STAGE;
        int k0 = koff + (c << 6);
        #pragma unroll
        for (int t2 = 0; t2 < (TERMS == 3 ? 2 : 1); t2++) {
            const __nv_bfloat16* s = t2 ? Alo : Ahi;
            #pragma unroll
            for (int it = 0; it < TM / 32; it++) {
                int idx = it * 256 + tid;
                int row = idx >> 3, ch = idx & 7;
                CP_ASYNC16(sb + t2 * ABYTES + ASM_OFF(row, ch),
                           s + (size_t)(m0 + row) * K + k0 + ch * 8);
            }
        }
        #pragma unroll
        for (int t2 = 0; t2 < (TERMS == 3 ? 2 : 1); t2++) {
            const __nv_bfloat16* s = t2 ? Blo : Bhi;
            #pragma unroll
            for (int it = 0; it < 4; it++) {
                int idx = it * 256 + tid;
                int row = idx >> 3, ch = idx & 7;
                CP_ASYNC16(sb + BOFF + t2 * 16384 + ASM_OFF(row, ch),
                           s + (size_t)(n0 + row) * K + k0 + ch * 8);
            }
        }
        CP_COMMIT();
    };

    loadChunk(0);
    if (nc > 1) loadChunk(1);

    for (int c = 0; c < nc; c++) {
        if (c + 1 < nc) CP_WAIT1(); else CP_WAIT0();
        __syncthreads();
        uint32_t sb = sbase + (uint32_t)(c & 1) * STAGE;
        uint32_t sAh = sb, sAl = sb + ABYTES, sBh = sb + BOFF, sBl = sb + BOFF + 16384;
        #pragma unroll
        for (int ks = 0; ks < 4; ks++) {
            uint32_t ah[MBN][4], al[MBN][4], bh[4][4], bl[4][4];
            {
                int sub = lane >> 3;
                int row16 = (lane & 7) + ((sub & 1) << 3);
                int kc = ks * 2 + (sub >> 1);
                #pragma unroll
                for (int mb = 0; mb < MBN; mb++) {
                    int row = wrow + mb * 16 + row16;
                    uint32_t off = ASM_OFF(row, kc);
                    ldsm4(ah[mb], sAh + off);
                    if (TERMS == 3) ldsm4(al[mb], sAl + off);
                }
            }
            {
                int sub = lane >> 3;
                int kc = ks * 2 + (sub & 1);
                int nr = ((sub >> 1) << 3) + (lane & 7);
                #pragma unroll
                for (int j = 0; j < 4; j++) {
                    int row = wcol + j * 16 + nr;
                    uint32_t off = ASM_OFF(row, kc);
                    ldsm4(bh[j], sBh + off);
                    if (TERMS == 3) ldsm4(bl[j], sBl + off);
                }
            }
            #pragma unroll
            for (int mb = 0; mb < MBN; mb++)
                #pragma unroll
                for (int j = 0; j < 4; j++) {
                    mma16816(acc[mb][2*j],     ah[mb], &bh[j][0]);
                    mma16816(acc[mb][2*j + 1], ah[mb], &bh[j][2]);
                    if (TERMS == 3) {
                        mma16816(acc[mb][2*j],     ah[mb], &bl[j][0]);
                        mma16816(acc[mb][2*j],     al[mb], &bh[j][0]);
                        mma16816(acc[mb][2*j + 1], ah[mb], &bl[j][2]);
                        mma16816(acc[mb][2*j + 1], al[mb], &bh[j][2]);
                    }
                }
        }
        __syncthreads();
        if (c + 2 < nc) loadChunk(c + 2);
    }

    const int r_l = lane >> 2;
    const int c_l = (lane & 3) << 1;
    float* Cz = C;
    if (SPLITK > 1) Cz = C + (size_t)blockIdx.z * NN * N;
    const bool useBias = (SPLITK == 1) || (blockIdx.z == 0);
    #pragma unroll
    for (int mb = 0; mb < MBN; mb++) {
        #pragma unroll
        for (int nb = 0; nb < 8; nb++) {
            int row = m0 + wrow + mb * 16 + r_l;
            int col = n0 + wcol + nb * 8 + c_l;
            float b0 = useBias ? bias[col]     : 0.f;
            float b1 = useBias ? bias[col + 1] : 0.f;
            float v0 = acc[mb][nb][0] + b0;
            float v1 = acc[mb][nb][1] + b1;
            float v2 = acc[mb][nb][2] + b0;
            float v3 = acc[mb][nb][3] + b1;
            if (EPI == 3) {
                v0 = 0.5f * v0 * (1.f + erff(v0 * 0.70710678118654752f));
                v1 = 0.5f * v1 * (1.f + erff(v1 * 0.70710678118654752f));
                v2 = 0.5f * v2 * (1.f + erff(v2 * 0.70710678118654752f));
                v3 = 0.5f * v3 * (1.f + erff(v3 * 0.70710678118654752f));
            }
            if (EPI == 0) {
                *reinterpret_cast<float2*>(Cz + (size_t)row * N + col)       = make_float2(v0, v1);
                *reinterpret_cast<float2*>(Cz + (size_t)(row + 8) * N + col) = make_float2(v2, v3);
            } else if (EPI == 4) {
                *reinterpret_cast<__nv_bfloat162*>(Chi + (size_t)row * N + col)       = __floats2bfloat162_rn(v0, v1);
                *reinterpret_cast<__nv_bfloat162*>(Chi + (size_t)(row + 8) * N + col) = __floats2bfloat162_rn(v2, v3);
            } else {
                __nv_bfloat162 h01 = __floats2bfloat162_rn(v0, v1);
                __nv_bfloat162 h23 = __floats2bfloat162_rn(v2, v3);
                __nv_bfloat162 l01 = __floats2bfloat162_rn(v0 - __bfloat162float(h01.x),
                                                           v1 - __bfloat162float(h01.y));
                __nv_bfloat162 l23 = __floats2bfloat162_rn(v2 - __bfloat162float(h23.x),
                                                           v3 - __bfloat162float(h23.y));
                *reinterpret_cast<__nv_bfloat162*>(Chi + (size_t)row * N + col)       = h01;
                *reinterpret_cast<__nv_bfloat162*>(Chi + (size_t)(row + 8) * N + col) = h23;
                *reinterpret_cast<__nv_bfloat162*>(Clo + (size_t)row * N + col)       = l01;
                *reinterpret_cast<__nv_bfloat162*>(Clo + (size_t)(row + 8) * N + col) = l23;
            }
        }
    }
}

// ============================ tensor-core attention (hi-only S and P·V) ============================
#define AT_QH   0
#define AT_KV   16384
#define AT_KVST 16384
#define AT_BIAS (16384 + 2 * 16384)
#define AT_SMEM (AT_BIAS + 512)
#define NCHUNK  (NN / NSL / 64)

__global__ void __launch_bounds__(128) attn_tc_kernel(
    const __nv_bfloat16* __restrict__ qh,
    const float* __restrict__ pep, float* __restrict__ part, float* __restrict__ plsum)
{
    extern __shared__ char sm[];
    const int h = blockIdx.y, sl = blockIdx.z;
    const int q0 = blockIdx.x * 128;
    const int tid = threadIdx.x, lane = tid & 31, wid = tid >> 5;
    const int wrow = wid * 32;
    const int sub = lane >> 3;
    const uint32_t sb = smem_to_u32(sm);
    float* bias = reinterpret_cast<float*>(sm + AT_BIAS);

    #pragma unroll
    for (int it = 0; it < 8; it++) {
        int idx = it * 128 + tid;
        int row = idx >> 3, ch = idx & 7;
        size_t g = (size_t)(q0 + row) * 1536 + h * 64 + ch * 8;
        CP_ASYNC16(sb + AT_QH + ASM_OFF(row, ch), qh + g);
    }
    {
        const int kk = sl * (NN / NSL);
        uint32_t stb = sb + AT_KV;
        #pragma unroll
        for (int it = 0; it < 4; it++) {
            int idx = it * 128 + tid;
            int row = idx >> 3, ch = idx & 7;
            size_t gk = (size_t)(kk + row) * 1536 + 512 + h * 64 + ch * 8;
            uint32_t off = ASM_OFF(row, ch);
            CP_ASYNC16(stb + off,        qh + gk);
            CP_ASYNC16(stb + 8192 + off, qh + gk + 512);
        }
        if (tid < 64) bias[tid] = pep[(size_t)(kk + tid) * HH + h];
    }
    CP_COMMIT();

    float O[2][8][4];
    float ls[2][2] = {{0.f, 0.f}, {0.f, 0.f}};
    #pragma unroll
    for (int mb = 0; mb < 2; mb++)
        #pragma unroll
        for (int nb = 0; nb < 8; nb++)
            #pragma unroll
            for (int u = 0; u < 4; u++) O[mb][nb][u] = 0.f;

    for (int c = 0; c < NCHUNK; c++) {
        CP_WAIT0();
        __syncthreads();
        if (c < NCHUNK - 1) {
            const int kn = sl * (NN / NSL) + (c + 1) * 64;
            uint32_t stb = sb + AT_KV + (uint32_t)((c + 1) & 1) * AT_KVST;
            #pragma unroll
            for (int it = 0; it < 4; it++) {
                int idx = it * 128 + tid;
                int row = idx >> 3, ch = idx & 7;
                size_t gk = (size_t)(kn + row) * 1536 + 512 + h * 64 + ch * 8;
                uint32_t off = ASM_OFF(row, ch);
                CP_ASYNC16(stb + off,        qh + gk);
                CP_ASYNC16(stb + 8192 + off, qh + gk + 512);
            }
            if (tid < 64) bias[((c + 1) & 1) * 64 + tid] = pep[(size_t)(kn + tid) * HH + h];
            CP_COMMIT();
        }
        const uint32_t stc = sb + AT_KV + (uint32_t)(c & 1) * AT_KVST;
        const uint32_t sKH = stc, sVH = stc + 8192;
        const float* bs = bias + (c & 1) * 64;

        float S[2][8][4];
        #pragma unroll
        for (int mb = 0; mb < 2; mb++)
            #pragma unroll
            for (int nb = 0; nb < 8; nb++)
                #pragma unroll
                for (int u = 0; u < 4; u++) S[mb][nb][u] = 0.f;
        #pragma unroll
        for (int kb = 0; kb < 4; kb++) {
            uint32_t ah[2][4];
            int r16 = (lane & 7) + ((sub & 1) << 3);
            int chA = kb * 2 + (sub >> 1);
            #pragma unroll
            for (int mb = 0; mb < 2; mb++) {
                int row = wrow + mb * 16 + r16;
                ldsm4(ah[mb], sb + AT_QH + ASM_OFF(row, chA));
            }
            int chB = kb * 2 + (sub & 1);
            int nr = ((sub >> 1) << 3) + (lane & 7);
            #pragma unroll
            for (int j = 0; j < 4; j++) {
                uint32_t bh[4];
                int row = j * 16 + nr;
                ldsm4(bh, sKH + ASM_OFF(row, chB));
                #pragma unroll
                for (int mb = 0; mb < 2; mb++) {
                    mma16816(S[mb][2*j],   ah[mb], &bh[0]);
                    mma16816(S[mb][2*j+1], ah[mb], &bh[2]);
                }
            }
        }

        uint32_t Ph[2][8][2];
        #pragma unroll
        for (int mb = 0; mb < 2; mb++)
            #pragma unroll
            for (int nb = 0; nb < 8; nb++) {
                int col = nb * 8 + ((lane & 3) << 1);
                float b0 = bs[col], b1 = bs[col + 1];
                float p0 = __expf(fmaf(S[mb][nb][0], 0.125f, -b0));
                float p1 = __expf(fmaf(S[mb][nb][1], 0.125f, -b1));
                float p2 = __expf(fmaf(S[mb][nb][2], 0.125f, -b0));
                float p3 = __expf(fmaf(S[mb][nb][3], 0.125f, -b1));
                ls[mb][0] += p0 + p1;
                ls[mb][1] += p2 + p3;
                __nv_bfloat162 h01 = __floats2bfloat162_rn(p0, p1);
                __nv_bfloat162 h23 = __floats2bfloat162_rn(p2, p3);
                Ph[mb][nb][0] = *reinterpret_cast<uint32_t*>(&h01);
                Ph[mb][nb][1] = *reinterpret_cast<uint32_t*>(&h23);
            }

        #pragma unroll
        for (int kb2 = 0; kb2 < 4; kb2++) {
            int krow = kb2 * 16 + ((sub & 1) << 3) + (lane & 7);
            #pragma unroll
            for (int dI = 0; dI < 4; dI++) {
                uint32_t vh[4];
                int ch = dI * 2 + (sub >> 1);
                ldsm4t(vh, sVH + ASM_OFF(krow, ch));
                #pragma unroll
                for (int mb = 0; mb < 2; mb++) {
                    uint32_t pa[4] = {Ph[mb][2*kb2][0], Ph[mb][2*kb2][1],
                                      Ph[mb][2*kb2+1][0], Ph[mb][2*kb2+1][1]};
                    mma16816(O[mb][2*dI],   pa, &vh[0]);
                    mma16816(O[mb][2*dI+1], pa, &vh[2]);
                }
            }
        }
    }

    #pragma unroll
    for (int mb = 0; mb < 2; mb++)
        #pragma unroll
        for (int r = 0; r < 2; r++) {
            float v = ls[mb][r];
            v += __shfl_xor_sync(0xffffffffu, v, 1);
            v += __shfl_xor_sync(0xffffffffu, v, 2);
            ls[mb][r] = v;
        }
    const size_t base = (size_t)(sl * HH + h) * NN;
    #pragma unroll
    for (int mb = 0; mb < 2; mb++) {
        int rowA = q0 + wrow + mb * 16 + (lane >> 2);
        int rowB = rowA + 8;
        if ((lane & 3) == 0) {
            plsum[base + rowA] = ls[mb][0];
            plsum[base + rowB] = ls[mb][1];
        }
        #pragma unroll
        for (int nb = 0; nb < 8; nb++) {
            int col = nb * 8 + ((lane & 3) << 1);
            *reinterpret_cast<float2*>(part + (base + rowA) * 64 + col) = make_float2(O[mb][nb][0], O[mb][nb][1]);
            *reinterpret_cast<float2*>(part + (base + rowB) * 64 + col) = make_float2(O[mb][nb][2], O[mb][nb][3]);
        }
    }
}

// combine writes hi only (out-proj is TERMS=1 and reads only Ahi)
__global__ void __launch_bounds__(512) attn_combine_kernel(const float* __restrict__ part, const float* __restrict__ pls,
                                                           __nv_bfloat16* __restrict__ ohi) {
    int i = blockIdx.x, idx = threadIdx.x;
    int h = idx >> 6, d = idx & 63;
    float v = 0.f, l = 0.f;
    #pragma unroll
    for (int s = 0; s < NSL; s++) {
        l += pls[(size_t)(s * HH + h) * NN + i];
        v += part[((size_t)(s * HH + h) * NN + i) * 64 + d];
    }
    ohi[(size_t)i * DD + idx] = __float2bfloat16_rn(v / l);
}

// ============================ LN over (a + p0 + p1) -> fp32 out + bf16 hi/lo ============================
__global__ void ln3_kernel(const float* __restrict__ a, const float* __restrict__ b,
                           const float* __restrict__ b2,
                           const float* __restrict__ g, const float* __restrict__ be,
                           float* __restrict__ out,
                           __nv_bfloat16* __restrict__ ohi, __nv_bfloat16* __restrict__ olo) {
    __shared__ float wsum[8];
    __shared__ float s_mu, s_r;
    int i = blockIdx.x, t = threadIdx.x;
    int lane = t & 31, wid = t >> 5;
    float v0 = a[(size_t)i * DD + t]       + b[(size_t)i * DD + t]       + b2[(size_t)i * DD + t];
    float v1 = a[(size_t)i * DD + 256 + t] + b[(size_t)i * DD + 256 + t] + b2[(size_t)i * DD + 256 + t];
    float s = v0 + v1;
    #pragma unroll
    for (int o = 16; o > 0; o >>= 1) s += __shfl_xor_sync(0xffffffffu, s, o);
    if (lane == 0) wsum[wid] = s;
    __syncthreads();
    if (t < 8) {
        float w = wsum[t];
        #pragma unroll
        for (int o = 4; o > 0; o >>= 1) w += __shfl_xor_sync(0xffu, w, o);
        if (t == 0) s_mu = w * (1.f / DD);
    }
    __syncthreads();
    float mu = s_mu;
    float d0 = v0 - mu, d1 = v1 - mu;
    float q = d0 * d0 + d1 * d1;
    #pragma unroll
    for (int o = 16; o > 0; o >>= 1) q += __shfl_xor_sync(0xffffffffu, q, o);
    if (lane == 0) wsum[wid] = q;
    __syncthreads();
    if (t < 8) {
        float w = wsum[t];
        #pragma unroll
        for (int o = 4; o > 0; o >>= 1) w += __shfl_xor_sync(0xffu, w, o);
        if (t == 0) s_r = rsqrtf(w * (1.f / DD) + 1e-5f);
    }
    __syncthreads();
    float r = s_r;
    float o0 = d0 * r * g[t]       + be[t];
    float o1 = d1 * r * g[256 + t] + be[256 + t];
    out[(size_t)i * DD + t]       = o0;
    out[(size_t)i * DD + 256 + t] = o1;
    __nv_bfloat16 h0 = __float2bfloat16_rn(o0);
    __nv_bfloat16 h1 = __float2bfloat16_rn(o1);
    ohi[(size_t)i * DD + t]       = h0;
    ohi[(size_t)i * DD + 256 + t] = h1;
    olo[(size_t)i * DD + t]       = __float2bfloat16_rn(o0 - __bfloat162float(h0));
    olo[(size_t)i * DD + 256 + t] = __float2bfloat16_rn(o1 - __bfloat162float(h1));
}

// ============================ launch ============================
extern "C" void kernel_launch(void* const* d_in, const int* in_sizes, int n_in,
                              void* d_out, int out_size) {
    const float* node_features = (const float*)d_in[0];
    const int*   edge_index    = (const int*)  d_in[1];
    const float* pe_proj_W     = (const float*)d_in[2];
    const float* pe_proj_b     = (const float*)d_in[3];
    const float* qkv_W         = (const float*)d_in[4];
    const float* qkv_b         = (const float*)d_in[5];
    const float* peb_W         = (const float*)d_in[6];
    const float* peb_b         = (const float*)d_in[7];
    const float* out_W         = (const float*)d_in[8];
    const float* out_b         = (const float*)d_in[9];
    const float* ffn_W1        = (const float*)d_in[10];
    const float* ffn_b1        = (const float*)d_in[11];
    const float* ffn_W2        = (const float*)d_in[12];
    const float* ffn_b2        = (const float*)d_in[13];
    const float* ln1_g         = (const float*)d_in[14];
    const float* ln1_b         = (const float*)d_in[15];
    const float* ln2_g         = (const float*)d_in[16];
    const float* ln2_b         = (const float*)d_in[17];
    float* outp = (float*)d_out;

    float *x_, *x1_, *o_, *pep_, *part_, *pls_;
    __nv_bfloat16 *Ahi_, *Alo_, *Hhi_, *Hlo_, *Qh_, *T2b_, *T3b_;
    __nv_bfloat16 *qWh_, *oWh_, *f1h_, *f1l_, *f2h_, *f2l_;
    cudaGetSymbolAddress((void**)&x_,   g_x);
    cudaGetSymbolAddress((void**)&x1_,  g_x1);
    cudaGetSymbolAddress((void**)&o_,   g_o);
    cudaGetSymbolAddress((void**)&pep_, g_pep);
    cudaGetSymbolAddress((void**)&part_,g_part);
    cudaGetSymbolAddress((void**)&pls_, g_plsum);
    cudaGetSymbolAddress((void**)&Ahi_, g_Ahi);
    cudaGetSymbolAddress((void**)&Alo_, g_Alo);
    cudaGetSymbolAddress((void**)&Hhi_, g_Hhi);
    cudaGetSymbolAddress((void**)&Hlo_, g_Hlo);
    cudaGetSymbolAddress((void**)&Qh_,  g_QKVhi);
    cudaGetSymbolAddress((void**)&T2b_, g_T2b);
    cudaGetSymbolAddress((void**)&T3b_, g_T3b);
    cudaGetSymbolAddress((void**)&qWh_, g_qkvW_hi);
    cudaGetSymbolAddress((void**)&oWh_, g_outW_hi);
    cudaGetSymbolAddress((void**)&f1h_, g_f1W_hi);
    cudaGetSymbolAddress((void**)&f1l_, g_f1W_lo);
    cudaGetSymbolAddress((void**)&f2h_, g_f2W_hi);
    cudaGetSymbolAddress((void**)&f2l_, g_f2W_lo);

    constexpr int GS64 = 2 * (2 * 64 * 128 + 32768);   // 96 KB (3-term)
    constexpr int GS1  = 2 * (64 * 128 + 16384);       // 48 KB (1-term) -> 4 CTA/SM
    cudaFuncSetAttribute((const void*)mma_gemm_kernel<4,64,1,1>, cudaFuncAttributeMaxDynamicSharedMemorySize, GS1);
    cudaFuncSetAttribute((const void*)mma_gemm_kernel<0,64,2,1>, cudaFuncAttributeMaxDynamicSharedMemorySize, GS1);
    cudaFuncSetAttribute((const void*)mma_gemm_kernel<3,64,1,3>, cudaFuncAttributeMaxDynamicSharedMemorySize, GS64);
    cudaFuncSetAttribute((const void*)mma_gemm_kernel<0,64,2,3>, cudaFuncAttributeMaxDynamicSharedMemorySize, GS64);
    cudaFuncSetAttribute(attn_tc_kernel, cudaFuncAttributeMaxDynamicSharedMemorySize, AT_SMEM);

    static cudaStream_t s_side = nullptr;
    static cudaEvent_t  ev_fork = nullptr, ev_pe = nullptr;
    if (s_side == nullptr) {
        cudaStreamCreateWithFlags(&s_side, cudaStreamNonBlocking);
        cudaEventCreateWithFlags(&ev_fork, cudaEventDisableTiming);
        cudaEventCreateWithFlags(&ev_pe,   cudaEventDisableTiming);
    }

    // ---- fork: PE pipeline on side stream ----
    cudaEventRecord(ev_fork, 0);
    cudaStreamWaitEvent(s_side, ev_fork, 0);
    zero_bm_kernel<<<(NN*64)/256, 256, 0, s_side>>>();
    scatter_bm_kernel<<<EEC/256, 256, 0, s_side>>>(edge_index);
    build_bm_kernel<<<NN, 64, 0, s_side>>>();
    t2_kernel<<<NN, 256, 0, s_side>>>();
    spmm_bf_kernel<<<NN, 256, 0, s_side>>>(T2b_, T3b_);
    spmm_diag_kernel<<<NN, 256, 0, s_side>>>();
    pe_kernel<<<(NN + 127) / 128, 128, 0, s_side>>>(pe_proj_W, pe_proj_b);
    pep_kernel<<<(NN + 127) / 128, 128, 0, s_side>>>(peb_W, peb_b);
    cudaEventRecord(ev_pe, s_side);

    // ---- main stream: only qkv prerequisites before the first GEMM ----
    convW_hi_kernel<<<dim3(1536/32, 512/32, LLC), dim3(32,8)>>>(qkv_W, qWh_, DD, 3*DD);
    split_copy_kernel<<<(NN*DD)/256, 256>>>(node_features);

    float* o2_ = o_ + (size_t)NN * DD;
    for (int l = 0; l < LLC; l++) {
        mma_gemm_kernel<4,64,1,1><<<dim3(1536/128, NN/64), 256, GS1>>>(
            Ahi_, Alo_, qWh_ + (size_t)l*3*DD*DD, nullptr,
            qkv_b + (size_t)l*3*DD, nullptr, Qh_, nullptr, 3*DD, DD);
        if (l == 0) {
            convW_hi_kernel<<<dim3(512/32, 512/32, LLC), dim3(32,8)>>>(out_W, oWh_, DD, DD);
            convW_kernel<<<dim3(2048/32, 512/32, LLC),  dim3(32,8)>>>(ffn_W1, f1h_, f1l_, DD,  DFFC);
            convW_kernel<<<dim3(512/32,  2048/32, LLC), dim3(32,8)>>>(ffn_W2, f2h_, f2l_, DFFC, DD);
            cudaStreamWaitEvent(0, ev_pe, 0);   // join: attention needs pep
        }
        attn_tc_kernel<<<dim3(NN/128, HH, NSL), 128, AT_SMEM>>>(Qh_, pep_ + (size_t)l*NN*HH, part_, pls_);
        attn_combine_kernel<<<NN, 512>>>(part_, pls_, Ahi_);
        // out-proj: hi-only (attention branch carries ~0.45% of residual -> error ~5e-6)
        mma_gemm_kernel<0,64,2,1><<<dim3(DD/128, NN/64, 2), 256, GS1>>>(
            Ahi_, nullptr, oWh_ + (size_t)l*DD*DD, nullptr,
            out_b + (size_t)l*DD, o_, nullptr, nullptr, DD, DD);
        const float* resid1 = (l == 0) ? node_features : x_;
        ln3_kernel<<<NN, 256>>>(resid1, o_, o2_, ln1_g + (size_t)l*DD, ln1_b + (size_t)l*DD, x1_, Ahi_, Alo_);
        mma_gemm_kernel<3,64,1,3><<<dim3(DFFC/128, NN/64), 256, GS64>>>(
            Ahi_, Alo_, f1h_ + (size_t)l*DD*DFFC, f1l_ + (size_t)l*DD*DFFC,
            ffn_b1 + (size_t)l*DFFC, nullptr, Hhi_, Hlo_, DFFC, DD);
        mma_gemm_kernel<0,64,2,3><<<dim3(DD/128, NN/64, 2), 256, GS64>>>(
            Hhi_, Hlo_, f2h_ + (size_t)l*DFFC*DD, f2l_ + (size_t)l*DFFC*DD,
            ffn_b2 + (size_t)l*DD, o_, nullptr, nullptr, DD, DFFC);
        float* xout = (l == LLC - 1) ? outp : x_;
        ln3_kernel<<<NN, 256>>>(x1_, o_, o2_, ln2_g + (size_t)l*DD, ln2_b + (size_t)l*DD, xout, Ahi_, Alo_);
    }
}